// round 1
// baseline (speedup 1.0000x reference)
#include <cuda_runtime.h>
#include <math.h>

#define Nn    4096
#define GENE  512
#define HID   256
#define OUTD  256
#define KBIG  768   // HID + GENE (fused QK + cosine-sim GEMM depth)

// ---------------- scratch (static device globals; no allocs) ----------------
__device__ float g_L[(size_t)Nn * Nn];     // logits, then normalized A (64 MB)
__device__ float g_Y[(size_t)Nn * KBIG];   // [Q/dk | xn] rows
__device__ float g_Z[(size_t)Nn * KBIG];   // [K    | xn] rows
__device__ float g_V[(size_t)Nn * OUTD];
__device__ float g_f[Nn];
__device__ float g_sq[Nn];

// ---------------- prep: row-normalize gene_expr, compute sq ----------------
__global__ void prep_kernel(const float* __restrict__ gene,
                            const float* __restrict__ sp) {
    int row = blockIdx.x;
    const float* x = gene + (size_t)row * GENE;
    __shared__ float red[256];
    float ss = 0.f;
    for (int c = threadIdx.x; c < GENE; c += 256) { float v = x[c]; ss += v * v; }
    red[threadIdx.x] = ss; __syncthreads();
    for (int s = 128; s > 0; s >>= 1) {
        if (threadIdx.x < s) red[threadIdx.x] += red[threadIdx.x + s];
        __syncthreads();
    }
    float inv = 1.0f / fmaxf(sqrtf(red[0]), 1e-12f);
    for (int c = threadIdx.x; c < GENE; c += 256) {
        float v = x[c] * inv;
        g_Y[(size_t)row * KBIG + HID + c] = v;
        g_Z[(size_t)row * KBIG + HID + c] = v;
    }
    if (threadIdx.x == 0) {
        float a = sp[2 * row], b = sp[2 * row + 1];
        g_sq[row] = a * a + b * b;
    }
}

// ---------------- small MLP -> scalar f per node ----------------
__global__ void mlp_kernel(const float* __restrict__ sp,
                           const float* __restrict__ Ws, const float* __restrict__ bs,
                           const float* __restrict__ W1, const float* __restrict__ b1,
                           const float* __restrict__ W2, const float* __restrict__ b2,
                           const float* __restrict__ Wf, const float* __restrict__ bf) {
    int row = blockIdx.x;
    int h = threadIdx.x;
    __shared__ float si[HID];
    __shared__ float h1[HID];
    __shared__ float red[HID];
    float a = sp[2 * row], b = sp[2 * row + 1];
    si[h] = a * Ws[h] + b * Ws[HID + h] + bs[h];
    __syncthreads();
    float acc = b1[h];
    #pragma unroll 8
    for (int k = 0; k < HID; k++) acc += si[k] * W1[k * HID + h];
    h1[h] = tanhf(acc);
    __syncthreads();
    acc = b2[h];
    #pragma unroll 8
    for (int k = 0; k < HID; k++) acc += h1[k] * W2[k * HID + h];
    float e = fmaxf(acc, 0.f);
    red[h] = e * Wf[h];
    __syncthreads();
    for (int s = 128; s > 0; s >>= 1) {
        if (h < s) red[h] += red[h + s];
        __syncthreads();
    }
    if (h == 0) g_f[row] = red[0] + bf[0];
}

// ---------------- generic tiled SGEMM: C = alpha*(A@B + bias) ----------------
// 64x64 tile, BK=16, 256 threads, 4x4 register micro-tile. All dims divisible.
#define BM 64
#define BN 64
#define BK 16
__global__ void gemm_bias_kernel(const float* __restrict__ A, int lda,
                                 const float* __restrict__ B, int ldb,
                                 float* __restrict__ C, int ldc,
                                 const float* __restrict__ bias,
                                 int K, float alpha) {
    __shared__ float As[BK][BM];
    __shared__ float Bs[BK][BN];
    int tid = threadIdx.x;
    int tx = tid % 16, ty = tid / 16;
    const float* Ab = A + (size_t)blockIdx.y * BM * lda;
    const float* Bb = B + blockIdx.x * BN;
    float acc[4][4] = {};
    for (int k0 = 0; k0 < K; k0 += BK) {
        for (int i = tid; i < BM * BK; i += 256) {
            int m = i / BK, kk = i % BK;
            As[kk][m] = Ab[(size_t)m * lda + k0 + kk];
        }
        for (int i = tid; i < BK * BN; i += 256) {
            int kk = i / BN, n = i % BN;
            Bs[kk][n] = Bb[(size_t)(k0 + kk) * ldb + n];
        }
        __syncthreads();
        #pragma unroll
        for (int kk = 0; kk < BK; kk++) {
            float a[4], b[4];
            #pragma unroll
            for (int m = 0; m < 4; m++) a[m] = As[kk][ty * 4 + m];
            #pragma unroll
            for (int n = 0; n < 4; n++) b[n] = Bs[kk][tx * 4 + n];
            #pragma unroll
            for (int m = 0; m < 4; m++)
                #pragma unroll
                for (int n = 0; n < 4; n++)
                    acc[m][n] += a[m] * b[n];
        }
        __syncthreads();
    }
    #pragma unroll
    for (int m = 0; m < 4; m++) {
        int gm = blockIdx.y * BM + ty * 4 + m;
        #pragma unroll
        for (int n = 0; n < 4; n++) {
            int gn = blockIdx.x * BN + tx * 4 + n;
            float v = acc[m][n];
            if (bias) v += bias[gn];
            C[(size_t)gm * ldc + gn] = alpha * v;
        }
    }
}

// ---------------- logits GEMM (K=768) with spatial epilogue ----------------
__global__ void logits_kernel(const float* __restrict__ sp) {
    __shared__ float As[BK][BM];
    __shared__ float Bs[BK][BN];
    int tid = threadIdx.x;
    int tx = tid % 16, ty = tid / 16;
    const float* Ab = g_Y + (size_t)blockIdx.y * BM * KBIG;
    const float* Bb = g_Z + (size_t)blockIdx.x * BN * KBIG;
    float acc[4][4] = {};
    for (int k0 = 0; k0 < KBIG; k0 += BK) {
        for (int i = tid; i < BM * BK; i += 256) {
            int m = i / BK, kk = i % BK;
            As[kk][m] = Ab[(size_t)m * KBIG + k0 + kk];
        }
        // B side is also row-major [N, KBIG]; we need Z_j dot Y_i -> load transposed
        for (int i = tid; i < BN * BK; i += 256) {
            int n = i / BK, kk = i % BK;
            Bs[kk][n] = Bb[(size_t)n * KBIG + k0 + kk];
        }
        __syncthreads();
        #pragma unroll
        for (int kk = 0; kk < BK; kk++) {
            float a[4], b[4];
            #pragma unroll
            for (int m = 0; m < 4; m++) a[m] = As[kk][ty * 4 + m];
            #pragma unroll
            for (int n = 0; n < 4; n++) b[n] = Bs[kk][tx * 4 + n];
            #pragma unroll
            for (int m = 0; m < 4; m++)
                #pragma unroll
                for (int n = 0; n < 4; n++)
                    acc[m][n] += a[m] * b[n];
        }
        __syncthreads();
    }
    #pragma unroll
    for (int m = 0; m < 4; m++) {
        int gm = blockIdx.y * BM + ty * 4 + m;
        float spa0 = sp[2 * gm], spa1 = sp[2 * gm + 1];
        float sqi = g_sq[gm], fi = g_f[gm];
        #pragma unroll
        for (int n = 0; n < 4; n++) {
            int gn = blockIdx.x * BN + tx * 4 + n;
            float spb0 = sp[2 * gn], spb1 = sp[2 * gn + 1];
            float d2 = sqi + g_sq[gn] - 2.0f * (spa0 * spb0 + spa1 * spb1);
            d2 = fmaxf(d2, 0.0f);
            float v = acc[m][n] + expf(-0.5f * d2) + tanhf(fi - g_f[gn]);
            g_L[(size_t)gm * Nn + gn] = v;
        }
    }
}

// ---------------- row softmax; writes A to g_L (in place) and d_out ----------------
__global__ void softmax_kernel(float* __restrict__ attn_out, int write_out) {
    int row = blockIdx.x;
    float* L = g_L + (size_t)row * Nn;
    __shared__ float red[256];
    float m = -1e30f;
    for (int j = threadIdx.x; j < Nn; j += 256) m = fmaxf(m, L[j]);
    red[threadIdx.x] = m; __syncthreads();
    for (int s = 128; s > 0; s >>= 1) {
        if (threadIdx.x < s) red[threadIdx.x] = fmaxf(red[threadIdx.x], red[threadIdx.x + s]);
        __syncthreads();
    }
    float rowm = red[0];
    __syncthreads();
    float sum = 0.f;
    for (int j = threadIdx.x; j < Nn; j += 256) sum += expf(L[j] - rowm);
    red[threadIdx.x] = sum; __syncthreads();
    for (int s = 128; s > 0; s >>= 1) {
        if (threadIdx.x < s) red[threadIdx.x] += red[threadIdx.x + s];
        __syncthreads();
    }
    float inv = 1.0f / red[0];
    for (int j = threadIdx.x; j < Nn; j += 256) {
        float a = expf(L[j] - rowm) * inv;
        L[j] = a;
        if (write_out) attn_out[(size_t)row * Nn + j] = a;
    }
}

// ---------------- launch ----------------
extern "C" void kernel_launch(void* const* d_in, const int* in_sizes, int n_in,
                              void* d_out, int out_size) {
    const float* gene = (const float*)d_in[0];
    const float* sp   = (const float*)d_in[1];
    const float* Wq   = (const float*)d_in[2];
    const float* bq   = (const float*)d_in[3];
    const float* Wk   = (const float*)d_in[4];
    const float* bk   = (const float*)d_in[5];
    const float* Wv   = (const float*)d_in[6];
    const float* bv   = (const float*)d_in[7];
    const float* Ws   = (const float*)d_in[8];
    const float* bs   = (const float*)d_in[9];
    const float* W1   = (const float*)d_in[10];
    const float* b1   = (const float*)d_in[11];
    const float* W2   = (const float*)d_in[12];
    const float* b2   = (const float*)d_in[13];
    const float* Wf   = (const float*)d_in[14];
    const float* bf   = (const float*)d_in[15];

    float* out = (float*)d_out;
    long long total = (long long)Nn * Nn + (long long)Nn * OUTD;
    int has_attn = ((long long)out_size >= total) ? 1 : 0;
    float* attn = out;
    float* upd  = has_attn ? out + (size_t)Nn * Nn : out;

    float *pY = nullptr, *pZ = nullptr, *pV = nullptr, *pL = nullptr;
    cudaGetSymbolAddress((void**)&pY, g_Y);
    cudaGetSymbolAddress((void**)&pZ, g_Z);
    cudaGetSymbolAddress((void**)&pV, g_V);
    cudaGetSymbolAddress((void**)&pL, g_L);

    // 1) normalize gene rows + sq
    prep_kernel<<<Nn, 256>>>(gene, sp);

    // 2) Q (scaled 1/sqrt(H)=1/16) -> g_Y[:, :256], K -> g_Z[:, :256], V -> g_V
    dim3 gQKV(HID / BN, Nn / BM);
    gemm_bias_kernel<<<gQKV, 256>>>(gene, GENE, Wq, HID, pY, KBIG, bq, GENE, 1.0f / 16.0f);
    gemm_bias_kernel<<<gQKV, 256>>>(gene, GENE, Wk, HID, pZ, KBIG, bk, GENE, 1.0f);
    gemm_bias_kernel<<<gQKV, 256>>>(gene, GENE, Wv, OUTD, pV, OUTD, bv, GENE, 1.0f);

    // 3) per-node MLP scalar f
    mlp_kernel<<<Nn, 256>>>(sp, Ws, bs, W1, b1, W2, b2, Wf, bf);

    // 4) fused logits GEMM (QK/dk + cosine sim) + spatial epilogue
    dim3 gL(Nn / BN, Nn / BM);
    logits_kernel<<<gL, 256>>>(sp);

    // 5) row softmax -> A (in g_L and d_out)
    softmax_kernel<<<Nn, 256>>>(attn, has_attn);

    // 6) updated = A @ V
    dim3 gAV(OUTD / BN, Nn / BM);
    gemm_bias_kernel<<<gAV, 256>>>(pL, Nn, pV, OUTD, upd, OUTD, nullptr, Nn, 1.0f);
}

// round 3
// speedup vs baseline: 2.6366x; 2.6366x over previous
#include <cuda_runtime.h>
#include <cuda_bf16.h>
#include <math.h>
#include <stdint.h>

#define Nn    4096
#define GENE  512
#define HID   256
#define OUTD  256
#define YK    768     // HID + GENE fused logits depth (per segment)

typedef __nv_bfloat16 bf16;

// ---------------- scratch (static device globals; no runtime allocs) ----------------
__device__ __align__(16) float g_L[(size_t)Nn * Nn];      // logits
__device__ __align__(16) float g_Qf[Nn * HID];
__device__ __align__(16) float g_Kf[Nn * HID];
__device__ __align__(16) bf16  g_Ghi[Nn * GENE];
__device__ __align__(16) bf16  g_Glo[Nn * GENE];
__device__ __align__(16) bf16  g_Yhi[Nn * YK];
__device__ __align__(16) bf16  g_Ylo[Nn * YK];
__device__ __align__(16) bf16  g_Zhi[Nn * YK];
__device__ __align__(16) bf16  g_Zlo[Nn * YK];
__device__ __align__(16) bf16  g_Ahi[(size_t)Nn * Nn];
__device__ __align__(16) bf16  g_Alo[(size_t)Nn * Nn];
__device__ __align__(16) bf16  g_Vthi[OUTD * Nn];
__device__ __align__(16) bf16  g_Vtlo[OUTD * Nn];
__device__ __align__(16) bf16  g_Wthi[3 * HID * GENE];    // W^T splits (q,k,v)
__device__ __align__(16) bf16  g_Wtlo[3 * HID * GENE];
__device__ float g_f[Nn];
__device__ float g_sq[Nn];

// ---------------- PTX helpers (sm_80+ baseline; NO tcgen05) ----------------
__device__ __forceinline__ uint32_t s2u(const void* p) {
    uint32_t a;
    asm("{ .reg .u64 t; cvta.to.shared.u64 t, %1; cvt.u32.u64 %0, t; }" : "=r"(a) : "l"(p));
    return a;
}
__device__ __forceinline__ void cp16(uint32_t dst, const void* src) {
    asm volatile("cp.async.cg.shared.global [%0], [%1], 16;" :: "r"(dst), "l"(src));
}
__device__ __forceinline__ void cp_commit() {
    asm volatile("cp.async.commit_group;" ::: "memory");
}
template <int N>
__device__ __forceinline__ void cp_wait() {
    asm volatile("cp.async.wait_group %0;" :: "n"(N) : "memory");
}
__device__ __forceinline__ void ldm4(uint32_t* r, uint32_t addr) {
    asm volatile("ldmatrix.sync.aligned.m8n8.x4.shared.b16 {%0,%1,%2,%3}, [%4];"
                 : "=r"(r[0]), "=r"(r[1]), "=r"(r[2]), "=r"(r[3]) : "r"(addr));
}
__device__ __forceinline__ void mma_bf16(float* d, const uint32_t* a, uint32_t b0, uint32_t b1) {
    asm volatile(
        "mma.sync.aligned.m16n8k16.row.col.f32.bf16.bf16.f32 "
        "{%0,%1,%2,%3}, {%4,%5,%6,%7}, {%8,%9}, {%0,%1,%2,%3};"
        : "+f"(d[0]), "+f"(d[1]), "+f"(d[2]), "+f"(d[3])
        : "r"(a[0]), "r"(a[1]), "r"(a[2]), "r"(a[3]), "r"(b0), "r"(b1));
}

// ---------------- prep: gene splits + normalized-row splits + sq ----------------
__global__ __launch_bounds__(256) void prep_kernel(const float* __restrict__ gene,
                                                   const float* __restrict__ sp) {
    int row = blockIdx.x;
    const float* x = gene + (size_t)row * GENE;
    __shared__ float red[256];
    float ss = 0.f;
    for (int c = threadIdx.x; c < GENE; c += 256) { float v = x[c]; ss += v * v; }
    red[threadIdx.x] = ss; __syncthreads();
    for (int s = 128; s > 0; s >>= 1) {
        if (threadIdx.x < s) red[threadIdx.x] += red[threadIdx.x + s];
        __syncthreads();
    }
    float inv = 1.0f / fmaxf(sqrtf(red[0]), 1e-12f);
    for (int c = threadIdx.x; c < GENE; c += 256) {
        float v = x[c];
        bf16 gh = __float2bfloat16(v);
        g_Ghi[(size_t)row * GENE + c] = gh;
        g_Glo[(size_t)row * GENE + c] = __float2bfloat16(v - __bfloat162float(gh));
        float xn = v * inv;
        bf16 xh = __float2bfloat16(xn);
        bf16 xl = __float2bfloat16(xn - __bfloat162float(xh));
        size_t o = (size_t)row * YK + HID + c;
        g_Yhi[o] = xh; g_Ylo[o] = xl;
        g_Zhi[o] = xh; g_Zlo[o] = xl;
    }
    if (threadIdx.x == 0) {
        float a = sp[2 * row], b = sp[2 * row + 1];
        g_sq[row] = a * a + b * b;
    }
}

// ---------------- weight transpose + split: W[GENE,HID] -> Wt hi/lo [HID,GENE] ----------------
__global__ __launch_bounds__(256) void wsplit_kernel(const float* __restrict__ W,
                                                     bf16* __restrict__ Thi,
                                                     bf16* __restrict__ Tlo) {
    int idx = blockIdx.x * 256 + threadIdx.x;
    if (idx >= HID * GENE) return;
    int n = idx / GENE, k = idx % GENE;
    float v = W[(size_t)k * HID + n];
    bf16 h = __float2bfloat16(v);
    Thi[idx] = h;
    Tlo[idx] = __float2bfloat16(v - __bfloat162float(h));
}

// ---------------- split fp32 [Nn,HID] into Y/Z cols 0..255 ----------------
__global__ __launch_bounds__(256) void splitqk_kernel(const float* __restrict__ S,
                                                      bf16* __restrict__ Dhi,
                                                      bf16* __restrict__ Dlo) {
    int idx = blockIdx.x * 256 + threadIdx.x;
    int m = idx >> 8, c = idx & 255;
    float v = S[idx];
    bf16 h = __float2bfloat16(v);
    Dhi[(size_t)m * YK + c] = h;
    Dlo[(size_t)m * YK + c] = __float2bfloat16(v - __bfloat162float(h));
}

// ---------------- small MLP -> scalar f per node ----------------
__global__ __launch_bounds__(256) void mlp_kernel(const float* __restrict__ sp,
                           const float* __restrict__ Ws, const float* __restrict__ bs,
                           const float* __restrict__ W1, const float* __restrict__ b1,
                           const float* __restrict__ W2, const float* __restrict__ b2,
                           const float* __restrict__ Wf, const float* __restrict__ bf_) {
    int row = blockIdx.x;
    int h = threadIdx.x;
    __shared__ float si[HID];
    __shared__ float h1[HID];
    __shared__ float red[HID];
    float a = sp[2 * row], b = sp[2 * row + 1];
    si[h] = a * Ws[h] + b * Ws[HID + h] + bs[h];
    __syncthreads();
    float acc = b1[h];
    #pragma unroll 8
    for (int k = 0; k < HID; k++) acc += si[k] * W1[k * HID + h];
    h1[h] = tanhf(acc);
    __syncthreads();
    acc = b2[h];
    #pragma unroll 8
    for (int k = 0; k < HID; k++) acc += h1[k] * W2[k * HID + h];
    float e = fmaxf(acc, 0.f);
    red[h] = e * Wf[h];
    __syncthreads();
    for (int s = 128; s > 0; s >>= 1) {
        if (h < s) red[h] += red[h + s];
        __syncthreads();
    }
    if (h == 0) g_f[row] = red[0] + bf_[0];
}

// ---------------- HMMA split-bf16 GEMM ----------------
// acc[m][n] = sum over 3 segments: Ahi*Bhi + Alo*Bhi + Ahi*Blo  (each [*,segK] row-major)
// MODE 0: C[m][n] = (acc + bias[n]) * alpha  (fp32, pitch ldc)
// MODE 1: logits epilogue -> g_L
// MODE 2: transpose-split -> Thi/Tlo[n][m] of (acc + bias[n])
#define BM 128
#define BN 128
#define BK 32
#define ROWB 80                      // padded bytes per smem row (32 bf16 + 16B pad)
#define TILEB (BM * ROWB)            // 10240
#define STAGEB (2 * TILEB)           // 20480 (A tile + B tile)

template <int MODE>
__global__ __launch_bounds__(256) void hmma_gemm(
    const bf16* __restrict__ Ahi_, const bf16* __restrict__ Alo_,
    const bf16* __restrict__ Bhi_, const bf16* __restrict__ Blo_,
    int segK, int nchunks,
    float* __restrict__ C, int ldc, const float* __restrict__ bias, float alpha,
    const float* __restrict__ sp,
    bf16* __restrict__ Thi, bf16* __restrict__ Tlo)
{
    __shared__ __align__(16) char smem[2 * STAGEB];   // 40 KB
    const uint32_t sbase = s2u(smem);
    const int tid  = threadIdx.x;
    const int lane = tid & 31;
    const int wid  = tid >> 5;
    const int wm   = (wid & 3) * 32;     // warp m offset
    const int wn   = (wid >> 2) * 64;    // warp n offset
    const int gm0  = blockIdx.y * BM;
    const int gn0  = blockIdx.x * BN;

    // ldmatrix per-lane addressing: matrix idx mi = lane/8
    const int mi    = lane >> 3;
    const int ldrow = ((mi & 1) << 3) + (lane & 7);
    const int ldcol = (mi >> 1) << 4;    // byte offset (0 or 16)

    // cp.async per-thread slot
    const int crow = tid >> 2;           // 0..63
    const int cch  = tid & 3;            // 16B chunk in row

    float acc[2][8][4];
    #pragma unroll
    for (int a = 0; a < 2; a++)
        #pragma unroll
        for (int b = 0; b < 8; b++)
            #pragma unroll
            for (int c = 0; c < 4; c++) acc[a][b][c] = 0.f;

    // ---- prologue load chunk 0 ----
    {
        const bf16* As = Ahi_;
        const bf16* Bs = Bhi_;
        uint32_t dst = sbase;
        cp16(dst + crow * ROWB + cch * 16,          As + (size_t)(gm0 + crow) * segK + cch * 8);
        cp16(dst + (crow + 64) * ROWB + cch * 16,   As + (size_t)(gm0 + crow + 64) * segK + cch * 8);
        cp16(dst + TILEB + crow * ROWB + cch * 16,        Bs + (size_t)(gn0 + crow) * segK + cch * 8);
        cp16(dst + TILEB + (crow + 64) * ROWB + cch * 16, Bs + (size_t)(gn0 + crow + 64) * segK + cch * 8);
        cp_commit();
    }

    for (int c = 0; c < nchunks; c++) {
        if (c + 1 < nchunks) {
            int kg = (c + 1) * BK;
            int seg = kg / segK;
            int kk = kg - seg * segK;
            const bf16* As = (seg == 1) ? Alo_ : Ahi_;
            const bf16* Bs = (seg == 2) ? Blo_ : Bhi_;
            uint32_t dst = sbase + ((c + 1) & 1) * STAGEB;
            cp16(dst + crow * ROWB + cch * 16,          As + (size_t)(gm0 + crow) * segK + kk + cch * 8);
            cp16(dst + (crow + 64) * ROWB + cch * 16,   As + (size_t)(gm0 + crow + 64) * segK + kk + cch * 8);
            cp16(dst + TILEB + crow * ROWB + cch * 16,        Bs + (size_t)(gn0 + crow) * segK + kk + cch * 8);
            cp16(dst + TILEB + (crow + 64) * ROWB + cch * 16, Bs + (size_t)(gn0 + crow + 64) * segK + kk + cch * 8);
            cp_commit();
            cp_wait<1>();
        } else {
            cp_wait<0>();
        }
        __syncthreads();

        uint32_t abase = sbase + (c & 1) * STAGEB;
        uint32_t bbase = abase + TILEB;
        #pragma unroll
        for (int ks = 0; ks < 2; ks++) {
            uint32_t afrag[2][4];
            uint32_t bfrag[4][4];
            #pragma unroll
            for (int mt = 0; mt < 2; mt++)
                ldm4(afrag[mt], abase + (wm + mt * 16 + ldrow) * ROWB + ks * 32 + ldcol);
            #pragma unroll
            for (int p = 0; p < 4; p++)
                ldm4(bfrag[p], bbase + (wn + p * 16 + ldrow) * ROWB + ks * 32 + ldcol);
            #pragma unroll
            for (int mt = 0; mt < 2; mt++) {
                #pragma unroll
                for (int p = 0; p < 4; p++) {
                    mma_bf16(acc[mt][2 * p],     afrag[mt], bfrag[p][0], bfrag[p][2]);
                    mma_bf16(acc[mt][2 * p + 1], afrag[mt], bfrag[p][1], bfrag[p][3]);
                }
            }
        }
        __syncthreads();
    }

    // ---- epilogue ----
    const int r0 = lane >> 2;          // row within m16 tile
    const int cl = 2 * (lane & 3);     // col within n8 tile

    if (MODE == 1) {
        // stage per-n data in smem (reuse tile memory)
        float* ex = (float*)smem;
        for (int i = tid; i < BN; i += 256) {
            int n = gn0 + i;
            ex[i]           = __ldg(sp + 2 * n);
            ex[BN + i]      = __ldg(sp + 2 * n + 1);
            ex[2 * BN + i]  = g_sq[n];
            ex[3 * BN + i]  = g_f[n];
        }
        __syncthreads();
        #pragma unroll
        for (int mt = 0; mt < 2; mt++) {
            #pragma unroll
            for (int half = 0; half < 2; half++) {
                int m = gm0 + wm + mt * 16 + r0 + half * 8;
                float sp0 = __ldg(sp + 2 * m), sp1 = __ldg(sp + 2 * m + 1);
                float sqi = g_sq[m], fi = g_f[m];
                #pragma unroll
                for (int nt = 0; nt < 8; nt++) {
                    int nl = wn + nt * 8 + cl;
                    float2 v;
                    #pragma unroll
                    for (int q = 0; q < 2; q++) {
                        int ci = nl + q;
                        float d2 = sqi + ex[2 * BN + ci]
                                 - 2.0f * (sp0 * ex[ci] + sp1 * ex[BN + ci]);
                        d2 = fmaxf(d2, 0.0f);
                        float a = acc[mt][nt][half * 2 + q];
                        ((float*)&v)[q] = a + __expf(-0.5f * d2) + tanhf(fi - ex[3 * BN + ci]);
                    }
                    *(float2*)(g_L + (size_t)m * Nn + gn0 + nl) = v;
                }
            }
        }
    } else if (MODE == 0) {
        #pragma unroll
        for (int mt = 0; mt < 2; mt++) {
            #pragma unroll
            for (int half = 0; half < 2; half++) {
                int m = gm0 + wm + mt * 16 + r0 + half * 8;
                #pragma unroll
                for (int nt = 0; nt < 8; nt++) {
                    int n = gn0 + wn + nt * 8 + cl;
                    float b0 = bias ? __ldg(bias + n)     : 0.f;
                    float b1 = bias ? __ldg(bias + n + 1) : 0.f;
                    float2 v;
                    v.x = (acc[mt][nt][half * 2 + 0] + b0) * alpha;
                    v.y = (acc[mt][nt][half * 2 + 1] + b1) * alpha;
                    *(float2*)(C + (size_t)m * ldc + n) = v;
                }
            }
        }
    } else {
        #pragma unroll
        for (int mt = 0; mt < 2; mt++) {
            #pragma unroll
            for (int half = 0; half < 2; half++) {
                int m = gm0 + wm + mt * 16 + r0 + half * 8;
                #pragma unroll
                for (int nt = 0; nt < 8; nt++) {
                    int n = gn0 + wn + nt * 8 + cl;
                    #pragma unroll
                    for (int q = 0; q < 2; q++) {
                        float v = acc[mt][nt][half * 2 + q] + __ldg(bias + n + q);
                        bf16 h = __float2bfloat16(v);
                        Thi[(size_t)(n + q) * Nn + m] = h;
                        Tlo[(size_t)(n + q) * Nn + m] = __float2bfloat16(v - __bfloat162float(h));
                    }
                }
            }
        }
    }
}

// ---------------- softmax: block per row, exp values held in regs ----------------
__global__ __launch_bounds__(256) void softmax_kernel(float* __restrict__ attn) {
    int row = blockIdx.x;
    int tid = threadIdx.x;
    float* L = g_L + (size_t)row * Nn;
    __shared__ float red[256];
    float4 v[4];
    float m = -1e30f;
    #pragma unroll
    for (int i = 0; i < 4; i++) {
        v[i] = *(const float4*)(L + tid * 4 + i * 1024);
        m = fmaxf(m, fmaxf(fmaxf(v[i].x, v[i].y), fmaxf(v[i].z, v[i].w)));
    }
    red[tid] = m; __syncthreads();
    for (int s = 128; s > 0; s >>= 1) {
        if (tid < s) red[tid] = fmaxf(red[tid], red[tid + s]);
        __syncthreads();
    }
    float rm = red[0];
    __syncthreads();
    float sum = 0.f;
    #pragma unroll
    for (int i = 0; i < 4; i++) {
        v[i].x = __expf(v[i].x - rm);
        v[i].y = __expf(v[i].y - rm);
        v[i].z = __expf(v[i].z - rm);
        v[i].w = __expf(v[i].w - rm);
        sum += (v[i].x + v[i].y) + (v[i].z + v[i].w);
    }
    red[tid] = sum; __syncthreads();
    for (int s = 128; s > 0; s >>= 1) {
        if (tid < s) red[tid] += red[tid + s];
        __syncthreads();
    }
    float inv = 1.0f / red[0];
    #pragma unroll
    for (int i = 0; i < 4; i++) {
        int j = tid * 4 + i * 1024;
        float4 a;
        a.x = v[i].x * inv; a.y = v[i].y * inv; a.z = v[i].z * inv; a.w = v[i].w * inv;
        *(float4*)(attn + (size_t)row * Nn + j) = a;
        float* ap = (float*)&a;
        bf16 h[4], l[4];
        #pragma unroll
        for (int q = 0; q < 4; q++) {
            h[q] = __float2bfloat16(ap[q]);
            l[q] = __float2bfloat16(ap[q] - __bfloat162float(h[q]));
        }
        *(__nv_bfloat162*)(g_Ahi + (size_t)row * Nn + j)     = __nv_bfloat162(h[0], h[1]);
        *(__nv_bfloat162*)(g_Ahi + (size_t)row * Nn + j + 2) = __nv_bfloat162(h[2], h[3]);
        *(__nv_bfloat162*)(g_Alo + (size_t)row * Nn + j)     = __nv_bfloat162(l[0], l[1]);
        *(__nv_bfloat162*)(g_Alo + (size_t)row * Nn + j + 2) = __nv_bfloat162(l[2], l[3]);
    }
}

// ---------------- launch ----------------
extern "C" void kernel_launch(void* const* d_in, const int* in_sizes, int n_in,
                              void* d_out, int out_size) {
    const float* gene = (const float*)d_in[0];
    const float* sp   = (const float*)d_in[1];
    const float* Wq   = (const float*)d_in[2];
    const float* bq   = (const float*)d_in[3];
    const float* Wk   = (const float*)d_in[4];
    const float* bk   = (const float*)d_in[5];
    const float* Wv   = (const float*)d_in[6];
    const float* bv   = (const float*)d_in[7];
    const float* Ws   = (const float*)d_in[8];
    const float* bs   = (const float*)d_in[9];
    const float* W1   = (const float*)d_in[10];
    const float* b1   = (const float*)d_in[11];
    const float* W2   = (const float*)d_in[12];
    const float* b2   = (const float*)d_in[13];
    const float* Wf   = (const float*)d_in[14];
    const float* bf_  = (const float*)d_in[15];

    float* out = (float*)d_out;
    long long total = (long long)Nn * Nn + (long long)Nn * OUTD;
    int has_attn = ((long long)out_size >= total) ? 1 : 0;
    float* attn = out;
    float* upd  = has_attn ? out + (size_t)Nn * Nn : out;

    bf16 *pGhi, *pGlo, *pYhi, *pYlo, *pZhi, *pZlo, *pAhi, *pAlo, *pVthi, *pVtlo, *pWthi, *pWtlo;
    float *pQf, *pKf;
    cudaGetSymbolAddress((void**)&pGhi, g_Ghi);
    cudaGetSymbolAddress((void**)&pGlo, g_Glo);
    cudaGetSymbolAddress((void**)&pYhi, g_Yhi);
    cudaGetSymbolAddress((void**)&pYlo, g_Ylo);
    cudaGetSymbolAddress((void**)&pZhi, g_Zhi);
    cudaGetSymbolAddress((void**)&pZlo, g_Zlo);
    cudaGetSymbolAddress((void**)&pAhi, g_Ahi);
    cudaGetSymbolAddress((void**)&pAlo, g_Alo);
    cudaGetSymbolAddress((void**)&pVthi, g_Vthi);
    cudaGetSymbolAddress((void**)&pVtlo, g_Vtlo);
    cudaGetSymbolAddress((void**)&pWthi, g_Wthi);
    cudaGetSymbolAddress((void**)&pWtlo, g_Wtlo);
    cudaGetSymbolAddress((void**)&pQf, g_Qf);
    cudaGetSymbolAddress((void**)&pKf, g_Kf);

    // 1) prep: gene splits, normalized splits, sq
    prep_kernel<<<Nn, 256>>>(gene, sp);

    // 2) weight transpose-splits
    int wblk = (HID * GENE + 255) / 256;
    wsplit_kernel<<<wblk, 256>>>(Wq, pWthi + 0 * HID * GENE, pWtlo + 0 * HID * GENE);
    wsplit_kernel<<<wblk, 256>>>(Wk, pWthi + 1 * HID * GENE, pWtlo + 1 * HID * GENE);
    wsplit_kernel<<<wblk, 256>>>(Wv, pWthi + 2 * HID * GENE, pWtlo + 2 * HID * GENE);

    // 3) QKV projections (K = 3*512 -> 48 chunks)
    dim3 gQKV(HID / BN, Nn / BM);
    hmma_gemm<0><<<gQKV, 256>>>(pGhi, pGlo, pWthi + 0 * HID * GENE, pWtlo + 0 * HID * GENE,
                                GENE, 48, pQf, HID, bq, 1.0f / 16.0f, nullptr, nullptr, nullptr);
    hmma_gemm<0><<<gQKV, 256>>>(pGhi, pGlo, pWthi + 1 * HID * GENE, pWtlo + 1 * HID * GENE,
                                GENE, 48, pKf, HID, bk, 1.0f, nullptr, nullptr, nullptr);
    hmma_gemm<2><<<gQKV, 256>>>(pGhi, pGlo, pWthi + 2 * HID * GENE, pWtlo + 2 * HID * GENE,
                                GENE, 48, nullptr, 0, bv, 1.0f, nullptr, pVthi, pVtlo);

    // 4) split Q,K into Y,Z cols 0..255
    splitqk_kernel<<<(Nn * HID) / 256, 256>>>(pQf, pYhi, pYlo);
    splitqk_kernel<<<(Nn * HID) / 256, 256>>>(pKf, pZhi, pZlo);

    // 5) per-node MLP scalar f
    mlp_kernel<<<Nn, 256>>>(sp, Ws, bs, W1, b1, W2, b2, Wf, bf_);

    // 6) fused logits GEMM (K = 3*768 -> 72 chunks) + spatial epilogue
    dim3 gLg(Nn / BN, Nn / BM);
    hmma_gemm<1><<<gLg, 256>>>(pYhi, pYlo, pZhi, pZlo,
                               YK, 72, nullptr, 0, nullptr, 1.0f, sp, nullptr, nullptr);

    // 7) softmax -> attn (d_out) + bf16 splits of A
    softmax_kernel<<<Nn, 256>>>(attn);

    // 8) updated = A @ V  (K = 3*4096 -> 384 chunks)
    dim3 gAV(OUTD / BN, Nn / BM);
    hmma_gemm<0><<<gAV, 256>>>(pAhi, pAlo, pVthi, pVtlo,
                               Nn, 384, upd, OUTD, nullptr, 1.0f, nullptr, nullptr, nullptr);
}

// round 4
// speedup vs baseline: 4.9379x; 1.8728x over previous
#include <cuda_runtime.h>
#include <cuda_bf16.h>
#include <math.h>
#include <stdint.h>

#define Nn    4096
#define GENE  512
#define HID   256
#define OUTD  256
#define YK    768     // HID + GENE fused logits depth

typedef __nv_bfloat16 bf16;

// ---------------- scratch (static device globals; no runtime allocs) ----------------
__device__ __align__(16) float g_L[(size_t)Nn * Nn];      // logits
__device__ __align__(16) bf16  g_Ghi[Nn * GENE];
__device__ __align__(16) bf16  g_Glo[Nn * GENE];
__device__ __align__(16) bf16  g_Yhi[Nn * YK];
__device__ __align__(16) bf16  g_Ylo[Nn * YK];
__device__ __align__(16) bf16  g_Zhi[Nn * YK];
__device__ __align__(16) bf16  g_Zlo[Nn * YK];
__device__ __align__(16) bf16  g_Ahi[(size_t)Nn * Nn];
__device__ __align__(16) bf16  g_Alo[(size_t)Nn * Nn];
__device__ __align__(16) bf16  g_Vthi[OUTD * Nn];
__device__ __align__(16) bf16  g_Vtlo[OUTD * Nn];
__device__ __align__(16) bf16  g_Wthi[3 * HID * GENE];    // W^T splits (q,k,v)
__device__ __align__(16) bf16  g_Wtlo[3 * HID * GENE];
__device__ __align__(16) bf16  g_W1thi[HID * HID];
__device__ __align__(16) bf16  g_W1tlo[HID * HID];
__device__ __align__(16) bf16  g_W2thi[HID * HID];
__device__ __align__(16) bf16  g_W2tlo[HID * HID];
__device__ __align__(16) bf16  g_sihi[Nn * HID];
__device__ __align__(16) bf16  g_silo[Nn * HID];
__device__ __align__(16) bf16  g_hhi[Nn * HID];
__device__ __align__(16) bf16  g_hlo[Nn * HID];
__device__ __align__(16) float g_E[Nn * HID];
__device__ __align__(16) float g_part[8 * (size_t)Nn * OUTD];   // A@V split-K partials
__device__ __align__(16) float g_bias[3 * 256];                  // bq|bk|bv
__device__ float g_f[Nn];
__device__ float g_sq[Nn];

// ---------------- PTX helpers (sm_80+ baseline) ----------------
__device__ __forceinline__ uint32_t s2u(const void* p) {
    uint32_t a;
    asm("{ .reg .u64 t; cvta.to.shared.u64 t, %1; cvt.u32.u64 %0, t; }" : "=r"(a) : "l"(p));
    return a;
}
__device__ __forceinline__ void cp16(uint32_t dst, const void* src) {
    asm volatile("cp.async.cg.shared.global [%0], [%1], 16;" :: "r"(dst), "l"(src));
}
__device__ __forceinline__ void cp_commit() {
    asm volatile("cp.async.commit_group;" ::: "memory");
}
template <int N>
__device__ __forceinline__ void cp_wait() {
    asm volatile("cp.async.wait_group %0;" :: "n"(N) : "memory");
}
__device__ __forceinline__ void ldm4(uint32_t* r, uint32_t addr) {
    asm volatile("ldmatrix.sync.aligned.m8n8.x4.shared.b16 {%0,%1,%2,%3}, [%4];"
                 : "=r"(r[0]), "=r"(r[1]), "=r"(r[2]), "=r"(r[3]) : "r"(addr));
}
__device__ __forceinline__ void mma_bf16(float* d, const uint32_t* a, uint32_t b0, uint32_t b1) {
    asm volatile(
        "mma.sync.aligned.m16n8k16.row.col.f32.bf16.bf16.f32 "
        "{%0,%1,%2,%3}, {%4,%5,%6,%7}, {%8,%9}, {%0,%1,%2,%3};"
        : "+f"(d[0]), "+f"(d[1]), "+f"(d[2]), "+f"(d[3])
        : "r"(a[0]), "r"(a[1]), "r"(a[2]), "r"(a[3]), "r"(b0), "r"(b1));
}

// ---------------- prep: gene splits + normalized-row splits + sq ----------------
__global__ __launch_bounds__(256) void prep_kernel(const float* __restrict__ gene,
                                                   const float* __restrict__ sp) {
    int row = blockIdx.x;
    const float* x = gene + (size_t)row * GENE;
    __shared__ float red[256];
    float ss = 0.f;
    for (int c = threadIdx.x; c < GENE; c += 256) { float v = x[c]; ss += v * v; }
    red[threadIdx.x] = ss; __syncthreads();
    for (int s = 128; s > 0; s >>= 1) {
        if (threadIdx.x < s) red[threadIdx.x] += red[threadIdx.x + s];
        __syncthreads();
    }
    float inv = 1.0f / fmaxf(sqrtf(red[0]), 1e-12f);
    for (int c = threadIdx.x; c < GENE; c += 256) {
        float v = x[c];
        bf16 gh = __float2bfloat16(v);
        g_Ghi[(size_t)row * GENE + c] = gh;
        g_Glo[(size_t)row * GENE + c] = __float2bfloat16(v - __bfloat162float(gh));
        float xn = v * inv;
        bf16 xh = __float2bfloat16(xn);
        bf16 xl = __float2bfloat16(xn - __bfloat162float(xh));
        size_t o = (size_t)row * YK + HID + c;
        g_Yhi[o] = xh; g_Ylo[o] = xl;
        g_Zhi[o] = xh; g_Zlo[o] = xl;
    }
    if (threadIdx.x == 0) {
        float a = sp[2 * row], b = sp[2 * row + 1];
        g_sq[row] = a * a + b * b;
    }
}

// ---------------- weight transpose + split: W[K,N] -> T hi/lo [N,K] ----------------
__global__ __launch_bounds__(256) void wsplit_kernel(const float* __restrict__ W,
                                                     bf16* __restrict__ Thi,
                                                     bf16* __restrict__ Tlo,
                                                     int K, int N) {
    int idx = blockIdx.x * 256 + threadIdx.x;
    if (idx >= N * K) return;
    int n = idx / K, k = idx % K;
    float v = W[(size_t)k * N + n];
    bf16 h = __float2bfloat16(v);
    Thi[idx] = h;
    Tlo[idx] = __float2bfloat16(v - __bfloat162float(h));
}

// ---------------- copy biases into one static ----------------
__global__ void biascopy_kernel(const float* bq, const float* bk, const float* bv) {
    int t = threadIdx.x;
    g_bias[t] = bq[t];
    g_bias[256 + t] = bk[t];
    g_bias[512 + t] = bv[t];
}

// ---------------- si = sp @ Ws + bs, split ----------------
__global__ __launch_bounds__(256) void si_kernel(const float* __restrict__ sp,
                                                 const float* __restrict__ Ws,
                                                 const float* __restrict__ bs) {
    int idx = blockIdx.x * 256 + threadIdx.x;
    int m = idx >> 8, h = idx & 255;
    float v = sp[2 * m] * Ws[h] + sp[2 * m + 1] * Ws[HID + h] + bs[h];
    bf16 hi = __float2bfloat16(v);
    g_sihi[idx] = hi;
    g_silo[idx] = __float2bfloat16(v - __bfloat162float(hi));
}

// ---------------- f = e @ Wf + bf (warp per row) ----------------
__global__ __launch_bounds__(256) void f_kernel(const float* __restrict__ Wf,
                                                const float* __restrict__ bf_) {
    int row = blockIdx.x * 8 + (threadIdx.x >> 5);
    int lane = threadIdx.x & 31;
    const float* e = g_E + (size_t)row * HID + lane * 8;
    float s = 0.f;
    #pragma unroll
    for (int i = 0; i < 8; i++) s += e[i] * __ldg(Wf + lane * 8 + i);
    #pragma unroll
    for (int o = 16; o > 0; o >>= 1) s += __shfl_xor_sync(0xFFFFFFFFu, s, o);
    if (lane == 0) g_f[row] = s + bf_[0];
}

// ---------------- HMMA split-bf16 GEMM (runtime mode epilogue) ----------------
// modes: 0 = fp32 C (+bias)*alpha (per-z C offset)
//        1 = logits epilogue -> g_L
//        4 = tanh split -> Dhi/Dlo
//        5 = relu fp32 -> C
//        6 = QKV combined (z: 0->Q split into Y, 1->K split into Z, 2->V transpose split)
#define BM 128
#define BN 128
#define BK 32
#define ROWB 80
#define TILEB (BM * ROWB)
#define STAGEB (2 * TILEB)

__global__ __launch_bounds__(256, 2) void hmma_gemm(
    const bf16* __restrict__ a0, const bf16* __restrict__ a1, const bf16* __restrict__ a2,
    const bf16* __restrict__ b0, const bf16* __restrict__ b1, const bf16* __restrict__ b2,
    int pitchA, int pitchB, int cb1, int cb2, int chunks_per_z, int zchunks,
    size_t zBstride, int mode,
    float* __restrict__ C, int ldc, size_t zCstride,
    const float* __restrict__ bias, float alpha,
    bf16* __restrict__ Dhi, bf16* __restrict__ Dlo, int ldd,
    const float* __restrict__ sp)
{
    __shared__ __align__(16) char smem[2 * STAGEB];   // 40 KB
    const uint32_t sbase = s2u(smem);
    const int tid  = threadIdx.x;
    const int lane = tid & 31;
    const int wid  = tid >> 5;
    const int wm   = (wid & 3) * 32;
    const int wn   = (wid >> 2) * 64;
    const int gm0  = blockIdx.y * BM;
    const int gn0  = blockIdx.x * BN;
    const int z    = blockIdx.z;

    if (zBstride) { b0 += z * zBstride; b1 += z * zBstride; b2 += z * zBstride; }
    const int g0 = z * zchunks;

    const int mi    = lane >> 3;
    const int ldrow = ((mi & 1) << 3) + (lane & 7);
    const int ldcol = (mi >> 1) << 4;
    const int crow = tid >> 2;
    const int cch  = tid & 3;

    float acc[2][8][4];
    #pragma unroll
    for (int a = 0; a < 2; a++)
        #pragma unroll
        for (int b = 0; b < 8; b++)
            #pragma unroll
            for (int c = 0; c < 4; c++) acc[a][b][c] = 0.f;

    // prologue: load chunk g0
    {
        int g = g0;
        const bf16 *As, *Bs; int kk;
        if (g < cb1)      { As = a0; Bs = b0; kk = g * BK; }
        else if (g < cb2) { As = a1; Bs = b1; kk = (g - cb1) * BK; }
        else              { As = a2; Bs = b2; kk = (g - cb2) * BK; }
        uint32_t dst = sbase;
        cp16(dst + crow * ROWB + cch * 16,          As + (size_t)(gm0 + crow) * pitchA + kk + cch * 8);
        cp16(dst + (crow + 64) * ROWB + cch * 16,   As + (size_t)(gm0 + crow + 64) * pitchA + kk + cch * 8);
        cp16(dst + TILEB + crow * ROWB + cch * 16,        Bs + (size_t)(gn0 + crow) * pitchB + kk + cch * 8);
        cp16(dst + TILEB + (crow + 64) * ROWB + cch * 16, Bs + (size_t)(gn0 + crow + 64) * pitchB + kk + cch * 8);
        cp_commit();
    }

    for (int c = 0; c < chunks_per_z; c++) {
        if (c + 1 < chunks_per_z) {
            int g = g0 + c + 1;
            const bf16 *As, *Bs; int kk;
            if (g < cb1)      { As = a0; Bs = b0; kk = g * BK; }
            else if (g < cb2) { As = a1; Bs = b1; kk = (g - cb1) * BK; }
            else              { As = a2; Bs = b2; kk = (g - cb2) * BK; }
            uint32_t dst = sbase + ((c + 1) & 1) * STAGEB;
            cp16(dst + crow * ROWB + cch * 16,          As + (size_t)(gm0 + crow) * pitchA + kk + cch * 8);
            cp16(dst + (crow + 64) * ROWB + cch * 16,   As + (size_t)(gm0 + crow + 64) * pitchA + kk + cch * 8);
            cp16(dst + TILEB + crow * ROWB + cch * 16,        Bs + (size_t)(gn0 + crow) * pitchB + kk + cch * 8);
            cp16(dst + TILEB + (crow + 64) * ROWB + cch * 16, Bs + (size_t)(gn0 + crow + 64) * pitchB + kk + cch * 8);
            cp_commit();
            cp_wait<1>();
        } else {
            cp_wait<0>();
        }
        __syncthreads();

        uint32_t abase = sbase + (c & 1) * STAGEB;
        uint32_t bbase = abase + TILEB;
        #pragma unroll
        for (int ks = 0; ks < 2; ks++) {
            uint32_t afrag[2][4];
            uint32_t bfrag[4][4];
            #pragma unroll
            for (int mt = 0; mt < 2; mt++)
                ldm4(afrag[mt], abase + (wm + mt * 16 + ldrow) * ROWB + ks * 32 + ldcol);
            #pragma unroll
            for (int p = 0; p < 4; p++)
                ldm4(bfrag[p], bbase + (wn + p * 16 + ldrow) * ROWB + ks * 32 + ldcol);
            #pragma unroll
            for (int mt = 0; mt < 2; mt++) {
                #pragma unroll
                for (int p = 0; p < 4; p++) {
                    mma_bf16(acc[mt][2 * p],     afrag[mt], bfrag[p][0], bfrag[p][2]);
                    mma_bf16(acc[mt][2 * p + 1], afrag[mt], bfrag[p][1], bfrag[p][3]);
                }
            }
        }
        __syncthreads();
    }

    // ---- epilogue ----
    const int r0 = lane >> 2;
    const int cl = 2 * (lane & 3);

    if (mode == 1) {
        float* ex = (float*)smem;
        for (int i = tid; i < BN; i += 256) {
            int n = gn0 + i;
            ex[i]           = __ldg(sp + 2 * n);
            ex[BN + i]      = __ldg(sp + 2 * n + 1);
            ex[2 * BN + i]  = g_sq[n];
            ex[3 * BN + i]  = g_f[n];
        }
        __syncthreads();
        #pragma unroll
        for (int mt = 0; mt < 2; mt++) {
            #pragma unroll
            for (int half = 0; half < 2; half++) {
                int m = gm0 + wm + mt * 16 + r0 + half * 8;
                float sp0 = __ldg(sp + 2 * m), sp1 = __ldg(sp + 2 * m + 1);
                float sqi = g_sq[m], fi = g_f[m];
                #pragma unroll
                for (int nt = 0; nt < 8; nt++) {
                    int nl = wn + nt * 8 + cl;
                    float2 v;
                    #pragma unroll
                    for (int q = 0; q < 2; q++) {
                        int ci = nl + q;
                        float d2 = sqi + ex[2 * BN + ci]
                                 - 2.0f * (sp0 * ex[ci] + sp1 * ex[BN + ci]);
                        d2 = fmaxf(d2, 0.0f);
                        float a = acc[mt][nt][half * 2 + q];
                        ((float*)&v)[q] = a + __expf(-0.5f * d2) + tanhf(fi - ex[3 * BN + ci]);
                    }
                    *(float2*)(g_L + (size_t)m * Nn + gn0 + nl) = v;
                }
            }
        }
    } else if (mode == 0) {
        float* Cz = C + z * zCstride;
        #pragma unroll
        for (int mt = 0; mt < 2; mt++)
            #pragma unroll
            for (int half = 0; half < 2; half++) {
                int m = gm0 + wm + mt * 16 + r0 + half * 8;
                #pragma unroll
                for (int nt = 0; nt < 8; nt++) {
                    int n = gn0 + wn + nt * 8 + cl;
                    float b0v = bias ? __ldg(bias + n)     : 0.f;
                    float b1v = bias ? __ldg(bias + n + 1) : 0.f;
                    float2 v;
                    v.x = (acc[mt][nt][half * 2 + 0] + b0v) * alpha;
                    v.y = (acc[mt][nt][half * 2 + 1] + b1v) * alpha;
                    *(float2*)(Cz + (size_t)m * ldc + n) = v;
                }
            }
    } else if (mode == 4 || mode == 5) {
        #pragma unroll
        for (int mt = 0; mt < 2; mt++)
            #pragma unroll
            for (int half = 0; half < 2; half++) {
                int m = gm0 + wm + mt * 16 + r0 + half * 8;
                #pragma unroll
                for (int nt = 0; nt < 8; nt++) {
                    int n = gn0 + wn + nt * 8 + cl;
                    #pragma unroll
                    for (int q = 0; q < 2; q++) {
                        float v = acc[mt][nt][half * 2 + q] + __ldg(bias + n + q);
                        if (mode == 4) {
                            v = tanhf(v);
                            bf16 h = __float2bfloat16(v);
                            Dhi[(size_t)m * ldd + n + q] = h;
                            Dlo[(size_t)m * ldd + n + q] = __float2bfloat16(v - __bfloat162float(h));
                        } else {
                            C[(size_t)m * ldc + n + q] = fmaxf(v, 0.f);
                        }
                    }
                }
            }
    } else { // mode 6: QKV combined
        const float* bias6 = g_bias + z * 256;
        if (z == 2) {
            #pragma unroll
            for (int mt = 0; mt < 2; mt++)
                #pragma unroll
                for (int half = 0; half < 2; half++) {
                    int m = gm0 + wm + mt * 16 + r0 + half * 8;
                    #pragma unroll
                    for (int nt = 0; nt < 8; nt++) {
                        int n = gn0 + wn + nt * 8 + cl;
                        #pragma unroll
                        for (int q = 0; q < 2; q++) {
                            float v = acc[mt][nt][half * 2 + q] + bias6[n + q];
                            bf16 h = __float2bfloat16(v);
                            g_Vthi[(size_t)(n + q) * Nn + m] = h;
                            g_Vtlo[(size_t)(n + q) * Nn + m] = __float2bfloat16(v - __bfloat162float(h));
                        }
                    }
                }
        } else {
            bf16* Dh = z ? g_Zhi : g_Yhi;
            bf16* Dl = z ? g_Zlo : g_Ylo;
            float al = z ? 1.0f : (1.0f / 16.0f);
            #pragma unroll
            for (int mt = 0; mt < 2; mt++)
                #pragma unroll
                for (int half = 0; half < 2; half++) {
                    int m = gm0 + wm + mt * 16 + r0 + half * 8;
                    #pragma unroll
                    for (int nt = 0; nt < 8; nt++) {
                        int n = gn0 + wn + nt * 8 + cl;
                        #pragma unroll
                        for (int q = 0; q < 2; q++) {
                            float v = (acc[mt][nt][half * 2 + q] + bias6[n + q]) * al;
                            bf16 h = __float2bfloat16(v);
                            Dh[(size_t)m * YK + n + q] = h;
                            Dl[(size_t)m * YK + n + q] = __float2bfloat16(v - __bfloat162float(h));
                        }
                    }
                }
        }
    }
}

// ---------------- softmax: block per row, exp values held in regs ----------------
__global__ __launch_bounds__(256) void softmax_kernel(float* __restrict__ attn) {
    int row = blockIdx.x;
    int tid = threadIdx.x;
    float* L = g_L + (size_t)row * Nn;
    __shared__ float red[256];
    float4 v[4];
    float m = -1e30f;
    #pragma unroll
    for (int i = 0; i < 4; i++) {
        v[i] = *(const float4*)(L + tid * 4 + i * 1024);
        m = fmaxf(m, fmaxf(fmaxf(v[i].x, v[i].y), fmaxf(v[i].z, v[i].w)));
    }
    red[tid] = m; __syncthreads();
    for (int s = 128; s > 0; s >>= 1) {
        if (tid < s) red[tid] = fmaxf(red[tid], red[tid + s]);
        __syncthreads();
    }
    float rm = red[0];
    __syncthreads();
    float sum = 0.f;
    #pragma unroll
    for (int i = 0; i < 4; i++) {
        v[i].x = __expf(v[i].x - rm);
        v[i].y = __expf(v[i].y - rm);
        v[i].z = __expf(v[i].z - rm);
        v[i].w = __expf(v[i].w - rm);
        sum += (v[i].x + v[i].y) + (v[i].z + v[i].w);
    }
    red[tid] = sum; __syncthreads();
    for (int s = 128; s > 0; s >>= 1) {
        if (tid < s) red[tid] += red[tid + s];
        __syncthreads();
    }
    float inv = 1.0f / red[0];
    #pragma unroll
    for (int i = 0; i < 4; i++) {
        int j = tid * 4 + i * 1024;
        float4 a;
        a.x = v[i].x * inv; a.y = v[i].y * inv; a.z = v[i].z * inv; a.w = v[i].w * inv;
        *(float4*)(attn + (size_t)row * Nn + j) = a;
        float* ap = (float*)&a;
        bf16 h[4], l[4];
        #pragma unroll
        for (int q = 0; q < 4; q++) {
            h[q] = __float2bfloat16(ap[q]);
            l[q] = __float2bfloat16(ap[q] - __bfloat162float(h[q]));
        }
        *(__nv_bfloat162*)(g_Ahi + (size_t)row * Nn + j)     = __nv_bfloat162(h[0], h[1]);
        *(__nv_bfloat162*)(g_Ahi + (size_t)row * Nn + j + 2) = __nv_bfloat162(h[2], h[3]);
        *(__nv_bfloat162*)(g_Alo + (size_t)row * Nn + j)     = __nv_bfloat162(l[0], l[1]);
        *(__nv_bfloat162*)(g_Alo + (size_t)row * Nn + j + 2) = __nv_bfloat162(l[2], l[3]);
    }
}

// ---------------- reduce split-K partials ----------------
__global__ __launch_bounds__(256) void reduce_kernel(float* __restrict__ upd) {
    size_t i = ((size_t)blockIdx.x * 256 + threadIdx.x) * 4;
    float4 s = *(const float4*)(g_part + i);
    #pragma unroll
    for (int z = 1; z < 8; z++) {
        const float4 p = *(const float4*)(g_part + z * (size_t)Nn * OUTD + i);
        s.x += p.x; s.y += p.y; s.z += p.z; s.w += p.w;
    }
    *(float4*)(upd + i) = s;
}

// ---------------- launch ----------------
extern "C" void kernel_launch(void* const* d_in, const int* in_sizes, int n_in,
                              void* d_out, int out_size) {
    const float* gene = (const float*)d_in[0];
    const float* sp   = (const float*)d_in[1];
    const float* Wq   = (const float*)d_in[2];
    const float* bq   = (const float*)d_in[3];
    const float* Wk   = (const float*)d_in[4];
    const float* bk   = (const float*)d_in[5];
    const float* Wv   = (const float*)d_in[6];
    const float* bv   = (const float*)d_in[7];
    const float* Ws   = (const float*)d_in[8];
    const float* bs   = (const float*)d_in[9];
    const float* W1   = (const float*)d_in[10];
    const float* b1   = (const float*)d_in[11];
    const float* W2   = (const float*)d_in[12];
    const float* b2   = (const float*)d_in[13];
    const float* Wf   = (const float*)d_in[14];
    const float* bf_  = (const float*)d_in[15];

    float* out = (float*)d_out;
    long long total = (long long)Nn * Nn + (long long)Nn * OUTD;
    int has_attn = ((long long)out_size >= total) ? 1 : 0;
    float* attn = out;
    float* upd  = has_attn ? out + (size_t)Nn * Nn : out;

    bf16 *pGhi, *pGlo, *pYhi, *pYlo, *pZhi, *pZlo, *pAhi, *pAlo, *pVthi, *pVtlo;
    bf16 *pWthi, *pWtlo, *pW1thi, *pW1tlo, *pW2thi, *pW2tlo, *psihi, *psilo, *phhi, *phlo;
    float *pE, *pPart;
    cudaGetSymbolAddress((void**)&pGhi, g_Ghi);
    cudaGetSymbolAddress((void**)&pGlo, g_Glo);
    cudaGetSymbolAddress((void**)&pYhi, g_Yhi);
    cudaGetSymbolAddress((void**)&pYlo, g_Ylo);
    cudaGetSymbolAddress((void**)&pZhi, g_Zhi);
    cudaGetSymbolAddress((void**)&pZlo, g_Zlo);
    cudaGetSymbolAddress((void**)&pAhi, g_Ahi);
    cudaGetSymbolAddress((void**)&pAlo, g_Alo);
    cudaGetSymbolAddress((void**)&pVthi, g_Vthi);
    cudaGetSymbolAddress((void**)&pVtlo, g_Vtlo);
    cudaGetSymbolAddress((void**)&pWthi, g_Wthi);
    cudaGetSymbolAddress((void**)&pWtlo, g_Wtlo);
    cudaGetSymbolAddress((void**)&pW1thi, g_W1thi);
    cudaGetSymbolAddress((void**)&pW1tlo, g_W1tlo);
    cudaGetSymbolAddress((void**)&pW2thi, g_W2thi);
    cudaGetSymbolAddress((void**)&pW2tlo, g_W2tlo);
    cudaGetSymbolAddress((void**)&psihi, g_sihi);
    cudaGetSymbolAddress((void**)&psilo, g_silo);
    cudaGetSymbolAddress((void**)&phhi, g_hhi);
    cudaGetSymbolAddress((void**)&phlo, g_hlo);
    cudaGetSymbolAddress((void**)&pE, g_E);
    cudaGetSymbolAddress((void**)&pPart, g_part);

    // 1) prep
    prep_kernel<<<Nn, 256>>>(gene, sp);

    // 2) weight transpose-splits
    wsplit_kernel<<<512, 256>>>(Wq, pWthi + 0 * HID * GENE, pWtlo + 0 * HID * GENE, GENE, HID);
    wsplit_kernel<<<512, 256>>>(Wk, pWthi + 1 * HID * GENE, pWtlo + 1 * HID * GENE, GENE, HID);
    wsplit_kernel<<<512, 256>>>(Wv, pWthi + 2 * HID * GENE, pWtlo + 2 * HID * GENE, GENE, HID);
    wsplit_kernel<<<256, 256>>>(W1, pW1thi, pW1tlo, HID, HID);
    wsplit_kernel<<<256, 256>>>(W2, pW2thi, pW2tlo, HID, HID);
    biascopy_kernel<<<1, 256>>>(bq, bk, bv);

    // 3) si = sp@Ws + bs (split)
    si_kernel<<<(Nn * HID) / 256, 256>>>(sp, Ws, bs);

    // 4) QKV combined (mode 6): grid (2, 32, 3)
    dim3 gQKV(HID / BN, Nn / BM, 3);
    hmma_gemm<<<gQKV, 256>>>(pGhi, pGlo, pGhi, pWthi, pWthi, pWtlo,
                             GENE, GENE, 16, 32, 48, 0, (size_t)HID * GENE, 6,
                             nullptr, 0, 0, nullptr, 1.0f, nullptr, nullptr, 0, nullptr);

    // 5) MLP: h = tanh(si@W1+b1) split; e = relu(h@W2+b2) fp32; f = e@Wf+bf
    dim3 gMLP(HID / BN, Nn / BM, 1);
    hmma_gemm<<<gMLP, 256>>>(psihi, psilo, psihi, pW1thi, pW1thi, pW1tlo,
                             HID, HID, 8, 16, 24, 0, 0, 4,
                             nullptr, 0, 0, b1, 1.0f, phhi, phlo, HID, nullptr);
    hmma_gemm<<<gMLP, 256>>>(phhi, phlo, phhi, pW2thi, pW2thi, pW2tlo,
                             HID, HID, 8, 16, 24, 0, 0, 5,
                             pE, HID, 0, b2, 1.0f, nullptr, nullptr, 0, nullptr);
    f_kernel<<<Nn / 8, 256>>>(Wf, bf_);

    // 6) logits: 2.5-segment (YhiZhi 768 | YloZhi 768 | YhiZlo 256) + epilogue
    dim3 gLg(Nn / BN, Nn / BM, 1);
    hmma_gemm<<<gLg, 256>>>(pYhi, pYlo, pYhi, pZhi, pZhi, pZlo,
                            YK, YK, 24, 48, 56, 0, 0, 1,
                            nullptr, 0, 0, nullptr, 1.0f, nullptr, nullptr, 0, sp);

    // 7) softmax -> attn + A splits
    softmax_kernel<<<Nn, 256>>>(attn);

    // 8) A@V split-K x8 -> partials, then reduce
    dim3 gAV(OUTD / BN, Nn / BM, 8);
    hmma_gemm<<<gAV, 256>>>(pAhi, pAlo, pAhi, pVthi, pVthi, pVtlo,
                            Nn, Nn, 128, 256, 48, 48, 0, 0,
                            pPart, OUTD, (size_t)Nn * OUTD, nullptr, 1.0f,
                            nullptr, nullptr, 0, nullptr);
    reduce_kernel<<<(Nn * OUTD) / 1024, 256>>>(upd);
}

// round 5
// speedup vs baseline: 6.3885x; 1.2938x over previous
#include <cuda_runtime.h>
#include <cuda_bf16.h>
#include <math.h>
#include <stdint.h>

#define Nn    4096
#define GENE  512
#define HID   256
#define OUTD  256
#define YK    768     // HID + GENE fused logits depth

typedef __nv_bfloat16 bf16;

// ---------------- scratch (static device globals; no runtime allocs) ----------------
__device__ __align__(16) float g_L[(size_t)Nn * Nn];      // logits
__device__ __align__(16) bf16  g_Ghi[Nn * GENE];
__device__ __align__(16) bf16  g_Glo[Nn * GENE];
__device__ __align__(16) bf16  g_Yhi[Nn * YK];
__device__ __align__(16) bf16  g_Ylo[Nn * YK];
__device__ __align__(16) bf16  g_Zhi[Nn * YK];
__device__ __align__(16) bf16  g_Zlo[Nn * YK];
__device__ __align__(16) bf16  g_Ahi[(size_t)Nn * Nn];
__device__ __align__(16) bf16  g_Alo[(size_t)Nn * Nn];
__device__ __align__(16) bf16  g_Vthi[OUTD * Nn];
__device__ __align__(16) bf16  g_Vtlo[OUTD * Nn];
__device__ __align__(16) bf16  g_Wthi[3 * HID * GENE];    // W^T splits (q,k,v)
__device__ __align__(16) bf16  g_Wtlo[3 * HID * GENE];
__device__ __align__(16) bf16  g_W1thi[HID * HID];
__device__ __align__(16) bf16  g_W1tlo[HID * HID];
__device__ __align__(16) bf16  g_W2thi[HID * HID];
__device__ __align__(16) bf16  g_W2tlo[HID * HID];
__device__ __align__(16) bf16  g_sihi[Nn * HID];
__device__ __align__(16) bf16  g_silo[Nn * HID];
__device__ __align__(16) bf16  g_hhi[Nn * HID];
__device__ __align__(16) bf16  g_hlo[Nn * HID];
__device__ __align__(16) float g_E[Nn * HID];
__device__ __align__(16) float g_part[8 * (size_t)Nn * OUTD];   // A@V split-K partials
__device__ __align__(16) float g_bias[3 * 256];                  // bq|bk|bv
__device__ float g_f[Nn];
__device__ float g_sq[Nn];

// ---------------- PTX helpers (sm_80+ baseline) ----------------
__device__ __forceinline__ uint32_t s2u(const void* p) {
    uint32_t a;
    asm("{ .reg .u64 t; cvta.to.shared.u64 t, %1; cvt.u32.u64 %0, t; }" : "=r"(a) : "l"(p));
    return a;
}
__device__ __forceinline__ void cp16(uint32_t dst, const void* src) {
    asm volatile("cp.async.cg.shared.global [%0], [%1], 16;" :: "r"(dst), "l"(src));
}
__device__ __forceinline__ void cp_commit() {
    asm volatile("cp.async.commit_group;" ::: "memory");
}
template <int N>
__device__ __forceinline__ void cp_wait() {
    asm volatile("cp.async.wait_group %0;" :: "n"(N) : "memory");
}
__device__ __forceinline__ void ldm4(uint32_t* r, uint32_t addr) {
    asm volatile("ldmatrix.sync.aligned.m8n8.x4.shared.b16 {%0,%1,%2,%3}, [%4];"
                 : "=r"(r[0]), "=r"(r[1]), "=r"(r[2]), "=r"(r[3]) : "r"(addr));
}
__device__ __forceinline__ void mma_bf16(float* d, const uint32_t* a, uint32_t b0, uint32_t b1) {
    asm volatile(
        "mma.sync.aligned.m16n8k16.row.col.f32.bf16.bf16.f32 "
        "{%0,%1,%2,%3}, {%4,%5,%6,%7}, {%8,%9}, {%0,%1,%2,%3};"
        : "+f"(d[0]), "+f"(d[1]), "+f"(d[2]), "+f"(d[3])
        : "r"(a[0]), "r"(a[1]), "r"(a[2]), "r"(a[3]), "r"(b0), "r"(b1));
}

// ---------------- prep: gene splits + normalized-row splits + sq + si ----------------
__global__ __launch_bounds__(256) void prep_kernel(const float* __restrict__ gene,
                                                   const float* __restrict__ sp,
                                                   const float* __restrict__ Ws,
                                                   const float* __restrict__ bs) {
    int row = blockIdx.x;
    const float* x = gene + (size_t)row * GENE;
    __shared__ float red[256];
    float a = __ldg(sp + 2 * row), b = __ldg(sp + 2 * row + 1);

    // si = sp @ Ws + bs  (one h per thread)
    {
        int h = threadIdx.x;
        float v = a * __ldg(Ws + h) + b * __ldg(Ws + HID + h) + __ldg(bs + h);
        bf16 hi = __float2bfloat16(v);
        g_sihi[row * HID + h] = hi;
        g_silo[row * HID + h] = __float2bfloat16(v - __bfloat162float(hi));
    }

    float ss = 0.f;
    for (int c = threadIdx.x; c < GENE; c += 256) { float v = x[c]; ss += v * v; }
    red[threadIdx.x] = ss; __syncthreads();
    for (int s = 128; s > 0; s >>= 1) {
        if (threadIdx.x < s) red[threadIdx.x] += red[threadIdx.x + s];
        __syncthreads();
    }
    float inv = 1.0f / fmaxf(sqrtf(red[0]), 1e-12f);
    for (int c = threadIdx.x; c < GENE; c += 256) {
        float v = x[c];
        bf16 gh = __float2bfloat16(v);
        g_Ghi[(size_t)row * GENE + c] = gh;
        g_Glo[(size_t)row * GENE + c] = __float2bfloat16(v - __bfloat162float(gh));
        float xn = v * inv;
        bf16 xh = __float2bfloat16(xn);
        bf16 xl = __float2bfloat16(xn - __bfloat162float(xh));
        size_t o = (size_t)row * YK + HID + c;
        g_Yhi[o] = xh; g_Ylo[o] = xl;
        g_Zhi[o] = xh; g_Zlo[o] = xl;
    }
    if (threadIdx.x == 0) g_sq[row] = a * a + b * b;
}

// ---------------- all weight transpose-splits + bias copies in one kernel ----------------
__global__ __launch_bounds__(256) void wsplit_all_kernel(
    const float* __restrict__ Wq, const float* __restrict__ Wk, const float* __restrict__ Wv,
    const float* __restrict__ W1, const float* __restrict__ W2,
    const float* __restrict__ bq, const float* __restrict__ bk, const float* __restrict__ bv) {
    int idx = blockIdx.x * 256 + threadIdx.x;
    if (idx < 393216) {                       // 3 x (256 x 512)
        int w = idx / 131072, r = idx % 131072;
        int n = r / GENE, k = r % GENE;
        const float* W = (w == 0) ? Wq : (w == 1) ? Wk : Wv;
        float v = W[(size_t)k * HID + n];
        bf16 h = __float2bfloat16(v);
        g_Wthi[idx] = h;
        g_Wtlo[idx] = __float2bfloat16(v - __bfloat162float(h));
    } else if (idx < 458752) {                // W1 (256 x 256)
        int r = idx - 393216;
        int n = r / HID, k = r % HID;
        float v = W1[(size_t)k * HID + n];
        bf16 h = __float2bfloat16(v);
        g_W1thi[r] = h;
        g_W1tlo[r] = __float2bfloat16(v - __bfloat162float(h));
    } else if (idx < 524288) {                // W2
        int r = idx - 458752;
        int n = r / HID, k = r % HID;
        float v = W2[(size_t)k * HID + n];
        bf16 h = __float2bfloat16(v);
        g_W2thi[r] = h;
        g_W2tlo[r] = __float2bfloat16(v - __bfloat162float(h));
    } else {                                  // biases
        int t = idx - 524288;
        if (t < 256)      g_bias[t] = bq[t];
        else if (t < 512) g_bias[t] = bk[t - 256];
        else if (t < 768) g_bias[t] = bv[t - 512];
    }
}

// ---------------- f = e @ Wf + bf (warp per row) ----------------
__global__ __launch_bounds__(256) void f_kernel(const float* __restrict__ Wf,
                                                const float* __restrict__ bf_) {
    int row = blockIdx.x * 8 + (threadIdx.x >> 5);
    int lane = threadIdx.x & 31;
    const float* e = g_E + (size_t)row * HID + lane * 8;
    float s = 0.f;
    #pragma unroll
    for (int i = 0; i < 8; i++) s += e[i] * __ldg(Wf + lane * 8 + i);
    #pragma unroll
    for (int o = 16; o > 0; o >>= 1) s += __shfl_xor_sync(0xFFFFFFFFu, s, o);
    if (lane == 0) g_f[row] = s + bf_[0];
}

// ---------------- HMMA split-bf16 GEMM, BK=64, XOR-swizzle, 3-stage pipeline ----------------
// modes: 0 = fp32 C (+bias)*alpha (per-z C offset)
//        1 = logits epilogue -> g_L
//        4 = tanh split -> Dhi/Dlo
//        5 = relu fp32 -> C
//        6 = QKV combined (z: 0->Q into Y, 1->K into Z, 2->V transpose split)
#define BM 128
#define BN 128
#define BK 64
#define TILEB  16384                 // 128 rows x 128B
#define STAGEB (2 * TILEB)           // A + B
#define NSTAGE 3
#define SMEMSZ (NSTAGE * STAGEB)     // 98304

__global__ __launch_bounds__(256, 2) void hmma_gemm(
    const bf16* __restrict__ a0, const bf16* __restrict__ a1, const bf16* __restrict__ a2,
    const bf16* __restrict__ b0, const bf16* __restrict__ b1, const bf16* __restrict__ b2,
    int pitchA, int pitchB, int cb1, int cb2, int chunks_per_z, int zchunks,
    size_t zBstride, int mode,
    float* __restrict__ C, int ldc, size_t zCstride,
    const float* __restrict__ bias, float alpha,
    bf16* __restrict__ Dhi, bf16* __restrict__ Dlo, int ldd,
    const float* __restrict__ sp)
{
    extern __shared__ __align__(16) char smem[];
    const uint32_t sbase = s2u(smem);
    const int tid  = threadIdx.x;
    const int lane = tid & 31;
    const int wid  = tid >> 5;
    const int wm   = (wid & 3) * 32;
    const int wn   = (wid >> 2) * 64;
    const int gm0  = blockIdx.y * BM;
    const int gn0  = blockIdx.x * BN;
    const int z    = blockIdx.z;

    if (zBstride) { b0 += z * zBstride; b1 += z * zBstride; b2 += z * zBstride; }
    const int g0 = z * zchunks;

    const int mi    = lane >> 3;
    const int ldrow = ((mi & 1) << 3) + (lane & 7);
    const int ldc16 = mi >> 1;           // 16B-chunk offset within 32B k-slice
    // cp.async slots: 1024 per tile, 4 per thread
    const int srow0 = tid >> 3;          // rows: tid>>3 + i*32
    const int sc    = tid & 7;

    float acc[2][8][4];
    #pragma unroll
    for (int a = 0; a < 2; a++)
        #pragma unroll
        for (int b = 0; b < 8; b++)
            #pragma unroll
            for (int c = 0; c < 4; c++) acc[a][b][c] = 0.f;

    // ---- chunk loader ----
    auto load_chunk = [&](int g, int stage) {
        const bf16 *As, *Bs; int kk;
        if (g < cb1)      { As = a0; Bs = b0; kk = g * BK; }
        else if (g < cb2) { As = a1; Bs = b1; kk = (g - cb1) * BK; }
        else              { As = a2; Bs = b2; kk = (g - cb2) * BK; }
        uint32_t dst = sbase + stage * STAGEB;
        #pragma unroll
        for (int i = 0; i < 4; i++) {
            int row = srow0 + i * 32;
            uint32_t off = (uint32_t)(row * 128 + ((sc ^ (row & 7)) << 4));
            cp16(dst + off,         As + (size_t)(gm0 + row) * pitchA + kk + sc * 8);
            cp16(dst + TILEB + off, Bs + (size_t)(gn0 + row) * pitchB + kk + sc * 8);
        }
        cp_commit();
    };

    // prologue: stages 0,1
    load_chunk(g0, 0);
    if (chunks_per_z > 1) load_chunk(g0 + 1, 1);
    else cp_commit();   // keep group count consistent

    for (int c = 0; c < chunks_per_z; c++) {
        if (c + 1 < chunks_per_z) cp_wait<1>(); else cp_wait<0>();
        __syncthreads();
        if (c + 2 < chunks_per_z) load_chunk(g0 + c + 2, (c + 2) % NSTAGE);

        uint32_t abase = sbase + (c % NSTAGE) * STAGEB;
        uint32_t bbase = abase + TILEB;
        #pragma unroll
        for (int ks = 0; ks < 4; ks++) {
            uint32_t afrag[2][4];
            uint32_t bfrag[4][4];
            int c16 = ks * 2 + ldc16;
            #pragma unroll
            for (int mt = 0; mt < 2; mt++) {
                int row = wm + mt * 16 + ldrow;
                ldm4(afrag[mt], abase + row * 128 + ((c16 ^ (row & 7)) << 4));
            }
            #pragma unroll
            for (int p = 0; p < 4; p++) {
                int row = wn + p * 16 + ldrow;
                ldm4(bfrag[p], bbase + row * 128 + ((c16 ^ (row & 7)) << 4));
            }
            #pragma unroll
            for (int mt = 0; mt < 2; mt++) {
                #pragma unroll
                for (int p = 0; p < 4; p++) {
                    mma_bf16(acc[mt][2 * p],     afrag[mt], bfrag[p][0], bfrag[p][2]);
                    mma_bf16(acc[mt][2 * p + 1], afrag[mt], bfrag[p][1], bfrag[p][3]);
                }
            }
        }
    }

    // ---- epilogue ----
    const int r0 = lane >> 2;
    const int cl = 2 * (lane & 3);

    if (mode == 1) {
        float* ex = (float*)smem;
        __syncthreads();
        for (int i = tid; i < BN; i += 256) {
            int n = gn0 + i;
            ex[i]           = __ldg(sp + 2 * n);
            ex[BN + i]      = __ldg(sp + 2 * n + 1);
            ex[2 * BN + i]  = g_sq[n];
            ex[3 * BN + i]  = g_f[n];
        }
        __syncthreads();
        #pragma unroll
        for (int mt = 0; mt < 2; mt++) {
            #pragma unroll
            for (int half = 0; half < 2; half++) {
                int m = gm0 + wm + mt * 16 + r0 + half * 8;
                float sp0 = __ldg(sp + 2 * m), sp1 = __ldg(sp + 2 * m + 1);
                float sqi = g_sq[m], fi = g_f[m];
                #pragma unroll
                for (int nt = 0; nt < 8; nt++) {
                    int nl = wn + nt * 8 + cl;
                    float2 v;
                    #pragma unroll
                    for (int q = 0; q < 2; q++) {
                        int ci = nl + q;
                        float d2 = sqi + ex[2 * BN + ci]
                                 - 2.0f * (sp0 * ex[ci] + sp1 * ex[BN + ci]);
                        d2 = fmaxf(d2, 0.0f);
                        float a = acc[mt][nt][half * 2 + q];
                        ((float*)&v)[q] = a + __expf(-0.5f * d2) + tanhf(fi - ex[3 * BN + ci]);
                    }
                    *(float2*)(g_L + (size_t)m * Nn + gn0 + nl) = v;
                }
            }
        }
    } else if (mode == 0) {
        float* Cz = C + z * zCstride;
        #pragma unroll
        for (int mt = 0; mt < 2; mt++)
            #pragma unroll
            for (int half = 0; half < 2; half++) {
                int m = gm0 + wm + mt * 16 + r0 + half * 8;
                #pragma unroll
                for (int nt = 0; nt < 8; nt++) {
                    int n = gn0 + wn + nt * 8 + cl;
                    float b0v = bias ? __ldg(bias + n)     : 0.f;
                    float b1v = bias ? __ldg(bias + n + 1) : 0.f;
                    float2 v;
                    v.x = (acc[mt][nt][half * 2 + 0] + b0v) * alpha;
                    v.y = (acc[mt][nt][half * 2 + 1] + b1v) * alpha;
                    *(float2*)(Cz + (size_t)m * ldc + n) = v;
                }
            }
    } else if (mode == 4 || mode == 5) {
        #pragma unroll
        for (int mt = 0; mt < 2; mt++)
            #pragma unroll
            for (int half = 0; half < 2; half++) {
                int m = gm0 + wm + mt * 16 + r0 + half * 8;
                #pragma unroll
                for (int nt = 0; nt < 8; nt++) {
                    int n = gn0 + wn + nt * 8 + cl;
                    #pragma unroll
                    for (int q = 0; q < 2; q++) {
                        float v = acc[mt][nt][half * 2 + q] + __ldg(bias + n + q);
                        if (mode == 4) {
                            v = tanhf(v);
                            bf16 h = __float2bfloat16(v);
                            Dhi[(size_t)m * ldd + n + q] = h;
                            Dlo[(size_t)m * ldd + n + q] = __float2bfloat16(v - __bfloat162float(h));
                        } else {
                            C[(size_t)m * ldc + n + q] = fmaxf(v, 0.f);
                        }
                    }
                }
            }
    } else { // mode 6: QKV combined
        const float* bias6 = g_bias + z * 256;
        if (z == 2) {
            #pragma unroll
            for (int mt = 0; mt < 2; mt++)
                #pragma unroll
                for (int half = 0; half < 2; half++) {
                    int m = gm0 + wm + mt * 16 + r0 + half * 8;
                    #pragma unroll
                    for (int nt = 0; nt < 8; nt++) {
                        int n = gn0 + wn + nt * 8 + cl;
                        #pragma unroll
                        for (int q = 0; q < 2; q++) {
                            float v = acc[mt][nt][half * 2 + q] + bias6[n + q];
                            bf16 h = __float2bfloat16(v);
                            g_Vthi[(size_t)(n + q) * Nn + m] = h;
                            g_Vtlo[(size_t)(n + q) * Nn + m] = __float2bfloat16(v - __bfloat162float(h));
                        }
                    }
                }
        } else {
            bf16* Dh = z ? g_Zhi : g_Yhi;
            bf16* Dl = z ? g_Zlo : g_Ylo;
            float al = z ? 1.0f : (1.0f / 16.0f);
            #pragma unroll
            for (int mt = 0; mt < 2; mt++)
                #pragma unroll
                for (int half = 0; half < 2; half++) {
                    int m = gm0 + wm + mt * 16 + r0 + half * 8;
                    #pragma unroll
                    for (int nt = 0; nt < 8; nt++) {
                        int n = gn0 + wn + nt * 8 + cl;
                        #pragma unroll
                        for (int q = 0; q < 2; q++) {
                            float v = (acc[mt][nt][half * 2 + q] + bias6[n + q]) * al;
                            bf16 h = __float2bfloat16(v);
                            Dh[(size_t)m * YK + n + q] = h;
                            Dl[(size_t)m * YK + n + q] = __float2bfloat16(v - __bfloat162float(h));
                        }
                    }
                }
        }
    }
}

// ---------------- softmax: block per row, exp values held in regs ----------------
__global__ __launch_bounds__(256) void softmax_kernel(float* __restrict__ attn) {
    int row = blockIdx.x;
    int tid = threadIdx.x;
    float* L = g_L + (size_t)row * Nn;
    __shared__ float red[256];
    float4 v[4];
    float m = -1e30f;
    #pragma unroll
    for (int i = 0; i < 4; i++) {
        v[i] = *(const float4*)(L + tid * 4 + i * 1024);
        m = fmaxf(m, fmaxf(fmaxf(v[i].x, v[i].y), fmaxf(v[i].z, v[i].w)));
    }
    red[tid] = m; __syncthreads();
    for (int s = 128; s > 0; s >>= 1) {
        if (tid < s) red[tid] = fmaxf(red[tid], red[tid + s]);
        __syncthreads();
    }
    float rm = red[0];
    __syncthreads();
    float sum = 0.f;
    #pragma unroll
    for (int i = 0; i < 4; i++) {
        v[i].x = __expf(v[i].x - rm);
        v[i].y = __expf(v[i].y - rm);
        v[i].z = __expf(v[i].z - rm);
        v[i].w = __expf(v[i].w - rm);
        sum += (v[i].x + v[i].y) + (v[i].z + v[i].w);
    }
    red[tid] = sum; __syncthreads();
    for (int s = 128; s > 0; s >>= 1) {
        if (tid < s) red[tid] += red[tid + s];
        __syncthreads();
    }
    float inv = 1.0f / red[0];
    #pragma unroll
    for (int i = 0; i < 4; i++) {
        int j = tid * 4 + i * 1024;
        float4 a;
        a.x = v[i].x * inv; a.y = v[i].y * inv; a.z = v[i].z * inv; a.w = v[i].w * inv;
        *(float4*)(attn + (size_t)row * Nn + j) = a;
        float* ap = (float*)&a;
        bf16 h[4], l[4];
        #pragma unroll
        for (int q = 0; q < 4; q++) {
            h[q] = __float2bfloat16(ap[q]);
            l[q] = __float2bfloat16(ap[q] - __bfloat162float(h[q]));
        }
        *(__nv_bfloat162*)(g_Ahi + (size_t)row * Nn + j)     = __nv_bfloat162(h[0], h[1]);
        *(__nv_bfloat162*)(g_Ahi + (size_t)row * Nn + j + 2) = __nv_bfloat162(h[2], h[3]);
        *(__nv_bfloat162*)(g_Alo + (size_t)row * Nn + j)     = __nv_bfloat162(l[0], l[1]);
        *(__nv_bfloat162*)(g_Alo + (size_t)row * Nn + j + 2) = __nv_bfloat162(l[2], l[3]);
    }
}

// ---------------- reduce split-K partials ----------------
__global__ __launch_bounds__(256) void reduce_kernel(float* __restrict__ upd) {
    size_t i = ((size_t)blockIdx.x * 256 + threadIdx.x) * 4;
    float4 s = *(const float4*)(g_part + i);
    #pragma unroll
    for (int z = 1; z < 8; z++) {
        const float4 p = *(const float4*)(g_part + z * (size_t)Nn * OUTD + i);
        s.x += p.x; s.y += p.y; s.z += p.z; s.w += p.w;
    }
    *(float4*)(upd + i) = s;
}

// ---------------- launch ----------------
extern "C" void kernel_launch(void* const* d_in, const int* in_sizes, int n_in,
                              void* d_out, int out_size) {
    const float* gene = (const float*)d_in[0];
    const float* sp   = (const float*)d_in[1];
    const float* Wq   = (const float*)d_in[2];
    const float* bq   = (const float*)d_in[3];
    const float* Wk   = (const float*)d_in[4];
    const float* bk   = (const float*)d_in[5];
    const float* Wv   = (const float*)d_in[6];
    const float* bv   = (const float*)d_in[7];
    const float* Ws   = (const float*)d_in[8];
    const float* bs   = (const float*)d_in[9];
    const float* W1   = (const float*)d_in[10];
    const float* b1   = (const float*)d_in[11];
    const float* W2   = (const float*)d_in[12];
    const float* b2   = (const float*)d_in[13];
    const float* Wf   = (const float*)d_in[14];
    const float* bf_  = (const float*)d_in[15];

    float* out = (float*)d_out;
    long long total = (long long)Nn * Nn + (long long)Nn * OUTD;
    int has_attn = ((long long)out_size >= total) ? 1 : 0;
    float* attn = out;
    float* upd  = has_attn ? out + (size_t)Nn * Nn : out;

    bf16 *pGhi, *pGlo, *pYhi, *pYlo, *pZhi, *pZlo, *pAhi, *pAlo, *pVthi, *pVtlo;
    bf16 *pWthi, *pWtlo, *pW1thi, *pW1tlo, *pW2thi, *pW2tlo, *psihi, *psilo, *phhi, *phlo;
    float *pE, *pPart;
    cudaGetSymbolAddress((void**)&pGhi, g_Ghi);
    cudaGetSymbolAddress((void**)&pGlo, g_Glo);
    cudaGetSymbolAddress((void**)&pYhi, g_Yhi);
    cudaGetSymbolAddress((void**)&pYlo, g_Ylo);
    cudaGetSymbolAddress((void**)&pZhi, g_Zhi);
    cudaGetSymbolAddress((void**)&pZlo, g_Zlo);
    cudaGetSymbolAddress((void**)&pAhi, g_Ahi);
    cudaGetSymbolAddress((void**)&pAlo, g_Alo);
    cudaGetSymbolAddress((void**)&pVthi, g_Vthi);
    cudaGetSymbolAddress((void**)&pVtlo, g_Vtlo);
    cudaGetSymbolAddress((void**)&pWthi, g_Wthi);
    cudaGetSymbolAddress((void**)&pWtlo, g_Wtlo);
    cudaGetSymbolAddress((void**)&pW1thi, g_W1thi);
    cudaGetSymbolAddress((void**)&pW1tlo, g_W1tlo);
    cudaGetSymbolAddress((void**)&pW2thi, g_W2thi);
    cudaGetSymbolAddress((void**)&pW2tlo, g_W2tlo);
    cudaGetSymbolAddress((void**)&psihi, g_sihi);
    cudaGetSymbolAddress((void**)&psilo, g_silo);
    cudaGetSymbolAddress((void**)&phhi, g_hhi);
    cudaGetSymbolAddress((void**)&phlo, g_hlo);
    cudaGetSymbolAddress((void**)&pE, g_E);
    cudaGetSymbolAddress((void**)&pPart, g_part);

    cudaFuncSetAttribute(hmma_gemm, cudaFuncAttributeMaxDynamicSharedMemorySize, SMEMSZ);

    // 0) prep (+ si)
    prep_kernel<<<Nn, 256>>>(gene, sp, Ws, bs);

    // 1) all weight splits + biases
    wsplit_all_kernel<<<2051, 256>>>(Wq, Wk, Wv, W1, W2, bq, bk, bv);

    // 2) MLP gemm 1: h = tanh(si@W1+b1) split  (chunks: 4|4|4)
    dim3 gMLP(HID / BN, Nn / BM, 1);
    hmma_gemm<<<gMLP, 256, SMEMSZ>>>(psihi, psilo, psihi, pW1thi, pW1thi, pW1tlo,
                                     HID, HID, 4, 8, 12, 0, 0, 4,
                                     nullptr, 0, 0, b1, 1.0f, phhi, phlo, HID, nullptr);
    // 3) MLP gemm 2: e = relu(h@W2+b2) fp32
    hmma_gemm<<<gMLP, 256, SMEMSZ>>>(phhi, phlo, phhi, pW2thi, pW2thi, pW2tlo,
                                     HID, HID, 4, 8, 12, 0, 0, 5,
                                     pE, HID, 0, b2, 1.0f, nullptr, nullptr, 0, nullptr);
    // 4) f = e@Wf + bf
    f_kernel<<<Nn / 8, 256>>>(Wf, bf_);

    // 5) QKV combined (mode 6): grid (2, 32, 3), chunks 8|8|8  <- ncu -s 5 captures this
    dim3 gQKV(HID / BN, Nn / BM, 3);
    hmma_gemm<<<gQKV, 256, SMEMSZ>>>(pGhi, pGlo, pGhi, pWthi, pWthi, pWtlo,
                                     GENE, GENE, 8, 16, 24, 0, (size_t)HID * GENE, 6,
                                     nullptr, 0, 0, nullptr, 1.0f, nullptr, nullptr, 0, nullptr);

    // 6) logits: 2.5-segment (YhiZhi 12 | YloZhi 12 | YhiZlo 4 chunks) + epilogue
    dim3 gLg(Nn / BN, Nn / BM, 1);
    hmma_gemm<<<gLg, 256, SMEMSZ>>>(pYhi, pYlo, pYhi, pZhi, pZhi, pZlo,
                                    YK, YK, 12, 24, 28, 0, 0, 1,
                                    nullptr, 0, 0, nullptr, 1.0f, nullptr, nullptr, 0, sp);

    // 7) softmax -> attn + A splits
    softmax_kernel<<<Nn, 256>>>(attn);

    // 8) A@V split-K x8 -> partials (chunks/z = 24, segs 64|64|64)
    dim3 gAV(OUTD / BN, Nn / BM, 8);
    hmma_gemm<<<gAV, 256, SMEMSZ>>>(pAhi, pAlo, pAhi, pVthi, pVthi, pVtlo,
                                    Nn, Nn, 64, 128, 24, 24, 0, 0,
                                    pPart, OUTD, (size_t)Nn * OUTD, nullptr, 1.0f,
                                    nullptr, nullptr, 0, nullptr);
    // 9) reduce partials
    reduce_kernel<<<(Nn * OUTD) / 1024, 256>>>(upd);
}

// round 6
// speedup vs baseline: 7.0627x; 1.1055x over previous
#include <cuda_runtime.h>
#include <cuda_bf16.h>
#include <math.h>
#include <stdint.h>

#define Nn    4096
#define GENE  512
#define HID   256
#define OUTD  256
#define YK    768     // HID + GENE fused logits depth

typedef __nv_bfloat16 bf16;

// ---------------- scratch (static device globals; no runtime allocs) ----------------
__device__ __align__(16) float g_L[(size_t)Nn * Nn];      // logits
__device__ __align__(16) bf16  g_Ghi[Nn * GENE];
__device__ __align__(16) bf16  g_Glo[Nn * GENE];
__device__ __align__(16) bf16  g_Yhi[Nn * YK];
__device__ __align__(16) bf16  g_Ylo[Nn * YK];
__device__ __align__(16) bf16  g_Zhi[Nn * YK];
__device__ __align__(16) bf16  g_Zlo[Nn * YK];
__device__ __align__(16) bf16  g_Ahi[(size_t)Nn * Nn];
__device__ __align__(16) bf16  g_Alo[(size_t)Nn * Nn];
__device__ __align__(16) bf16  g_Vthi[OUTD * Nn];
__device__ __align__(16) bf16  g_Vtlo[OUTD * Nn];
__device__ __align__(16) bf16  g_Wthi[3 * HID * GENE];    // W^T splits (q,k,v)
__device__ __align__(16) bf16  g_Wtlo[3 * HID * GENE];
__device__ __align__(16) bf16  g_W1thi[HID * HID];
__device__ __align__(16) bf16  g_W1tlo[HID * HID];
__device__ __align__(16) bf16  g_W2thi[HID * HID];
__device__ __align__(16) bf16  g_W2tlo[HID * HID];
__device__ __align__(16) bf16  g_sihi[Nn * HID];
__device__ __align__(16) bf16  g_silo[Nn * HID];
__device__ __align__(16) bf16  g_hhi[Nn * HID];
__device__ __align__(16) bf16  g_hlo[Nn * HID];
__device__ __align__(16) float g_E[Nn * HID];
__device__ __align__(16) float g_part[8 * (size_t)Nn * OUTD];   // A@V split-K partials
__device__ __align__(16) float g_bias[3 * 256];                  // bq|bk|bv
__device__ float g_f[Nn];
__device__ float g_sq[Nn];

// ---------------- PTX helpers (sm_80+ baseline) ----------------
__device__ __forceinline__ uint32_t s2u(const void* p) {
    uint32_t a;
    asm("{ .reg .u64 t; cvta.to.shared.u64 t, %1; cvt.u32.u64 %0, t; }" : "=r"(a) : "l"(p));
    return a;
}
__device__ __forceinline__ void cp16(uint32_t dst, const void* src) {
    asm volatile("cp.async.cg.shared.global [%0], [%1], 16;" :: "r"(dst), "l"(src));
}
__device__ __forceinline__ void cp_commit() {
    asm volatile("cp.async.commit_group;" ::: "memory");
}
template <int N>
__device__ __forceinline__ void cp_wait() {
    asm volatile("cp.async.wait_group %0;" :: "n"(N) : "memory");
}
__device__ __forceinline__ void ldm4(uint32_t* r, uint32_t addr) {
    asm volatile("ldmatrix.sync.aligned.m8n8.x4.shared.b16 {%0,%1,%2,%3}, [%4];"
                 : "=r"(r[0]), "=r"(r[1]), "=r"(r[2]), "=r"(r[3]) : "r"(addr));
}
__device__ __forceinline__ void mma_bf16(float* d, const uint32_t* a, uint32_t b0, uint32_t b1) {
    asm volatile(
        "mma.sync.aligned.m16n8k16.row.col.f32.bf16.bf16.f32 "
        "{%0,%1,%2,%3}, {%4,%5,%6,%7}, {%8,%9}, {%0,%1,%2,%3};"
        : "+f"(d[0]), "+f"(d[1]), "+f"(d[2]), "+f"(d[3])
        : "r"(a[0]), "r"(a[1]), "r"(a[2]), "r"(a[3]), "r"(b0), "r"(b1));
}

// ---------------- prep: gene splits + normalized-row splits + sq + si ----------------
__global__ __launch_bounds__(256) void prep_kernel(const float* __restrict__ gene,
                                                   const float* __restrict__ sp,
                                                   const float* __restrict__ Ws,
                                                   const float* __restrict__ bs) {
    int row = blockIdx.x;
    const float* x = gene + (size_t)row * GENE;
    __shared__ float red[256];
    float a = __ldg(sp + 2 * row), b = __ldg(sp + 2 * row + 1);

    // si = sp @ Ws + bs  (one h per thread)
    {
        int h = threadIdx.x;
        float v = a * __ldg(Ws + h) + b * __ldg(Ws + HID + h) + __ldg(bs + h);
        bf16 hi = __float2bfloat16(v);
        g_sihi[row * HID + h] = hi;
        g_silo[row * HID + h] = __float2bfloat16(v - __bfloat162float(hi));
    }

    float ss = 0.f;
    for (int c = threadIdx.x; c < GENE; c += 256) { float v = x[c]; ss += v * v; }
    red[threadIdx.x] = ss; __syncthreads();
    for (int s = 128; s > 0; s >>= 1) {
        if (threadIdx.x < s) red[threadIdx.x] += red[threadIdx.x + s];
        __syncthreads();
    }
    float inv = 1.0f / fmaxf(sqrtf(red[0]), 1e-12f);
    for (int c = threadIdx.x; c < GENE; c += 256) {
        float v = x[c];
        bf16 gh = __float2bfloat16(v);
        g_Ghi[(size_t)row * GENE + c] = gh;
        g_Glo[(size_t)row * GENE + c] = __float2bfloat16(v - __bfloat162float(gh));
        float xn = v * inv;
        bf16 xh = __float2bfloat16(xn);
        bf16 xl = __float2bfloat16(xn - __bfloat162float(xh));
        size_t o = (size_t)row * YK + HID + c;
        g_Yhi[o] = xh; g_Ylo[o] = xl;
        g_Zhi[o] = xh; g_Zlo[o] = xl;
    }
    if (threadIdx.x == 0) g_sq[row] = a * a + b * b;
}

// ---------------- all weight transpose-splits + bias copies in one kernel ----------------
__global__ __launch_bounds__(256) void wsplit_all_kernel(
    const float* __restrict__ Wq, const float* __restrict__ Wk, const float* __restrict__ Wv,
    const float* __restrict__ W1, const float* __restrict__ W2,
    const float* __restrict__ bq, const float* __restrict__ bk, const float* __restrict__ bv) {
    int idx = blockIdx.x * 256 + threadIdx.x;
    if (idx < 393216) {                       // 3 x (256 x 512)
        int w = idx / 131072, r = idx % 131072;
        int n = r / GENE, k = r % GENE;
        const float* W = (w == 0) ? Wq : (w == 1) ? Wk : Wv;
        float v = W[(size_t)k * HID + n];
        bf16 h = __float2bfloat16(v);
        g_Wthi[idx] = h;
        g_Wtlo[idx] = __float2bfloat16(v - __bfloat162float(h));
    } else if (idx < 458752) {                // W1 (256 x 256)
        int r = idx - 393216;
        int n = r / HID, k = r % HID;
        float v = W1[(size_t)k * HID + n];
        bf16 h = __float2bfloat16(v);
        g_W1thi[r] = h;
        g_W1tlo[r] = __float2bfloat16(v - __bfloat162float(h));
    } else if (idx < 524288) {                // W2
        int r = idx - 458752;
        int n = r / HID, k = r % HID;
        float v = W2[(size_t)k * HID + n];
        bf16 h = __float2bfloat16(v);
        g_W2thi[r] = h;
        g_W2tlo[r] = __float2bfloat16(v - __bfloat162float(h));
    } else {                                  // biases
        int t = idx - 524288;
        if (t < 256)      g_bias[t] = bq[t];
        else if (t < 512) g_bias[t] = bk[t - 256];
        else if (t < 768) g_bias[t] = bv[t - 512];
    }
}

// ---------------- f = e @ Wf + bf (warp per row) ----------------
__global__ __launch_bounds__(256) void f_kernel(const float* __restrict__ Wf,
                                                const float* __restrict__ bf_) {
    int row = blockIdx.x * 8 + (threadIdx.x >> 5);
    int lane = threadIdx.x & 31;
    const float* e = g_E + (size_t)row * HID + lane * 8;
    float s = 0.f;
    #pragma unroll
    for (int i = 0; i < 8; i++) s += e[i] * __ldg(Wf + lane * 8 + i);
    #pragma unroll
    for (int o = 16; o > 0; o >>= 1) s += __shfl_xor_sync(0xFFFFFFFFu, s, o);
    if (lane == 0) g_f[row] = s + bf_[0];
}

// ---------------- HMMA split-bf16 GEMM, BK=64, XOR-swizzle, 3-stage pipeline ----------------
// modes: 0 = fp32 C (+bias)*alpha (per-z C offset)
//        1 = logits epilogue -> g_L
//        4 = tanh split -> Dhi/Dlo
//        5 = relu fp32 -> C
//        6 = QKV combined (z: 0->Q into Y, 1->K into Z, 2->V transpose split)
#define BM 128
#define BN 128
#define BK 64
#define TILEB  16384                 // 128 rows x 128B
#define STAGEB (2 * TILEB)           // A + B
#define NSTAGE 3
#define SMEMSZ (NSTAGE * STAGEB)     // 98304

__global__ __launch_bounds__(256, 2) void hmma_gemm(
    const bf16* __restrict__ a0, const bf16* __restrict__ a1, const bf16* __restrict__ a2,
    const bf16* __restrict__ b0, const bf16* __restrict__ b1, const bf16* __restrict__ b2,
    int pitchA, int pitchB, int cb1, int cb2, int chunks_per_z, int zchunks,
    size_t zBstride, int mode,
    float* __restrict__ C, int ldc, size_t zCstride,
    const float* __restrict__ bias, float alpha,
    bf16* __restrict__ Dhi, bf16* __restrict__ Dlo, int ldd,
    const float* __restrict__ sp)
{
    extern __shared__ __align__(16) char smem[];
    const uint32_t sbase = s2u(smem);
    const int tid  = threadIdx.x;
    const int lane = tid & 31;
    const int wid  = tid >> 5;
    const int wm   = (wid & 3) * 32;
    const int wn   = (wid >> 2) * 64;
    const int gm0  = blockIdx.y * BM;
    const int gn0  = blockIdx.x * BN;
    const int z    = blockIdx.z;

    if (zBstride) { b0 += z * zBstride; b1 += z * zBstride; b2 += z * zBstride; }
    const int g0 = z * zchunks;

    const int mi    = lane >> 3;
    const int ldrow = ((mi & 1) << 3) + (lane & 7);
    const int ldc16 = mi >> 1;           // 16B-chunk offset within 32B k-slice
    // cp.async slots: 1024 per tile, 4 per thread
    const int srow0 = tid >> 3;          // rows: tid>>3 + i*32
    const int sc    = tid & 7;

    float acc[2][8][4];
    #pragma unroll
    for (int a = 0; a < 2; a++)
        #pragma unroll
        for (int b = 0; b < 8; b++)
            #pragma unroll
            for (int c = 0; c < 4; c++) acc[a][b][c] = 0.f;

    // ---- chunk loader ----
    auto load_chunk = [&](int g, int stage) {
        const bf16 *As, *Bs; int kk;
        if (g < cb1)      { As = a0; Bs = b0; kk = g * BK; }
        else if (g < cb2) { As = a1; Bs = b1; kk = (g - cb1) * BK; }
        else              { As = a2; Bs = b2; kk = (g - cb2) * BK; }
        uint32_t dst = sbase + stage * STAGEB;
        #pragma unroll
        for (int i = 0; i < 4; i++) {
            int row = srow0 + i * 32;
            uint32_t off = (uint32_t)(row * 128 + ((sc ^ (row & 7)) << 4));
            cp16(dst + off,         As + (size_t)(gm0 + row) * pitchA + kk + sc * 8);
            cp16(dst + TILEB + off, Bs + (size_t)(gn0 + row) * pitchB + kk + sc * 8);
        }
        cp_commit();
    };

    // prologue: stages 0,1
    load_chunk(g0, 0);
    if (chunks_per_z > 1) load_chunk(g0 + 1, 1);
    else cp_commit();   // keep group count consistent

    for (int c = 0; c < chunks_per_z; c++) {
        if (c + 1 < chunks_per_z) cp_wait<1>(); else cp_wait<0>();
        __syncthreads();
        if (c + 2 < chunks_per_z) load_chunk(g0 + c + 2, (c + 2) % NSTAGE);

        uint32_t abase = sbase + (c % NSTAGE) * STAGEB;
        uint32_t bbase = abase + TILEB;
        #pragma unroll
        for (int ks = 0; ks < 4; ks++) {
            uint32_t afrag[2][4];
            uint32_t bfrag[4][4];
            int c16 = ks * 2 + ldc16;
            #pragma unroll
            for (int mt = 0; mt < 2; mt++) {
                int row = wm + mt * 16 + ldrow;
                ldm4(afrag[mt], abase + row * 128 + ((c16 ^ (row & 7)) << 4));
            }
            #pragma unroll
            for (int p = 0; p < 4; p++) {
                int row = wn + p * 16 + ldrow;
                ldm4(bfrag[p], bbase + row * 128 + ((c16 ^ (row & 7)) << 4));
            }
            #pragma unroll
            for (int mt = 0; mt < 2; mt++) {
                #pragma unroll
                for (int p = 0; p < 4; p++) {
                    mma_bf16(acc[mt][2 * p],     afrag[mt], bfrag[p][0], bfrag[p][2]);
                    mma_bf16(acc[mt][2 * p + 1], afrag[mt], bfrag[p][1], bfrag[p][3]);
                }
            }
        }
    }

    // ---- epilogue ----
    const int r0 = lane >> 2;
    const int cl = 2 * (lane & 3);

    if (mode == 1) {
        float* ex = (float*)smem;
        __syncthreads();
        for (int i = tid; i < BN; i += 256) {
            int n = gn0 + i;
            ex[i]           = __ldg(sp + 2 * n);
            ex[BN + i]      = __ldg(sp + 2 * n + 1);
            ex[2 * BN + i]  = g_sq[n];
            ex[3 * BN + i]  = g_f[n];
        }
        __syncthreads();
        #pragma unroll
        for (int mt = 0; mt < 2; mt++) {
            #pragma unroll
            for (int half = 0; half < 2; half++) {
                int m = gm0 + wm + mt * 16 + r0 + half * 8;
                float sp0 = __ldg(sp + 2 * m), sp1 = __ldg(sp + 2 * m + 1);
                float sqi = g_sq[m], fi = g_f[m];
                #pragma unroll
                for (int nt = 0; nt < 8; nt++) {
                    int nl = wn + nt * 8 + cl;
                    float2 v;
                    #pragma unroll
                    for (int q = 0; q < 2; q++) {
                        int ci = nl + q;
                        float d2 = sqi + ex[2 * BN + ci]
                                 - 2.0f * (sp0 * ex[ci] + sp1 * ex[BN + ci]);
                        d2 = fmaxf(d2, 0.0f);
                        float a = acc[mt][nt][half * 2 + q];
                        ((float*)&v)[q] = a + __expf(-0.5f * d2) + tanhf(fi - ex[3 * BN + ci]);
                    }
                    *(float2*)(g_L + (size_t)m * Nn + gn0 + nl) = v;
                }
            }
        }
    } else if (mode == 0) {
        float* Cz = C + z * zCstride;
        #pragma unroll
        for (int mt = 0; mt < 2; mt++)
            #pragma unroll
            for (int half = 0; half < 2; half++) {
                int m = gm0 + wm + mt * 16 + r0 + half * 8;
                #pragma unroll
                for (int nt = 0; nt < 8; nt++) {
                    int n = gn0 + wn + nt * 8 + cl;
                    float b0v = bias ? __ldg(bias + n)     : 0.f;
                    float b1v = bias ? __ldg(bias + n + 1) : 0.f;
                    float2 v;
                    v.x = (acc[mt][nt][half * 2 + 0] + b0v) * alpha;
                    v.y = (acc[mt][nt][half * 2 + 1] + b1v) * alpha;
                    *(float2*)(Cz + (size_t)m * ldc + n) = v;
                }
            }
    } else if (mode == 4 || mode == 5) {
        #pragma unroll
        for (int mt = 0; mt < 2; mt++)
            #pragma unroll
            for (int half = 0; half < 2; half++) {
                int m = gm0 + wm + mt * 16 + r0 + half * 8;
                #pragma unroll
                for (int nt = 0; nt < 8; nt++) {
                    int n = gn0 + wn + nt * 8 + cl;
                    #pragma unroll
                    for (int q = 0; q < 2; q++) {
                        float v = acc[mt][nt][half * 2 + q] + __ldg(bias + n + q);
                        if (mode == 4) {
                            v = tanhf(v);
                            bf16 h = __float2bfloat16(v);
                            Dhi[(size_t)m * ldd + n + q] = h;
                            Dlo[(size_t)m * ldd + n + q] = __float2bfloat16(v - __bfloat162float(h));
                        } else {
                            C[(size_t)m * ldc + n + q] = fmaxf(v, 0.f);
                        }
                    }
                }
            }
    } else { // mode 6: QKV combined
        const float* bias6 = g_bias + z * 256;
        if (z == 2) {
            #pragma unroll
            for (int mt = 0; mt < 2; mt++)
                #pragma unroll
                for (int half = 0; half < 2; half++) {
                    int m = gm0 + wm + mt * 16 + r0 + half * 8;
                    #pragma unroll
                    for (int nt = 0; nt < 8; nt++) {
                        int n = gn0 + wn + nt * 8 + cl;
                        #pragma unroll
                        for (int q = 0; q < 2; q++) {
                            float v = acc[mt][nt][half * 2 + q] + bias6[n + q];
                            bf16 h = __float2bfloat16(v);
                            g_Vthi[(size_t)(n + q) * Nn + m] = h;
                            g_Vtlo[(size_t)(n + q) * Nn + m] = __float2bfloat16(v - __bfloat162float(h));
                        }
                    }
                }
        } else {
            bf16* Dh = z ? g_Zhi : g_Yhi;
            bf16* Dl = z ? g_Zlo : g_Ylo;
            float al = z ? 1.0f : (1.0f / 16.0f);
            #pragma unroll
            for (int mt = 0; mt < 2; mt++)
                #pragma unroll
                for (int half = 0; half < 2; half++) {
                    int m = gm0 + wm + mt * 16 + r0 + half * 8;
                    #pragma unroll
                    for (int nt = 0; nt < 8; nt++) {
                        int n = gn0 + wn + nt * 8 + cl;
                        #pragma unroll
                        for (int q = 0; q < 2; q++) {
                            float v = (acc[mt][nt][half * 2 + q] + bias6[n + q]) * al;
                            bf16 h = __float2bfloat16(v);
                            Dh[(size_t)m * YK + n + q] = h;
                            Dl[(size_t)m * YK + n + q] = __float2bfloat16(v - __bfloat162float(h));
                        }
                    }
                }
        }
    }
}

// ---------------- softmax: 512 threads per row, exp values held in regs ----------------
__global__ __launch_bounds__(512) void softmax_kernel(float* __restrict__ attn) {
    int row = blockIdx.x;
    int tid = threadIdx.x;
    float* L = g_L + (size_t)row * Nn;
    __shared__ float red[512];
    float4 v[2];
    float m = -1e30f;
    #pragma unroll
    for (int i = 0; i < 2; i++) {
        v[i] = *(const float4*)(L + tid * 4 + i * 2048);
        m = fmaxf(m, fmaxf(fmaxf(v[i].x, v[i].y), fmaxf(v[i].z, v[i].w)));
    }
    red[tid] = m; __syncthreads();
    for (int s = 256; s > 0; s >>= 1) {
        if (tid < s) red[tid] = fmaxf(red[tid], red[tid + s]);
        __syncthreads();
    }
    float rm = red[0];
    __syncthreads();
    float sum = 0.f;
    #pragma unroll
    for (int i = 0; i < 2; i++) {
        v[i].x = __expf(v[i].x - rm);
        v[i].y = __expf(v[i].y - rm);
        v[i].z = __expf(v[i].z - rm);
        v[i].w = __expf(v[i].w - rm);
        sum += (v[i].x + v[i].y) + (v[i].z + v[i].w);
    }
    red[tid] = sum; __syncthreads();
    for (int s = 256; s > 0; s >>= 1) {
        if (tid < s) red[tid] += red[tid + s];
        __syncthreads();
    }
    float inv = 1.0f / red[0];
    #pragma unroll
    for (int i = 0; i < 2; i++) {
        int j = tid * 4 + i * 2048;
        float4 a;
        a.x = v[i].x * inv; a.y = v[i].y * inv; a.z = v[i].z * inv; a.w = v[i].w * inv;
        *(float4*)(attn + (size_t)row * Nn + j) = a;
        float* ap = (float*)&a;
        bf16 h[4], l[4];
        #pragma unroll
        for (int q = 0; q < 4; q++) {
            h[q] = __float2bfloat16(ap[q]);
            l[q] = __float2bfloat16(ap[q] - __bfloat162float(h[q]));
        }
        *(__nv_bfloat162*)(g_Ahi + (size_t)row * Nn + j)     = __nv_bfloat162(h[0], h[1]);
        *(__nv_bfloat162*)(g_Ahi + (size_t)row * Nn + j + 2) = __nv_bfloat162(h[2], h[3]);
        *(__nv_bfloat162*)(g_Alo + (size_t)row * Nn + j)     = __nv_bfloat162(l[0], l[1]);
        *(__nv_bfloat162*)(g_Alo + (size_t)row * Nn + j + 2) = __nv_bfloat162(l[2], l[3]);
    }
}

// ---------------- reduce split-K partials ----------------
__global__ __launch_bounds__(256) void reduce_kernel(float* __restrict__ upd) {
    size_t i = ((size_t)blockIdx.x * 256 + threadIdx.x) * 4;
    float4 s = *(const float4*)(g_part + i);
    #pragma unroll
    for (int z = 1; z < 8; z++) {
        const float4 p = *(const float4*)(g_part + z * (size_t)Nn * OUTD + i);
        s.x += p.x; s.y += p.y; s.z += p.z; s.w += p.w;
    }
    *(float4*)(upd + i) = s;
}

// ---------------- launch ----------------
extern "C" void kernel_launch(void* const* d_in, const int* in_sizes, int n_in,
                              void* d_out, int out_size) {
    const float* gene = (const float*)d_in[0];
    const float* sp   = (const float*)d_in[1];
    const float* Wq   = (const float*)d_in[2];
    const float* bq   = (const float*)d_in[3];
    const float* Wk   = (const float*)d_in[4];
    const float* bk   = (const float*)d_in[5];
    const float* Wv   = (const float*)d_in[6];
    const float* bv   = (const float*)d_in[7];
    const float* Ws   = (const float*)d_in[8];
    const float* bs   = (const float*)d_in[9];
    const float* W1   = (const float*)d_in[10];
    const float* b1   = (const float*)d_in[11];
    const float* W2   = (const float*)d_in[12];
    const float* b2   = (const float*)d_in[13];
    const float* Wf   = (const float*)d_in[14];
    const float* bf_  = (const float*)d_in[15];

    float* out = (float*)d_out;
    long long total = (long long)Nn * Nn + (long long)Nn * OUTD;
    int has_attn = ((long long)out_size >= total) ? 1 : 0;
    float* attn = out;
    float* upd  = has_attn ? out + (size_t)Nn * Nn : out;

    bf16 *pGhi, *pGlo, *pYhi, *pYlo, *pZhi, *pZlo, *pAhi, *pAlo, *pVthi, *pVtlo;
    bf16 *pWthi, *pWtlo, *pW1thi, *pW1tlo, *pW2thi, *pW2tlo, *psihi, *psilo, *phhi, *phlo;
    float *pE, *pPart;
    cudaGetSymbolAddress((void**)&pGhi, g_Ghi);
    cudaGetSymbolAddress((void**)&pGlo, g_Glo);
    cudaGetSymbolAddress((void**)&pYhi, g_Yhi);
    cudaGetSymbolAddress((void**)&pYlo, g_Ylo);
    cudaGetSymbolAddress((void**)&pZhi, g_Zhi);
    cudaGetSymbolAddress((void**)&pZlo, g_Zlo);
    cudaGetSymbolAddress((void**)&pAhi, g_Ahi);
    cudaGetSymbolAddress((void**)&pAlo, g_Alo);
    cudaGetSymbolAddress((void**)&pVthi, g_Vthi);
    cudaGetSymbolAddress((void**)&pVtlo, g_Vtlo);
    cudaGetSymbolAddress((void**)&pWthi, g_Wthi);
    cudaGetSymbolAddress((void**)&pWtlo, g_Wtlo);
    cudaGetSymbolAddress((void**)&pW1thi, g_W1thi);
    cudaGetSymbolAddress((void**)&pW1tlo, g_W1tlo);
    cudaGetSymbolAddress((void**)&pW2thi, g_W2thi);
    cudaGetSymbolAddress((void**)&pW2tlo, g_W2tlo);
    cudaGetSymbolAddress((void**)&psihi, g_sihi);
    cudaGetSymbolAddress((void**)&psilo, g_silo);
    cudaGetSymbolAddress((void**)&phhi, g_hhi);
    cudaGetSymbolAddress((void**)&phlo, g_hlo);
    cudaGetSymbolAddress((void**)&pE, g_E);
    cudaGetSymbolAddress((void**)&pPart, g_part);

    cudaFuncSetAttribute(hmma_gemm, cudaFuncAttributeMaxDynamicSharedMemorySize, SMEMSZ);

    // 0) prep (+ si)
    prep_kernel<<<Nn, 256>>>(gene, sp, Ws, bs);

    // 1) all weight splits + biases
    wsplit_all_kernel<<<2051, 256>>>(Wq, Wk, Wv, W1, W2, bq, bk, bv);

    // 2) MLP gemm 1: h = tanh(si@W1+b1) split  (chunks: 4|4|4)
    dim3 gMLP(HID / BN, Nn / BM, 1);
    hmma_gemm<<<gMLP, 256, SMEMSZ>>>(psihi, psilo, psihi, pW1thi, pW1thi, pW1tlo,
                                     HID, HID, 4, 8, 12, 0, 0, 4,
                                     nullptr, 0, 0, b1, 1.0f, phhi, phlo, HID, nullptr);
    // 3) MLP gemm 2: e = relu(h@W2+b2) fp32
    hmma_gemm<<<gMLP, 256, SMEMSZ>>>(phhi, phlo, phhi, pW2thi, pW2thi, pW2tlo,
                                     HID, HID, 4, 8, 12, 0, 0, 5,
                                     pE, HID, 0, b2, 1.0f, nullptr, nullptr, 0, nullptr);
    // 4) f = e@Wf + bf
    f_kernel<<<Nn / 8, 256>>>(Wf, bf_);

    // 5) QKV combined (mode 6): grid (2, 32, 3), chunks 8|8|8
    dim3 gQKV(HID / BN, Nn / BM, 3);
    hmma_gemm<<<gQKV, 256, SMEMSZ>>>(pGhi, pGlo, pGhi, pWthi, pWthi, pWtlo,
                                     GENE, GENE, 8, 16, 24, 0, (size_t)HID * GENE, 6,
                                     nullptr, 0, 0, nullptr, 1.0f, nullptr, nullptr, 0, nullptr);

    // 6) logits: YhiZhi(768->12ch) | YloZhi(QK 256->4ch) | YhiZlo(QK 256->4ch) + epilogue
    dim3 gLg(Nn / BN, Nn / BM, 1);
    hmma_gemm<<<gLg, 256, SMEMSZ>>>(pYhi, pYlo, pYhi, pZhi, pZhi, pZlo,
                                    YK, YK, 12, 16, 20, 0, 0, 1,
                                    nullptr, 0, 0, nullptr, 1.0f, nullptr, nullptr, 0, sp);

    // 7) softmax -> attn + A splits
    softmax_kernel<<<Nn, 512>>>(attn);

    // 8) A@V split-K x8 -> partials (chunks/z = 24, segs 64|64|64)
    dim3 gAV(OUTD / BN, Nn / BM, 8);
    hmma_gemm<<<gAV, 256, SMEMSZ>>>(pAhi, pAlo, pAhi, pVthi, pVthi, pVtlo,
                                    Nn, Nn, 64, 128, 24, 24, 0, 0,
                                    pPart, OUTD, (size_t)Nn * OUTD, nullptr, 1.0f,
                                    nullptr, nullptr, 0, nullptr);
    // 9) reduce partials
    reduce_kernel<<<(Nn * OUTD) / 1024, 256>>>(upd);
}

// round 7
// speedup vs baseline: 7.1421x; 1.0112x over previous
#include <cuda_runtime.h>
#include <cuda_bf16.h>
#include <math.h>
#include <stdint.h>

#define Nn    4096
#define GENE  512
#define HID   256
#define OUTD  256
#define YK    768     // HID + GENE fused logits depth

typedef __nv_bfloat16 bf16;

// ---------------- scratch (static device globals; no runtime allocs) ----------------
__device__ __align__(16) float g_L[(size_t)Nn * Nn];      // logits
__device__ __align__(16) bf16  g_Ghi[Nn * GENE];
__device__ __align__(16) bf16  g_Glo[Nn * GENE];
__device__ __align__(16) bf16  g_Yhi[Nn * YK];
__device__ __align__(16) bf16  g_Ylo[Nn * YK];
__device__ __align__(16) bf16  g_Zhi[Nn * YK];
__device__ __align__(16) bf16  g_Zlo[Nn * YK];
__device__ __align__(16) bf16  g_Ahi[(size_t)Nn * Nn];
__device__ __align__(16) bf16  g_Alo[(size_t)Nn * Nn];
__device__ __align__(16) bf16  g_Vthi[OUTD * Nn];
__device__ __align__(16) bf16  g_Vtlo[OUTD * Nn];
__device__ __align__(16) bf16  g_Wthi[3 * HID * GENE];    // W^T splits (q,k,v)
__device__ __align__(16) bf16  g_Wtlo[3 * HID * GENE];
__device__ __align__(16) bf16  g_W1thi[HID * HID];
__device__ __align__(16) bf16  g_W1tlo[HID * HID];
__device__ __align__(16) bf16  g_W2thi[HID * HID];
__device__ __align__(16) bf16  g_W2tlo[HID * HID];
__device__ __align__(16) bf16  g_sihi[Nn * HID];
__device__ __align__(16) bf16  g_silo[Nn * HID];
__device__ __align__(16) bf16  g_hhi[Nn * HID];
__device__ __align__(16) bf16  g_hlo[Nn * HID];
__device__ __align__(16) float g_E[Nn * HID];
__device__ __align__(16) float g_part[8 * (size_t)Nn * OUTD];   // A@V split-K partials
__device__ __align__(16) float g_bias[3 * 256];                  // bq|bk|bv
__device__ float g_f[Nn];     // holds clamp(tanh(f)) after f_kernel
__device__ float g_sq[Nn];

// ---------------- PTX helpers (sm_80+ baseline) ----------------
__device__ __forceinline__ uint32_t s2u(const void* p) {
    uint32_t a;
    asm("{ .reg .u64 t; cvta.to.shared.u64 t, %1; cvt.u32.u64 %0, t; }" : "=r"(a) : "l"(p));
    return a;
}
__device__ __forceinline__ void cp16(uint32_t dst, const void* src) {
    asm volatile("cp.async.cg.shared.global [%0], [%1], 16;" :: "r"(dst), "l"(src));
}
__device__ __forceinline__ void cp_commit() {
    asm volatile("cp.async.commit_group;" ::: "memory");
}
template <int N>
__device__ __forceinline__ void cp_wait() {
    asm volatile("cp.async.wait_group %0;" :: "n"(N) : "memory");
}
__device__ __forceinline__ void ldm4(uint32_t* r, uint32_t addr) {
    asm volatile("ldmatrix.sync.aligned.m8n8.x4.shared.b16 {%0,%1,%2,%3}, [%4];"
                 : "=r"(r[0]), "=r"(r[1]), "=r"(r[2]), "=r"(r[3]) : "r"(addr));
}
__device__ __forceinline__ void mma_bf16(float* d, const uint32_t* a, uint32_t b0, uint32_t b1) {
    asm volatile(
        "mma.sync.aligned.m16n8k16.row.col.f32.bf16.bf16.f32 "
        "{%0,%1,%2,%3}, {%4,%5,%6,%7}, {%8,%9}, {%0,%1,%2,%3};"
        : "+f"(d[0]), "+f"(d[1]), "+f"(d[2]), "+f"(d[3])
        : "r"(a[0]), "r"(a[1]), "r"(a[2]), "r"(a[3]), "r"(b0), "r"(b1));
}

// ---------------- prep: gene splits + normalized-row splits + sq + si ----------------
__global__ __launch_bounds__(256) void prep_kernel(const float* __restrict__ gene,
                                                   const float* __restrict__ sp,
                                                   const float* __restrict__ Ws,
                                                   const float* __restrict__ bs) {
    int row = blockIdx.x;
    const float* x = gene + (size_t)row * GENE;
    __shared__ float red[256];
    float a = __ldg(sp + 2 * row), b = __ldg(sp + 2 * row + 1);

    // si = sp @ Ws + bs  (one h per thread)
    {
        int h = threadIdx.x;
        float v = a * __ldg(Ws + h) + b * __ldg(Ws + HID + h) + __ldg(bs + h);
        bf16 hi = __float2bfloat16(v);
        g_sihi[row * HID + h] = hi;
        g_silo[row * HID + h] = __float2bfloat16(v - __bfloat162float(hi));
    }

    float ss = 0.f;
    for (int c = threadIdx.x; c < GENE; c += 256) { float v = x[c]; ss += v * v; }
    red[threadIdx.x] = ss; __syncthreads();
    for (int s = 128; s > 0; s >>= 1) {
        if (threadIdx.x < s) red[threadIdx.x] += red[threadIdx.x + s];
        __syncthreads();
    }
    float inv = 1.0f / fmaxf(sqrtf(red[0]), 1e-12f);
    for (int c = threadIdx.x; c < GENE; c += 256) {
        float v = x[c];
        bf16 gh = __float2bfloat16(v);
        g_Ghi[(size_t)row * GENE + c] = gh;
        g_Glo[(size_t)row * GENE + c] = __float2bfloat16(v - __bfloat162float(gh));
        float xn = v * inv;
        bf16 xh = __float2bfloat16(xn);
        bf16 xl = __float2bfloat16(xn - __bfloat162float(xh));
        size_t o = (size_t)row * YK + HID + c;
        g_Yhi[o] = xh; g_Ylo[o] = xl;
        g_Zhi[o] = xh; g_Zlo[o] = xl;
    }
    if (threadIdx.x == 0) g_sq[row] = a * a + b * b;
}

// ---------------- all weight transpose-splits + bias copies in one kernel ----------------
__global__ __launch_bounds__(256) void wsplit_all_kernel(
    const float* __restrict__ Wq, const float* __restrict__ Wk, const float* __restrict__ Wv,
    const float* __restrict__ W1, const float* __restrict__ W2,
    const float* __restrict__ bq, const float* __restrict__ bk, const float* __restrict__ bv) {
    int idx = blockIdx.x * 256 + threadIdx.x;
    if (idx < 393216) {                       // 3 x (256 x 512)
        int w = idx / 131072, r = idx % 131072;
        int n = r / GENE, k = r % GENE;
        const float* W = (w == 0) ? Wq : (w == 1) ? Wk : Wv;
        float v = W[(size_t)k * HID + n];
        bf16 h = __float2bfloat16(v);
        g_Wthi[idx] = h;
        g_Wtlo[idx] = __float2bfloat16(v - __bfloat162float(h));
    } else if (idx < 458752) {                // W1 (256 x 256)
        int r = idx - 393216;
        int n = r / HID, k = r % HID;
        float v = W1[(size_t)k * HID + n];
        bf16 h = __float2bfloat16(v);
        g_W1thi[r] = h;
        g_W1tlo[r] = __float2bfloat16(v - __bfloat162float(h));
    } else if (idx < 524288) {                // W2
        int r = idx - 458752;
        int n = r / HID, k = r % HID;
        float v = W2[(size_t)k * HID + n];
        bf16 h = __float2bfloat16(v);
        g_W2thi[r] = h;
        g_W2tlo[r] = __float2bfloat16(v - __bfloat162float(h));
    } else {                                  // biases
        int t = idx - 524288;
        if (t < 256)      g_bias[t] = bq[t];
        else if (t < 512) g_bias[t] = bk[t - 256];
        else if (t < 768) g_bias[t] = bv[t - 512];
    }
}

// ---------------- f_kernel: g_f = clamp(tanh(e @ Wf + bf)) (warp per row) ----------------
__global__ __launch_bounds__(256) void f_kernel(const float* __restrict__ Wf,
                                                const float* __restrict__ bf_) {
    int row = blockIdx.x * 8 + (threadIdx.x >> 5);
    int lane = threadIdx.x & 31;
    const float* e = g_E + (size_t)row * HID + lane * 8;
    float s = 0.f;
    #pragma unroll
    for (int i = 0; i < 8; i++) s += e[i] * __ldg(Wf + lane * 8 + i);
    #pragma unroll
    for (int o = 16; o > 0; o >>= 1) s += __shfl_xor_sync(0xFFFFFFFFu, s, o);
    if (lane == 0) {
        float t = tanhf(s + bf_[0]);
        g_f[row] = fminf(fmaxf(t, -0.999999f), 0.999999f);
    }
}

// ---------------- HMMA split-bf16 GEMM, BK=64, XOR-swizzle, 3-stage pipeline ----------------
// modes: 0 = fp32 C (+bias)*alpha (per-z C offset)
//        1 = logits epilogue -> g_L   (uses tanh-identity for spatial bias)
//        4 = tanh split -> Dhi/Dlo
//        5 = relu fp32 -> C
//        6 = QKV combined (z: 0->Q into Y, 1->K into Z, 2->V transpose split)
#define BM 128
#define BN 128
#define BK 64
#define TILEB  16384                 // 128 rows x 128B
#define STAGEB (2 * TILEB)           // A + B
#define NSTAGE 3
#define SMEMSZ (NSTAGE * STAGEB)     // 98304

__global__ __launch_bounds__(256, 2) void hmma_gemm(
    const bf16* __restrict__ a0, const bf16* __restrict__ a1, const bf16* __restrict__ a2,
    const bf16* __restrict__ b0, const bf16* __restrict__ b1, const bf16* __restrict__ b2,
    int pitchA, int pitchB, int cb1, int cb2, int chunks_per_z, int zchunks,
    size_t zBstride, int mode,
    float* __restrict__ C, int ldc, size_t zCstride,
    const float* __restrict__ bias, float alpha,
    bf16* __restrict__ Dhi, bf16* __restrict__ Dlo, int ldd,
    const float* __restrict__ sp)
{
    extern __shared__ __align__(16) char smem[];
    const uint32_t sbase = s2u(smem);
    const int tid  = threadIdx.x;
    const int lane = tid & 31;
    const int wid  = tid >> 5;
    const int wm   = (wid & 3) * 32;
    const int wn   = (wid >> 2) * 64;
    const int gm0  = blockIdx.y * BM;
    const int gn0  = blockIdx.x * BN;
    const int z    = blockIdx.z;

    if (zBstride) { b0 += z * zBstride; b1 += z * zBstride; b2 += z * zBstride; }
    const int g0 = z * zchunks;

    const int mi    = lane >> 3;
    const int ldrow = ((mi & 1) << 3) + (lane & 7);
    const int ldc16 = mi >> 1;           // 16B-chunk offset within 32B k-slice
    // cp.async slots: 1024 per tile, 4 per thread
    const int srow0 = tid >> 3;          // rows: tid>>3 + i*32
    const int sc    = tid & 7;

    float acc[2][8][4];
    #pragma unroll
    for (int a = 0; a < 2; a++)
        #pragma unroll
        for (int b = 0; b < 8; b++)
            #pragma unroll
            for (int c = 0; c < 4; c++) acc[a][b][c] = 0.f;

    // ---- chunk loader ----
    auto load_chunk = [&](int g, int stage) {
        const bf16 *As, *Bs; int kk;
        if (g < cb1)      { As = a0; Bs = b0; kk = g * BK; }
        else if (g < cb2) { As = a1; Bs = b1; kk = (g - cb1) * BK; }
        else              { As = a2; Bs = b2; kk = (g - cb2) * BK; }
        uint32_t dst = sbase + stage * STAGEB;
        #pragma unroll
        for (int i = 0; i < 4; i++) {
            int row = srow0 + i * 32;
            uint32_t off = (uint32_t)(row * 128 + ((sc ^ (row & 7)) << 4));
            cp16(dst + off,         As + (size_t)(gm0 + row) * pitchA + kk + sc * 8);
            cp16(dst + TILEB + off, Bs + (size_t)(gn0 + row) * pitchB + kk + sc * 8);
        }
        cp_commit();
    };

    // prologue: stages 0,1
    load_chunk(g0, 0);
    if (chunks_per_z > 1) load_chunk(g0 + 1, 1);
    else cp_commit();   // keep group count consistent

    for (int c = 0; c < chunks_per_z; c++) {
        if (c + 1 < chunks_per_z) cp_wait<1>(); else cp_wait<0>();
        __syncthreads();
        if (c + 2 < chunks_per_z) load_chunk(g0 + c + 2, (c + 2) % NSTAGE);

        uint32_t abase = sbase + (c % NSTAGE) * STAGEB;
        uint32_t bbase = abase + TILEB;
        #pragma unroll
        for (int ks = 0; ks < 4; ks++) {
            uint32_t afrag[2][4];
            uint32_t bfrag[4][4];
            int c16 = ks * 2 + ldc16;
            #pragma unroll
            for (int mt = 0; mt < 2; mt++) {
                int row = wm + mt * 16 + ldrow;
                ldm4(afrag[mt], abase + row * 128 + ((c16 ^ (row & 7)) << 4));
            }
            #pragma unroll
            for (int p = 0; p < 4; p++) {
                int row = wn + p * 16 + ldrow;
                ldm4(bfrag[p], bbase + row * 128 + ((c16 ^ (row & 7)) << 4));
            }
            #pragma unroll
            for (int mt = 0; mt < 2; mt++) {
                #pragma unroll
                for (int p = 0; p < 4; p++) {
                    mma_bf16(acc[mt][2 * p],     afrag[mt], bfrag[p][0], bfrag[p][2]);
                    mma_bf16(acc[mt][2 * p + 1], afrag[mt], bfrag[p][1], bfrag[p][3]);
                }
            }
        }
    }

    // ---- epilogue ----
    const int r0 = lane >> 2;
    const int cl = 2 * (lane & 3);

    if (mode == 1) {
        float* ex = (float*)smem;
        __syncthreads();
        for (int i = tid; i < BN; i += 256) {
            int n = gn0 + i;
            ex[i]           = __ldg(sp + 2 * n);
            ex[BN + i]      = __ldg(sp + 2 * n + 1);
            ex[2 * BN + i]  = g_sq[n];
            ex[3 * BN + i]  = g_f[n];     // tj = tanh(f_j), clamped
        }
        __syncthreads();
        #pragma unroll
        for (int mt = 0; mt < 2; mt++) {
            #pragma unroll
            for (int half = 0; half < 2; half++) {
                int m = gm0 + wm + mt * 16 + r0 + half * 8;
                float sp0 = __ldg(sp + 2 * m), sp1 = __ldg(sp + 2 * m + 1);
                float sqi = g_sq[m], ti = g_f[m];
                #pragma unroll
                for (int nt = 0; nt < 8; nt++) {
                    int nl = wn + nt * 8 + cl;
                    float2 v;
                    #pragma unroll
                    for (int q = 0; q < 2; q++) {
                        int ci = nl + q;
                        float d2 = sqi + ex[2 * BN + ci]
                                 - 2.0f * (sp0 * ex[ci] + sp1 * ex[BN + ci]);
                        d2 = fmaxf(d2, 0.0f);
                        float tj = ex[3 * BN + ci];
                        // tanh(fi - fj) = (ti - tj) / (1 - ti*tj)
                        float tb = __fdividef(ti - tj, fmaf(-ti, tj, 1.0f));
                        float a = acc[mt][nt][half * 2 + q];
                        ((float*)&v)[q] = a + __expf(-0.5f * d2) + tb;
                    }
                    *(float2*)(g_L + (size_t)m * Nn + gn0 + nl) = v;
                }
            }
        }
    } else if (mode == 0) {
        float* Cz = C + z * zCstride;
        #pragma unroll
        for (int mt = 0; mt < 2; mt++)
            #pragma unroll
            for (int half = 0; half < 2; half++) {
                int m = gm0 + wm + mt * 16 + r0 + half * 8;
                #pragma unroll
                for (int nt = 0; nt < 8; nt++) {
                    int n = gn0 + wn + nt * 8 + cl;
                    float b0v = bias ? __ldg(bias + n)     : 0.f;
                    float b1v = bias ? __ldg(bias + n + 1) : 0.f;
                    float2 v;
                    v.x = (acc[mt][nt][half * 2 + 0] + b0v) * alpha;
                    v.y = (acc[mt][nt][half * 2 + 1] + b1v) * alpha;
                    *(float2*)(Cz + (size_t)m * ldc + n) = v;
                }
            }
    } else if (mode == 4 || mode == 5) {
        #pragma unroll
        for (int mt = 0; mt < 2; mt++)
            #pragma unroll
            for (int half = 0; half < 2; half++) {
                int m = gm0 + wm + mt * 16 + r0 + half * 8;
                #pragma unroll
                for (int nt = 0; nt < 8; nt++) {
                    int n = gn0 + wn + nt * 8 + cl;
                    #pragma unroll
                    for (int q = 0; q < 2; q++) {
                        float v = acc[mt][nt][half * 2 + q] + __ldg(bias + n + q);
                        if (mode == 4) {
                            v = tanhf(v);
                            bf16 h = __float2bfloat16(v);
                            Dhi[(size_t)m * ldd + n + q] = h;
                            Dlo[(size_t)m * ldd + n + q] = __float2bfloat16(v - __bfloat162float(h));
                        } else {
                            C[(size_t)m * ldc + n + q] = fmaxf(v, 0.f);
                        }
                    }
                }
            }
    } else { // mode 6: QKV combined
        const float* bias6 = g_bias + z * 256;
        if (z == 2) {
            #pragma unroll
            for (int mt = 0; mt < 2; mt++)
                #pragma unroll
                for (int half = 0; half < 2; half++) {
                    int m = gm0 + wm + mt * 16 + r0 + half * 8;
                    #pragma unroll
                    for (int nt = 0; nt < 8; nt++) {
                        int n = gn0 + wn + nt * 8 + cl;
                        #pragma unroll
                        for (int q = 0; q < 2; q++) {
                            float v = acc[mt][nt][half * 2 + q] + bias6[n + q];
                            bf16 h = __float2bfloat16(v);
                            g_Vthi[(size_t)(n + q) * Nn + m] = h;
                            g_Vtlo[(size_t)(n + q) * Nn + m] = __float2bfloat16(v - __bfloat162float(h));
                        }
                    }
                }
        } else {
            bf16* Dh = z ? g_Zhi : g_Yhi;
            bf16* Dl = z ? g_Zlo : g_Ylo;
            float al = z ? 1.0f : (1.0f / 16.0f);
            #pragma unroll
            for (int mt = 0; mt < 2; mt++)
                #pragma unroll
                for (int half = 0; half < 2; half++) {
                    int m = gm0 + wm + mt * 16 + r0 + half * 8;
                    #pragma unroll
                    for (int nt = 0; nt < 8; nt++) {
                        int n = gn0 + wn + nt * 8 + cl;
                        #pragma unroll
                        for (int q = 0; q < 2; q++) {
                            float v = (acc[mt][nt][half * 2 + q] + bias6[n + q]) * al;
                            bf16 h = __float2bfloat16(v);
                            Dh[(size_t)m * YK + n + q] = h;
                            Dl[(size_t)m * YK + n + q] = __float2bfloat16(v - __bfloat162float(h));
                        }
                    }
                }
        }
    }
}

// ---------------- softmax: 512 threads per row, exp values held in regs ----------------
__global__ __launch_bounds__(512) void softmax_kernel(float* __restrict__ attn) {
    int row = blockIdx.x;
    int tid = threadIdx.x;
    float* L = g_L + (size_t)row * Nn;
    __shared__ float red[512];
    float4 v[2];
    float m = -1e30f;
    #pragma unroll
    for (int i = 0; i < 2; i++) {
        v[i] = *(const float4*)(L + tid * 4 + i * 2048);
        m = fmaxf(m, fmaxf(fmaxf(v[i].x, v[i].y), fmaxf(v[i].z, v[i].w)));
    }
    red[tid] = m; __syncthreads();
    for (int s = 256; s > 0; s >>= 1) {
        if (tid < s) red[tid] = fmaxf(red[tid], red[tid + s]);
        __syncthreads();
    }
    float rm = red[0];
    __syncthreads();
    float sum = 0.f;
    #pragma unroll
    for (int i = 0; i < 2; i++) {
        v[i].x = __expf(v[i].x - rm);
        v[i].y = __expf(v[i].y - rm);
        v[i].z = __expf(v[i].z - rm);
        v[i].w = __expf(v[i].w - rm);
        sum += (v[i].x + v[i].y) + (v[i].z + v[i].w);
    }
    red[tid] = sum; __syncthreads();
    for (int s = 256; s > 0; s >>= 1) {
        if (tid < s) red[tid] += red[tid + s];
        __syncthreads();
    }
    float inv = 1.0f / red[0];
    #pragma unroll
    for (int i = 0; i < 2; i++) {
        int j = tid * 4 + i * 2048;
        float4 a;
        a.x = v[i].x * inv; a.y = v[i].y * inv; a.z = v[i].z * inv; a.w = v[i].w * inv;
        *(float4*)(attn + (size_t)row * Nn + j) = a;
        float* ap = (float*)&a;
        bf16 h[4], l[4];
        #pragma unroll
        for (int q = 0; q < 4; q++) {
            h[q] = __float2bfloat16(ap[q]);
            l[q] = __float2bfloat16(ap[q] - __bfloat162float(h[q]));
        }
        *(__nv_bfloat162*)(g_Ahi + (size_t)row * Nn + j)     = __nv_bfloat162(h[0], h[1]);
        *(__nv_bfloat162*)(g_Ahi + (size_t)row * Nn + j + 2) = __nv_bfloat162(h[2], h[3]);
        *(__nv_bfloat162*)(g_Alo + (size_t)row * Nn + j)     = __nv_bfloat162(l[0], l[1]);
        *(__nv_bfloat162*)(g_Alo + (size_t)row * Nn + j + 2) = __nv_bfloat162(l[2], l[3]);
    }
}

// ---------------- reduce split-K partials ----------------
__global__ __launch_bounds__(256) void reduce_kernel(float* __restrict__ upd) {
    size_t i = ((size_t)blockIdx.x * 256 + threadIdx.x) * 4;
    float4 s = *(const float4*)(g_part + i);
    #pragma unroll
    for (int z = 1; z < 8; z++) {
        const float4 p = *(const float4*)(g_part + z * (size_t)Nn * OUTD + i);
        s.x += p.x; s.y += p.y; s.z += p.z; s.w += p.w;
    }
    *(float4*)(upd + i) = s;
}

// ---------------- launch ----------------
extern "C" void kernel_launch(void* const* d_in, const int* in_sizes, int n_in,
                              void* d_out, int out_size) {
    const float* gene = (const float*)d_in[0];
    const float* sp   = (const float*)d_in[1];
    const float* Wq   = (const float*)d_in[2];
    const float* bq   = (const float*)d_in[3];
    const float* Wk   = (const float*)d_in[4];
    const float* bk   = (const float*)d_in[5];
    const float* Wv   = (const float*)d_in[6];
    const float* bv   = (const float*)d_in[7];
    const float* Ws   = (const float*)d_in[8];
    const float* bs   = (const float*)d_in[9];
    const float* W1   = (const float*)d_in[10];
    const float* b1   = (const float*)d_in[11];
    const float* W2   = (const float*)d_in[12];
    const float* b2   = (const float*)d_in[13];
    const float* Wf   = (const float*)d_in[14];
    const float* bf_  = (const float*)d_in[15];

    float* out = (float*)d_out;
    long long total = (long long)Nn * Nn + (long long)Nn * OUTD;
    int has_attn = ((long long)out_size >= total) ? 1 : 0;
    float* attn = out;
    float* upd  = has_attn ? out + (size_t)Nn * Nn : out;

    bf16 *pGhi, *pGlo, *pYhi, *pYlo, *pZhi, *pZlo, *pAhi, *pAlo, *pVthi, *pVtlo;
    bf16 *pWthi, *pWtlo, *pW1thi, *pW1tlo, *pW2thi, *pW2tlo, *psihi, *psilo, *phhi, *phlo;
    float *pE, *pPart;
    cudaGetSymbolAddress((void**)&pGhi, g_Ghi);
    cudaGetSymbolAddress((void**)&pGlo, g_Glo);
    cudaGetSymbolAddress((void**)&pYhi, g_Yhi);
    cudaGetSymbolAddress((void**)&pYlo, g_Ylo);
    cudaGetSymbolAddress((void**)&pZhi, g_Zhi);
    cudaGetSymbolAddress((void**)&pZlo, g_Zlo);
    cudaGetSymbolAddress((void**)&pAhi, g_Ahi);
    cudaGetSymbolAddress((void**)&pAlo, g_Alo);
    cudaGetSymbolAddress((void**)&pVthi, g_Vthi);
    cudaGetSymbolAddress((void**)&pVtlo, g_Vtlo);
    cudaGetSymbolAddress((void**)&pWthi, g_Wthi);
    cudaGetSymbolAddress((void**)&pWtlo, g_Wtlo);
    cudaGetSymbolAddress((void**)&pW1thi, g_W1thi);
    cudaGetSymbolAddress((void**)&pW1tlo, g_W1tlo);
    cudaGetSymbolAddress((void**)&pW2thi, g_W2thi);
    cudaGetSymbolAddress((void**)&pW2tlo, g_W2tlo);
    cudaGetSymbolAddress((void**)&psihi, g_sihi);
    cudaGetSymbolAddress((void**)&psilo, g_silo);
    cudaGetSymbolAddress((void**)&phhi, g_hhi);
    cudaGetSymbolAddress((void**)&phlo, g_hlo);
    cudaGetSymbolAddress((void**)&pE, g_E);
    cudaGetSymbolAddress((void**)&pPart, g_part);

    cudaFuncSetAttribute(hmma_gemm, cudaFuncAttributeMaxDynamicSharedMemorySize, SMEMSZ);

    // 0) prep (+ si)
    prep_kernel<<<Nn, 256>>>(gene, sp, Ws, bs);

    // 1) all weight splits + biases
    wsplit_all_kernel<<<2051, 256>>>(Wq, Wk, Wv, W1, W2, bq, bk, bv);

    // 2) MLP gemm 1: h = tanh(si@W1+b1) split  (chunks: 4|4|4)
    dim3 gMLP(HID / BN, Nn / BM, 1);
    hmma_gemm<<<gMLP, 256, SMEMSZ>>>(psihi, psilo, psihi, pW1thi, pW1thi, pW1tlo,
                                     HID, HID, 4, 8, 12, 0, 0, 4,
                                     nullptr, 0, 0, b1, 1.0f, phhi, phlo, HID, nullptr);
    // 3) MLP gemm 2: e = relu(h@W2+b2) fp32
    hmma_gemm<<<gMLP, 256, SMEMSZ>>>(phhi, phlo, phhi, pW2thi, pW2thi, pW2tlo,
                                     HID, HID, 4, 8, 12, 0, 0, 5,
                                     pE, HID, 0, b2, 1.0f, nullptr, nullptr, 0, nullptr);
    // 4) g_f = clamp(tanh(e@Wf + bf))
    f_kernel<<<Nn / 8, 256>>>(Wf, bf_);

    // 5) QKV combined (mode 6): grid (2, 32, 3), chunks 8|8|8
    dim3 gQKV(HID / BN, Nn / BM, 3);
    hmma_gemm<<<gQKV, 256, SMEMSZ>>>(pGhi, pGlo, pGhi, pWthi, pWthi, pWtlo,
                                     GENE, GENE, 8, 16, 24, 0, (size_t)HID * GENE, 6,
                                     nullptr, 0, 0, nullptr, 1.0f, nullptr, nullptr, 0, nullptr);

    // 6) logits: YhiZhi(768->12ch) | YloZhi(QK 256->4ch) | YhiZlo(QK 256->4ch) + epilogue
    dim3 gLg(Nn / BN, Nn / BM, 1);
    hmma_gemm<<<gLg, 256, SMEMSZ>>>(pYhi, pYlo, pYhi, pZhi, pZhi, pZlo,
                                    YK, YK, 12, 16, 20, 0, 0, 1,
                                    nullptr, 0, 0, nullptr, 1.0f, nullptr, nullptr, 0, sp);

    // 7) softmax -> attn + A splits
    softmax_kernel<<<Nn, 512>>>(attn);

    // 8) A@V split-K x8 -> partials (chunks/z = 24, segs 64|64|64)
    dim3 gAV(OUTD / BN, Nn / BM, 8);
    hmma_gemm<<<gAV, 256, SMEMSZ>>>(pAhi, pAlo, pAhi, pVthi, pVthi, pVtlo,
                                    Nn, Nn, 64, 128, 24, 24, 0, 0,
                                    pPart, OUTD, (size_t)Nn * OUTD, nullptr, 1.0f,
                                    nullptr, nullptr, 0, nullptr);
    // 9) reduce partials
    reduce_kernel<<<(Nn * OUTD) / 1024, 256>>>(upd);
}

// round 8
// speedup vs baseline: 8.7455x; 1.2245x over previous
#include <cuda_runtime.h>
#include <cuda_fp16.h>
#include <math.h>
#include <stdint.h>

#define Nn    4096
#define GENE  512
#define HID   256
#define OUTD  256
#define YK    768     // HID + GENE fused logits depth

typedef __half hf;

// ---------------- scratch (static device globals; no runtime allocs) ----------------
__device__ __align__(16) float g_L[(size_t)Nn * Nn];      // logits
__device__ __align__(16) hf    g_Ghi[Nn * GENE];
__device__ __align__(16) hf    g_Glo[Nn * GENE];
__device__ __align__(16) hf    g_Yhi[Nn * YK];
__device__ __align__(16) hf    g_Ylo[Nn * YK];
__device__ __align__(16) hf    g_Zhi[Nn * YK];
__device__ __align__(16) hf    g_Ahi[(size_t)Nn * Nn];
__device__ __align__(16) hf    g_Alo[(size_t)Nn * Nn];
__device__ __align__(16) hf    g_Vthi[OUTD * Nn];
__device__ __align__(16) hf    g_Wthi[3 * HID * GENE];    // W^T hi (q,k,v)
__device__ __align__(16) hf    g_W1thi[HID * HID];
__device__ __align__(16) hf    g_W2thi[HID * HID];
__device__ __align__(16) hf    g_sihi[Nn * HID];
__device__ __align__(16) hf    g_silo[Nn * HID];
__device__ __align__(16) hf    g_hhi[Nn * HID];
__device__ __align__(16) hf    g_hlo[Nn * HID];
__device__ __align__(16) float g_E[Nn * HID];
__device__ __align__(16) float g_part[8 * (size_t)Nn * OUTD];   // A@V split-K partials
__device__ __align__(16) float g_bias[3 * 256];                  // bq|bk|bv
__device__ float g_f[Nn];     // holds clamp(tanh(f)) after f_kernel
__device__ float g_sq[Nn];

// ---------------- PTX helpers (sm_80+ baseline) ----------------
__device__ __forceinline__ uint32_t s2u(const void* p) {
    uint32_t a;
    asm("{ .reg .u64 t; cvta.to.shared.u64 t, %1; cvt.u32.u64 %0, t; }" : "=r"(a) : "l"(p));
    return a;
}
__device__ __forceinline__ void cp16(uint32_t dst, const void* src) {
    asm volatile("cp.async.cg.shared.global [%0], [%1], 16;" :: "r"(dst), "l"(src));
}
__device__ __forceinline__ void cp_commit() {
    asm volatile("cp.async.commit_group;" ::: "memory");
}
template <int N>
__device__ __forceinline__ void cp_wait() {
    asm volatile("cp.async.wait_group %0;" :: "n"(N) : "memory");
}
__device__ __forceinline__ void ldm4(uint32_t* r, uint32_t addr) {
    asm volatile("ldmatrix.sync.aligned.m8n8.x4.shared.b16 {%0,%1,%2,%3}, [%4];"
                 : "=r"(r[0]), "=r"(r[1]), "=r"(r[2]), "=r"(r[3]) : "r"(addr));
}
__device__ __forceinline__ void mma_f16(float* d, const uint32_t* a, uint32_t b0, uint32_t b1) {
    asm volatile(
        "mma.sync.aligned.m16n8k16.row.col.f32.f16.f16.f32 "
        "{%0,%1,%2,%3}, {%4,%5,%6,%7}, {%8,%9}, {%0,%1,%2,%3};"
        : "+f"(d[0]), "+f"(d[1]), "+f"(d[2]), "+f"(d[3])
        : "r"(a[0]), "r"(a[1]), "r"(a[2]), "r"(a[3]), "r"(b0), "r"(b1));
}
__device__ __forceinline__ void split2(float v, hf& h, hf& l) {
    h = __float2half(v);
    l = __float2half(v - __half2float(h));
}

// ---------------- prep: gene splits + normalized-row splits + sq + si ----------------
__global__ __launch_bounds__(256) void prep_kernel(const float* __restrict__ gene,
                                                   const float* __restrict__ sp,
                                                   const float* __restrict__ Ws,
                                                   const float* __restrict__ bs) {
    int row = blockIdx.x;
    const float* x = gene + (size_t)row * GENE;
    __shared__ float red[256];
    float a = __ldg(sp + 2 * row), b = __ldg(sp + 2 * row + 1);

    // si = sp @ Ws + bs  (one h per thread)
    {
        int h = threadIdx.x;
        float v = a * __ldg(Ws + h) + b * __ldg(Ws + HID + h) + __ldg(bs + h);
        split2(v, g_sihi[row * HID + h], g_silo[row * HID + h]);
    }

    float ss = 0.f;
    for (int c = threadIdx.x; c < GENE; c += 256) { float v = x[c]; ss += v * v; }
    red[threadIdx.x] = ss; __syncthreads();
    for (int s = 128; s > 0; s >>= 1) {
        if (threadIdx.x < s) red[threadIdx.x] += red[threadIdx.x + s];
        __syncthreads();
    }
    float inv = 1.0f / fmaxf(sqrtf(red[0]), 1e-12f);
    for (int c = threadIdx.x; c < GENE; c += 256) {
        float v = x[c];
        split2(v, g_Ghi[(size_t)row * GENE + c], g_Glo[(size_t)row * GENE + c]);
        float xn = v * inv;
        hf xh = __float2half(xn);
        size_t o = (size_t)row * YK + HID + c;
        g_Yhi[o] = xh;
        g_Zhi[o] = xh;
    }
    if (threadIdx.x == 0) g_sq[row] = a * a + b * b;
}

// ---------------- all weight transpose-splits + bias copies ----------------
__global__ __launch_bounds__(256) void wsplit_all_kernel(
    const float* __restrict__ Wq, const float* __restrict__ Wk, const float* __restrict__ Wv,
    const float* __restrict__ W1, const float* __restrict__ W2,
    const float* __restrict__ bq, const float* __restrict__ bk, const float* __restrict__ bv) {
    int idx = blockIdx.x * 256 + threadIdx.x;
    if (idx < 393216) {                       // 3 x (256 x 512)
        int w = idx / 131072, r = idx % 131072;
        int n = r / GENE, k = r % GENE;
        const float* W = (w == 0) ? Wq : (w == 1) ? Wk : Wv;
        g_Wthi[idx] = __float2half(W[(size_t)k * HID + n]);
    } else if (idx < 458752) {                // W1 (256 x 256)
        int r = idx - 393216;
        int n = r / HID, k = r % HID;
        g_W1thi[r] = __float2half(W1[(size_t)k * HID + n]);
    } else if (idx < 524288) {                // W2
        int r = idx - 458752;
        int n = r / HID, k = r % HID;
        g_W2thi[r] = __float2half(W2[(size_t)k * HID + n]);
    } else {                                  // biases
        int t = idx - 524288;
        if (t < 256)      g_bias[t] = bq[t];
        else if (t < 512) g_bias[t] = bk[t - 256];
        else if (t < 768) g_bias[t] = bv[t - 512];
    }
}

// ---------------- f_kernel: g_f = clamp(tanh(e @ Wf + bf)) (warp per row) ----------------
__global__ __launch_bounds__(256) void f_kernel(const float* __restrict__ Wf,
                                                const float* __restrict__ bf_) {
    int row = blockIdx.x * 8 + (threadIdx.x >> 5);
    int lane = threadIdx.x & 31;
    const float* e = g_E + (size_t)row * HID + lane * 8;
    float s = 0.f;
    #pragma unroll
    for (int i = 0; i < 8; i++) s += e[i] * __ldg(Wf + lane * 8 + i);
    #pragma unroll
    for (int o = 16; o > 0; o >>= 1) s += __shfl_xor_sync(0xFFFFFFFFu, s, o);
    if (lane == 0) {
        float t = tanhf(s + bf_[0]);
        g_f[row] = fminf(fmaxf(t, -0.999999f), 0.999999f);
    }
}

// ---------------- HMMA split-fp16 GEMM, BK=64, XOR-swizzle, 3-stage pipeline ----------------
// modes: 0 = fp32 C (+bias)*alpha (per-z C offset)
//        1 = logits epilogue -> g_L   (tanh-identity spatial bias)
//        4 = tanh split -> Dhi/Dlo
//        5 = relu fp32 -> C
//        6 = QKV combined (z: 0->Q into Y, 1->K into Z, 2->V transpose)
#define BM 128
#define BN 128
#define BK 64
#define TILEB  16384                 // 128 rows x 128B
#define STAGEB (2 * TILEB)           // A + B
#define NSTAGE 3
#define SMEMSZ (NSTAGE * STAGEB)     // 98304

__global__ __launch_bounds__(256, 2) void hmma_gemm(
    const hf* __restrict__ a0, const hf* __restrict__ a1, const hf* __restrict__ a2,
    const hf* __restrict__ b0, const hf* __restrict__ b1, const hf* __restrict__ b2,
    int pitchA, int pitchB, int cb1, int cb2, int chunks_per_z, int zchunks,
    size_t zBstride, int mode,
    float* __restrict__ C, int ldc, size_t zCstride,
    const float* __restrict__ bias, float alpha,
    hf* __restrict__ Dhi, hf* __restrict__ Dlo, int ldd,
    const float* __restrict__ sp)
{
    extern __shared__ __align__(16) char smem[];
    const uint32_t sbase = s2u(smem);
    const int tid  = threadIdx.x;
    const int lane = tid & 31;
    const int wid  = tid >> 5;
    const int wm   = (wid & 3) * 32;
    const int wn   = (wid >> 2) * 64;
    const int gm0  = blockIdx.y * BM;
    const int gn0  = blockIdx.x * BN;
    const int z    = blockIdx.z;

    if (zBstride) { b0 += z * zBstride; b1 += z * zBstride; b2 += z * zBstride; }
    const int g0 = z * zchunks;

    const int mi    = lane >> 3;
    const int ldrow = ((mi & 1) << 3) + (lane & 7);
    const int ldc16 = mi >> 1;           // 16B-chunk offset within 32B k-slice
    const int srow0 = tid >> 3;          // cp.async rows: tid>>3 + i*32
    const int sc    = tid & 7;

    float acc[2][8][4];
    #pragma unroll
    for (int a = 0; a < 2; a++)
        #pragma unroll
        for (int b = 0; b < 8; b++)
            #pragma unroll
            for (int c = 0; c < 4; c++) acc[a][b][c] = 0.f;

    // ---- chunk loader ----
    auto load_chunk = [&](int g, int stage) {
        const hf *As, *Bs; int kk;
        if (g < cb1)      { As = a0; Bs = b0; kk = g * BK; }
        else if (g < cb2) { As = a1; Bs = b1; kk = (g - cb1) * BK; }
        else              { As = a2; Bs = b2; kk = (g - cb2) * BK; }
        uint32_t dst = sbase + stage * STAGEB;
        #pragma unroll
        for (int i = 0; i < 4; i++) {
            int row = srow0 + i * 32;
            uint32_t off = (uint32_t)(row * 128 + ((sc ^ (row & 7)) << 4));
            cp16(dst + off,         As + (size_t)(gm0 + row) * pitchA + kk + sc * 8);
            cp16(dst + TILEB + off, Bs + (size_t)(gn0 + row) * pitchB + kk + sc * 8);
        }
        cp_commit();
    };

    // prologue: stages 0,1
    load_chunk(g0, 0);
    if (chunks_per_z > 1) load_chunk(g0 + 1, 1);
    else cp_commit();   // keep group count consistent

    for (int c = 0; c < chunks_per_z; c++) {
        if (c + 1 < chunks_per_z) cp_wait<1>(); else cp_wait<0>();
        __syncthreads();
        if (c + 2 < chunks_per_z) load_chunk(g0 + c + 2, (c + 2) % NSTAGE);

        uint32_t abase = sbase + (c % NSTAGE) * STAGEB;
        uint32_t bbase = abase + TILEB;
        #pragma unroll
        for (int ks = 0; ks < 4; ks++) {
            uint32_t afrag[2][4];
            uint32_t bfrag[4][4];
            int c16 = ks * 2 + ldc16;
            #pragma unroll
            for (int mt = 0; mt < 2; mt++) {
                int row = wm + mt * 16 + ldrow;
                ldm4(afrag[mt], abase + row * 128 + ((c16 ^ (row & 7)) << 4));
            }
            #pragma unroll
            for (int p = 0; p < 4; p++) {
                int row = wn + p * 16 + ldrow;
                ldm4(bfrag[p], bbase + row * 128 + ((c16 ^ (row & 7)) << 4));
            }
            #pragma unroll
            for (int mt = 0; mt < 2; mt++) {
                #pragma unroll
                for (int p = 0; p < 4; p++) {
                    mma_f16(acc[mt][2 * p],     afrag[mt], bfrag[p][0], bfrag[p][2]);
                    mma_f16(acc[mt][2 * p + 1], afrag[mt], bfrag[p][1], bfrag[p][3]);
                }
            }
        }
    }

    // ---- epilogue ----
    const int r0 = lane >> 2;
    const int cl = 2 * (lane & 3);

    if (mode == 1) {
        float* ex = (float*)smem;
        __syncthreads();
        for (int i = tid; i < BN; i += 256) {
            int n = gn0 + i;
            ex[i]           = __ldg(sp + 2 * n);
            ex[BN + i]      = __ldg(sp + 2 * n + 1);
            ex[2 * BN + i]  = g_sq[n];
            ex[3 * BN + i]  = g_f[n];     // tj = tanh(f_j), clamped
        }
        __syncthreads();
        #pragma unroll
        for (int mt = 0; mt < 2; mt++) {
            #pragma unroll
            for (int half = 0; half < 2; half++) {
                int m = gm0 + wm + mt * 16 + r0 + half * 8;
                float sp0 = __ldg(sp + 2 * m), sp1 = __ldg(sp + 2 * m + 1);
                float sqi = g_sq[m], ti = g_f[m];
                #pragma unroll
                for (int nt = 0; nt < 8; nt++) {
                    int nl = wn + nt * 8 + cl;
                    float2 v;
                    #pragma unroll
                    for (int q = 0; q < 2; q++) {
                        int ci = nl + q;
                        float d2 = sqi + ex[2 * BN + ci]
                                 - 2.0f * (sp0 * ex[ci] + sp1 * ex[BN + ci]);
                        d2 = fmaxf(d2, 0.0f);
                        float tj = ex[3 * BN + ci];
                        float tb = __fdividef(ti - tj, fmaf(-ti, tj, 1.0f));
                        float a = acc[mt][nt][half * 2 + q];
                        ((float*)&v)[q] = a + __expf(-0.5f * d2) + tb;
                    }
                    *(float2*)(g_L + (size_t)m * Nn + gn0 + nl) = v;
                }
            }
        }
    } else if (mode == 0) {
        float* Cz = C + z * zCstride;
        #pragma unroll
        for (int mt = 0; mt < 2; mt++)
            #pragma unroll
            for (int half = 0; half < 2; half++) {
                int m = gm0 + wm + mt * 16 + r0 + half * 8;
                #pragma unroll
                for (int nt = 0; nt < 8; nt++) {
                    int n = gn0 + wn + nt * 8 + cl;
                    float b0v = bias ? __ldg(bias + n)     : 0.f;
                    float b1v = bias ? __ldg(bias + n + 1) : 0.f;
                    float2 v;
                    v.x = (acc[mt][nt][half * 2 + 0] + b0v) * alpha;
                    v.y = (acc[mt][nt][half * 2 + 1] + b1v) * alpha;
                    *(float2*)(Cz + (size_t)m * ldc + n) = v;
                }
            }
    } else if (mode == 4 || mode == 5) {
        #pragma unroll
        for (int mt = 0; mt < 2; mt++)
            #pragma unroll
            for (int half = 0; half < 2; half++) {
                int m = gm0 + wm + mt * 16 + r0 + half * 8;
                #pragma unroll
                for (int nt = 0; nt < 8; nt++) {
                    int n = gn0 + wn + nt * 8 + cl;
                    #pragma unroll
                    for (int q = 0; q < 2; q++) {
                        float v = acc[mt][nt][half * 2 + q] + __ldg(bias + n + q);
                        if (mode == 4) {
                            v = tanhf(v);
                            split2(v, Dhi[(size_t)m * ldd + n + q], Dlo[(size_t)m * ldd + n + q]);
                        } else {
                            C[(size_t)m * ldc + n + q] = fmaxf(v, 0.f);
                        }
                    }
                }
            }
    } else { // mode 6: QKV combined
        const float* bias6 = g_bias + z * 256;
        if (z == 2) {
            #pragma unroll
            for (int mt = 0; mt < 2; mt++)
                #pragma unroll
                for (int half = 0; half < 2; half++) {
                    int m = gm0 + wm + mt * 16 + r0 + half * 8;
                    #pragma unroll
                    for (int nt = 0; nt < 8; nt++) {
                        int n = gn0 + wn + nt * 8 + cl;
                        #pragma unroll
                        for (int q = 0; q < 2; q++) {
                            float v = acc[mt][nt][half * 2 + q] + bias6[n + q];
                            g_Vthi[(size_t)(n + q) * Nn + m] = __float2half(v);
                        }
                    }
                }
        } else {
            hf* Dh = z ? g_Zhi : g_Yhi;
            hf* Dl = z ? (hf*)nullptr : g_Ylo;
            float al = z ? 1.0f : (1.0f / 16.0f);
            #pragma unroll
            for (int mt = 0; mt < 2; mt++)
                #pragma unroll
                for (int half = 0; half < 2; half++) {
                    int m = gm0 + wm + mt * 16 + r0 + half * 8;
                    #pragma unroll
                    for (int nt = 0; nt < 8; nt++) {
                        int n = gn0 + wn + nt * 8 + cl;
                        #pragma unroll
                        for (int q = 0; q < 2; q++) {
                            float v = (acc[mt][nt][half * 2 + q] + bias6[n + q]) * al;
                            hf h = __float2half(v);
                            Dh[(size_t)m * YK + n + q] = h;
                            if (Dl) Dl[(size_t)m * YK + n + q] = __float2half(v - __half2float(h));
                        }
                    }
                }
        }
    }
}

// ---------------- softmax: 512 threads per row, exp values held in regs ----------------
__global__ __launch_bounds__(512) void softmax_kernel(float* __restrict__ attn) {
    int row = blockIdx.x;
    int tid = threadIdx.x;
    float* L = g_L + (size_t)row * Nn;
    __shared__ float red[512];
    float4 v[2];
    float m = -1e30f;
    #pragma unroll
    for (int i = 0; i < 2; i++) {
        v[i] = *(const float4*)(L + tid * 4 + i * 2048);
        m = fmaxf(m, fmaxf(fmaxf(v[i].x, v[i].y), fmaxf(v[i].z, v[i].w)));
    }
    red[tid] = m; __syncthreads();
    for (int s = 256; s > 0; s >>= 1) {
        if (tid < s) red[tid] = fmaxf(red[tid], red[tid + s]);
        __syncthreads();
    }
    float rm = red[0];
    __syncthreads();
    float sum = 0.f;
    #pragma unroll
    for (int i = 0; i < 2; i++) {
        v[i].x = __expf(v[i].x - rm);
        v[i].y = __expf(v[i].y - rm);
        v[i].z = __expf(v[i].z - rm);
        v[i].w = __expf(v[i].w - rm);
        sum += (v[i].x + v[i].y) + (v[i].z + v[i].w);
    }
    red[tid] = sum; __syncthreads();
    for (int s = 256; s > 0; s >>= 1) {
        if (tid < s) red[tid] += red[tid + s];
        __syncthreads();
    }
    float inv = 1.0f / red[0];
    #pragma unroll
    for (int i = 0; i < 2; i++) {
        int j = tid * 4 + i * 2048;
        float4 a;
        a.x = v[i].x * inv; a.y = v[i].y * inv; a.z = v[i].z * inv; a.w = v[i].w * inv;
        *(float4*)(attn + (size_t)row * Nn + j) = a;
        float* ap = (float*)&a;
        hf h[4], l[4];
        #pragma unroll
        for (int q = 0; q < 4; q++) split2(ap[q], h[q], l[q]);
        *(__half2*)(g_Ahi + (size_t)row * Nn + j)     = __halves2half2(h[0], h[1]);
        *(__half2*)(g_Ahi + (size_t)row * Nn + j + 2) = __halves2half2(h[2], h[3]);
        *(__half2*)(g_Alo + (size_t)row * Nn + j)     = __halves2half2(l[0], l[1]);
        *(__half2*)(g_Alo + (size_t)row * Nn + j + 2) = __halves2half2(l[2], l[3]);
    }
}

// ---------------- reduce split-K partials ----------------
__global__ __launch_bounds__(256) void reduce_kernel(float* __restrict__ upd) {
    size_t i = ((size_t)blockIdx.x * 256 + threadIdx.x) * 4;
    float4 s = *(const float4*)(g_part + i);
    #pragma unroll
    for (int z = 1; z < 8; z++) {
        const float4 p = *(const float4*)(g_part + z * (size_t)Nn * OUTD + i);
        s.x += p.x; s.y += p.y; s.z += p.z; s.w += p.w;
    }
    *(float4*)(upd + i) = s;
}

// ---------------- launch ----------------
extern "C" void kernel_launch(void* const* d_in, const int* in_sizes, int n_in,
                              void* d_out, int out_size) {
    const float* gene = (const float*)d_in[0];
    const float* sp   = (const float*)d_in[1];
    const float* Wq   = (const float*)d_in[2];
    const float* bq   = (const float*)d_in[3];
    const float* Wk   = (const float*)d_in[4];
    const float* bk   = (const float*)d_in[5];
    const float* Wv   = (const float*)d_in[6];
    const float* bv   = (const float*)d_in[7];
    const float* Ws   = (const float*)d_in[8];
    const float* bs   = (const float*)d_in[9];
    const float* W1   = (const float*)d_in[10];
    const float* b1   = (const float*)d_in[11];
    const float* W2   = (const float*)d_in[12];
    const float* b2   = (const float*)d_in[13];
    const float* Wf   = (const float*)d_in[14];
    const float* bf_  = (const float*)d_in[15];

    float* out = (float*)d_out;
    long long total = (long long)Nn * Nn + (long long)Nn * OUTD;
    int has_attn = ((long long)out_size >= total) ? 1 : 0;
    float* attn = out;
    float* upd  = has_attn ? out + (size_t)Nn * Nn : out;

    hf *pGhi, *pGlo, *pYhi, *pYlo, *pZhi, *pAhi, *pAlo, *pVthi;
    hf *pWthi, *pW1thi, *pW2thi, *psihi, *psilo, *phhi, *phlo;
    float *pE, *pPart;
    cudaGetSymbolAddress((void**)&pGhi, g_Ghi);
    cudaGetSymbolAddress((void**)&pGlo, g_Glo);
    cudaGetSymbolAddress((void**)&pYhi, g_Yhi);
    cudaGetSymbolAddress((void**)&pYlo, g_Ylo);
    cudaGetSymbolAddress((void**)&pZhi, g_Zhi);
    cudaGetSymbolAddress((void**)&pAhi, g_Ahi);
    cudaGetSymbolAddress((void**)&pAlo, g_Alo);
    cudaGetSymbolAddress((void**)&pVthi, g_Vthi);
    cudaGetSymbolAddress((void**)&pWthi, g_Wthi);
    cudaGetSymbolAddress((void**)&pW1thi, g_W1thi);
    cudaGetSymbolAddress((void**)&pW2thi, g_W2thi);
    cudaGetSymbolAddress((void**)&psihi, g_sihi);
    cudaGetSymbolAddress((void**)&psilo, g_silo);
    cudaGetSymbolAddress((void**)&phhi, g_hhi);
    cudaGetSymbolAddress((void**)&phlo, g_hlo);
    cudaGetSymbolAddress((void**)&pE, g_E);
    cudaGetSymbolAddress((void**)&pPart, g_part);

    cudaFuncSetAttribute(hmma_gemm, cudaFuncAttributeMaxDynamicSharedMemorySize, SMEMSZ);

    // 0) prep (+ si)
    prep_kernel<<<Nn, 256>>>(gene, sp, Ws, bs);

    // 1) all weight splits + biases
    wsplit_all_kernel<<<2051, 256>>>(Wq, Wk, Wv, W1, W2, bq, bk, bv);

    // 2) MLP gemm 1: h = tanh(si@W1+b1) split  (segs hi|lo: 4+4 chunks)
    dim3 gMLP(HID / BN, Nn / BM, 1);
    hmma_gemm<<<gMLP, 256, SMEMSZ>>>(psihi, psilo, psihi, pW1thi, pW1thi, pW1thi,
                                     HID, HID, 4, 8, 8, 0, 0, 4,
                                     nullptr, 0, 0, b1, 1.0f, phhi, phlo, HID, nullptr);
    // 3) MLP gemm 2: e = relu(h@W2+b2) fp32
    hmma_gemm<<<gMLP, 256, SMEMSZ>>>(phhi, phlo, phhi, pW2thi, pW2thi, pW2thi,
                                     HID, HID, 4, 8, 8, 0, 0, 5,
                                     pE, HID, 0, b2, 1.0f, nullptr, nullptr, 0, nullptr);
    // 4) g_f = clamp(tanh(e@Wf + bf))
    f_kernel<<<Nn / 8, 256>>>(Wf, bf_);

    // 5) QKV combined (mode 6): segs Ghi|Glo (8+8 chunks), grid (2, 32, 3)
    dim3 gQKV(HID / BN, Nn / BM, 3);
    hmma_gemm<<<gQKV, 256, SMEMSZ>>>(pGhi, pGlo, pGhi, pWthi, pWthi, pWthi,
                                     GENE, GENE, 8, 16, 16, 0, (size_t)HID * GENE, 6,
                                     nullptr, 0, 0, nullptr, 1.0f, nullptr, nullptr, 0, nullptr);

    // 6) logits: YhiZhi(768->12ch) | YloZhi(QK 256->4ch) + epilogue
    dim3 gLg(Nn / BN, Nn / BM, 1);
    hmma_gemm<<<gLg, 256, SMEMSZ>>>(pYhi, pYlo, pYhi, pZhi, pZhi, pZhi,
                                    YK, YK, 12, 16, 16, 0, 0, 1,
                                    nullptr, 0, 0, nullptr, 1.0f, nullptr, nullptr, 0, sp);

    // 7) softmax -> attn + A splits
    softmax_kernel<<<Nn, 512>>>(attn);

    // 8) A@V split-K x8 -> partials (segs AhiV|AloV: 64+64 chunks, 16/z)
    dim3 gAV(OUTD / BN, Nn / BM, 8);
    hmma_gemm<<<gAV, 256, SMEMSZ>>>(pAhi, pAlo, pAhi, pVthi, pVthi, pVthi,
                                    Nn, Nn, 64, 128, 16, 16, 0, 0,
                                    pPart, OUTD, (size_t)Nn * OUTD, nullptr, 1.0f,
                                    nullptr, nullptr, 0, nullptr);
    // 9) reduce partials
    reduce_kernel<<<(Nn * OUTD) / 1024, 256>>>(upd);
}

// round 9
// speedup vs baseline: 9.1322x; 1.0442x over previous
#include <cuda_runtime.h>
#include <cuda_fp16.h>
#include <math.h>
#include <stdint.h>

#define Nn    4096
#define GENE  512
#define HID   256
#define OUTD  256
#define YK    768     // HID + GENE fused logits depth

typedef __half hf;

// ---------------- scratch (static device globals; no runtime allocs) ----------------
__device__ __align__(16) float g_L[(size_t)Nn * Nn];      // logits
__device__ __align__(16) hf    g_Ghi[Nn * GENE];
__device__ __align__(16) hf    g_Glo[Nn * GENE];
__device__ __align__(16) hf    g_Yhi[Nn * YK];
__device__ __align__(16) hf    g_Ylo[Nn * YK];
__device__ __align__(16) hf    g_Zhi[Nn * YK];
__device__ __align__(16) hf    g_Ahi[(size_t)Nn * Nn];
__device__ __align__(16) hf    g_Alo[(size_t)Nn * Nn];
__device__ __align__(16) hf    g_Vthi[OUTD * Nn];
__device__ __align__(16) hf    g_Wthi[3 * HID * GENE];    // W^T hi (q,k,v)
__device__ __align__(16) hf    g_W1thi[HID * HID];
__device__ __align__(16) hf    g_W2thi[HID * HID];
__device__ __align__(16) hf    g_sihi[Nn * HID];
__device__ __align__(16) hf    g_silo[Nn * HID];
__device__ __align__(16) hf    g_hhi[Nn * HID];
__device__ __align__(16) hf    g_hlo[Nn * HID];
__device__ __align__(16) float g_part[8 * (size_t)Nn * OUTD];   // split-K partials
__device__ __align__(16) float g_bias[3 * 256];                  // bq|bk|bv
__device__ float g_f[Nn];     // clamp(tanh(f))
__device__ float g_sq[Nn];

// ---------------- PTX helpers (sm_80+ baseline) ----------------
__device__ __forceinline__ uint32_t s2u(const void* p) {
    uint32_t a;
    asm("{ .reg .u64 t; cvta.to.shared.u64 t, %1; cvt.u32.u64 %0, t; }" : "=r"(a) : "l"(p));
    return a;
}
__device__ __forceinline__ void cp16(uint32_t dst, const void* src) {
    asm volatile("cp.async.cg.shared.global [%0], [%1], 16;" :: "r"(dst), "l"(src));
}
__device__ __forceinline__ void cp_commit() {
    asm volatile("cp.async.commit_group;" ::: "memory");
}
template <int N>
__device__ __forceinline__ void cp_wait() {
    asm volatile("cp.async.wait_group %0;" :: "n"(N) : "memory");
}
__device__ __forceinline__ void ldm4(uint32_t* r, uint32_t addr) {
    asm volatile("ldmatrix.sync.aligned.m8n8.x4.shared.b16 {%0,%1,%2,%3}, [%4];"
                 : "=r"(r[0]), "=r"(r[1]), "=r"(r[2]), "=r"(r[3]) : "r"(addr));
}
__device__ __forceinline__ void mma_f16(float* d, const uint32_t* a, uint32_t b0, uint32_t b1) {
    asm volatile(
        "mma.sync.aligned.m16n8k16.row.col.f32.f16.f16.f32 "
        "{%0,%1,%2,%3}, {%4,%5,%6,%7}, {%8,%9}, {%0,%1,%2,%3};"
        : "+f"(d[0]), "+f"(d[1]), "+f"(d[2]), "+f"(d[3])
        : "r"(a[0]), "r"(a[1]), "r"(a[2]), "r"(a[3]), "r"(b0), "r"(b1));
}
__device__ __forceinline__ void split2(float v, hf& h, hf& l) {
    h = __float2half(v);
    l = __float2half(v - __half2float(h));
}

// ---------------- prep: gene splits + normalized-row splits + sq + si ----------------
__global__ __launch_bounds__(256) void prep_kernel(const float* __restrict__ gene,
                                                   const float* __restrict__ sp,
                                                   const float* __restrict__ Ws,
                                                   const float* __restrict__ bs) {
    int row = blockIdx.x;
    const float* x = gene + (size_t)row * GENE;
    __shared__ float red[256];
    float a = __ldg(sp + 2 * row), b = __ldg(sp + 2 * row + 1);

    {
        int h = threadIdx.x;
        float v = a * __ldg(Ws + h) + b * __ldg(Ws + HID + h) + __ldg(bs + h);
        split2(v, g_sihi[row * HID + h], g_silo[row * HID + h]);
    }

    float ss = 0.f;
    for (int c = threadIdx.x; c < GENE; c += 256) { float v = x[c]; ss += v * v; }
    red[threadIdx.x] = ss; __syncthreads();
    for (int s = 128; s > 0; s >>= 1) {
        if (threadIdx.x < s) red[threadIdx.x] += red[threadIdx.x + s];
        __syncthreads();
    }
    float inv = 1.0f / fmaxf(sqrtf(red[0]), 1e-12f);
    for (int c = threadIdx.x; c < GENE; c += 256) {
        float v = x[c];
        split2(v, g_Ghi[(size_t)row * GENE + c], g_Glo[(size_t)row * GENE + c]);
        float xn = v * inv;
        hf xh = __float2half(xn);
        size_t o = (size_t)row * YK + HID + c;
        g_Yhi[o] = xh;
        g_Zhi[o] = xh;
    }
    if (threadIdx.x == 0) g_sq[row] = a * a + b * b;
}

// ---------------- all weight transpose-splits + bias copies ----------------
__global__ __launch_bounds__(256) void wsplit_all_kernel(
    const float* __restrict__ Wq, const float* __restrict__ Wk, const float* __restrict__ Wv,
    const float* __restrict__ W1, const float* __restrict__ W2,
    const float* __restrict__ bq, const float* __restrict__ bk, const float* __restrict__ bv) {
    int idx = blockIdx.x * 256 + threadIdx.x;
    if (idx < 393216) {                       // 3 x (256 x 512)
        int w = idx / 131072, r = idx % 131072;
        int n = r / GENE, k = r % GENE;
        const float* W = (w == 0) ? Wq : (w == 1) ? Wk : Wv;
        g_Wthi[idx] = __float2half(W[(size_t)k * HID + n]);
    } else if (idx < 458752) {                // W1 (256 x 256)
        int r = idx - 393216;
        int n = r / HID, k = r % HID;
        g_W1thi[r] = __float2half(W1[(size_t)k * HID + n]);
    } else if (idx < 524288) {                // W2
        int r = idx - 458752;
        int n = r / HID, k = r % HID;
        g_W2thi[r] = __float2half(W2[(size_t)k * HID + n]);
    } else {                                  // biases
        int t = idx - 524288;
        if (t < 256)      g_bias[t] = bq[t];
        else if (t < 512) g_bias[t] = bk[t - 256];
        else if (t < 768) g_bias[t] = bv[t - 512];
    }
}

// ---------------- reduce MLP1 partials: h = tanh(sum + b1), split ----------------
__global__ __launch_bounds__(256) void reduce_mlp1_kernel(const float* __restrict__ b1) {
    int i = blockIdx.x * 256 + threadIdx.x;   // over Nn*HID
    int col = i & (HID - 1);
    float s = g_part[i] + g_part[(size_t)Nn * HID + i]
            + g_part[2 * (size_t)Nn * HID + i] + g_part[3 * (size_t)Nn * HID + i];
    float t = tanhf(s + __ldg(b1 + col));
    split2(t, g_hhi[i], g_hlo[i]);
}

// ---------------- reduce MLP2 partials + f: block per row ----------------
// e = relu(sum + b2); f_raw = e . Wf + bf; g_f = clamp(tanh(f_raw))
__global__ __launch_bounds__(256) void reduce_f_kernel(const float* __restrict__ b2,
                                                       const float* __restrict__ Wf,
                                                       const float* __restrict__ bf_) {
    int row = blockIdx.x;
    int col = threadIdx.x;
    size_t i = (size_t)row * HID + col;
    float s = g_part[i] + g_part[(size_t)Nn * HID + i]
            + g_part[2 * (size_t)Nn * HID + i] + g_part[3 * (size_t)Nn * HID + i];
    float e = fmaxf(s + __ldg(b2 + col), 0.f);
    __shared__ float red[256];
    red[col] = e * __ldg(Wf + col);
    __syncthreads();
    for (int st = 128; st > 0; st >>= 1) {
        if (col < st) red[col] += red[col + st];
        __syncthreads();
    }
    if (col == 0) {
        float t = tanhf(red[0] + bf_[0]);
        g_f[row] = fminf(fmaxf(t, -0.999999f), 0.999999f);
    }
}

// ---------------- HMMA split-fp16 GEMM, BK=64, XOR-swizzle, 3-stage pipeline ----------------
// modes: 0 = fp32 C (+bias)*alpha (per-z C offset)
//        1 = logits epilogue -> g_L   (tanh-identity spatial bias)
//        6 = QKV combined (z: 0->Q into Y, 1->K into Z, 2->V transpose)
#define BM 128
#define BN 128
#define BK 64
#define TILEB  16384                 // 128 rows x 128B
#define STAGEB (2 * TILEB)           // A + B
#define NSTAGE 3
#define SMEMSZ (NSTAGE * STAGEB)     // 98304

__global__ __launch_bounds__(256, 2) void hmma_gemm(
    const hf* __restrict__ a0, const hf* __restrict__ a1, const hf* __restrict__ a2,
    const hf* __restrict__ b0, const hf* __restrict__ b1, const hf* __restrict__ b2,
    int pitchA, int pitchB, int cb1, int cb2, int chunks_per_z, int zchunks,
    size_t zBstride, int mode,
    float* __restrict__ C, int ldc, size_t zCstride,
    const float* __restrict__ bias, float alpha,
    hf* __restrict__ Dhi, hf* __restrict__ Dlo, int ldd,
    const float* __restrict__ sp)
{
    extern __shared__ __align__(16) char smem[];
    const uint32_t sbase = s2u(smem);
    const int tid  = threadIdx.x;
    const int lane = tid & 31;
    const int wid  = tid >> 5;
    const int wm   = (wid & 3) * 32;
    const int wn   = (wid >> 2) * 64;
    const int gm0  = blockIdx.y * BM;
    const int gn0  = blockIdx.x * BN;
    const int z    = blockIdx.z;

    if (zBstride) { b0 += z * zBstride; b1 += z * zBstride; b2 += z * zBstride; }
    const int g0 = z * zchunks;

    const int mi    = lane >> 3;
    const int ldrow = ((mi & 1) << 3) + (lane & 7);
    const int ldc16 = mi >> 1;
    const int srow0 = tid >> 3;
    const int sc    = tid & 7;

    float acc[2][8][4];
    #pragma unroll
    for (int a = 0; a < 2; a++)
        #pragma unroll
        for (int b = 0; b < 8; b++)
            #pragma unroll
            for (int c = 0; c < 4; c++) acc[a][b][c] = 0.f;

    auto load_chunk = [&](int g, int stage) {
        const hf *As, *Bs; int kk;
        if (g < cb1)      { As = a0; Bs = b0; kk = g * BK; }
        else if (g < cb2) { As = a1; Bs = b1; kk = (g - cb1) * BK; }
        else              { As = a2; Bs = b2; kk = (g - cb2) * BK; }
        uint32_t dst = sbase + stage * STAGEB;
        #pragma unroll
        for (int i = 0; i < 4; i++) {
            int row = srow0 + i * 32;
            uint32_t off = (uint32_t)(row * 128 + ((sc ^ (row & 7)) << 4));
            cp16(dst + off,         As + (size_t)(gm0 + row) * pitchA + kk + sc * 8);
            cp16(dst + TILEB + off, Bs + (size_t)(gn0 + row) * pitchB + kk + sc * 8);
        }
        cp_commit();
    };

    load_chunk(g0, 0);
    if (chunks_per_z > 1) load_chunk(g0 + 1, 1);
    else cp_commit();

    for (int c = 0; c < chunks_per_z; c++) {
        if (c + 1 < chunks_per_z) cp_wait<1>(); else cp_wait<0>();
        __syncthreads();
        if (c + 2 < chunks_per_z) load_chunk(g0 + c + 2, (c + 2) % NSTAGE);

        uint32_t abase = sbase + (c % NSTAGE) * STAGEB;
        uint32_t bbase = abase + TILEB;
        #pragma unroll
        for (int ks = 0; ks < 4; ks++) {
            uint32_t afrag[2][4];
            uint32_t bfrag[4][4];
            int c16 = ks * 2 + ldc16;
            #pragma unroll
            for (int mt = 0; mt < 2; mt++) {
                int row = wm + mt * 16 + ldrow;
                ldm4(afrag[mt], abase + row * 128 + ((c16 ^ (row & 7)) << 4));
            }
            #pragma unroll
            for (int p = 0; p < 4; p++) {
                int row = wn + p * 16 + ldrow;
                ldm4(bfrag[p], bbase + row * 128 + ((c16 ^ (row & 7)) << 4));
            }
            #pragma unroll
            for (int mt = 0; mt < 2; mt++) {
                #pragma unroll
                for (int p = 0; p < 4; p++) {
                    mma_f16(acc[mt][2 * p],     afrag[mt], bfrag[p][0], bfrag[p][2]);
                    mma_f16(acc[mt][2 * p + 1], afrag[mt], bfrag[p][1], bfrag[p][3]);
                }
            }
        }
    }

    // ---- epilogue ----
    const int r0 = lane >> 2;
    const int cl = 2 * (lane & 3);

    if (mode == 1) {
        float* ex = (float*)smem;
        __syncthreads();
        for (int i = tid; i < BN; i += 256) {
            int n = gn0 + i;
            ex[i]           = __ldg(sp + 2 * n);
            ex[BN + i]      = __ldg(sp + 2 * n + 1);
            ex[2 * BN + i]  = g_sq[n];
            ex[3 * BN + i]  = g_f[n];
        }
        __syncthreads();
        #pragma unroll
        for (int mt = 0; mt < 2; mt++) {
            #pragma unroll
            for (int half = 0; half < 2; half++) {
                int m = gm0 + wm + mt * 16 + r0 + half * 8;
                float sp0 = __ldg(sp + 2 * m), sp1 = __ldg(sp + 2 * m + 1);
                float sqi = g_sq[m], ti = g_f[m];
                #pragma unroll
                for (int nt = 0; nt < 8; nt++) {
                    int nl = wn + nt * 8 + cl;
                    float2 v;
                    #pragma unroll
                    for (int q = 0; q < 2; q++) {
                        int ci = nl + q;
                        float d2 = sqi + ex[2 * BN + ci]
                                 - 2.0f * (sp0 * ex[ci] + sp1 * ex[BN + ci]);
                        d2 = fmaxf(d2, 0.0f);
                        float tj = ex[3 * BN + ci];
                        float tb = __fdividef(ti - tj, fmaf(-ti, tj, 1.0f));
                        float a = acc[mt][nt][half * 2 + q];
                        ((float*)&v)[q] = a + __expf(-0.5f * d2) + tb;
                    }
                    *(float2*)(g_L + (size_t)m * Nn + gn0 + nl) = v;
                }
            }
        }
    } else if (mode == 0) {
        float* Cz = C + z * zCstride;
        #pragma unroll
        for (int mt = 0; mt < 2; mt++)
            #pragma unroll
            for (int half = 0; half < 2; half++) {
                int m = gm0 + wm + mt * 16 + r0 + half * 8;
                #pragma unroll
                for (int nt = 0; nt < 8; nt++) {
                    int n = gn0 + wn + nt * 8 + cl;
                    float b0v = bias ? __ldg(bias + n)     : 0.f;
                    float b1v = bias ? __ldg(bias + n + 1) : 0.f;
                    float2 v;
                    v.x = (acc[mt][nt][half * 2 + 0] + b0v) * alpha;
                    v.y = (acc[mt][nt][half * 2 + 1] + b1v) * alpha;
                    *(float2*)(Cz + (size_t)m * ldc + n) = v;
                }
            }
    } else { // mode 6: QKV combined
        const float* bias6 = g_bias + z * 256;
        if (z == 2) {
            #pragma unroll
            for (int mt = 0; mt < 2; mt++)
                #pragma unroll
                for (int half = 0; half < 2; half++) {
                    int m = gm0 + wm + mt * 16 + r0 + half * 8;
                    #pragma unroll
                    for (int nt = 0; nt < 8; nt++) {
                        int n = gn0 + wn + nt * 8 + cl;
                        #pragma unroll
                        for (int q = 0; q < 2; q++) {
                            float v = acc[mt][nt][half * 2 + q] + bias6[n + q];
                            g_Vthi[(size_t)(n + q) * Nn + m] = __float2half(v);
                        }
                    }
                }
        } else {
            hf* Dh = z ? g_Zhi : g_Yhi;
            hf* Dl = z ? (hf*)nullptr : g_Ylo;
            float al = z ? 1.0f : (1.0f / 16.0f);
            #pragma unroll
            for (int mt = 0; mt < 2; mt++)
                #pragma unroll
                for (int half = 0; half < 2; half++) {
                    int m = gm0 + wm + mt * 16 + r0 + half * 8;
                    #pragma unroll
                    for (int nt = 0; nt < 8; nt++) {
                        int n = gn0 + wn + nt * 8 + cl;
                        #pragma unroll
                        for (int q = 0; q < 2; q++) {
                            float v = (acc[mt][nt][half * 2 + q] + bias6[n + q]) * al;
                            hf h = __float2half(v);
                            Dh[(size_t)m * YK + n + q] = h;
                            if (Dl) Dl[(size_t)m * YK + n + q] = __float2half(v - __half2float(h));
                        }
                    }
                }
        }
    }
}

// ---------------- softmax: 512 threads per row, exp values held in regs ----------------
__global__ __launch_bounds__(512) void softmax_kernel(float* __restrict__ attn) {
    int row = blockIdx.x;
    int tid = threadIdx.x;
    float* L = g_L + (size_t)row * Nn;
    __shared__ float red[512];
    float4 v[2];
    float m = -1e30f;
    #pragma unroll
    for (int i = 0; i < 2; i++) {
        v[i] = *(const float4*)(L + tid * 4 + i * 2048);
        m = fmaxf(m, fmaxf(fmaxf(v[i].x, v[i].y), fmaxf(v[i].z, v[i].w)));
    }
    red[tid] = m; __syncthreads();
    for (int s = 256; s > 0; s >>= 1) {
        if (tid < s) red[tid] = fmaxf(red[tid], red[tid + s]);
        __syncthreads();
    }
    float rm = red[0];
    __syncthreads();
    float sum = 0.f;
    #pragma unroll
    for (int i = 0; i < 2; i++) {
        v[i].x = __expf(v[i].x - rm);
        v[i].y = __expf(v[i].y - rm);
        v[i].z = __expf(v[i].z - rm);
        v[i].w = __expf(v[i].w - rm);
        sum += (v[i].x + v[i].y) + (v[i].z + v[i].w);
    }
    red[tid] = sum; __syncthreads();
    for (int s = 256; s > 0; s >>= 1) {
        if (tid < s) red[tid] += red[tid + s];
        __syncthreads();
    }
    float inv = 1.0f / red[0];
    #pragma unroll
    for (int i = 0; i < 2; i++) {
        int j = tid * 4 + i * 2048;
        float4 a;
        a.x = v[i].x * inv; a.y = v[i].y * inv; a.z = v[i].z * inv; a.w = v[i].w * inv;
        *(float4*)(attn + (size_t)row * Nn + j) = a;
        float* ap = (float*)&a;
        hf h[4], l[4];
        #pragma unroll
        for (int q = 0; q < 4; q++) split2(ap[q], h[q], l[q]);
        *(__half2*)(g_Ahi + (size_t)row * Nn + j)     = __halves2half2(h[0], h[1]);
        *(__half2*)(g_Ahi + (size_t)row * Nn + j + 2) = __halves2half2(h[2], h[3]);
        *(__half2*)(g_Alo + (size_t)row * Nn + j)     = __halves2half2(l[0], l[1]);
        *(__half2*)(g_Alo + (size_t)row * Nn + j + 2) = __halves2half2(l[2], l[3]);
    }
}

// ---------------- reduce A@V split-K partials (4-way) ----------------
__global__ __launch_bounds__(256) void reduce_kernel(float* __restrict__ upd) {
    size_t i = ((size_t)blockIdx.x * 256 + threadIdx.x) * 4;
    float4 s = *(const float4*)(g_part + i);
    #pragma unroll
    for (int z = 1; z < 4; z++) {
        const float4 p = *(const float4*)(g_part + z * (size_t)Nn * OUTD + i);
        s.x += p.x; s.y += p.y; s.z += p.z; s.w += p.w;
    }
    *(float4*)(upd + i) = s;
}

// ---------------- launch ----------------
extern "C" void kernel_launch(void* const* d_in, const int* in_sizes, int n_in,
                              void* d_out, int out_size) {
    const float* gene = (const float*)d_in[0];
    const float* sp   = (const float*)d_in[1];
    const float* Wq   = (const float*)d_in[2];
    const float* bq   = (const float*)d_in[3];
    const float* Wk   = (const float*)d_in[4];
    const float* bk   = (const float*)d_in[5];
    const float* Wv   = (const float*)d_in[6];
    const float* bv   = (const float*)d_in[7];
    const float* Ws   = (const float*)d_in[8];
    const float* bs   = (const float*)d_in[9];
    const float* W1   = (const float*)d_in[10];
    const float* b1   = (const float*)d_in[11];
    const float* W2   = (const float*)d_in[12];
    const float* b2   = (const float*)d_in[13];
    const float* Wf   = (const float*)d_in[14];
    const float* bf_  = (const float*)d_in[15];

    float* out = (float*)d_out;
    long long total = (long long)Nn * Nn + (long long)Nn * OUTD;
    int has_attn = ((long long)out_size >= total) ? 1 : 0;
    float* attn = out;
    float* upd  = has_attn ? out + (size_t)Nn * Nn : out;

    hf *pGhi, *pGlo, *pYhi, *pYlo, *pZhi, *pAhi, *pAlo, *pVthi;
    hf *pWthi, *pW1thi, *pW2thi, *psihi, *psilo, *phhi, *phlo;
    float *pPart;
    cudaGetSymbolAddress((void**)&pGhi, g_Ghi);
    cudaGetSymbolAddress((void**)&pGlo, g_Glo);
    cudaGetSymbolAddress((void**)&pYhi, g_Yhi);
    cudaGetSymbolAddress((void**)&pYlo, g_Ylo);
    cudaGetSymbolAddress((void**)&pZhi, g_Zhi);
    cudaGetSymbolAddress((void**)&pAhi, g_Ahi);
    cudaGetSymbolAddress((void**)&pAlo, g_Alo);
    cudaGetSymbolAddress((void**)&pVthi, g_Vthi);
    cudaGetSymbolAddress((void**)&pWthi, g_Wthi);
    cudaGetSymbolAddress((void**)&pW1thi, g_W1thi);
    cudaGetSymbolAddress((void**)&pW2thi, g_W2thi);
    cudaGetSymbolAddress((void**)&psihi, g_sihi);
    cudaGetSymbolAddress((void**)&psilo, g_silo);
    cudaGetSymbolAddress((void**)&phhi, g_hhi);
    cudaGetSymbolAddress((void**)&phlo, g_hlo);
    cudaGetSymbolAddress((void**)&pPart, g_part);

    cudaFuncSetAttribute(hmma_gemm, cudaFuncAttributeMaxDynamicSharedMemorySize, SMEMSZ);

    // 0) prep (+ si)
    prep_kernel<<<Nn, 256>>>(gene, sp, Ws, bs);

    // 1) all weight splits + biases
    wsplit_all_kernel<<<2051, 256>>>(Wq, Wk, Wv, W1, W2, bq, bk, bv);

    // 2) MLP gemm 1 split-K x4: partials (segs hi|lo: 4+4 chunks total, 2/z)
    dim3 gMLP(HID / BN, Nn / BM, 4);
    hmma_gemm<<<gMLP, 256, SMEMSZ>>>(psihi, psilo, psihi, pW1thi, pW1thi, pW1thi,
                                     HID, HID, 4, 8, 2, 2, 0, 0,
                                     pPart, HID, (size_t)Nn * HID, nullptr, 1.0f,
                                     nullptr, nullptr, 0, nullptr);
    // 3) reduce1: h = tanh(sum+b1) split
    reduce_mlp1_kernel<<<(Nn * HID) / 256, 256>>>(b1);

    // 4) MLP gemm 2 split-K x4: partials
    hmma_gemm<<<gMLP, 256, SMEMSZ>>>(phhi, phlo, phhi, pW2thi, pW2thi, pW2thi,
                                     HID, HID, 4, 8, 2, 2, 0, 0,
                                     pPart, HID, (size_t)Nn * HID, nullptr, 1.0f,
                                     nullptr, nullptr, 0, nullptr);
    // 5) reduce2 + f: e = relu(sum+b2); g_f = clamp(tanh(e.Wf + bf))
    reduce_f_kernel<<<Nn, 256>>>(b2, Wf, bf_);

    // 6) QKV combined (mode 6): segs Ghi|Glo (8+8 chunks), grid (2, 32, 3)
    dim3 gQKV(HID / BN, Nn / BM, 3);
    hmma_gemm<<<gQKV, 256, SMEMSZ>>>(pGhi, pGlo, pGhi, pWthi, pWthi, pWthi,
                                     GENE, GENE, 8, 16, 16, 0, (size_t)HID * GENE, 6,
                                     nullptr, 0, 0, nullptr, 1.0f, nullptr, nullptr, 0, nullptr);

    // 7) logits: YhiZhi(768->12ch) | YloZhi(QK 256->4ch) + epilogue
    dim3 gLg(Nn / BN, Nn / BM, 1);
    hmma_gemm<<<gLg, 256, SMEMSZ>>>(pYhi, pYlo, pYhi, pZhi, pZhi, pZhi,
                                    YK, YK, 12, 16, 16, 0, 0, 1,
                                    nullptr, 0, 0, nullptr, 1.0f, nullptr, nullptr, 0, sp);

    // 8) softmax -> attn + A splits
    softmax_kernel<<<Nn, 512>>>(attn);

    // 9) A@V split-K x4 -> partials (segs AhiV|AloV: 64+64 chunks, 32/z)
    dim3 gAV(OUTD / BN, Nn / BM, 4);
    hmma_gemm<<<gAV, 256, SMEMSZ>>>(pAhi, pAlo, pAhi, pVthi, pVthi, pVthi,
                                    Nn, Nn, 64, 128, 32, 32, 0, 0,
                                    pPart, OUTD, (size_t)Nn * OUTD, nullptr, 1.0f,
                                    nullptr, nullptr, 0, nullptr);
    // 10) reduce partials
    reduce_kernel<<<(Nn * OUTD) / 1024, 256>>>(upd);
}

// round 10
// speedup vs baseline: 10.3336x; 1.1316x over previous
#include <cuda_runtime.h>
#include <cuda_fp16.h>
#include <math.h>
#include <stdint.h>

#define Nn    4096
#define GENE  512
#define HID   256
#define OUTD  256
#define YK    768     // HID + GENE fused logits depth

typedef __half hf;

// ---------------- scratch (static device globals; no runtime allocs) ----------------
__device__ __align__(16) float g_L[(size_t)Nn * Nn];      // logits
__device__ __align__(16) hf    g_Ghi[Nn * GENE];
__device__ __align__(16) hf    g_Glo[Nn * GENE];
__device__ __align__(16) hf    g_Yhi[Nn * YK];
__device__ __align__(16) hf    g_Ylo[Nn * YK];
__device__ __align__(16) hf    g_Zhi[Nn * YK];
__device__ __align__(16) hf    g_Ahi[(size_t)Nn * Nn];
__device__ __align__(16) hf    g_Vthi[OUTD * Nn];
__device__ __align__(16) hf    g_Wthi[3 * HID * GENE];    // W^T hi (q,k,v)
__device__ __align__(16) hf    g_W1thi[HID * HID];
__device__ __align__(16) hf    g_W2thi[HID * HID];
__device__ __align__(16) hf    g_sihi[Nn * HID];
__device__ __align__(16) hf    g_silo[Nn * HID];
__device__ __align__(16) hf    g_hhi[Nn * HID];
__device__ __align__(16) hf    g_hlo[Nn * HID];
__device__ __align__(16) float g_part[4 * (size_t)Nn * OUTD];   // split-K partials
__device__ __align__(16) float g_bias[3 * 256];                  // bq|bk|bv
__device__ float g_f[Nn];     // clamp(tanh(f))
__device__ float g_sq[Nn];

// ---------------- PTX helpers (sm_80+ baseline) ----------------
__device__ __forceinline__ uint32_t s2u(const void* p) {
    uint32_t a;
    asm("{ .reg .u64 t; cvta.to.shared.u64 t, %1; cvt.u32.u64 %0, t; }" : "=r"(a) : "l"(p));
    return a;
}
__device__ __forceinline__ void cp16(uint32_t dst, const void* src) {
    asm volatile("cp.async.cg.shared.global [%0], [%1], 16;" :: "r"(dst), "l"(src));
}
__device__ __forceinline__ void cp_commit() {
    asm volatile("cp.async.commit_group;" ::: "memory");
}
template <int N>
__device__ __forceinline__ void cp_wait() {
    asm volatile("cp.async.wait_group %0;" :: "n"(N) : "memory");
}
__device__ __forceinline__ void ldm4(uint32_t* r, uint32_t addr) {
    asm volatile("ldmatrix.sync.aligned.m8n8.x4.shared.b16 {%0,%1,%2,%3}, [%4];"
                 : "=r"(r[0]), "=r"(r[1]), "=r"(r[2]), "=r"(r[3]) : "r"(addr));
}
__device__ __forceinline__ void mma_f16(float* d, const uint32_t* a, uint32_t b0, uint32_t b1) {
    asm volatile(
        "mma.sync.aligned.m16n8k16.row.col.f32.f16.f16.f32 "
        "{%0,%1,%2,%3}, {%4,%5,%6,%7}, {%8,%9}, {%0,%1,%2,%3};"
        : "+f"(d[0]), "+f"(d[1]), "+f"(d[2]), "+f"(d[3])
        : "r"(a[0]), "r"(a[1]), "r"(a[2]), "r"(a[3]), "r"(b0), "r"(b1));
}
__device__ __forceinline__ void split2(float v, hf& h, hf& l) {
    h = __float2half(v);
    l = __float2half(v - __half2float(h));
}

// ---------------- prep: gene splits + normalized-row splits + sq + si ----------------
__global__ __launch_bounds__(256) void prep_kernel(const float* __restrict__ gene,
                                                   const float* __restrict__ sp,
                                                   const float* __restrict__ Ws,
                                                   const float* __restrict__ bs) {
    int row = blockIdx.x;
    const float* x = gene + (size_t)row * GENE;
    __shared__ float red[256];
    float a = __ldg(sp + 2 * row), b = __ldg(sp + 2 * row + 1);

    {
        int h = threadIdx.x;
        float v = a * __ldg(Ws + h) + b * __ldg(Ws + HID + h) + __ldg(bs + h);
        split2(v, g_sihi[row * HID + h], g_silo[row * HID + h]);
    }

    float ss = 0.f;
    for (int c = threadIdx.x; c < GENE; c += 256) { float v = x[c]; ss += v * v; }
    red[threadIdx.x] = ss; __syncthreads();
    for (int s = 128; s > 0; s >>= 1) {
        if (threadIdx.x < s) red[threadIdx.x] += red[threadIdx.x + s];
        __syncthreads();
    }
    float inv = 1.0f / fmaxf(sqrtf(red[0]), 1e-12f);
    for (int c = threadIdx.x; c < GENE; c += 256) {
        float v = x[c];
        split2(v, g_Ghi[(size_t)row * GENE + c], g_Glo[(size_t)row * GENE + c]);
        float xn = v * inv;
        hf xh = __float2half(xn);
        size_t o = (size_t)row * YK + HID + c;
        g_Yhi[o] = xh;
        g_Zhi[o] = xh;
    }
    if (threadIdx.x == 0) g_sq[row] = a * a + b * b;
}

// ---------------- all weight transpose-splits + bias copies ----------------
__global__ __launch_bounds__(256) void wsplit_all_kernel(
    const float* __restrict__ Wq, const float* __restrict__ Wk, const float* __restrict__ Wv,
    const float* __restrict__ W1, const float* __restrict__ W2,
    const float* __restrict__ bq, const float* __restrict__ bk, const float* __restrict__ bv) {
    int idx = blockIdx.x * 256 + threadIdx.x;
    if (idx < 393216) {                       // 3 x (256 x 512)
        int w = idx / 131072, r = idx % 131072;
        int n = r / GENE, k = r % GENE;
        const float* W = (w == 0) ? Wq : (w == 1) ? Wk : Wv;
        g_Wthi[idx] = __float2half(W[(size_t)k * HID + n]);
    } else if (idx < 458752) {                // W1 (256 x 256)
        int r = idx - 393216;
        int n = r / HID, k = r % HID;
        g_W1thi[r] = __float2half(W1[(size_t)k * HID + n]);
    } else if (idx < 524288) {                // W2
        int r = idx - 458752;
        int n = r / HID, k = r % HID;
        g_W2thi[r] = __float2half(W2[(size_t)k * HID + n]);
    } else {                                  // biases
        int t = idx - 524288;
        if (t < 256)      g_bias[t] = bq[t];
        else if (t < 512) g_bias[t] = bk[t - 256];
        else if (t < 768) g_bias[t] = bv[t - 512];
    }
}

// ---------------- reduce MLP1 partials (float4): h = tanh(sum + b1), split ----------------
__global__ __launch_bounds__(256) void reduce_mlp1_kernel(const float* __restrict__ b1) {
    size_t i4 = ((size_t)blockIdx.x * 256 + threadIdx.x) * 4;   // over Nn*HID
    int col = (int)(i4 & (HID - 1));
    float4 s = *(const float4*)(g_part + i4);
    #pragma unroll
    for (int z = 1; z < 4; z++) {
        float4 p = *(const float4*)(g_part + z * (size_t)Nn * HID + i4);
        s.x += p.x; s.y += p.y; s.z += p.z; s.w += p.w;
    }
    float4 bb = *(const float4*)(b1 + col);
    float t0 = tanhf(s.x + bb.x), t1 = tanhf(s.y + bb.y);
    float t2 = tanhf(s.z + bb.z), t3 = tanhf(s.w + bb.w);
    hf h[4], l[4];
    split2(t0, h[0], l[0]); split2(t1, h[1], l[1]);
    split2(t2, h[2], l[2]); split2(t3, h[3], l[3]);
    *(__half2*)(g_hhi + i4)     = __halves2half2(h[0], h[1]);
    *(__half2*)(g_hhi + i4 + 2) = __halves2half2(h[2], h[3]);
    *(__half2*)(g_hlo + i4)     = __halves2half2(l[0], l[1]);
    *(__half2*)(g_hlo + i4 + 2) = __halves2half2(l[2], l[3]);
}

// ---------------- reduce MLP2 partials + f: 4 rows per block, float4 ----------------
// e = relu(sum + b2); g_f = clamp(tanh(e . Wf + bf))
__global__ __launch_bounds__(256) void reduce_f_kernel(const float* __restrict__ b2,
                                                       const float* __restrict__ Wf,
                                                       const float* __restrict__ bf_) {
    int rloc = threadIdx.x >> 6;              // 0..3
    int c4   = (threadIdx.x & 63) * 4;
    int row  = blockIdx.x * 4 + rloc;
    size_t i4 = (size_t)row * HID + c4;
    float4 s = *(const float4*)(g_part + i4);
    #pragma unroll
    for (int z = 1; z < 4; z++) {
        float4 p = *(const float4*)(g_part + z * (size_t)Nn * HID + i4);
        s.x += p.x; s.y += p.y; s.z += p.z; s.w += p.w;
    }
    float4 bb = *(const float4*)(b2 + c4);
    float4 wf = *(const float4*)(Wf + c4);
    float d = fmaxf(s.x + bb.x, 0.f) * wf.x + fmaxf(s.y + bb.y, 0.f) * wf.y
            + fmaxf(s.z + bb.z, 0.f) * wf.z + fmaxf(s.w + bb.w, 0.f) * wf.w;
    __shared__ float red[256];
    red[threadIdx.x] = d;
    __syncthreads();
    #pragma unroll
    for (int st = 32; st > 0; st >>= 1) {
        if ((threadIdx.x & 63) < st) red[threadIdx.x] += red[threadIdx.x + st];
        __syncthreads();
    }
    if ((threadIdx.x & 63) == 0) {
        float t = tanhf(red[rloc * 64] + bf_[0]);
        g_f[row] = fminf(fmaxf(t, -0.999999f), 0.999999f);
    }
}

// ---------------- HMMA split-fp16 GEMM, BK=64, XOR-swizzle, 3-stage pipeline ----------------
// modes: 0 = fp32 C (+bias)*alpha (per-z C offset)
//        1 = logits epilogue -> g_L   (tanh-identity spatial bias)
//        6 = QKV combined (z: 0->Q into Y, 1->K into Z, 2->V transpose)
#define BM 128
#define BN 128
#define BK 64
#define TILEB  16384                 // 128 rows x 128B
#define STAGEB (2 * TILEB)           // A + B
#define NSTAGE 3
#define SMEMSZ (NSTAGE * STAGEB)     // 98304

__global__ __launch_bounds__(256, 2) void hmma_gemm(
    const hf* __restrict__ a0, const hf* __restrict__ a1, const hf* __restrict__ a2,
    const hf* __restrict__ b0, const hf* __restrict__ b1, const hf* __restrict__ b2,
    int pitchA, int pitchB, int cb1, int cb2, int chunks_per_z, int zchunks,
    size_t zBstride, int mode,
    float* __restrict__ C, int ldc, size_t zCstride,
    const float* __restrict__ bias, float alpha,
    hf* __restrict__ Dhi, hf* __restrict__ Dlo, int ldd,
    const float* __restrict__ sp)
{
    extern __shared__ __align__(16) char smem[];
    const uint32_t sbase = s2u(smem);
    const int tid  = threadIdx.x;
    const int lane = tid & 31;
    const int wid  = tid >> 5;
    const int wm   = (wid & 3) * 32;
    const int wn   = (wid >> 2) * 64;
    const int gm0  = blockIdx.y * BM;
    const int gn0  = blockIdx.x * BN;
    const int z    = blockIdx.z;

    if (zBstride) { b0 += z * zBstride; b1 += z * zBstride; b2 += z * zBstride; }
    const int g0 = z * zchunks;

    const int mi    = lane >> 3;
    const int ldrow = ((mi & 1) << 3) + (lane & 7);
    const int ldc16 = mi >> 1;
    const int srow0 = tid >> 3;
    const int sc    = tid & 7;

    float acc[2][8][4];
    #pragma unroll
    for (int a = 0; a < 2; a++)
        #pragma unroll
        for (int b = 0; b < 8; b++)
            #pragma unroll
            for (int c = 0; c < 4; c++) acc[a][b][c] = 0.f;

    auto load_chunk = [&](int g, int stage) {
        const hf *As, *Bs; int kk;
        if (g < cb1)      { As = a0; Bs = b0; kk = g * BK; }
        else if (g < cb2) { As = a1; Bs = b1; kk = (g - cb1) * BK; }
        else              { As = a2; Bs = b2; kk = (g - cb2) * BK; }
        uint32_t dst = sbase + stage * STAGEB;
        #pragma unroll
        for (int i = 0; i < 4; i++) {
            int row = srow0 + i * 32;
            uint32_t off = (uint32_t)(row * 128 + ((sc ^ (row & 7)) << 4));
            cp16(dst + off,         As + (size_t)(gm0 + row) * pitchA + kk + sc * 8);
            cp16(dst + TILEB + off, Bs + (size_t)(gn0 + row) * pitchB + kk + sc * 8);
        }
        cp_commit();
    };

    load_chunk(g0, 0);
    if (chunks_per_z > 1) load_chunk(g0 + 1, 1);
    else cp_commit();

    for (int c = 0; c < chunks_per_z; c++) {
        if (c + 1 < chunks_per_z) cp_wait<1>(); else cp_wait<0>();
        __syncthreads();
        if (c + 2 < chunks_per_z) load_chunk(g0 + c + 2, (c + 2) % NSTAGE);

        uint32_t abase = sbase + (c % NSTAGE) * STAGEB;
        uint32_t bbase = abase + TILEB;
        #pragma unroll
        for (int ks = 0; ks < 4; ks++) {
            uint32_t afrag[2][4];
            uint32_t bfrag[4][4];
            int c16 = ks * 2 + ldc16;
            #pragma unroll
            for (int mt = 0; mt < 2; mt++) {
                int row = wm + mt * 16 + ldrow;
                ldm4(afrag[mt], abase + row * 128 + ((c16 ^ (row & 7)) << 4));
            }
            #pragma unroll
            for (int p = 0; p < 4; p++) {
                int row = wn + p * 16 + ldrow;
                ldm4(bfrag[p], bbase + row * 128 + ((c16 ^ (row & 7)) << 4));
            }
            #pragma unroll
            for (int mt = 0; mt < 2; mt++) {
                #pragma unroll
                for (int p = 0; p < 4; p++) {
                    mma_f16(acc[mt][2 * p],     afrag[mt], bfrag[p][0], bfrag[p][2]);
                    mma_f16(acc[mt][2 * p + 1], afrag[mt], bfrag[p][1], bfrag[p][3]);
                }
            }
        }
    }

    // ---- epilogue ----
    const int r0 = lane >> 2;
    const int cl = 2 * (lane & 3);

    if (mode == 1) {
        float* ex = (float*)smem;
        __syncthreads();
        for (int i = tid; i < BN; i += 256) {
            int n = gn0 + i;
            ex[i]           = __ldg(sp + 2 * n);
            ex[BN + i]      = __ldg(sp + 2 * n + 1);
            ex[2 * BN + i]  = g_sq[n];
            ex[3 * BN + i]  = g_f[n];
        }
        __syncthreads();
        #pragma unroll
        for (int mt = 0; mt < 2; mt++) {
            #pragma unroll
            for (int half = 0; half < 2; half++) {
                int m = gm0 + wm + mt * 16 + r0 + half * 8;
                float sp0 = __ldg(sp + 2 * m), sp1 = __ldg(sp + 2 * m + 1);
                float sqi = g_sq[m], ti = g_f[m];
                #pragma unroll
                for (int nt = 0; nt < 8; nt++) {
                    int nl = wn + nt * 8 + cl;
                    float2 v;
                    #pragma unroll
                    for (int q = 0; q < 2; q++) {
                        int ci = nl + q;
                        float d2 = sqi + ex[2 * BN + ci]
                                 - 2.0f * (sp0 * ex[ci] + sp1 * ex[BN + ci]);
                        d2 = fmaxf(d2, 0.0f);
                        float tj = ex[3 * BN + ci];
                        float tb = __fdividef(ti - tj, fmaf(-ti, tj, 1.0f));
                        float a = acc[mt][nt][half * 2 + q];
                        ((float*)&v)[q] = a + __expf(-0.5f * d2) + tb;
                    }
                    *(float2*)(g_L + (size_t)m * Nn + gn0 + nl) = v;
                }
            }
        }
    } else if (mode == 0) {
        float* Cz = C + z * zCstride;
        #pragma unroll
        for (int mt = 0; mt < 2; mt++)
            #pragma unroll
            for (int half = 0; half < 2; half++) {
                int m = gm0 + wm + mt * 16 + r0 + half * 8;
                #pragma unroll
                for (int nt = 0; nt < 8; nt++) {
                    int n = gn0 + wn + nt * 8 + cl;
                    float b0v = bias ? __ldg(bias + n)     : 0.f;
                    float b1v = bias ? __ldg(bias + n + 1) : 0.f;
                    float2 v;
                    v.x = (acc[mt][nt][half * 2 + 0] + b0v) * alpha;
                    v.y = (acc[mt][nt][half * 2 + 1] + b1v) * alpha;
                    *(float2*)(Cz + (size_t)m * ldc + n) = v;
                }
            }
    } else { // mode 6: QKV combined
        const float* bias6 = g_bias + z * 256;
        if (z == 2) {
            #pragma unroll
            for (int mt = 0; mt < 2; mt++)
                #pragma unroll
                for (int half = 0; half < 2; half++) {
                    int m = gm0 + wm + mt * 16 + r0 + half * 8;
                    #pragma unroll
                    for (int nt = 0; nt < 8; nt++) {
                        int n = gn0 + wn + nt * 8 + cl;
                        #pragma unroll
                        for (int q = 0; q < 2; q++) {
                            float v = acc[mt][nt][half * 2 + q] + bias6[n + q];
                            g_Vthi[(size_t)(n + q) * Nn + m] = __float2half(v);
                        }
                    }
                }
        } else {
            hf* Dh = z ? g_Zhi : g_Yhi;
            hf* Dl = z ? (hf*)nullptr : g_Ylo;
            float al = z ? 1.0f : (1.0f / 16.0f);
            #pragma unroll
            for (int mt = 0; mt < 2; mt++)
                #pragma unroll
                for (int half = 0; half < 2; half++) {
                    int m = gm0 + wm + mt * 16 + r0 + half * 8;
                    #pragma unroll
                    for (int nt = 0; nt < 8; nt++) {
                        int n = gn0 + wn + nt * 8 + cl;
                        #pragma unroll
                        for (int q = 0; q < 2; q++) {
                            float v = (acc[mt][nt][half * 2 + q] + bias6[n + q]) * al;
                            hf h = __float2half(v);
                            Dh[(size_t)m * YK + n + q] = h;
                            if (Dl) Dl[(size_t)m * YK + n + q] = __float2half(v - __half2float(h));
                        }
                    }
                }
        }
    }
}

// ---------------- softmax: 512 threads per row; writes attn fp32 + A hi only ----------------
__global__ __launch_bounds__(512) void softmax_kernel(float* __restrict__ attn) {
    int row = blockIdx.x;
    int tid = threadIdx.x;
    float* L = g_L + (size_t)row * Nn;
    __shared__ float red[512];
    float4 v[2];
    float m = -1e30f;
    #pragma unroll
    for (int i = 0; i < 2; i++) {
        v[i] = *(const float4*)(L + tid * 4 + i * 2048);
        m = fmaxf(m, fmaxf(fmaxf(v[i].x, v[i].y), fmaxf(v[i].z, v[i].w)));
    }
    red[tid] = m; __syncthreads();
    for (int s = 256; s > 0; s >>= 1) {
        if (tid < s) red[tid] = fmaxf(red[tid], red[tid + s]);
        __syncthreads();
    }
    float rm = red[0];
    __syncthreads();
    float sum = 0.f;
    #pragma unroll
    for (int i = 0; i < 2; i++) {
        v[i].x = __expf(v[i].x - rm);
        v[i].y = __expf(v[i].y - rm);
        v[i].z = __expf(v[i].z - rm);
        v[i].w = __expf(v[i].w - rm);
        sum += (v[i].x + v[i].y) + (v[i].z + v[i].w);
    }
    red[tid] = sum; __syncthreads();
    for (int s = 256; s > 0; s >>= 1) {
        if (tid < s) red[tid] += red[tid + s];
        __syncthreads();
    }
    float inv = 1.0f / red[0];
    #pragma unroll
    for (int i = 0; i < 2; i++) {
        int j = tid * 4 + i * 2048;
        float4 a;
        a.x = v[i].x * inv; a.y = v[i].y * inv; a.z = v[i].z * inv; a.w = v[i].w * inv;
        *(float4*)(attn + (size_t)row * Nn + j) = a;
        *(__half2*)(g_Ahi + (size_t)row * Nn + j) =
            __halves2half2(__float2half(a.x), __float2half(a.y));
        *(__half2*)(g_Ahi + (size_t)row * Nn + j + 2) =
            __halves2half2(__float2half(a.z), __float2half(a.w));
    }
}

// ---------------- reduce A@V split-K partials (4-way) ----------------
__global__ __launch_bounds__(256) void reduce_kernel(float* __restrict__ upd) {
    size_t i = ((size_t)blockIdx.x * 256 + threadIdx.x) * 4;
    float4 s = *(const float4*)(g_part + i);
    #pragma unroll
    for (int z = 1; z < 4; z++) {
        const float4 p = *(const float4*)(g_part + z * (size_t)Nn * OUTD + i);
        s.x += p.x; s.y += p.y; s.z += p.z; s.w += p.w;
    }
    *(float4*)(upd + i) = s;
}

// ---------------- launch ----------------
extern "C" void kernel_launch(void* const* d_in, const int* in_sizes, int n_in,
                              void* d_out, int out_size) {
    const float* gene = (const float*)d_in[0];
    const float* sp   = (const float*)d_in[1];
    const float* Wq   = (const float*)d_in[2];
    const float* bq   = (const float*)d_in[3];
    const float* Wk   = (const float*)d_in[4];
    const float* bk   = (const float*)d_in[5];
    const float* Wv   = (const float*)d_in[6];
    const float* bv   = (const float*)d_in[7];
    const float* Ws   = (const float*)d_in[8];
    const float* bs   = (const float*)d_in[9];
    const float* W1   = (const float*)d_in[10];
    const float* b1   = (const float*)d_in[11];
    const float* W2   = (const float*)d_in[12];
    const float* b2   = (const float*)d_in[13];
    const float* Wf   = (const float*)d_in[14];
    const float* bf_  = (const float*)d_in[15];

    float* out = (float*)d_out;
    long long total = (long long)Nn * Nn + (long long)Nn * OUTD;
    int has_attn = ((long long)out_size >= total) ? 1 : 0;
    float* attn = out;
    float* upd  = has_attn ? out + (size_t)Nn * Nn : out;

    hf *pGhi, *pGlo, *pYhi, *pYlo, *pZhi, *pAhi, *pVthi;
    hf *pWthi, *pW1thi, *pW2thi, *psihi, *psilo, *phhi, *phlo;
    float *pPart;
    cudaGetSymbolAddress((void**)&pGhi, g_Ghi);
    cudaGetSymbolAddress((void**)&pGlo, g_Glo);
    cudaGetSymbolAddress((void**)&pYhi, g_Yhi);
    cudaGetSymbolAddress((void**)&pYlo, g_Ylo);
    cudaGetSymbolAddress((void**)&pZhi, g_Zhi);
    cudaGetSymbolAddress((void**)&pAhi, g_Ahi);
    cudaGetSymbolAddress((void**)&pVthi, g_Vthi);
    cudaGetSymbolAddress((void**)&pWthi, g_Wthi);
    cudaGetSymbolAddress((void**)&pW1thi, g_W1thi);
    cudaGetSymbolAddress((void**)&pW2thi, g_W2thi);
    cudaGetSymbolAddress((void**)&psihi, g_sihi);
    cudaGetSymbolAddress((void**)&psilo, g_silo);
    cudaGetSymbolAddress((void**)&phhi, g_hhi);
    cudaGetSymbolAddress((void**)&phlo, g_hlo);
    cudaGetSymbolAddress((void**)&pPart, g_part);

    cudaFuncSetAttribute(hmma_gemm, cudaFuncAttributeMaxDynamicSharedMemorySize, SMEMSZ);

    // 0) prep (+ si)
    prep_kernel<<<Nn, 256>>>(gene, sp, Ws, bs);

    // 1) all weight splits + biases
    wsplit_all_kernel<<<2051, 256>>>(Wq, Wk, Wv, W1, W2, bq, bk, bv);

    // 2) MLP gemm 1 split-K x4 (segs hi|lo: 4+4 chunks, 2/z)
    dim3 gMLP(HID / BN, Nn / BM, 4);
    hmma_gemm<<<gMLP, 256, SMEMSZ>>>(psihi, psilo, psihi, pW1thi, pW1thi, pW1thi,
                                     HID, HID, 4, 8, 2, 2, 0, 0,
                                     pPart, HID, (size_t)Nn * HID, nullptr, 1.0f,
                                     nullptr, nullptr, 0, nullptr);
    // 3) reduce1 (float4): h = tanh(sum+b1) split
    reduce_mlp1_kernel<<<(Nn * HID) / 1024, 256>>>(b1);

    // 4) MLP gemm 2 split-K x4
    hmma_gemm<<<gMLP, 256, SMEMSZ>>>(phhi, phlo, phhi, pW2thi, pW2thi, pW2thi,
                                     HID, HID, 4, 8, 2, 2, 0, 0,
                                     pPart, HID, (size_t)Nn * HID, nullptr, 1.0f,
                                     nullptr, nullptr, 0, nullptr);
    // 5) reduce2 + f (4 rows/block, float4)
    reduce_f_kernel<<<Nn / 4, 256>>>(b2, Wf, bf_);

    // 6) QKV combined (mode 6): segs Ghi|Glo (8+8 chunks), grid (2, 32, 3)
    dim3 gQKV(HID / BN, Nn / BM, 3);
    hmma_gemm<<<gQKV, 256, SMEMSZ>>>(pGhi, pGlo, pGhi, pWthi, pWthi, pWthi,
                                     GENE, GENE, 8, 16, 16, 0, (size_t)HID * GENE, 6,
                                     nullptr, 0, 0, nullptr, 1.0f, nullptr, nullptr, 0, nullptr);

    // 7) logits: YhiZhi(768->12ch) | YloZhi(QK 256->4ch) + epilogue
    dim3 gLg(Nn / BN, Nn / BM, 1);
    hmma_gemm<<<gLg, 256, SMEMSZ>>>(pYhi, pYlo, pYhi, pZhi, pZhi, pZhi,
                                    YK, YK, 12, 16, 16, 0, 0, 1,
                                    nullptr, 0, 0, nullptr, 1.0f, nullptr, nullptr, 0, sp);

    // 8) softmax -> attn + A hi split
    softmax_kernel<<<Nn, 512>>>(attn);

    // 9) A@V split-K x4 -> partials (hi-only: 64 chunks, 16/z)
    dim3 gAV(OUTD / BN, Nn / BM, 4);
    hmma_gemm<<<gAV, 256, SMEMSZ>>>(pAhi, pAhi, pAhi, pVthi, pVthi, pVthi,
                                    Nn, Nn, 64, 64, 16, 16, 0, 0,
                                    pPart, OUTD, (size_t)Nn * OUTD, nullptr, 1.0f,
                                    nullptr, nullptr, 0, nullptr);
    // 10) reduce partials
    reduce_kernel<<<(Nn * OUTD) / 1024, 256>>>(upd);
}

// round 11
// speedup vs baseline: 11.9795x; 1.1593x over previous
#include <cuda_runtime.h>
#include <cuda_fp16.h>
#include <math.h>
#include <stdint.h>

#define Nn    4096
#define GENE  512
#define HID   256
#define OUTD  256
#define YK    768     // HID + GENE fused logits depth

typedef __half hf;

// ---------------- scratch (static device globals; no runtime allocs) ----------------
__device__ __align__(16) float g_L[(size_t)Nn * Nn];      // logits
__device__ __align__(16) hf    g_Ghi[Nn * GENE];
__device__ __align__(16) hf    g_Glo[Nn * GENE];
__device__ __align__(16) hf    g_Yhi[Nn * YK];
__device__ __align__(16) hf    g_Zhi[Nn * YK];
__device__ __align__(16) hf    g_Ahi[(size_t)Nn * Nn];
__device__ __align__(16) hf    g_Vthi[OUTD * Nn];
__device__ __align__(16) hf    g_Wthi[3 * HID * GENE];    // W^T hi (q,k,v)
__device__ __align__(16) hf    g_W1thi[HID * HID];
__device__ __align__(16) hf    g_W2thi[HID * HID];
__device__ __align__(16) hf    g_sihi[Nn * HID];
__device__ __align__(16) hf    g_silo[Nn * HID];
__device__ __align__(16) hf    g_hhi[Nn * HID];
__device__ __align__(16) hf    g_hlo[Nn * HID];
__device__ __align__(16) float g_part[4 * (size_t)Nn * OUTD];   // split-K partials
__device__ __align__(16) float g_bias[3 * 256];                  // bq|bk|bv
__device__ float g_f[Nn];     // clamp(tanh(f))
__device__ float g_sq[Nn];

// ---------------- PTX helpers (sm_80+ baseline) ----------------
__device__ __forceinline__ uint32_t s2u(const void* p) {
    uint32_t a;
    asm("{ .reg .u64 t; cvta.to.shared.u64 t, %1; cvt.u32.u64 %0, t; }" : "=r"(a) : "l"(p));
    return a;
}
__device__ __forceinline__ void cp16(uint32_t dst, const void* src) {
    asm volatile("cp.async.cg.shared.global [%0], [%1], 16;" :: "r"(dst), "l"(src));
}
__device__ __forceinline__ void cp_commit() {
    asm volatile("cp.async.commit_group;" ::: "memory");
}
template <int N>
__device__ __forceinline__ void cp_wait() {
    asm volatile("cp.async.wait_group %0;" :: "n"(N) : "memory");
}
__device__ __forceinline__ void ldm4(uint32_t* r, uint32_t addr) {
    asm volatile("ldmatrix.sync.aligned.m8n8.x4.shared.b16 {%0,%1,%2,%3}, [%4];"
                 : "=r"(r[0]), "=r"(r[1]), "=r"(r[2]), "=r"(r[3]) : "r"(addr));
}
__device__ __forceinline__ void mma_f16(float* d, const uint32_t* a, uint32_t b0, uint32_t b1) {
    asm volatile(
        "mma.sync.aligned.m16n8k16.row.col.f32.f16.f16.f32 "
        "{%0,%1,%2,%3}, {%4,%5,%6,%7}, {%8,%9}, {%0,%1,%2,%3};"
        : "+f"(d[0]), "+f"(d[1]), "+f"(d[2]), "+f"(d[3])
        : "r"(a[0]), "r"(a[1]), "r"(a[2]), "r"(a[3]), "r"(b0), "r"(b1));
}
__device__ __forceinline__ void split2(float v, hf& h, hf& l) {
    h = __float2half(v);
    l = __float2half(v - __half2float(h));
}

// ---------------- prep: gene splits + normalized rows + sq + si ----------------
__global__ __launch_bounds__(256) void prep_kernel(const float* __restrict__ gene,
                                                   const float* __restrict__ sp,
                                                   const float* __restrict__ Ws,
                                                   const float* __restrict__ bs) {
    int row = blockIdx.x;
    const float* x = gene + (size_t)row * GENE;
    __shared__ float red[256];
    float a = __ldg(sp + 2 * row), b = __ldg(sp + 2 * row + 1);

    {
        int h = threadIdx.x;
        float v = a * __ldg(Ws + h) + b * __ldg(Ws + HID + h) + __ldg(bs + h);
        split2(v, g_sihi[row * HID + h], g_silo[row * HID + h]);
    }

    float ss = 0.f;
    for (int c = threadIdx.x; c < GENE; c += 256) { float v = x[c]; ss += v * v; }
    red[threadIdx.x] = ss; __syncthreads();
    for (int s = 128; s > 0; s >>= 1) {
        if (threadIdx.x < s) red[threadIdx.x] += red[threadIdx.x + s];
        __syncthreads();
    }
    float inv = 1.0f / fmaxf(sqrtf(red[0]), 1e-12f);
    for (int c = threadIdx.x; c < GENE; c += 256) {
        float v = x[c];
        split2(v, g_Ghi[(size_t)row * GENE + c], g_Glo[(size_t)row * GENE + c]);
        hf xh = __float2half(v * inv);
        size_t o = (size_t)row * YK + HID + c;
        g_Yhi[o] = xh;
        g_Zhi[o] = xh;
    }
    if (threadIdx.x == 0) g_sq[row] = a * a + b * b;
}

// ---------------- all weight transpose-splits + bias copies ----------------
__global__ __launch_bounds__(256) void wsplit_all_kernel(
    const float* __restrict__ Wq, const float* __restrict__ Wk, const float* __restrict__ Wv,
    const float* __restrict__ W1, const float* __restrict__ W2,
    const float* __restrict__ bq, const float* __restrict__ bk, const float* __restrict__ bv) {
    int idx = blockIdx.x * 256 + threadIdx.x;
    if (idx < 393216) {                       // 3 x (256 x 512)
        int w = idx / 131072, r = idx % 131072;
        int n = r / GENE, k = r % GENE;
        const float* W = (w == 0) ? Wq : (w == 1) ? Wk : Wv;
        g_Wthi[idx] = __float2half(W[(size_t)k * HID + n]);
    } else if (idx < 458752) {                // W1 (256 x 256)
        int r = idx - 393216;
        int n = r / HID, k = r % HID;
        g_W1thi[r] = __float2half(W1[(size_t)k * HID + n]);
    } else if (idx < 524288) {                // W2
        int r = idx - 458752;
        int n = r / HID, k = r % HID;
        g_W2thi[r] = __float2half(W2[(size_t)k * HID + n]);
    } else {                                  // biases
        int t = idx - 524288;
        if (t < 256)      g_bias[t] = bq[t];
        else if (t < 512) g_bias[t] = bk[t - 256];
        else if (t < 768) g_bias[t] = bv[t - 512];
    }
}

// ---------------- reduce MLP1 partials (float4): h = tanh(sum + b1), split ----------------
__global__ __launch_bounds__(256) void reduce_mlp1_kernel(const float* __restrict__ b1) {
    size_t i4 = ((size_t)blockIdx.x * 256 + threadIdx.x) * 4;   // over Nn*HID
    int col = (int)(i4 & (HID - 1));
    float4 s = *(const float4*)(g_part + i4);
    #pragma unroll
    for (int z = 1; z < 4; z++) {
        float4 p = *(const float4*)(g_part + z * (size_t)Nn * HID + i4);
        s.x += p.x; s.y += p.y; s.z += p.z; s.w += p.w;
    }
    float4 bb = *(const float4*)(b1 + col);
    float t0 = tanhf(s.x + bb.x), t1 = tanhf(s.y + bb.y);
    float t2 = tanhf(s.z + bb.z), t3 = tanhf(s.w + bb.w);
    hf h[4], l[4];
    split2(t0, h[0], l[0]); split2(t1, h[1], l[1]);
    split2(t2, h[2], l[2]); split2(t3, h[3], l[3]);
    *(__half2*)(g_hhi + i4)     = __halves2half2(h[0], h[1]);
    *(__half2*)(g_hhi + i4 + 2) = __halves2half2(h[2], h[3]);
    *(__half2*)(g_hlo + i4)     = __halves2half2(l[0], l[1]);
    *(__half2*)(g_hlo + i4 + 2) = __halves2half2(l[2], l[3]);
}

// ---------------- reduce MLP2 partials + f: 4 rows per block, float4 ----------------
__global__ __launch_bounds__(256) void reduce_f_kernel(const float* __restrict__ b2,
                                                       const float* __restrict__ Wf,
                                                       const float* __restrict__ bf_) {
    int rloc = threadIdx.x >> 6;              // 0..3
    int c4   = (threadIdx.x & 63) * 4;
    int row  = blockIdx.x * 4 + rloc;
    size_t i4 = (size_t)row * HID + c4;
    float4 s = *(const float4*)(g_part + i4);
    #pragma unroll
    for (int z = 1; z < 4; z++) {
        float4 p = *(const float4*)(g_part + z * (size_t)Nn * HID + i4);
        s.x += p.x; s.y += p.y; s.z += p.z; s.w += p.w;
    }
    float4 bb = *(const float4*)(b2 + c4);
    float4 wf = *(const float4*)(Wf + c4);
    float d = fmaxf(s.x + bb.x, 0.f) * wf.x + fmaxf(s.y + bb.y, 0.f) * wf.y
            + fmaxf(s.z + bb.z, 0.f) * wf.z + fmaxf(s.w + bb.w, 0.f) * wf.w;
    __shared__ float red[256];
    red[threadIdx.x] = d;
    __syncthreads();
    #pragma unroll
    for (int st = 32; st > 0; st >>= 1) {
        if ((threadIdx.x & 63) < st) red[threadIdx.x] += red[threadIdx.x + st];
        __syncthreads();
    }
    if ((threadIdx.x & 63) == 0) {
        float t = tanhf(red[rloc * 64] + bf_[0]);
        g_f[row] = fminf(fmaxf(t, -0.999999f), 0.999999f);
    }
}

// ---------------- HMMA split-fp16 GEMM, BK=64, XOR-swizzle, 3-stage pipeline ----------------
// modes: 0 = fp32 C (+bias)*alpha (per-z C offset)
//        1 = logits epilogue -> g_L   (tanh-identity spatial bias)
//        6 = QKV combined (z: 0->Q into Y, 1->K into Z, 2->V transpose)
#define BM 128
#define BN 128
#define BK 64
#define TILEB  16384                 // 128 rows x 128B
#define STAGEB (2 * TILEB)           // A + B
#define NSTAGE 3
#define SMEMSZ (NSTAGE * STAGEB)     // 98304

__global__ __launch_bounds__(256, 2) void hmma_gemm(
    const hf* __restrict__ a0, const hf* __restrict__ a1, const hf* __restrict__ a2,
    const hf* __restrict__ b0, const hf* __restrict__ b1, const hf* __restrict__ b2,
    int pitchA, int pitchB, int cb1, int cb2, int chunks_per_z, int zchunks,
    size_t zBstride, int mode,
    float* __restrict__ C, int ldc, size_t zCstride,
    const float* __restrict__ bias, float alpha,
    hf* __restrict__ Dhi, hf* __restrict__ Dlo, int ldd,
    const float* __restrict__ sp)
{
    extern __shared__ __align__(16) char smem[];
    const uint32_t sbase = s2u(smem);
    const int tid  = threadIdx.x;
    const int lane = tid & 31;
    const int wid  = tid >> 5;
    const int wm   = (wid & 3) * 32;
    const int wn   = (wid >> 2) * 64;
    const int gm0  = blockIdx.y * BM;
    const int gn0  = blockIdx.x * BN;
    const int z    = blockIdx.z;

    if (zBstride) { b0 += z * zBstride; b1 += z * zBstride; b2 += z * zBstride; }
    const int g0 = z * zchunks;

    const int mi    = lane >> 3;
    const int ldrow = ((mi & 1) << 3) + (lane & 7);
    const int ldc16 = mi >> 1;
    const int srow0 = tid >> 3;
    const int sc    = tid & 7;

    float acc[2][8][4];
    #pragma unroll
    for (int a = 0; a < 2; a++)
        #pragma unroll
        for (int b = 0; b < 8; b++)
            #pragma unroll
            for (int c = 0; c < 4; c++) acc[a][b][c] = 0.f;

    auto load_chunk = [&](int g, int stage) {
        const hf *As, *Bs; int kk;
        if (g < cb1)      { As = a0; Bs = b0; kk = g * BK; }
        else if (g < cb2) { As = a1; Bs = b1; kk = (g - cb1) * BK; }
        else              { As = a2; Bs = b2; kk = (g - cb2) * BK; }
        uint32_t dst = sbase + stage * STAGEB;
        #pragma unroll
        for (int i = 0; i < 4; i++) {
            int row = srow0 + i * 32;
            uint32_t off = (uint32_t)(row * 128 + ((sc ^ (row & 7)) << 4));
            cp16(dst + off,         As + (size_t)(gm0 + row) * pitchA + kk + sc * 8);
            cp16(dst + TILEB + off, Bs + (size_t)(gn0 + row) * pitchB + kk + sc * 8);
        }
        cp_commit();
    };

    load_chunk(g0, 0);
    if (chunks_per_z > 1) load_chunk(g0 + 1, 1);
    else cp_commit();

    for (int c = 0; c < chunks_per_z; c++) {
        if (c + 1 < chunks_per_z) cp_wait<1>(); else cp_wait<0>();
        __syncthreads();
        if (c + 2 < chunks_per_z) load_chunk(g0 + c + 2, (c + 2) % NSTAGE);

        uint32_t abase = sbase + (c % NSTAGE) * STAGEB;
        uint32_t bbase = abase + TILEB;
        #pragma unroll
        for (int ks = 0; ks < 4; ks++) {
            uint32_t afrag[2][4];
            uint32_t bfrag[4][4];
            int c16 = ks * 2 + ldc16;
            #pragma unroll
            for (int mt = 0; mt < 2; mt++) {
                int row = wm + mt * 16 + ldrow;
                ldm4(afrag[mt], abase + row * 128 + ((c16 ^ (row & 7)) << 4));
            }
            #pragma unroll
            for (int p = 0; p < 4; p++) {
                int row = wn + p * 16 + ldrow;
                ldm4(bfrag[p], bbase + row * 128 + ((c16 ^ (row & 7)) << 4));
            }
            #pragma unroll
            for (int mt = 0; mt < 2; mt++) {
                #pragma unroll
                for (int p = 0; p < 4; p++) {
                    mma_f16(acc[mt][2 * p],     afrag[mt], bfrag[p][0], bfrag[p][2]);
                    mma_f16(acc[mt][2 * p + 1], afrag[mt], bfrag[p][1], bfrag[p][3]);
                }
            }
        }
    }

    // ---- epilogue ----
    const int r0 = lane >> 2;
    const int cl = 2 * (lane & 3);

    if (mode == 1) {
        float* ex = (float*)smem;
        __syncthreads();
        for (int i = tid; i < BN; i += 256) {
            int n = gn0 + i;
            ex[i]           = __ldg(sp + 2 * n);
            ex[BN + i]      = __ldg(sp + 2 * n + 1);
            ex[2 * BN + i]  = g_sq[n];
            ex[3 * BN + i]  = g_f[n];
        }
        __syncthreads();
        #pragma unroll
        for (int mt = 0; mt < 2; mt++) {
            #pragma unroll
            for (int half = 0; half < 2; half++) {
                int m = gm0 + wm + mt * 16 + r0 + half * 8;
                float sp0 = __ldg(sp + 2 * m), sp1 = __ldg(sp + 2 * m + 1);
                float sqi = g_sq[m], ti = g_f[m];
                #pragma unroll
                for (int nt = 0; nt < 8; nt++) {
                    int nl = wn + nt * 8 + cl;
                    float2 v;
                    #pragma unroll
                    for (int q = 0; q < 2; q++) {
                        int ci = nl + q;
                        float d2 = sqi + ex[2 * BN + ci]
                                 - 2.0f * (sp0 * ex[ci] + sp1 * ex[BN + ci]);
                        d2 = fmaxf(d2, 0.0f);
                        float tj = ex[3 * BN + ci];
                        float tb = __fdividef(ti - tj, fmaf(-ti, tj, 1.0f));
                        float a = acc[mt][nt][half * 2 + q];
                        ((float*)&v)[q] = a + __expf(-0.5f * d2) + tb;
                    }
                    *(float2*)(g_L + (size_t)m * Nn + gn0 + nl) = v;
                }
            }
        }
    } else if (mode == 0) {
        float* Cz = C + z * zCstride;
        #pragma unroll
        for (int mt = 0; mt < 2; mt++)
            #pragma unroll
            for (int half = 0; half < 2; half++) {
                int m = gm0 + wm + mt * 16 + r0 + half * 8;
                #pragma unroll
                for (int nt = 0; nt < 8; nt++) {
                    int n = gn0 + wn + nt * 8 + cl;
                    float b0v = bias ? __ldg(bias + n)     : 0.f;
                    float b1v = bias ? __ldg(bias + n + 1) : 0.f;
                    float2 v;
                    v.x = (acc[mt][nt][half * 2 + 0] + b0v) * alpha;
                    v.y = (acc[mt][nt][half * 2 + 1] + b1v) * alpha;
                    *(float2*)(Cz + (size_t)m * ldc + n) = v;
                }
            }
    } else { // mode 6: QKV combined
        const float* bias6 = g_bias + z * 256;
        if (z == 2) {
            #pragma unroll
            for (int mt = 0; mt < 2; mt++)
                #pragma unroll
                for (int half = 0; half < 2; half++) {
                    int m = gm0 + wm + mt * 16 + r0 + half * 8;
                    #pragma unroll
                    for (int nt = 0; nt < 8; nt++) {
                        int n = gn0 + wn + nt * 8 + cl;
                        #pragma unroll
                        for (int q = 0; q < 2; q++) {
                            float v = acc[mt][nt][half * 2 + q] + bias6[n + q];
                            g_Vthi[(size_t)(n + q) * Nn + m] = __float2half(v);
                        }
                    }
                }
        } else {
            hf* Dh = z ? g_Zhi : g_Yhi;
            float al = z ? 1.0f : (1.0f / 16.0f);
            #pragma unroll
            for (int mt = 0; mt < 2; mt++)
                #pragma unroll
                for (int half = 0; half < 2; half++) {
                    int m = gm0 + wm + mt * 16 + r0 + half * 8;
                    #pragma unroll
                    for (int nt = 0; nt < 8; nt++) {
                        int n = gn0 + wn + nt * 8 + cl;
                        #pragma unroll
                        for (int q = 0; q < 2; q++) {
                            float v = (acc[mt][nt][half * 2 + q] + bias6[n + q]) * al;
                            Dh[(size_t)m * YK + n + q] = __float2half(v);
                        }
                    }
                }
        }
    }
}

// ---------------- softmax: 512 threads/row, warp-shuffle reductions ----------------
__global__ __launch_bounds__(512) void softmax_kernel(float* __restrict__ attn) {
    int row = blockIdx.x;
    int tid = threadIdx.x;
    int lane = tid & 31, wrp = tid >> 5;
    float* L = g_L + (size_t)row * Nn;
    __shared__ float red[16];
    float4 v[2];
    float m = -1e30f;
    #pragma unroll
    for (int i = 0; i < 2; i++) {
        v[i] = *(const float4*)(L + tid * 4 + i * 2048);
        m = fmaxf(m, fmaxf(fmaxf(v[i].x, v[i].y), fmaxf(v[i].z, v[i].w)));
    }
    #pragma unroll
    for (int o = 16; o > 0; o >>= 1) m = fmaxf(m, __shfl_xor_sync(0xFFFFFFFFu, m, o));
    if (lane == 0) red[wrp] = m;
    __syncthreads();
    m = red[lane & 15];
    #pragma unroll
    for (int o = 8; o > 0; o >>= 1) m = fmaxf(m, __shfl_xor_sync(0xFFFFFFFFu, m, o));
    float rm = m;   // uniform across warp

    float sum = 0.f;
    #pragma unroll
    for (int i = 0; i < 2; i++) {
        v[i].x = __expf(v[i].x - rm);
        v[i].y = __expf(v[i].y - rm);
        v[i].z = __expf(v[i].z - rm);
        v[i].w = __expf(v[i].w - rm);
        sum += (v[i].x + v[i].y) + (v[i].z + v[i].w);
    }
    #pragma unroll
    for (int o = 16; o > 0; o >>= 1) sum += __shfl_xor_sync(0xFFFFFFFFu, sum, o);
    __syncthreads();       // protect red reuse
    if (lane == 0) red[wrp] = sum;
    __syncthreads();
    sum = red[lane & 15];
    #pragma unroll
    for (int o = 8; o > 0; o >>= 1) sum += __shfl_xor_sync(0xFFFFFFFFu, sum, o);
    float inv = 1.0f / sum;

    #pragma unroll
    for (int i = 0; i < 2; i++) {
        int j = tid * 4 + i * 2048;
        float4 a;
        a.x = v[i].x * inv; a.y = v[i].y * inv; a.z = v[i].z * inv; a.w = v[i].w * inv;
        *(float4*)(attn + (size_t)row * Nn + j) = a;
        *(__half2*)(g_Ahi + (size_t)row * Nn + j) =
            __halves2half2(__float2half(a.x), __float2half(a.y));
        *(__half2*)(g_Ahi + (size_t)row * Nn + j + 2) =
            __halves2half2(__float2half(a.z), __float2half(a.w));
    }
}

// ---------------- reduce A@V split-K partials (4-way) ----------------
__global__ __launch_bounds__(256) void reduce_kernel(float* __restrict__ upd) {
    size_t i = ((size_t)blockIdx.x * 256 + threadIdx.x) * 4;
    float4 s = *(const float4*)(g_part + i);
    #pragma unroll
    for (int z = 1; z < 4; z++) {
        const float4 p = *(const float4*)(g_part + z * (size_t)Nn * OUTD + i);
        s.x += p.x; s.y += p.y; s.z += p.z; s.w += p.w;
    }
    *(float4*)(upd + i) = s;
}

// ---------------- launch ----------------
extern "C" void kernel_launch(void* const* d_in, const int* in_sizes, int n_in,
                              void* d_out, int out_size) {
    const float* gene = (const float*)d_in[0];
    const float* sp   = (const float*)d_in[1];
    const float* Wq   = (const float*)d_in[2];
    const float* bq   = (const float*)d_in[3];
    const float* Wk   = (const float*)d_in[4];
    const float* bk   = (const float*)d_in[5];
    const float* Wv   = (const float*)d_in[6];
    const float* bv   = (const float*)d_in[7];
    const float* Ws   = (const float*)d_in[8];
    const float* bs   = (const float*)d_in[9];
    const float* W1   = (const float*)d_in[10];
    const float* b1   = (const float*)d_in[11];
    const float* W2   = (const float*)d_in[12];
    const float* b2   = (const float*)d_in[13];
    const float* Wf   = (const float*)d_in[14];
    const float* bf_  = (const float*)d_in[15];

    float* out = (float*)d_out;
    long long total = (long long)Nn * Nn + (long long)Nn * OUTD;
    int has_attn = ((long long)out_size >= total) ? 1 : 0;
    float* attn = out;
    float* upd  = has_attn ? out + (size_t)Nn * Nn : out;

    hf *pGhi, *pGlo, *pYhi, *pZhi, *pAhi, *pVthi;
    hf *pWthi, *pW1thi, *pW2thi, *psihi, *psilo, *phhi, *phlo;
    float *pPart;
    cudaGetSymbolAddress((void**)&pGhi, g_Ghi);
    cudaGetSymbolAddress((void**)&pGlo, g_Glo);
    cudaGetSymbolAddress((void**)&pYhi, g_Yhi);
    cudaGetSymbolAddress((void**)&pZhi, g_Zhi);
    cudaGetSymbolAddress((void**)&pAhi, g_Ahi);
    cudaGetSymbolAddress((void**)&pVthi, g_Vthi);
    cudaGetSymbolAddress((void**)&pWthi, g_Wthi);
    cudaGetSymbolAddress((void**)&pW1thi, g_W1thi);
    cudaGetSymbolAddress((void**)&pW2thi, g_W2thi);
    cudaGetSymbolAddress((void**)&psihi, g_sihi);
    cudaGetSymbolAddress((void**)&psilo, g_silo);
    cudaGetSymbolAddress((void**)&phhi, g_hhi);
    cudaGetSymbolAddress((void**)&phlo, g_hlo);
    cudaGetSymbolAddress((void**)&pPart, g_part);

    cudaFuncSetAttribute(hmma_gemm, cudaFuncAttributeMaxDynamicSharedMemorySize, SMEMSZ);

    // 0) prep (+ si)
    prep_kernel<<<Nn, 256>>>(gene, sp, Ws, bs);

    // 1) all weight splits + biases
    wsplit_all_kernel<<<2051, 256>>>(Wq, Wk, Wv, W1, W2, bq, bk, bv);

    // 2) MLP gemm 1 split-K x4 (segs hi|lo: 4+4 chunks, 2/z)
    dim3 gMLP(HID / BN, Nn / BM, 4);
    hmma_gemm<<<gMLP, 256, SMEMSZ>>>(psihi, psilo, psihi, pW1thi, pW1thi, pW1thi,
                                     HID, HID, 4, 8, 2, 2, 0, 0,
                                     pPart, HID, (size_t)Nn * HID, nullptr, 1.0f,
                                     nullptr, nullptr, 0, nullptr);
    // 3) reduce1 (float4): h = tanh(sum+b1) split
    reduce_mlp1_kernel<<<(Nn * HID) / 1024, 256>>>(b1);

    // 4) MLP gemm 2 split-K x4
    hmma_gemm<<<gMLP, 256, SMEMSZ>>>(phhi, phlo, phhi, pW2thi, pW2thi, pW2thi,
                                     HID, HID, 4, 8, 2, 2, 0, 0,
                                     pPart, HID, (size_t)Nn * HID, nullptr, 1.0f,
                                     nullptr, nullptr, 0, nullptr);
    // 5) reduce2 + f (4 rows/block, float4)
    reduce_f_kernel<<<Nn / 4, 256>>>(b2, Wf, bf_);

    // 6) QKV combined (mode 6): segs Ghi|Glo (8+8 chunks), grid (2, 32, 3)
    dim3 gQKV(HID / BN, Nn / BM, 3);
    hmma_gemm<<<gQKV, 256, SMEMSZ>>>(pGhi, pGlo, pGhi, pWthi, pWthi, pWthi,
                                     GENE, GENE, 8, 16, 16, 0, (size_t)HID * GENE, 6,
                                     nullptr, 0, 0, nullptr, 1.0f, nullptr, nullptr, 0, nullptr);

    // 7) logits: single-segment Yhi·Zhi (768 -> 12 chunks) + epilogue
    dim3 gLg(Nn / BN, Nn / BM, 1);
    hmma_gemm<<<gLg, 256, SMEMSZ>>>(pYhi, pYhi, pYhi, pZhi, pZhi, pZhi,
                                    YK, YK, 12, 12, 12, 0, 0, 1,
                                    nullptr, 0, 0, nullptr, 1.0f, nullptr, nullptr, 0, sp);

    // 8) softmax -> attn + A hi split
    softmax_kernel<<<Nn, 512>>>(attn);

    // 9) A@V split-K x4 -> partials (hi-only: 64 chunks, 16/z)
    dim3 gAV(OUTD / BN, Nn / BM, 4);
    hmma_gemm<<<gAV, 256, SMEMSZ>>>(pAhi, pAhi, pAhi, pVthi, pVthi, pVthi,
                                    Nn, Nn, 64, 64, 16, 16, 0, 0,
                                    pPart, OUTD, (size_t)Nn * OUTD, nullptr, 1.0f,
                                    nullptr, nullptr, 0, nullptr);
    // 10) reduce partials
    reduce_kernel<<<(Nn * OUTD) / 1024, 256>>>(upd);
}

// round 12
// speedup vs baseline: 13.2557x; 1.1065x over previous
#include <cuda_runtime.h>
#include <cuda_fp16.h>
#include <math.h>
#include <stdint.h>

#define Nn    4096
#define GENE  512
#define HID   256
#define OUTD  256
#define YK    768     // HID + GENE fused logits depth

typedef __half hf;

// ---------------- scratch (static device globals; no runtime allocs) ----------------
__device__ __align__(16) float g_L[(size_t)Nn * Nn];      // logits
__device__ __align__(16) hf    g_Ghi[Nn * GENE];
__device__ __align__(16) hf    g_Yhi[Nn * YK];
__device__ __align__(16) hf    g_Zhi[Nn * YK];
__device__ __align__(16) hf    g_Ahi[(size_t)Nn * Nn];
__device__ __align__(16) hf    g_Vthi[OUTD * Nn];
__device__ __align__(16) hf    g_Wthi[3 * HID * GENE];    // W^T hi (q,k,v)
__device__ __align__(16) hf    g_W2thi[HID * HID];
__device__ __align__(16) hf    g_hhi[Nn * HID];
__device__ __align__(16) hf    g_hlo[Nn * HID];
__device__ __align__(16) float g_part[4 * (size_t)Nn * OUTD];   // split-K partials
__device__ __align__(16) float g_bias[3 * 256];                  // bq|bk|bv
__device__ __align__(16) float g_W1c[2 * HID];                   // Ws @ W1
__device__ __align__(16) float g_b1c[HID];                       // bs @ W1 + b1
__device__ float g_f[Nn];     // clamp(tanh(f))
__device__ float g_sq[Nn];

// ---------------- PTX helpers (sm_80+ baseline) ----------------
__device__ __forceinline__ uint32_t s2u(const void* p) {
    uint32_t a;
    asm("{ .reg .u64 t; cvta.to.shared.u64 t, %1; cvt.u32.u64 %0, t; }" : "=r"(a) : "l"(p));
    return a;
}
__device__ __forceinline__ void cp16(uint32_t dst, const void* src) {
    asm volatile("cp.async.cg.shared.global [%0], [%1], 16;" :: "r"(dst), "l"(src));
}
__device__ __forceinline__ void cp_commit() {
    asm volatile("cp.async.commit_group;" ::: "memory");
}
template <int N>
__device__ __forceinline__ void cp_wait() {
    asm volatile("cp.async.wait_group %0;" :: "n"(N) : "memory");
}
__device__ __forceinline__ void ldm4(uint32_t* r, uint32_t addr) {
    asm volatile("ldmatrix.sync.aligned.m8n8.x4.shared.b16 {%0,%1,%2,%3}, [%4];"
                 : "=r"(r[0]), "=r"(r[1]), "=r"(r[2]), "=r"(r[3]) : "r"(addr));
}
__device__ __forceinline__ void mma_f16(float* d, const uint32_t* a, uint32_t b0, uint32_t b1) {
    asm volatile(
        "mma.sync.aligned.m16n8k16.row.col.f32.f16.f16.f32 "
        "{%0,%1,%2,%3}, {%4,%5,%6,%7}, {%8,%9}, {%0,%1,%2,%3};"
        : "+f"(d[0]), "+f"(d[1]), "+f"(d[2]), "+f"(d[3])
        : "r"(a[0]), "r"(a[1]), "r"(a[2]), "r"(a[3]), "r"(b0), "r"(b1));
}
__device__ __forceinline__ void split2(float v, hf& h, hf& l) {
    h = __float2half(v);
    l = __float2half(v - __half2float(h));
}

// ---------------- combine: W1c = Ws@W1 (2x256), b1c = bs@W1 + b1 ----------------
__global__ __launch_bounds__(256) void combine_kernel(const float* __restrict__ Ws,
                                                      const float* __restrict__ bs,
                                                      const float* __restrict__ W1,
                                                      const float* __restrict__ b1) {
    int h = blockIdx.x;
    int k = threadIdx.x;
    float w = __ldg(W1 + k * HID + h);
    __shared__ float r0[256], r1[256], r2[256];
    r0[k] = __ldg(Ws + k) * w;
    r1[k] = __ldg(Ws + HID + k) * w;
    r2[k] = __ldg(bs + k) * w;
    __syncthreads();
    for (int s = 128; s > 0; s >>= 1) {
        if (k < s) { r0[k] += r0[k + s]; r1[k] += r1[k + s]; r2[k] += r2[k + s]; }
        __syncthreads();
    }
    if (k == 0) {
        g_W1c[h]       = r0[0];
        g_W1c[HID + h] = r1[0];
        g_b1c[h]       = r2[0] + __ldg(b1 + h);
    }
}

// ---------------- prep: gene fp16 + normalized rows + sq + h (=tanh MLP1) ----------------
__global__ __launch_bounds__(256) void prep_kernel(const float* __restrict__ gene,
                                                   const float* __restrict__ sp) {
    int row = blockIdx.x;
    const float* x = gene + (size_t)row * GENE;
    __shared__ float red[256];
    float a = __ldg(sp + 2 * row), b = __ldg(sp + 2 * row + 1);

    // h = tanh(sp @ W1c + b1c)  (exact rank-2 MLP1 collapse)
    {
        int h = threadIdx.x;
        float v = a * g_W1c[h] + b * g_W1c[HID + h] + g_b1c[h];
        float t = tanhf(v);
        split2(t, g_hhi[row * HID + h], g_hlo[row * HID + h]);
    }

    float ss = 0.f;
    for (int c = threadIdx.x; c < GENE; c += 256) { float v = x[c]; ss += v * v; }
    red[threadIdx.x] = ss; __syncthreads();
    for (int s = 128; s > 0; s >>= 1) {
        if (threadIdx.x < s) red[threadIdx.x] += red[threadIdx.x + s];
        __syncthreads();
    }
    float inv = 1.0f / fmaxf(sqrtf(red[0]), 1e-12f);
    for (int c = threadIdx.x; c < GENE; c += 256) {
        float v = x[c];
        g_Ghi[(size_t)row * GENE + c] = __float2half(v);
        hf xh = __float2half(v * inv);
        size_t o = (size_t)row * YK + HID + c;
        g_Yhi[o] = xh;
        g_Zhi[o] = xh;
    }
    if (threadIdx.x == 0) g_sq[row] = a * a + b * b;
}

// ---------------- weight transposes (fp16) + bias copies ----------------
__global__ __launch_bounds__(256) void wsplit_all_kernel(
    const float* __restrict__ Wq, const float* __restrict__ Wk, const float* __restrict__ Wv,
    const float* __restrict__ W2,
    const float* __restrict__ bq, const float* __restrict__ bk, const float* __restrict__ bv) {
    int idx = blockIdx.x * 256 + threadIdx.x;
    if (idx < 393216) {                       // 3 x (256 x 512)
        int w = idx / 131072, r = idx % 131072;
        int n = r / GENE, k = r % GENE;
        const float* W = (w == 0) ? Wq : (w == 1) ? Wk : Wv;
        g_Wthi[idx] = __float2half(W[(size_t)k * HID + n]);
    } else if (idx < 458752) {                // W2 (256 x 256)
        int r = idx - 393216;
        int n = r / HID, k = r % HID;
        g_W2thi[r] = __float2half(W2[(size_t)k * HID + n]);
    } else if (idx < 459520) {                // biases
        int t = idx - 458752;
        if (t < 256)      g_bias[t] = bq[t];
        else if (t < 512) g_bias[t] = bk[t - 256];
        else              g_bias[t] = bv[t - 512];
    }
}

// ---------------- reduce MLP2 partials + f: 4 rows per block, float4 ----------------
__global__ __launch_bounds__(256) void reduce_f_kernel(const float* __restrict__ b2,
                                                       const float* __restrict__ Wf,
                                                       const float* __restrict__ bf_) {
    int rloc = threadIdx.x >> 6;              // 0..3
    int c4   = (threadIdx.x & 63) * 4;
    int row  = blockIdx.x * 4 + rloc;
    size_t i4 = (size_t)row * HID + c4;
    float4 s = *(const float4*)(g_part + i4);
    #pragma unroll
    for (int z = 1; z < 4; z++) {
        float4 p = *(const float4*)(g_part + z * (size_t)Nn * HID + i4);
        s.x += p.x; s.y += p.y; s.z += p.z; s.w += p.w;
    }
    float4 bb = *(const float4*)(b2 + c4);
    float4 wf = *(const float4*)(Wf + c4);
    float d = fmaxf(s.x + bb.x, 0.f) * wf.x + fmaxf(s.y + bb.y, 0.f) * wf.y
            + fmaxf(s.z + bb.z, 0.f) * wf.z + fmaxf(s.w + bb.w, 0.f) * wf.w;
    __shared__ float red[256];
    red[threadIdx.x] = d;
    __syncthreads();
    #pragma unroll
    for (int st = 32; st > 0; st >>= 1) {
        if ((threadIdx.x & 63) < st) red[threadIdx.x] += red[threadIdx.x + st];
        __syncthreads();
    }
    if ((threadIdx.x & 63) == 0) {
        float t = tanhf(red[rloc * 64] + bf_[0]);
        g_f[row] = fminf(fmaxf(t, -0.999999f), 0.999999f);
    }
}

// ---------------- HMMA fp16 GEMM, BK=64, XOR-swizzle, 3-stage pipeline ----------------
// modes: 0 = fp32 C (+bias)*alpha (per-z C offset)
//        1 = logits epilogue -> g_L   (tanh-identity spatial bias)
//        6 = QKV combined (z: 0->Q into Y, 1->K into Z, 2->V transpose)
#define BM 128
#define BN 128
#define BK 64
#define TILEB  16384                 // 128 rows x 128B
#define STAGEB (2 * TILEB)           // A + B
#define NSTAGE 3
#define SMEMSZ (NSTAGE * STAGEB)     // 98304

__global__ __launch_bounds__(256, 2) void hmma_gemm(
    const hf* __restrict__ a0, const hf* __restrict__ a1, const hf* __restrict__ a2,
    const hf* __restrict__ b0, const hf* __restrict__ b1, const hf* __restrict__ b2,
    int pitchA, int pitchB, int cb1, int cb2, int chunks_per_z, int zchunks,
    size_t zBstride, int mode,
    float* __restrict__ C, int ldc, size_t zCstride,
    const float* __restrict__ bias, float alpha,
    hf* __restrict__ Dhi, hf* __restrict__ Dlo, int ldd,
    const float* __restrict__ sp)
{
    extern __shared__ __align__(16) char smem[];
    const uint32_t sbase = s2u(smem);
    const int tid  = threadIdx.x;
    const int lane = tid & 31;
    const int wid  = tid >> 5;
    const int wm   = (wid & 3) * 32;
    const int wn   = (wid >> 2) * 64;
    const int gm0  = blockIdx.y * BM;
    const int gn0  = blockIdx.x * BN;
    const int z    = blockIdx.z;

    if (zBstride) { b0 += z * zBstride; b1 += z * zBstride; b2 += z * zBstride; }
    const int g0 = z * zchunks;

    const int mi    = lane >> 3;
    const int ldrow = ((mi & 1) << 3) + (lane & 7);
    const int ldc16 = mi >> 1;
    const int srow0 = tid >> 3;
    const int sc    = tid & 7;

    float acc[2][8][4];
    #pragma unroll
    for (int a = 0; a < 2; a++)
        #pragma unroll
        for (int b = 0; b < 8; b++)
            #pragma unroll
            for (int c = 0; c < 4; c++) acc[a][b][c] = 0.f;

    auto load_chunk = [&](int g, int stage) {
        const hf *As, *Bs; int kk;
        if (g < cb1)      { As = a0; Bs = b0; kk = g * BK; }
        else if (g < cb2) { As = a1; Bs = b1; kk = (g - cb1) * BK; }
        else              { As = a2; Bs = b2; kk = (g - cb2) * BK; }
        uint32_t dst = sbase + stage * STAGEB;
        #pragma unroll
        for (int i = 0; i < 4; i++) {
            int row = srow0 + i * 32;
            uint32_t off = (uint32_t)(row * 128 + ((sc ^ (row & 7)) << 4));
            cp16(dst + off,         As + (size_t)(gm0 + row) * pitchA + kk + sc * 8);
            cp16(dst + TILEB + off, Bs + (size_t)(gn0 + row) * pitchB + kk + sc * 8);
        }
        cp_commit();
    };

    load_chunk(g0, 0);
    if (chunks_per_z > 1) load_chunk(g0 + 1, 1);
    else cp_commit();

    for (int c = 0; c < chunks_per_z; c++) {
        if (c + 1 < chunks_per_z) cp_wait<1>(); else cp_wait<0>();
        __syncthreads();
        if (c + 2 < chunks_per_z) load_chunk(g0 + c + 2, (c + 2) % NSTAGE);

        uint32_t abase = sbase + (c % NSTAGE) * STAGEB;
        uint32_t bbase = abase + TILEB;
        #pragma unroll
        for (int ks = 0; ks < 4; ks++) {
            uint32_t afrag[2][4];
            uint32_t bfrag[4][4];
            int c16 = ks * 2 + ldc16;
            #pragma unroll
            for (int mt = 0; mt < 2; mt++) {
                int row = wm + mt * 16 + ldrow;
                ldm4(afrag[mt], abase + row * 128 + ((c16 ^ (row & 7)) << 4));
            }
            #pragma unroll
            for (int p = 0; p < 4; p++) {
                int row = wn + p * 16 + ldrow;
                ldm4(bfrag[p], bbase + row * 128 + ((c16 ^ (row & 7)) << 4));
            }
            #pragma unroll
            for (int mt = 0; mt < 2; mt++) {
                #pragma unroll
                for (int p = 0; p < 4; p++) {
                    mma_f16(acc[mt][2 * p],     afrag[mt], bfrag[p][0], bfrag[p][2]);
                    mma_f16(acc[mt][2 * p + 1], afrag[mt], bfrag[p][1], bfrag[p][3]);
                }
            }
        }
    }

    // ---- epilogue ----
    const int r0 = lane >> 2;
    const int cl = 2 * (lane & 3);

    if (mode == 1) {
        float* ex = (float*)smem;
        __syncthreads();
        for (int i = tid; i < BN; i += 256) {
            int n = gn0 + i;
            ex[i]           = __ldg(sp + 2 * n);
            ex[BN + i]      = __ldg(sp + 2 * n + 1);
            ex[2 * BN + i]  = g_sq[n];
            ex[3 * BN + i]  = g_f[n];
        }
        __syncthreads();
        #pragma unroll
        for (int mt = 0; mt < 2; mt++) {
            #pragma unroll
            for (int half = 0; half < 2; half++) {
                int m = gm0 + wm + mt * 16 + r0 + half * 8;
                float sp0 = __ldg(sp + 2 * m), sp1 = __ldg(sp + 2 * m + 1);
                float sqi = g_sq[m], ti = g_f[m];
                #pragma unroll
                for (int nt = 0; nt < 8; nt++) {
                    int nl = wn + nt * 8 + cl;
                    float2 v;
                    #pragma unroll
                    for (int q = 0; q < 2; q++) {
                        int ci = nl + q;
                        float d2 = sqi + ex[2 * BN + ci]
                                 - 2.0f * (sp0 * ex[ci] + sp1 * ex[BN + ci]);
                        d2 = fmaxf(d2, 0.0f);
                        float tj = ex[3 * BN + ci];
                        float tb = __fdividef(ti - tj, fmaf(-ti, tj, 1.0f));
                        float a = acc[mt][nt][half * 2 + q];
                        ((float*)&v)[q] = a + __expf(-0.5f * d2) + tb;
                    }
                    *(float2*)(g_L + (size_t)m * Nn + gn0 + nl) = v;
                }
            }
        }
    } else if (mode == 0) {
        float* Cz = C + z * zCstride;
        #pragma unroll
        for (int mt = 0; mt < 2; mt++)
            #pragma unroll
            for (int half = 0; half < 2; half++) {
                int m = gm0 + wm + mt * 16 + r0 + half * 8;
                #pragma unroll
                for (int nt = 0; nt < 8; nt++) {
                    int n = gn0 + wn + nt * 8 + cl;
                    float b0v = bias ? __ldg(bias + n)     : 0.f;
                    float b1v = bias ? __ldg(bias + n + 1) : 0.f;
                    float2 v;
                    v.x = (acc[mt][nt][half * 2 + 0] + b0v) * alpha;
                    v.y = (acc[mt][nt][half * 2 + 1] + b1v) * alpha;
                    *(float2*)(Cz + (size_t)m * ldc + n) = v;
                }
            }
    } else { // mode 6: QKV combined
        const float* bias6 = g_bias + z * 256;
        if (z == 2) {
            #pragma unroll
            for (int mt = 0; mt < 2; mt++)
                #pragma unroll
                for (int half = 0; half < 2; half++) {
                    int m = gm0 + wm + mt * 16 + r0 + half * 8;
                    #pragma unroll
                    for (int nt = 0; nt < 8; nt++) {
                        int n = gn0 + wn + nt * 8 + cl;
                        #pragma unroll
                        for (int q = 0; q < 2; q++) {
                            float v = acc[mt][nt][half * 2 + q] + bias6[n + q];
                            g_Vthi[(size_t)(n + q) * Nn + m] = __float2half(v);
                        }
                    }
                }
        } else {
            hf* Dh = z ? g_Zhi : g_Yhi;
            float al = z ? 1.0f : (1.0f / 16.0f);
            #pragma unroll
            for (int mt = 0; mt < 2; mt++)
                #pragma unroll
                for (int half = 0; half < 2; half++) {
                    int m = gm0 + wm + mt * 16 + r0 + half * 8;
                    #pragma unroll
                    for (int nt = 0; nt < 8; nt++) {
                        int n = gn0 + wn + nt * 8 + cl;
                        #pragma unroll
                        for (int q = 0; q < 2; q++) {
                            float v = (acc[mt][nt][half * 2 + q] + bias6[n + q]) * al;
                            Dh[(size_t)m * YK + n + q] = __float2half(v);
                        }
                    }
                }
        }
    }
}

// ---------------- softmax: 512 threads/row, warp-shuffle reductions ----------------
__global__ __launch_bounds__(512) void softmax_kernel(float* __restrict__ attn) {
    int row = blockIdx.x;
    int tid = threadIdx.x;
    int lane = tid & 31, wrp = tid >> 5;
    float* L = g_L + (size_t)row * Nn;
    __shared__ float red[16];
    float4 v[2];
    float m = -1e30f;
    #pragma unroll
    for (int i = 0; i < 2; i++) {
        v[i] = *(const float4*)(L + tid * 4 + i * 2048);
        m = fmaxf(m, fmaxf(fmaxf(v[i].x, v[i].y), fmaxf(v[i].z, v[i].w)));
    }
    #pragma unroll
    for (int o = 16; o > 0; o >>= 1) m = fmaxf(m, __shfl_xor_sync(0xFFFFFFFFu, m, o));
    if (lane == 0) red[wrp] = m;
    __syncthreads();
    m = red[lane & 15];
    #pragma unroll
    for (int o = 8; o > 0; o >>= 1) m = fmaxf(m, __shfl_xor_sync(0xFFFFFFFFu, m, o));
    float rm = m;

    float sum = 0.f;
    #pragma unroll
    for (int i = 0; i < 2; i++) {
        v[i].x = __expf(v[i].x - rm);
        v[i].y = __expf(v[i].y - rm);
        v[i].z = __expf(v[i].z - rm);
        v[i].w = __expf(v[i].w - rm);
        sum += (v[i].x + v[i].y) + (v[i].z + v[i].w);
    }
    #pragma unroll
    for (int o = 16; o > 0; o >>= 1) sum += __shfl_xor_sync(0xFFFFFFFFu, sum, o);
    __syncthreads();
    if (lane == 0) red[wrp] = sum;
    __syncthreads();
    sum = red[lane & 15];
    #pragma unroll
    for (int o = 8; o > 0; o >>= 1) sum += __shfl_xor_sync(0xFFFFFFFFu, sum, o);
    float inv = 1.0f / sum;

    #pragma unroll
    for (int i = 0; i < 2; i++) {
        int j = tid * 4 + i * 2048;
        float4 a;
        a.x = v[i].x * inv; a.y = v[i].y * inv; a.z = v[i].z * inv; a.w = v[i].w * inv;
        *(float4*)(attn + (size_t)row * Nn + j) = a;
        *(__half2*)(g_Ahi + (size_t)row * Nn + j) =
            __halves2half2(__float2half(a.x), __float2half(a.y));
        *(__half2*)(g_Ahi + (size_t)row * Nn + j + 2) =
            __halves2half2(__float2half(a.z), __float2half(a.w));
    }
}

// ---------------- reduce A@V split-K partials (4-way) ----------------
__global__ __launch_bounds__(256) void reduce_kernel(float* __restrict__ upd) {
    size_t i = ((size_t)blockIdx.x * 256 + threadIdx.x) * 4;
    float4 s = *(const float4*)(g_part + i);
    #pragma unroll
    for (int z = 1; z < 4; z++) {
        const float4 p = *(const float4*)(g_part + z * (size_t)Nn * OUTD + i);
        s.x += p.x; s.y += p.y; s.z += p.z; s.w += p.w;
    }
    *(float4*)(upd + i) = s;
}

// ---------------- launch ----------------
extern "C" void kernel_launch(void* const* d_in, const int* in_sizes, int n_in,
                              void* d_out, int out_size) {
    const float* gene = (const float*)d_in[0];
    const float* sp   = (const float*)d_in[1];
    const float* Wq   = (const float*)d_in[2];
    const float* bq   = (const float*)d_in[3];
    const float* Wk   = (const float*)d_in[4];
    const float* bk   = (const float*)d_in[5];
    const float* Wv   = (const float*)d_in[6];
    const float* bv   = (const float*)d_in[7];
    const float* Ws   = (const float*)d_in[8];
    const float* bs   = (const float*)d_in[9];
    const float* W1   = (const float*)d_in[10];
    const float* b1   = (const float*)d_in[11];
    const float* W2   = (const float*)d_in[12];
    const float* b2   = (const float*)d_in[13];
    const float* Wf   = (const float*)d_in[14];
    const float* bf_  = (const float*)d_in[15];

    float* out = (float*)d_out;
    long long total = (long long)Nn * Nn + (long long)Nn * OUTD;
    int has_attn = ((long long)out_size >= total) ? 1 : 0;
    float* attn = out;
    float* upd  = has_attn ? out + (size_t)Nn * Nn : out;

    hf *pGhi, *pYhi, *pZhi, *pAhi, *pVthi, *pWthi, *pW2thi, *phhi, *phlo;
    float *pPart;
    cudaGetSymbolAddress((void**)&pGhi, g_Ghi);
    cudaGetSymbolAddress((void**)&pYhi, g_Yhi);
    cudaGetSymbolAddress((void**)&pZhi, g_Zhi);
    cudaGetSymbolAddress((void**)&pAhi, g_Ahi);
    cudaGetSymbolAddress((void**)&pVthi, g_Vthi);
    cudaGetSymbolAddress((void**)&pWthi, g_Wthi);
    cudaGetSymbolAddress((void**)&pW2thi, g_W2thi);
    cudaGetSymbolAddress((void**)&phhi, g_hhi);
    cudaGetSymbolAddress((void**)&phlo, g_hlo);
    cudaGetSymbolAddress((void**)&pPart, g_part);

    cudaFuncSetAttribute(hmma_gemm, cudaFuncAttributeMaxDynamicSharedMemorySize, SMEMSZ);

    // 0) combine MLP1 into rank-2 form
    combine_kernel<<<HID, 256>>>(Ws, bs, W1, b1);

    // 1) weight transposes + biases
    wsplit_all_kernel<<<1795, 256>>>(Wq, Wk, Wv, W2, bq, bk, bv);

    // 2) prep: Ghi, normalized rows, sq, h = tanh(MLP1) splits
    prep_kernel<<<Nn, 256>>>(gene, sp);

    // 3) MLP gemm 2 split-K x4: partials (segs hhi|hlo: 4+4 chunks, 2/z)
    dim3 gMLP(HID / BN, Nn / BM, 4);
    hmma_gemm<<<gMLP, 256, SMEMSZ>>>(phhi, phlo, phhi, pW2thi, pW2thi, pW2thi,
                                     HID, HID, 4, 8, 2, 2, 0, 0,
                                     pPart, HID, (size_t)Nn * HID, nullptr, 1.0f,
                                     nullptr, nullptr, 0, nullptr);
    // 4) reduce2 + f (4 rows/block, float4)
    reduce_f_kernel<<<Nn / 4, 256>>>(b2, Wf, bf_);

    // 5) QKV combined (mode 6): hi-only, 8 chunks, grid (2, 32, 3)
    dim3 gQKV(HID / BN, Nn / BM, 3);
    hmma_gemm<<<gQKV, 256, SMEMSZ>>>(pGhi, pGhi, pGhi, pWthi, pWthi, pWthi,
                                     GENE, GENE, 8, 8, 8, 0, (size_t)HID * GENE, 6,
                                     nullptr, 0, 0, nullptr, 1.0f, nullptr, nullptr, 0, nullptr);

    // 6) logits: single-segment Yhi·Zhi (768 -> 12 chunks) + epilogue
    dim3 gLg(Nn / BN, Nn / BM, 1);
    hmma_gemm<<<gLg, 256, SMEMSZ>>>(pYhi, pYhi, pYhi, pZhi, pZhi, pZhi,
                                    YK, YK, 12, 12, 12, 0, 0, 1,
                                    nullptr, 0, 0, nullptr, 1.0f, nullptr, nullptr, 0, sp);

    // 7) softmax -> attn + A hi split
    softmax_kernel<<<Nn, 512>>>(attn);

    // 8) A@V split-K x4 -> partials (hi-only: 64 chunks, 16/z)
    dim3 gAV(OUTD / BN, Nn / BM, 4);
    hmma_gemm<<<gAV, 256, SMEMSZ>>>(pAhi, pAhi, pAhi, pVthi, pVthi, pVthi,
                                    Nn, Nn, 64, 64, 16, 16, 0, 0,
                                    pPart, OUTD, (size_t)Nn * OUTD, nullptr, 1.0f,
                                    nullptr, nullptr, 0, nullptr);
    // 9) reduce partials
    reduce_kernel<<<(Nn * OUTD) / 1024, 256>>>(upd);
}

// round 13
// speedup vs baseline: 13.6653x; 1.0309x over previous
#include <cuda_runtime.h>
#include <cuda_fp16.h>
#include <math.h>
#include <stdint.h>

#define Nn    4096
#define GENE  512
#define HID   256
#define OUTD  256
#define YK    768     // HID + GENE fused logits depth

typedef __half hf;

// ---------------- scratch (static device globals; no runtime allocs) ----------------
__device__ __align__(16) float g_L[(size_t)Nn * Nn];      // logits
__device__ __align__(16) hf    g_Ghi[Nn * GENE];
__device__ __align__(16) hf    g_Yhi[Nn * YK];
__device__ __align__(16) hf    g_Zhi[Nn * YK];
__device__ __align__(16) hf    g_Ahi[(size_t)Nn * Nn];
__device__ __align__(16) hf    g_Vthi[OUTD * Nn];
__device__ __align__(16) hf    g_Wthi[3 * HID * GENE];    // W^T hi (q,k,v)
__device__ __align__(16) hf    g_W2thi[HID * HID];
__device__ __align__(16) hf    g_hhi[Nn * HID];
__device__ __align__(16) hf    g_hlo[Nn * HID];
__device__ __align__(16) float g_part[4 * (size_t)Nn * OUTD];   // split-K partials
__device__ __align__(16) float g_bias[3 * 256];                  // bq|bk|bv
__device__ __align__(16) float g_W1c[2 * HID];                   // Ws @ W1
__device__ __align__(16) float g_b1c[HID];                       // bs @ W1 + b1
__device__ float g_f[Nn];     // clamp(tanh(f))
__device__ float g_sq[Nn];

// ---------------- PTX helpers (sm_80+ baseline) ----------------
__device__ __forceinline__ uint32_t s2u(const void* p) {
    uint32_t a;
    asm("{ .reg .u64 t; cvta.to.shared.u64 t, %1; cvt.u32.u64 %0, t; }" : "=r"(a) : "l"(p));
    return a;
}
__device__ __forceinline__ void cp16(uint32_t dst, const void* src) {
    asm volatile("cp.async.cg.shared.global [%0], [%1], 16;" :: "r"(dst), "l"(src));
}
__device__ __forceinline__ void cp_commit() {
    asm volatile("cp.async.commit_group;" ::: "memory");
}
template <int N>
__device__ __forceinline__ void cp_wait() {
    asm volatile("cp.async.wait_group %0;" :: "n"(N) : "memory");
}
__device__ __forceinline__ void ldm4(uint32_t* r, uint32_t addr) {
    asm volatile("ldmatrix.sync.aligned.m8n8.x4.shared.b16 {%0,%1,%2,%3}, [%4];"
                 : "=r"(r[0]), "=r"(r[1]), "=r"(r[2]), "=r"(r[3]) : "r"(addr));
}
__device__ __forceinline__ void mma_f16(float* d, const uint32_t* a, uint32_t b0, uint32_t b1) {
    asm volatile(
        "mma.sync.aligned.m16n8k16.row.col.f32.f16.f16.f32 "
        "{%0,%1,%2,%3}, {%4,%5,%6,%7}, {%8,%9}, {%0,%1,%2,%3};"
        : "+f"(d[0]), "+f"(d[1]), "+f"(d[2]), "+f"(d[3])
        : "r"(a[0]), "r"(a[1]), "r"(a[2]), "r"(a[3]), "r"(b0), "r"(b1));
}
__device__ __forceinline__ void split2(float v, hf& h, hf& l) {
    h = __float2half(v);
    l = __float2half(v - __half2float(h));
}

// ---------------- combine: W1c = Ws@W1 (2x256), b1c = bs@W1 + b1 ----------------
__global__ __launch_bounds__(256) void combine_kernel(const float* __restrict__ Ws,
                                                      const float* __restrict__ bs,
                                                      const float* __restrict__ W1,
                                                      const float* __restrict__ b1) {
    int h = blockIdx.x;
    int k = threadIdx.x;
    float w = __ldg(W1 + k * HID + h);
    __shared__ float r0[256], r1[256], r2[256];
    r0[k] = __ldg(Ws + k) * w;
    r1[k] = __ldg(Ws + HID + k) * w;
    r2[k] = __ldg(bs + k) * w;
    __syncthreads();
    for (int s = 128; s > 0; s >>= 1) {
        if (k < s) { r0[k] += r0[k + s]; r1[k] += r1[k + s]; r2[k] += r2[k + s]; }
        __syncthreads();
    }
    if (k == 0) {
        g_W1c[h]       = r0[0];
        g_W1c[HID + h] = r1[0];
        g_b1c[h]       = r2[0] + __ldg(b1 + h);
    }
}

// ---------------- prep: gene fp16 + normalized rows + sq + h (=tanh MLP1) ----------------
__global__ __launch_bounds__(256) void prep_kernel(const float* __restrict__ gene,
                                                   const float* __restrict__ sp) {
    int row = blockIdx.x;
    const float* x = gene + (size_t)row * GENE;
    __shared__ float red[256];
    float a = __ldg(sp + 2 * row), b = __ldg(sp + 2 * row + 1);

    {
        int h = threadIdx.x;
        float v = a * g_W1c[h] + b * g_W1c[HID + h] + g_b1c[h];
        float t = tanhf(v);
        split2(t, g_hhi[row * HID + h], g_hlo[row * HID + h]);
    }

    float ss = 0.f;
    for (int c = threadIdx.x; c < GENE; c += 256) { float v = x[c]; ss += v * v; }
    red[threadIdx.x] = ss; __syncthreads();
    for (int s = 128; s > 0; s >>= 1) {
        if (threadIdx.x < s) red[threadIdx.x] += red[threadIdx.x + s];
        __syncthreads();
    }
    float inv = 1.0f / fmaxf(sqrtf(red[0]), 1e-12f);
    for (int c = threadIdx.x; c < GENE; c += 256) {
        float v = x[c];
        g_Ghi[(size_t)row * GENE + c] = __float2half(v);
        hf xh = __float2half(v * inv);
        size_t o = (size_t)row * YK + HID + c;
        g_Yhi[o] = xh;
        g_Zhi[o] = xh;
    }
    if (threadIdx.x == 0) g_sq[row] = a * a + b * b;
}

// ---------------- weight transposes (fp16) + bias copies ----------------
__global__ __launch_bounds__(256) void wsplit_all_kernel(
    const float* __restrict__ Wq, const float* __restrict__ Wk, const float* __restrict__ Wv,
    const float* __restrict__ W2,
    const float* __restrict__ bq, const float* __restrict__ bk, const float* __restrict__ bv) {
    int idx = blockIdx.x * 256 + threadIdx.x;
    if (idx < 393216) {                       // 3 x (256 x 512)
        int w = idx / 131072, r = idx % 131072;
        int n = r / GENE, k = r % GENE;
        const float* W = (w == 0) ? Wq : (w == 1) ? Wk : Wv;
        g_Wthi[idx] = __float2half(W[(size_t)k * HID + n]);
    } else if (idx < 458752) {                // W2 (256 x 256)
        int r = idx - 393216;
        int n = r / HID, k = r % HID;
        g_W2thi[r] = __float2half(W2[(size_t)k * HID + n]);
    } else if (idx < 459520) {                // biases
        int t = idx - 458752;
        if (t < 256)      g_bias[t] = bq[t];
        else if (t < 512) g_bias[t] = bk[t - 256];
        else              g_bias[t] = bv[t - 512];
    }
}

// ---------------- reduce MLP2 partials + f: 4 rows per block, float4 ----------------
__global__ __launch_bounds__(256) void reduce_f_kernel(const float* __restrict__ b2,
                                                       const float* __restrict__ Wf,
                                                       const float* __restrict__ bf_) {
    int rloc = threadIdx.x >> 6;              // 0..3
    int c4   = (threadIdx.x & 63) * 4;
    int row  = blockIdx.x * 4 + rloc;
    size_t i4 = (size_t)row * HID + c4;
    float4 s = *(const float4*)(g_part + i4);
    #pragma unroll
    for (int z = 1; z < 4; z++) {
        float4 p = *(const float4*)(g_part + z * (size_t)Nn * HID + i4);
        s.x += p.x; s.y += p.y; s.z += p.z; s.w += p.w;
    }
    float4 bb = *(const float4*)(b2 + c4);
    float4 wf = *(const float4*)(Wf + c4);
    float d = fmaxf(s.x + bb.x, 0.f) * wf.x + fmaxf(s.y + bb.y, 0.f) * wf.y
            + fmaxf(s.z + bb.z, 0.f) * wf.z + fmaxf(s.w + bb.w, 0.f) * wf.w;
    __shared__ float red[256];
    red[threadIdx.x] = d;
    __syncthreads();
    #pragma unroll
    for (int st = 32; st > 0; st >>= 1) {
        if ((threadIdx.x & 63) < st) red[threadIdx.x] += red[threadIdx.x + st];
        __syncthreads();
    }
    if ((threadIdx.x & 63) == 0) {
        float t = tanhf(red[rloc * 64] + bf_[0]);
        g_f[row] = fminf(fmaxf(t, -0.999999f), 0.999999f);
    }
}

// ---------------- HMMA fp16 GEMM, BK=64, XOR-swizzle, 3-stage pipeline ----------------
// modes: 0 = fp32 C (+bias)*alpha (per-z C offset)
//        1 = logits epilogue -> g_L   (tanh-identity spatial bias)
//        6 = QKV combined (z: 0->Q into Y, 1->K into Z, 2->V transpose)
//        7 = fused QKV (z<3) + MLP2 split-K partials (z=3..6)
#define BM 128
#define BN 128
#define BK 64
#define TILEB  16384                 // 128 rows x 128B
#define STAGEB (2 * TILEB)           // A + B
#define NSTAGE 3
#define SMEMSZ (NSTAGE * STAGEB)     // 98304

__global__ __launch_bounds__(256, 2) void hmma_gemm(
    const hf* __restrict__ a0, const hf* __restrict__ a1, const hf* __restrict__ a2,
    const hf* __restrict__ b0, const hf* __restrict__ b1, const hf* __restrict__ b2,
    int pitchA, int pitchB, int cb1, int cb2, int chunks_per_z, int zchunks,
    size_t zBstride, int mode,
    float* __restrict__ C, int ldc, size_t zCstride,
    const float* __restrict__ bias, float alpha,
    const float* __restrict__ sp)
{
    extern __shared__ __align__(16) char smem[];
    const uint32_t sbase = s2u(smem);
    const int tid  = threadIdx.x;
    const int lane = tid & 31;
    const int wid  = tid >> 5;
    const int wm   = (wid & 3) * 32;
    const int wn   = (wid >> 2) * 64;
    const int gm0  = blockIdx.y * BM;
    const int gn0  = blockIdx.x * BN;
    const int z    = blockIdx.z;

    int eff_mode = mode;
    int zc = z;
    int g0 = z * zchunks;

    if (mode == 7) {
        if (z < 3) {
            eff_mode = 6;
            g0 = 0;
            b0 += z * zBstride; b1 += z * zBstride; b2 += z * zBstride;
        } else {
            eff_mode = 0; zc = z - 3;
            a0 = g_hhi; a1 = g_hlo; a2 = g_hhi;
            b0 = g_W2thi; b1 = g_W2thi; b2 = g_W2thi;
            pitchA = HID; pitchB = HID; cb1 = 4; cb2 = 8;
            chunks_per_z = 2; g0 = zc * 2;
            C = g_part; ldc = HID; zCstride = (size_t)Nn * HID;
            bias = nullptr; alpha = 1.0f;
        }
    } else if (zBstride) {
        b0 += z * zBstride; b1 += z * zBstride; b2 += z * zBstride;
    }

    const int mi    = lane >> 3;
    const int ldrow = ((mi & 1) << 3) + (lane & 7);
    const int ldc16 = mi >> 1;
    const int srow0 = tid >> 3;
    const int sc    = tid & 7;

    float acc[2][8][4];
    #pragma unroll
    for (int a = 0; a < 2; a++)
        #pragma unroll
        for (int b = 0; b < 8; b++)
            #pragma unroll
            for (int c = 0; c < 4; c++) acc[a][b][c] = 0.f;

    auto load_chunk = [&](int g, int stage) {
        const hf *As, *Bs; int kk;
        if (g < cb1)      { As = a0; Bs = b0; kk = g * BK; }
        else if (g < cb2) { As = a1; Bs = b1; kk = (g - cb1) * BK; }
        else              { As = a2; Bs = b2; kk = (g - cb2) * BK; }
        uint32_t dst = sbase + stage * STAGEB;
        #pragma unroll
        for (int i = 0; i < 4; i++) {
            int row = srow0 + i * 32;
            uint32_t off = (uint32_t)(row * 128 + ((sc ^ (row & 7)) << 4));
            cp16(dst + off,         As + (size_t)(gm0 + row) * pitchA + kk + sc * 8);
            cp16(dst + TILEB + off, Bs + (size_t)(gn0 + row) * pitchB + kk + sc * 8);
        }
        cp_commit();
    };

    load_chunk(g0, 0);
    if (chunks_per_z > 1) load_chunk(g0 + 1, 1);
    else cp_commit();

    for (int c = 0; c < chunks_per_z; c++) {
        if (c + 1 < chunks_per_z) cp_wait<1>(); else cp_wait<0>();
        __syncthreads();
        if (c + 2 < chunks_per_z) load_chunk(g0 + c + 2, (c + 2) % NSTAGE);

        uint32_t abase = sbase + (c % NSTAGE) * STAGEB;
        uint32_t bbase = abase + TILEB;
        #pragma unroll
        for (int ks = 0; ks < 4; ks++) {
            uint32_t afrag[2][4];
            uint32_t bfrag[4][4];
            int c16 = ks * 2 + ldc16;
            #pragma unroll
            for (int mt = 0; mt < 2; mt++) {
                int row = wm + mt * 16 + ldrow;
                ldm4(afrag[mt], abase + row * 128 + ((c16 ^ (row & 7)) << 4));
            }
            #pragma unroll
            for (int p = 0; p < 4; p++) {
                int row = wn + p * 16 + ldrow;
                ldm4(bfrag[p], bbase + row * 128 + ((c16 ^ (row & 7)) << 4));
            }
            #pragma unroll
            for (int mt = 0; mt < 2; mt++) {
                #pragma unroll
                for (int p = 0; p < 4; p++) {
                    mma_f16(acc[mt][2 * p],     afrag[mt], bfrag[p][0], bfrag[p][2]);
                    mma_f16(acc[mt][2 * p + 1], afrag[mt], bfrag[p][1], bfrag[p][3]);
                }
            }
        }
    }

    // ---- epilogue ----
    const int r0 = lane >> 2;
    const int cl = 2 * (lane & 3);

    if (eff_mode == 1) {
        float* ex = (float*)smem;
        __syncthreads();
        for (int i = tid; i < BN; i += 256) {
            int n = gn0 + i;
            ex[i]           = __ldg(sp + 2 * n);
            ex[BN + i]      = __ldg(sp + 2 * n + 1);
            ex[2 * BN + i]  = g_sq[n];
            ex[3 * BN + i]  = g_f[n];
        }
        __syncthreads();
        #pragma unroll
        for (int mt = 0; mt < 2; mt++) {
            #pragma unroll
            for (int half = 0; half < 2; half++) {
                int m = gm0 + wm + mt * 16 + r0 + half * 8;
                float sp0 = __ldg(sp + 2 * m), sp1 = __ldg(sp + 2 * m + 1);
                float sqi = g_sq[m], ti = g_f[m];
                #pragma unroll
                for (int nt = 0; nt < 8; nt++) {
                    int nl = wn + nt * 8 + cl;
                    float2 v;
                    #pragma unroll
                    for (int q = 0; q < 2; q++) {
                        int ci = nl + q;
                        float d2 = sqi + ex[2 * BN + ci]
                                 - 2.0f * (sp0 * ex[ci] + sp1 * ex[BN + ci]);
                        d2 = fmaxf(d2, 0.0f);
                        float tj = ex[3 * BN + ci];
                        float tb = __fdividef(ti - tj, fmaf(-ti, tj, 1.0f));
                        float a = acc[mt][nt][half * 2 + q];
                        ((float*)&v)[q] = a + __expf(-0.5f * d2) + tb;
                    }
                    *(float2*)(g_L + (size_t)m * Nn + gn0 + nl) = v;
                }
            }
        }
    } else if (eff_mode == 0) {
        float* Cz = C + zc * zCstride;
        #pragma unroll
        for (int mt = 0; mt < 2; mt++)
            #pragma unroll
            for (int half = 0; half < 2; half++) {
                int m = gm0 + wm + mt * 16 + r0 + half * 8;
                #pragma unroll
                for (int nt = 0; nt < 8; nt++) {
                    int n = gn0 + wn + nt * 8 + cl;
                    float b0v = bias ? __ldg(bias + n)     : 0.f;
                    float b1v = bias ? __ldg(bias + n + 1) : 0.f;
                    float2 v;
                    v.x = (acc[mt][nt][half * 2 + 0] + b0v) * alpha;
                    v.y = (acc[mt][nt][half * 2 + 1] + b1v) * alpha;
                    *(float2*)(Cz + (size_t)m * ldc + n) = v;
                }
            }
    } else { // eff_mode 6: QKV combined
        const float* bias6 = g_bias + z * 256;
        if (z == 2) {
            #pragma unroll
            for (int mt = 0; mt < 2; mt++)
                #pragma unroll
                for (int half = 0; half < 2; half++) {
                    int m = gm0 + wm + mt * 16 + r0 + half * 8;
                    #pragma unroll
                    for (int nt = 0; nt < 8; nt++) {
                        int n = gn0 + wn + nt * 8 + cl;
                        #pragma unroll
                        for (int q = 0; q < 2; q++) {
                            float v = acc[mt][nt][half * 2 + q] + bias6[n + q];
                            g_Vthi[(size_t)(n + q) * Nn + m] = __float2half(v);
                        }
                    }
                }
        } else {
            hf* Dh = z ? g_Zhi : g_Yhi;
            float al = z ? 1.0f : (1.0f / 16.0f);
            #pragma unroll
            for (int mt = 0; mt < 2; mt++)
                #pragma unroll
                for (int half = 0; half < 2; half++) {
                    int m = gm0 + wm + mt * 16 + r0 + half * 8;
                    #pragma unroll
                    for (int nt = 0; nt < 8; nt++) {
                        int n = gn0 + wn + nt * 8 + cl;
                        #pragma unroll
                        for (int q = 0; q < 2; q++) {
                            float v = (acc[mt][nt][half * 2 + q] + bias6[n + q]) * al;
                            Dh[(size_t)m * YK + n + q] = __float2half(v);
                        }
                    }
                }
        }
    }
}

// ---------------- softmax: 512 threads/row, warp-shuffle reductions ----------------
__global__ __launch_bounds__(512) void softmax_kernel(float* __restrict__ attn) {
    int row = blockIdx.x;
    int tid = threadIdx.x;
    int lane = tid & 31, wrp = tid >> 5;
    float* L = g_L + (size_t)row * Nn;
    __shared__ float red[16];
    float4 v[2];
    float m = -1e30f;
    #pragma unroll
    for (int i = 0; i < 2; i++) {
        v[i] = *(const float4*)(L + tid * 4 + i * 2048);
        m = fmaxf(m, fmaxf(fmaxf(v[i].x, v[i].y), fmaxf(v[i].z, v[i].w)));
    }
    #pragma unroll
    for (int o = 16; o > 0; o >>= 1) m = fmaxf(m, __shfl_xor_sync(0xFFFFFFFFu, m, o));
    if (lane == 0) red[wrp] = m;
    __syncthreads();
    m = red[lane & 15];
    #pragma unroll
    for (int o = 8; o > 0; o >>= 1) m = fmaxf(m, __shfl_xor_sync(0xFFFFFFFFu, m, o));
    float rm = m;

    float sum = 0.f;
    #pragma unroll
    for (int i = 0; i < 2; i++) {
        v[i].x = __expf(v[i].x - rm);
        v[i].y = __expf(v[i].y - rm);
        v[i].z = __expf(v[i].z - rm);
        v[i].w = __expf(v[i].w - rm);
        sum += (v[i].x + v[i].y) + (v[i].z + v[i].w);
    }
    #pragma unroll
    for (int o = 16; o > 0; o >>= 1) sum += __shfl_xor_sync(0xFFFFFFFFu, sum, o);
    __syncthreads();
    if (lane == 0) red[wrp] = sum;
    __syncthreads();
    sum = red[lane & 15];
    #pragma unroll
    for (int o = 8; o > 0; o >>= 1) sum += __shfl_xor_sync(0xFFFFFFFFu, sum, o);
    float inv = 1.0f / sum;

    #pragma unroll
    for (int i = 0; i < 2; i++) {
        int j = tid * 4 + i * 2048;
        float4 a;
        a.x = v[i].x * inv; a.y = v[i].y * inv; a.z = v[i].z * inv; a.w = v[i].w * inv;
        *(float4*)(attn + (size_t)row * Nn + j) = a;
        *(__half2*)(g_Ahi + (size_t)row * Nn + j) =
            __halves2half2(__float2half(a.x), __float2half(a.y));
        *(__half2*)(g_Ahi + (size_t)row * Nn + j + 2) =
            __halves2half2(__float2half(a.z), __float2half(a.w));
    }
}

// ---------------- reduce A@V split-K partials (4-way) ----------------
__global__ __launch_bounds__(256) void reduce_kernel(float* __restrict__ upd) {
    size_t i = ((size_t)blockIdx.x * 256 + threadIdx.x) * 4;
    float4 s = *(const float4*)(g_part + i);
    #pragma unroll
    for (int z = 1; z < 4; z++) {
        const float4 p = *(const float4*)(g_part + z * (size_t)Nn * OUTD + i);
        s.x += p.x; s.y += p.y; s.z += p.z; s.w += p.w;
    }
    *(float4*)(upd + i) = s;
}

// ---------------- launch ----------------
extern "C" void kernel_launch(void* const* d_in, const int* in_sizes, int n_in,
                              void* d_out, int out_size) {
    const float* gene = (const float*)d_in[0];
    const float* sp   = (const float*)d_in[1];
    const float* Wq   = (const float*)d_in[2];
    const float* bq   = (const float*)d_in[3];
    const float* Wk   = (const float*)d_in[4];
    const float* bk   = (const float*)d_in[5];
    const float* Wv   = (const float*)d_in[6];
    const float* bv   = (const float*)d_in[7];
    const float* Ws   = (const float*)d_in[8];
    const float* bs   = (const float*)d_in[9];
    const float* W1   = (const float*)d_in[10];
    const float* b1   = (const float*)d_in[11];
    const float* W2   = (const float*)d_in[12];
    const float* b2   = (const float*)d_in[13];
    const float* Wf   = (const float*)d_in[14];
    const float* bf_  = (const float*)d_in[15];

    float* out = (float*)d_out;
    long long total = (long long)Nn * Nn + (long long)Nn * OUTD;
    int has_attn = ((long long)out_size >= total) ? 1 : 0;
    float* attn = out;
    float* upd  = has_attn ? out + (size_t)Nn * Nn : out;

    hf *pGhi, *pYhi, *pZhi, *pAhi, *pVthi, *pWthi;
    float *pPart;
    cudaGetSymbolAddress((void**)&pGhi, g_Ghi);
    cudaGetSymbolAddress((void**)&pYhi, g_Yhi);
    cudaGetSymbolAddress((void**)&pZhi, g_Zhi);
    cudaGetSymbolAddress((void**)&pAhi, g_Ahi);
    cudaGetSymbolAddress((void**)&pVthi, g_Vthi);
    cudaGetSymbolAddress((void**)&pWthi, g_Wthi);
    cudaGetSymbolAddress((void**)&pPart, g_part);

    cudaFuncSetAttribute(hmma_gemm, cudaFuncAttributeMaxDynamicSharedMemorySize, SMEMSZ);

    // 0) combine MLP1 into rank-2 form
    combine_kernel<<<HID, 256>>>(Ws, bs, W1, b1);

    // 1) weight transposes + biases
    wsplit_all_kernel<<<1795, 256>>>(Wq, Wk, Wv, W2, bq, bk, bv);

    // 2) prep: Ghi, normalized rows, sq, h = tanh(MLP1) splits
    prep_kernel<<<Nn, 256>>>(gene, sp);

    // 3) FUSED: QKV (z=0..2, 8 chunks) + MLP2 split-K x4 (z=3..6, 2 chunks)  [mode 7]
    dim3 gFU(HID / BN, Nn / BM, 7);
    hmma_gemm<<<gFU, 256, SMEMSZ>>>(pGhi, pGhi, pGhi, pWthi, pWthi, pWthi,
                                    GENE, GENE, 8, 8, 8, 0, (size_t)HID * GENE, 7,
                                    nullptr, 0, 0, nullptr, 1.0f, nullptr);

    // 4) reduce2 + f (4 rows/block, float4)
    reduce_f_kernel<<<Nn / 4, 256>>>(b2, Wf, bf_);

    // 5) logits: single-segment Yhi·Zhi (768 -> 12 chunks) + epilogue
    dim3 gLg(Nn / BN, Nn / BM, 1);
    hmma_gemm<<<gLg, 256, SMEMSZ>>>(pYhi, pYhi, pYhi, pZhi, pZhi, pZhi,
                                    YK, YK, 12, 12, 12, 0, 0, 1,
                                    nullptr, 0, 0, nullptr, 1.0f, sp);

    // 6) softmax -> attn + A hi split
    softmax_kernel<<<Nn, 512>>>(attn);

    // 7) A@V split-K x4 -> partials (hi-only: 64 chunks, 16/z)
    dim3 gAV(OUTD / BN, Nn / BM, 4);
    hmma_gemm<<<gAV, 256, SMEMSZ>>>(pAhi, pAhi, pAhi, pVthi, pVthi, pVthi,
                                    Nn, Nn, 64, 64, 16, 16, 0, 0,
                                    pPart, OUTD, (size_t)Nn * OUTD, nullptr, 1.0f, nullptr);
    // 8) reduce partials
    reduce_kernel<<<(Nn * OUTD) / 1024, 256>>>(upd);
}

// round 14
// speedup vs baseline: 13.9177x; 1.0185x over previous
#include <cuda_runtime.h>
#include <cuda_fp16.h>
#include <math.h>
#include <stdint.h>

#define Nn    4096
#define GENE  512
#define HID   256
#define OUTD  256
#define YK    768     // HID + GENE fused logits depth

typedef __half hf;

// ---------------- scratch (static device globals; no runtime allocs) ----------------
__device__ __align__(16) float g_L[(size_t)Nn * Nn];      // logits
__device__ __align__(16) hf    g_Ghi[Nn * GENE];
__device__ __align__(16) hf    g_Yhi[Nn * YK];
__device__ __align__(16) hf    g_Zhi[Nn * YK];
__device__ __align__(16) hf    g_Ahi[(size_t)Nn * Nn];
__device__ __align__(16) hf    g_Vthi[OUTD * Nn];
__device__ __align__(16) hf    g_Wthi[3 * HID * GENE];    // W^T hi (q,k,v)
__device__ __align__(16) hf    g_W2thi[HID * HID];
__device__ __align__(16) hf    g_hhi[Nn * HID];
__device__ __align__(16) hf    g_hlo[Nn * HID];
__device__ __align__(16) float g_part[4 * (size_t)Nn * OUTD];   // split-K partials
__device__ __align__(16) float g_bias[3 * 256];                  // bq|bk|bv
__device__ __align__(16) float g_W1c[2 * HID];                   // Ws @ W1
__device__ __align__(16) float g_b1c[HID];                       // bs @ W1 + b1
__device__ float g_f[Nn];     // clamp(tanh(f))
__device__ float g_sq[Nn];

// ---------------- PTX helpers (sm_80+ baseline) ----------------
__device__ __forceinline__ uint32_t s2u(const void* p) {
    uint32_t a;
    asm("{ .reg .u64 t; cvta.to.shared.u64 t, %1; cvt.u32.u64 %0, t; }" : "=r"(a) : "l"(p));
    return a;
}
__device__ __forceinline__ void cp16(uint32_t dst, const void* src) {
    asm volatile("cp.async.cg.shared.global [%0], [%1], 16;" :: "r"(dst), "l"(src));
}
__device__ __forceinline__ void cp_commit() {
    asm volatile("cp.async.commit_group;" ::: "memory");
}
template <int N>
__device__ __forceinline__ void cp_wait() {
    asm volatile("cp.async.wait_group %0;" :: "n"(N) : "memory");
}
__device__ __forceinline__ void ldm4(uint32_t* r, uint32_t addr) {
    asm volatile("ldmatrix.sync.aligned.m8n8.x4.shared.b16 {%0,%1,%2,%3}, [%4];"
                 : "=r"(r[0]), "=r"(r[1]), "=r"(r[2]), "=r"(r[3]) : "r"(addr));
}
__device__ __forceinline__ void mma_f16(float* d, const uint32_t* a, uint32_t b0, uint32_t b1) {
    asm volatile(
        "mma.sync.aligned.m16n8k16.row.col.f32.f16.f16.f32 "
        "{%0,%1,%2,%3}, {%4,%5,%6,%7}, {%8,%9}, {%0,%1,%2,%3};"
        : "+f"(d[0]), "+f"(d[1]), "+f"(d[2]), "+f"(d[3])
        : "r"(a[0]), "r"(a[1]), "r"(a[2]), "r"(a[3]), "r"(b0), "r"(b1));
}
__device__ __forceinline__ void split2(float v, hf& h, hf& l) {
    h = __float2half(v);
    l = __float2half(v - __half2float(h));
}

// ---------------- combine: W1c = Ws@W1 (2x256), b1c = bs@W1 + b1 ----------------
__global__ __launch_bounds__(256) void combine_kernel(const float* __restrict__ Ws,
                                                      const float* __restrict__ bs,
                                                      const float* __restrict__ W1,
                                                      const float* __restrict__ b1) {
    int h = blockIdx.x;
    int k = threadIdx.x;
    float w = __ldg(W1 + k * HID + h);
    __shared__ float r0[256], r1[256], r2[256];
    r0[k] = __ldg(Ws + k) * w;
    r1[k] = __ldg(Ws + HID + k) * w;
    r2[k] = __ldg(bs + k) * w;
    __syncthreads();
    for (int s = 128; s > 0; s >>= 1) {
        if (k < s) { r0[k] += r0[k + s]; r1[k] += r1[k + s]; r2[k] += r2[k + s]; }
        __syncthreads();
    }
    if (k == 0) {
        g_W1c[h]       = r0[0];
        g_W1c[HID + h] = r1[0];
        g_b1c[h]       = r2[0] + __ldg(b1 + h);
    }
}

// ---------------- prep: gene fp16 + normalized rows + sq + h (=tanh MLP1) ----------------
__global__ __launch_bounds__(256) void prep_kernel(const float* __restrict__ gene,
                                                   const float* __restrict__ sp) {
    int row = blockIdx.x;
    const float* x = gene + (size_t)row * GENE;
    __shared__ float red[256];
    float a = __ldg(sp + 2 * row), b = __ldg(sp + 2 * row + 1);

    {
        int h = threadIdx.x;
        float v = a * g_W1c[h] + b * g_W1c[HID + h] + g_b1c[h];
        float t = tanhf(v);
        split2(t, g_hhi[row * HID + h], g_hlo[row * HID + h]);
    }

    float ss = 0.f;
    for (int c = threadIdx.x; c < GENE; c += 256) { float v = x[c]; ss += v * v; }
    red[threadIdx.x] = ss; __syncthreads();
    for (int s = 128; s > 0; s >>= 1) {
        if (threadIdx.x < s) red[threadIdx.x] += red[threadIdx.x + s];
        __syncthreads();
    }
    float inv = 1.0f / fmaxf(sqrtf(red[0]), 1e-12f);
    for (int c = threadIdx.x; c < GENE; c += 256) {
        float v = x[c];
        g_Ghi[(size_t)row * GENE + c] = __float2half(v);
        hf xh = __float2half(v * inv);
        size_t o = (size_t)row * YK + HID + c;
        g_Yhi[o] = xh;
        g_Zhi[o] = xh;
    }
    if (threadIdx.x == 0) g_sq[row] = a * a + b * b;
}

// ---------------- weight transposes (fp16) + bias copies ----------------
__global__ __launch_bounds__(256) void wsplit_all_kernel(
    const float* __restrict__ Wq, const float* __restrict__ Wk, const float* __restrict__ Wv,
    const float* __restrict__ W2,
    const float* __restrict__ bq, const float* __restrict__ bk, const float* __restrict__ bv) {
    int idx = blockIdx.x * 256 + threadIdx.x;
    if (idx < 393216) {                       // 3 x (256 x 512)
        int w = idx / 131072, r = idx % 131072;
        int n = r / GENE, k = r % GENE;
        const float* W = (w == 0) ? Wq : (w == 1) ? Wk : Wv;
        g_Wthi[idx] = __float2half(W[(size_t)k * HID + n]);
    } else if (idx < 458752) {                // W2 (256 x 256)
        int r = idx - 393216;
        int n = r / HID, k = r % HID;
        g_W2thi[r] = __float2half(W2[(size_t)k * HID + n]);
    } else if (idx < 459520) {                // biases
        int t = idx - 458752;
        if (t < 256)      g_bias[t] = bq[t];
        else if (t < 512) g_bias[t] = bk[t - 256];
        else              g_bias[t] = bv[t - 512];
    }
}

// ---------------- reduce MLP2 partials + f: 4 rows per block, float4 ----------------
__global__ __launch_bounds__(256) void reduce_f_kernel(const float* __restrict__ b2,
                                                       const float* __restrict__ Wf,
                                                       const float* __restrict__ bf_) {
    int rloc = threadIdx.x >> 6;              // 0..3
    int c4   = (threadIdx.x & 63) * 4;
    int row  = blockIdx.x * 4 + rloc;
    size_t i4 = (size_t)row * HID + c4;
    float4 s = __ldcs((const float4*)(g_part + i4));
    #pragma unroll
    for (int z = 1; z < 4; z++) {
        float4 p = __ldcs((const float4*)(g_part + z * (size_t)Nn * HID + i4));
        s.x += p.x; s.y += p.y; s.z += p.z; s.w += p.w;
    }
    float4 bb = *(const float4*)(b2 + c4);
    float4 wf = *(const float4*)(Wf + c4);
    float d = fmaxf(s.x + bb.x, 0.f) * wf.x + fmaxf(s.y + bb.y, 0.f) * wf.y
            + fmaxf(s.z + bb.z, 0.f) * wf.z + fmaxf(s.w + bb.w, 0.f) * wf.w;
    __shared__ float red[256];
    red[threadIdx.x] = d;
    __syncthreads();
    #pragma unroll
    for (int st = 32; st > 0; st >>= 1) {
        if ((threadIdx.x & 63) < st) red[threadIdx.x] += red[threadIdx.x + st];
        __syncthreads();
    }
    if ((threadIdx.x & 63) == 0) {
        float t = tanhf(red[rloc * 64] + bf_[0]);
        g_f[row] = fminf(fmaxf(t, -0.999999f), 0.999999f);
    }
}

// ---------------- HMMA fp16 GEMM, BK=64, XOR-swizzle, 3-stage pipeline ----------------
// modes: 0 = fp32 C (+bias)*alpha (per-z C offset)
//        1 = logits epilogue -> g_L   (tanh-identity spatial bias)
//        6 = QKV combined (z: 0->Q into Y, 1->K into Z, 2->V transpose)
//        7 = fused QKV (z<3) + MLP2 split-K partials (z=3..6)
#define BM 128
#define BN 128
#define BK 64
#define TILEB  16384                 // 128 rows x 128B
#define STAGEB (2 * TILEB)           // A + B
#define NSTAGE 3
#define SMEMSZ (NSTAGE * STAGEB)     // 98304

__global__ __launch_bounds__(256, 2) void hmma_gemm(
    const hf* __restrict__ a0, const hf* __restrict__ a1, const hf* __restrict__ a2,
    const hf* __restrict__ b0, const hf* __restrict__ b1, const hf* __restrict__ b2,
    int pitchA, int pitchB, int cb1, int cb2, int chunks_per_z, int zchunks,
    size_t zBstride, int mode,
    float* __restrict__ C, int ldc, size_t zCstride,
    const float* __restrict__ bias, float alpha,
    const float* __restrict__ sp)
{
    extern __shared__ __align__(16) char smem[];
    const uint32_t sbase = s2u(smem);
    const int tid  = threadIdx.x;
    const int lane = tid & 31;
    const int wid  = tid >> 5;
    const int wm   = (wid & 3) * 32;
    const int wn   = (wid >> 2) * 64;
    const int gm0  = blockIdx.y * BM;
    const int gn0  = blockIdx.x * BN;
    const int z    = blockIdx.z;

    int eff_mode = mode;
    int zc = z;
    int g0 = z * zchunks;

    if (mode == 7) {
        if (z < 3) {
            eff_mode = 6;
            g0 = 0;
            b0 += z * zBstride; b1 += z * zBstride; b2 += z * zBstride;
        } else {
            eff_mode = 0; zc = z - 3;
            a0 = g_hhi; a1 = g_hlo; a2 = g_hhi;
            b0 = g_W2thi; b1 = g_W2thi; b2 = g_W2thi;
            pitchA = HID; pitchB = HID; cb1 = 4; cb2 = 8;
            chunks_per_z = 2; g0 = zc * 2;
            C = g_part; ldc = HID; zCstride = (size_t)Nn * HID;
            bias = nullptr; alpha = 1.0f;
        }
    } else if (zBstride) {
        b0 += z * zBstride; b1 += z * zBstride; b2 += z * zBstride;
    }

    const int mi    = lane >> 3;
    const int ldrow = ((mi & 1) << 3) + (lane & 7);
    const int ldc16 = mi >> 1;
    const int srow0 = tid >> 3;
    const int sc    = tid & 7;

    float acc[2][8][4];
    #pragma unroll
    for (int a = 0; a < 2; a++)
        #pragma unroll
        for (int b = 0; b < 8; b++)
            #pragma unroll
            for (int c = 0; c < 4; c++) acc[a][b][c] = 0.f;

    auto load_chunk = [&](int g, int stage) {
        const hf *As, *Bs; int kk;
        if (g < cb1)      { As = a0; Bs = b0; kk = g * BK; }
        else if (g < cb2) { As = a1; Bs = b1; kk = (g - cb1) * BK; }
        else              { As = a2; Bs = b2; kk = (g - cb2) * BK; }
        uint32_t dst = sbase + stage * STAGEB;
        #pragma unroll
        for (int i = 0; i < 4; i++) {
            int row = srow0 + i * 32;
            uint32_t off = (uint32_t)(row * 128 + ((sc ^ (row & 7)) << 4));
            cp16(dst + off,         As + (size_t)(gm0 + row) * pitchA + kk + sc * 8);
            cp16(dst + TILEB + off, Bs + (size_t)(gn0 + row) * pitchB + kk + sc * 8);
        }
        cp_commit();
    };

    load_chunk(g0, 0);
    if (chunks_per_z > 1) load_chunk(g0 + 1, 1);
    else cp_commit();

    for (int c = 0; c < chunks_per_z; c++) {
        if (c + 1 < chunks_per_z) cp_wait<1>(); else cp_wait<0>();
        __syncthreads();
        if (c + 2 < chunks_per_z) load_chunk(g0 + c + 2, (c + 2) % NSTAGE);

        uint32_t abase = sbase + (c % NSTAGE) * STAGEB;
        uint32_t bbase = abase + TILEB;
        #pragma unroll
        for (int ks = 0; ks < 4; ks++) {
            uint32_t afrag[2][4];
            uint32_t bfrag[4][4];
            int c16 = ks * 2 + ldc16;
            #pragma unroll
            for (int mt = 0; mt < 2; mt++) {
                int row = wm + mt * 16 + ldrow;
                ldm4(afrag[mt], abase + row * 128 + ((c16 ^ (row & 7)) << 4));
            }
            #pragma unroll
            for (int p = 0; p < 4; p++) {
                int row = wn + p * 16 + ldrow;
                ldm4(bfrag[p], bbase + row * 128 + ((c16 ^ (row & 7)) << 4));
            }
            #pragma unroll
            for (int mt = 0; mt < 2; mt++) {
                #pragma unroll
                for (int p = 0; p < 4; p++) {
                    mma_f16(acc[mt][2 * p],     afrag[mt], bfrag[p][0], bfrag[p][2]);
                    mma_f16(acc[mt][2 * p + 1], afrag[mt], bfrag[p][1], bfrag[p][3]);
                }
            }
        }
    }

    // ---- epilogue ----
    const int r0 = lane >> 2;
    const int cl = 2 * (lane & 3);

    if (eff_mode == 1) {
        float* ex = (float*)smem;
        __syncthreads();
        for (int i = tid; i < BN; i += 256) {
            int n = gn0 + i;
            ex[i]           = __ldg(sp + 2 * n);
            ex[BN + i]      = __ldg(sp + 2 * n + 1);
            ex[2 * BN + i]  = g_sq[n];
            ex[3 * BN + i]  = g_f[n];
        }
        __syncthreads();
        #pragma unroll
        for (int mt = 0; mt < 2; mt++) {
            #pragma unroll
            for (int half = 0; half < 2; half++) {
                int m = gm0 + wm + mt * 16 + r0 + half * 8;
                float sp0 = __ldg(sp + 2 * m), sp1 = __ldg(sp + 2 * m + 1);
                float sqi = g_sq[m], ti = g_f[m];
                #pragma unroll
                for (int nt = 0; nt < 8; nt++) {
                    int nl = wn + nt * 8 + cl;
                    float2 v;
                    #pragma unroll
                    for (int q = 0; q < 2; q++) {
                        int ci = nl + q;
                        float d2 = sqi + ex[2 * BN + ci]
                                 - 2.0f * (sp0 * ex[ci] + sp1 * ex[BN + ci]);
                        d2 = fmaxf(d2, 0.0f);
                        float tj = ex[3 * BN + ci];
                        float tb = __fdividef(ti - tj, fmaf(-ti, tj, 1.0f));
                        float a = acc[mt][nt][half * 2 + q];
                        ((float*)&v)[q] = a + __expf(-0.5f * d2) + tb;
                    }
                    *(float2*)(g_L + (size_t)m * Nn + gn0 + nl) = v;
                }
            }
        }
    } else if (eff_mode == 0) {
        float* Cz = C + zc * zCstride;
        #pragma unroll
        for (int mt = 0; mt < 2; mt++)
            #pragma unroll
            for (int half = 0; half < 2; half++) {
                int m = gm0 + wm + mt * 16 + r0 + half * 8;
                #pragma unroll
                for (int nt = 0; nt < 8; nt++) {
                    int n = gn0 + wn + nt * 8 + cl;
                    float b0v = bias ? __ldg(bias + n)     : 0.f;
                    float b1v = bias ? __ldg(bias + n + 1) : 0.f;
                    float2 v;
                    v.x = (acc[mt][nt][half * 2 + 0] + b0v) * alpha;
                    v.y = (acc[mt][nt][half * 2 + 1] + b1v) * alpha;
                    *(float2*)(Cz + (size_t)m * ldc + n) = v;
                }
            }
    } else { // eff_mode 6: QKV combined
        const float* bias6 = g_bias + z * 256;
        if (z == 2) {
            #pragma unroll
            for (int mt = 0; mt < 2; mt++)
                #pragma unroll
                for (int half = 0; half < 2; half++) {
                    int m = gm0 + wm + mt * 16 + r0 + half * 8;
                    #pragma unroll
                    for (int nt = 0; nt < 8; nt++) {
                        int n = gn0 + wn + nt * 8 + cl;
                        #pragma unroll
                        for (int q = 0; q < 2; q++) {
                            float v = acc[mt][nt][half * 2 + q] + bias6[n + q];
                            g_Vthi[(size_t)(n + q) * Nn + m] = __float2half(v);
                        }
                    }
                }
        } else {
            hf* Dh = z ? g_Zhi : g_Yhi;
            float al = z ? 1.0f : (1.0f / 16.0f);
            #pragma unroll
            for (int mt = 0; mt < 2; mt++)
                #pragma unroll
                for (int half = 0; half < 2; half++) {
                    int m = gm0 + wm + mt * 16 + r0 + half * 8;
                    #pragma unroll
                    for (int nt = 0; nt < 8; nt++) {
                        int n = gn0 + wn + nt * 8 + cl;
                        #pragma unroll
                        for (int q = 0; q < 2; q++) {
                            float v = (acc[mt][nt][half * 2 + q] + bias6[n + q]) * al;
                            Dh[(size_t)m * YK + n + q] = __float2half(v);
                        }
                    }
                }
        }
    }
}

// ---------------- softmax: 512 threads/row, warp-shuffle reductions, cache hints ----------------
__global__ __launch_bounds__(512) void softmax_kernel(float* __restrict__ attn) {
    int row = blockIdx.x;
    int tid = threadIdx.x;
    int lane = tid & 31, wrp = tid >> 5;
    float* L = g_L + (size_t)row * Nn;
    __shared__ float red[16];
    float4 v[2];
    float m = -1e30f;
    #pragma unroll
    for (int i = 0; i < 2; i++) {
        v[i] = __ldcs((const float4*)(L + tid * 4 + i * 2048));   // read-once: evict-first
        m = fmaxf(m, fmaxf(fmaxf(v[i].x, v[i].y), fmaxf(v[i].z, v[i].w)));
    }
    #pragma unroll
    for (int o = 16; o > 0; o >>= 1) m = fmaxf(m, __shfl_xor_sync(0xFFFFFFFFu, m, o));
    if (lane == 0) red[wrp] = m;
    __syncthreads();
    m = red[lane & 15];
    #pragma unroll
    for (int o = 8; o > 0; o >>= 1) m = fmaxf(m, __shfl_xor_sync(0xFFFFFFFFu, m, o));
    float rm = m;

    float sum = 0.f;
    #pragma unroll
    for (int i = 0; i < 2; i++) {
        v[i].x = __expf(v[i].x - rm);
        v[i].y = __expf(v[i].y - rm);
        v[i].z = __expf(v[i].z - rm);
        v[i].w = __expf(v[i].w - rm);
        sum += (v[i].x + v[i].y) + (v[i].z + v[i].w);
    }
    #pragma unroll
    for (int o = 16; o > 0; o >>= 1) sum += __shfl_xor_sync(0xFFFFFFFFu, sum, o);
    __syncthreads();
    if (lane == 0) red[wrp] = sum;
    __syncthreads();
    sum = red[lane & 15];
    #pragma unroll
    for (int o = 8; o > 0; o >>= 1) sum += __shfl_xor_sync(0xFFFFFFFFu, sum, o);
    float inv = 1.0f / sum;

    #pragma unroll
    for (int i = 0; i < 2; i++) {
        int j = tid * 4 + i * 2048;
        float4 a;
        a.x = v[i].x * inv; a.y = v[i].y * inv; a.z = v[i].z * inv; a.w = v[i].w * inv;
        __stcs((float4*)(attn + (size_t)row * Nn + j), a);        // never re-read: stream
        *(__half2*)(g_Ahi + (size_t)row * Nn + j) =
            __halves2half2(__float2half(a.x), __float2half(a.y)); // re-read by A@V: keep in L2
        *(__half2*)(g_Ahi + (size_t)row * Nn + j + 2) =
            __halves2half2(__float2half(a.z), __float2half(a.w));
    }
}

// ---------------- reduce A@V split-K partials (4-way), cache hints ----------------
__global__ __launch_bounds__(256) void reduce_kernel(float* __restrict__ upd) {
    size_t i = ((size_t)blockIdx.x * 256 + threadIdx.x) * 4;
    float4 s = __ldcs((const float4*)(g_part + i));
    #pragma unroll
    for (int z = 1; z < 4; z++) {
        const float4 p = __ldcs((const float4*)(g_part + z * (size_t)Nn * OUTD + i));
        s.x += p.x; s.y += p.y; s.z += p.z; s.w += p.w;
    }
    __stcs((float4*)(upd + i), s);
}

// ---------------- launch ----------------
extern "C" void kernel_launch(void* const* d_in, const int* in_sizes, int n_in,
                              void* d_out, int out_size) {
    const float* gene = (const float*)d_in[0];
    const float* sp   = (const float*)d_in[1];
    const float* Wq   = (const float*)d_in[2];
    const float* bq   = (const float*)d_in[3];
    const float* Wk   = (const float*)d_in[4];
    const float* bk   = (const float*)d_in[5];
    const float* Wv   = (const float*)d_in[6];
    const float* bv   = (const float*)d_in[7];
    const float* Ws   = (const float*)d_in[8];
    const float* bs   = (const float*)d_in[9];
    const float* W1   = (const float*)d_in[10];
    const float* b1   = (const float*)d_in[11];
    const float* W2   = (const float*)d_in[12];
    const float* b2   = (const float*)d_in[13];
    const float* Wf   = (const float*)d_in[14];
    const float* bf_  = (const float*)d_in[15];

    float* out = (float*)d_out;
    long long total = (long long)Nn * Nn + (long long)Nn * OUTD;
    int has_attn = ((long long)out_size >= total) ? 1 : 0;
    float* attn = out;
    float* upd  = has_attn ? out + (size_t)Nn * Nn : out;

    hf *pGhi, *pYhi, *pZhi, *pAhi, *pVthi, *pWthi;
    float *pPart;
    cudaGetSymbolAddress((void**)&pGhi, g_Ghi);
    cudaGetSymbolAddress((void**)&pYhi, g_Yhi);
    cudaGetSymbolAddress((void**)&pZhi, g_Zhi);
    cudaGetSymbolAddress((void**)&pAhi, g_Ahi);
    cudaGetSymbolAddress((void**)&pVthi, g_Vthi);
    cudaGetSymbolAddress((void**)&pWthi, g_Wthi);
    cudaGetSymbolAddress((void**)&pPart, g_part);

    cudaFuncSetAttribute(hmma_gemm, cudaFuncAttributeMaxDynamicSharedMemorySize, SMEMSZ);

    // 0) combine MLP1 into rank-2 form
    combine_kernel<<<HID, 256>>>(Ws, bs, W1, b1);

    // 1) weight transposes + biases
    wsplit_all_kernel<<<1795, 256>>>(Wq, Wk, Wv, W2, bq, bk, bv);

    // 2) prep: Ghi, normalized rows, sq, h = tanh(MLP1) splits
    prep_kernel<<<Nn, 256>>>(gene, sp);

    // 3) FUSED: QKV (z=0..2, 8 chunks) + MLP2 split-K x4 (z=3..6, 2 chunks)  [mode 7]
    dim3 gFU(HID / BN, Nn / BM, 7);
    hmma_gemm<<<gFU, 256, SMEMSZ>>>(pGhi, pGhi, pGhi, pWthi, pWthi, pWthi,
                                    GENE, GENE, 8, 8, 8, 0, (size_t)HID * GENE, 7,
                                    nullptr, 0, 0, nullptr, 1.0f, nullptr);

    // 4) reduce2 + f (4 rows/block, float4)
    reduce_f_kernel<<<Nn / 4, 256>>>(b2, Wf, bf_);

    // 5) logits: single-segment Yhi·Zhi (768 -> 12 chunks) + epilogue
    dim3 gLg(Nn / BN, Nn / BM, 1);
    hmma_gemm<<<gLg, 256, SMEMSZ>>>(pYhi, pYhi, pYhi, pZhi, pZhi, pZhi,
                                    YK, YK, 12, 12, 12, 0, 0, 1,
                                    nullptr, 0, 0, nullptr, 1.0f, sp);

    // 6) softmax -> attn (streaming) + A hi split (L2-resident)
    softmax_kernel<<<Nn, 512>>>(attn);

    // 7) A@V split-K x4 -> partials (hi-only: 64 chunks, 16/z)
    dim3 gAV(OUTD / BN, Nn / BM, 4);
    hmma_gemm<<<gAV, 256, SMEMSZ>>>(pAhi, pAhi, pAhi, pVthi, pVthi, pVthi,
                                    Nn, Nn, 64, 64, 16, 16, 0, 0,
                                    pPart, OUTD, (size_t)Nn * OUTD, nullptr, 1.0f, nullptr);
    // 8) reduce partials
    reduce_kernel<<<(Nn * OUTD) / 1024, 256>>>(upd);
}

// round 15
// speedup vs baseline: 13.9679x; 1.0036x over previous
#include <cuda_runtime.h>
#include <cuda_fp16.h>
#include <math.h>
#include <stdint.h>

#define Nn    4096
#define GENE  512
#define HID   256
#define OUTD  256
#define YK    768     // HID + GENE fused logits depth

typedef __half hf;

// ---------------- scratch (static device globals; no runtime allocs) ----------------
__device__ __align__(16) hf    g_Ghi[Nn * GENE];
__device__ __align__(16) hf    g_Yhi[Nn * YK];
__device__ __align__(16) hf    g_Zhi[Nn * YK];
__device__ __align__(16) hf    g_Ahi[(size_t)Nn * Nn];    // unnormalized exp(logits), fp16
__device__ __align__(16) hf    g_Vthi[OUTD * Nn];
__device__ __align__(16) hf    g_Wthi[3 * HID * GENE];    // W^T hi (q,k,v)
__device__ __align__(16) hf    g_W2thi[HID * HID];
__device__ __align__(16) hf    g_hhi[Nn * HID];
__device__ __align__(16) hf    g_hlo[Nn * HID];
__device__ __align__(16) float g_part[4 * (size_t)Nn * OUTD];   // split-K partials
__device__ __align__(16) float g_bias[3 * 256];                  // bq|bk|bv
__device__ __align__(16) float g_W1c[2 * HID];                   // Ws @ W1
__device__ __align__(16) float g_b1c[HID];                       // bs @ W1 + b1
__device__ float g_f[Nn];     // clamp(tanh(f))
__device__ float g_sq[Nn];
__device__ float g_inv[Nn];   // 1 / rowsum(exp)

// ---------------- PTX helpers (sm_80+ baseline) ----------------
__device__ __forceinline__ uint32_t s2u(const void* p) {
    uint32_t a;
    asm("{ .reg .u64 t; cvta.to.shared.u64 t, %1; cvt.u32.u64 %0, t; }" : "=r"(a) : "l"(p));
    return a;
}
__device__ __forceinline__ void cp16(uint32_t dst, const void* src) {
    asm volatile("cp.async.cg.shared.global [%0], [%1], 16;" :: "r"(dst), "l"(src));
}
__device__ __forceinline__ void cp_commit() {
    asm volatile("cp.async.commit_group;" ::: "memory");
}
template <int N>
__device__ __forceinline__ void cp_wait() {
    asm volatile("cp.async.wait_group %0;" :: "n"(N) : "memory");
}
__device__ __forceinline__ void ldm4(uint32_t* r, uint32_t addr) {
    asm volatile("ldmatrix.sync.aligned.m8n8.x4.shared.b16 {%0,%1,%2,%3}, [%4];"
                 : "=r"(r[0]), "=r"(r[1]), "=r"(r[2]), "=r"(r[3]) : "r"(addr));
}
__device__ __forceinline__ void mma_f16(float* d, const uint32_t* a, uint32_t b0, uint32_t b1) {
    asm volatile(
        "mma.sync.aligned.m16n8k16.row.col.f32.f16.f16.f32 "
        "{%0,%1,%2,%3}, {%4,%5,%6,%7}, {%8,%9}, {%0,%1,%2,%3};"
        : "+f"(d[0]), "+f"(d[1]), "+f"(d[2]), "+f"(d[3])
        : "r"(a[0]), "r"(a[1]), "r"(a[2]), "r"(a[3]), "r"(b0), "r"(b1));
}
__device__ __forceinline__ void split2(float v, hf& h, hf& l) {
    h = __float2half(v);
    l = __float2half(v - __half2float(h));
}

// ---------------- combine: W1c = Ws@W1 (2x256), b1c = bs@W1 + b1 ----------------
__global__ __launch_bounds__(256) void combine_kernel(const float* __restrict__ Ws,
                                                      const float* __restrict__ bs,
                                                      const float* __restrict__ W1,
                                                      const float* __restrict__ b1) {
    int h = blockIdx.x;
    int k = threadIdx.x;
    float w = __ldg(W1 + k * HID + h);
    __shared__ float r0[256], r1[256], r2[256];
    r0[k] = __ldg(Ws + k) * w;
    r1[k] = __ldg(Ws + HID + k) * w;
    r2[k] = __ldg(bs + k) * w;
    __syncthreads();
    for (int s = 128; s > 0; s >>= 1) {
        if (k < s) { r0[k] += r0[k + s]; r1[k] += r1[k + s]; r2[k] += r2[k + s]; }
        __syncthreads();
    }
    if (k == 0) {
        g_W1c[h]       = r0[0];
        g_W1c[HID + h] = r1[0];
        g_b1c[h]       = r2[0] + __ldg(b1 + h);
    }
}

// ---------------- prep: gene fp16 + normalized rows + sq + h (=tanh MLP1) ----------------
__global__ __launch_bounds__(256) void prep_kernel(const float* __restrict__ gene,
                                                   const float* __restrict__ sp) {
    int row = blockIdx.x;
    const float* x = gene + (size_t)row * GENE;
    __shared__ float red[256];
    float a = __ldg(sp + 2 * row), b = __ldg(sp + 2 * row + 1);

    {
        int h = threadIdx.x;
        float v = a * g_W1c[h] + b * g_W1c[HID + h] + g_b1c[h];
        float t = tanhf(v);
        split2(t, g_hhi[row * HID + h], g_hlo[row * HID + h]);
    }

    float ss = 0.f;
    for (int c = threadIdx.x; c < GENE; c += 256) { float v = x[c]; ss += v * v; }
    red[threadIdx.x] = ss; __syncthreads();
    for (int s = 128; s > 0; s >>= 1) {
        if (threadIdx.x < s) red[threadIdx.x] += red[threadIdx.x + s];
        __syncthreads();
    }
    float inv = 1.0f / fmaxf(sqrtf(red[0]), 1e-12f);
    for (int c = threadIdx.x; c < GENE; c += 256) {
        float v = x[c];
        g_Ghi[(size_t)row * GENE + c] = __float2half(v);
        hf xh = __float2half(v * inv);
        size_t o = (size_t)row * YK + HID + c;
        g_Yhi[o] = xh;
        g_Zhi[o] = xh;
    }
    if (threadIdx.x == 0) g_sq[row] = a * a + b * b;
}

// ---------------- weight transposes (fp16) + bias copies ----------------
__global__ __launch_bounds__(256) void wsplit_all_kernel(
    const float* __restrict__ Wq, const float* __restrict__ Wk, const float* __restrict__ Wv,
    const float* __restrict__ W2,
    const float* __restrict__ bq, const float* __restrict__ bk, const float* __restrict__ bv) {
    int idx = blockIdx.x * 256 + threadIdx.x;
    if (idx < 393216) {                       // 3 x (256 x 512)
        int w = idx / 131072, r = idx % 131072;
        int n = r / GENE, k = r % GENE;
        const float* W = (w == 0) ? Wq : (w == 1) ? Wk : Wv;
        g_Wthi[idx] = __float2half(W[(size_t)k * HID + n]);
    } else if (idx < 458752) {                // W2 (256 x 256)
        int r = idx - 393216;
        int n = r / HID, k = r % HID;
        g_W2thi[r] = __float2half(W2[(size_t)k * HID + n]);
    } else if (idx < 459520) {                // biases
        int t = idx - 458752;
        if (t < 256)      g_bias[t] = bq[t];
        else if (t < 512) g_bias[t] = bk[t - 256];
        else              g_bias[t] = bv[t - 512];
    }
}

// ---------------- reduce MLP2 partials + f: 4 rows per block, float4 ----------------
__global__ __launch_bounds__(256) void reduce_f_kernel(const float* __restrict__ b2,
                                                       const float* __restrict__ Wf,
                                                       const float* __restrict__ bf_) {
    int rloc = threadIdx.x >> 6;              // 0..3
    int c4   = (threadIdx.x & 63) * 4;
    int row  = blockIdx.x * 4 + rloc;
    size_t i4 = (size_t)row * HID + c4;
    float4 s = __ldcs((const float4*)(g_part + i4));
    #pragma unroll
    for (int z = 1; z < 4; z++) {
        float4 p = __ldcs((const float4*)(g_part + z * (size_t)Nn * HID + i4));
        s.x += p.x; s.y += p.y; s.z += p.z; s.w += p.w;
    }
    float4 bb = *(const float4*)(b2 + c4);
    float4 wf = *(const float4*)(Wf + c4);
    float d = fmaxf(s.x + bb.x, 0.f) * wf.x + fmaxf(s.y + bb.y, 0.f) * wf.y
            + fmaxf(s.z + bb.z, 0.f) * wf.z + fmaxf(s.w + bb.w, 0.f) * wf.w;
    __shared__ float red[256];
    red[threadIdx.x] = d;
    __syncthreads();
    #pragma unroll
    for (int st = 32; st > 0; st >>= 1) {
        if ((threadIdx.x & 63) < st) red[threadIdx.x] += red[threadIdx.x + st];
        __syncthreads();
    }
    if ((threadIdx.x & 63) == 0) {
        float t = tanhf(red[rloc * 64] + bf_[0]);
        g_f[row] = fminf(fmaxf(t, -0.999999f), 0.999999f);
    }
}

// ---------------- HMMA fp16 GEMM, BK=64, XOR-swizzle, 3-stage pipeline ----------------
// modes: 0 = fp32 C (+bias)*alpha (per-z C offset)
//        1 = exp-logits epilogue -> g_Ahi fp16 (unnormalized softmax numerator)
//        6 = QKV combined (z: 0->Q into Y, 1->K into Z, 2->V transpose)
//        7 = fused QKV (z<3) + MLP2 split-K partials (z=3..6)
#define BM 128
#define BN 128
#define BK 64
#define TILEB  16384                 // 128 rows x 128B
#define STAGEB (2 * TILEB)           // A + B
#define NSTAGE 3
#define SMEMSZ (NSTAGE * STAGEB)     // 98304

__global__ __launch_bounds__(256, 2) void hmma_gemm(
    const hf* __restrict__ a0, const hf* __restrict__ a1, const hf* __restrict__ a2,
    const hf* __restrict__ b0, const hf* __restrict__ b1, const hf* __restrict__ b2,
    int pitchA, int pitchB, int cb1, int cb2, int chunks_per_z, int zchunks,
    size_t zBstride, int mode,
    float* __restrict__ C, int ldc, size_t zCstride,
    const float* __restrict__ bias, float alpha,
    const float* __restrict__ sp)
{
    extern __shared__ __align__(16) char smem[];
    const uint32_t sbase = s2u(smem);
    const int tid  = threadIdx.x;
    const int lane = tid & 31;
    const int wid  = tid >> 5;
    const int wm   = (wid & 3) * 32;
    const int wn   = (wid >> 2) * 64;
    const int gm0  = blockIdx.y * BM;
    const int gn0  = blockIdx.x * BN;
    const int z    = blockIdx.z;

    int eff_mode = mode;
    int zc = z;
    int g0 = z * zchunks;

    if (mode == 7) {
        if (z < 3) {
            eff_mode = 6;
            g0 = 0;
            b0 += z * zBstride; b1 += z * zBstride; b2 += z * zBstride;
        } else {
            eff_mode = 0; zc = z - 3;
            a0 = g_hhi; a1 = g_hlo; a2 = g_hhi;
            b0 = g_W2thi; b1 = g_W2thi; b2 = g_W2thi;
            pitchA = HID; pitchB = HID; cb1 = 4; cb2 = 8;
            chunks_per_z = 2; g0 = zc * 2;
            C = g_part; ldc = HID; zCstride = (size_t)Nn * HID;
            bias = nullptr; alpha = 1.0f;
        }
    } else if (zBstride) {
        b0 += z * zBstride; b1 += z * zBstride; b2 += z * zBstride;
    }

    const int mi    = lane >> 3;
    const int ldrow = ((mi & 1) << 3) + (lane & 7);
    const int ldc16 = mi >> 1;
    const int srow0 = tid >> 3;
    const int sc    = tid & 7;

    float acc[2][8][4];
    #pragma unroll
    for (int a = 0; a < 2; a++)
        #pragma unroll
        for (int b = 0; b < 8; b++)
            #pragma unroll
            for (int c = 0; c < 4; c++) acc[a][b][c] = 0.f;

    auto load_chunk = [&](int g, int stage) {
        const hf *As, *Bs; int kk;
        if (g < cb1)      { As = a0; Bs = b0; kk = g * BK; }
        else if (g < cb2) { As = a1; Bs = b1; kk = (g - cb1) * BK; }
        else              { As = a2; Bs = b2; kk = (g - cb2) * BK; }
        uint32_t dst = sbase + stage * STAGEB;
        #pragma unroll
        for (int i = 0; i < 4; i++) {
            int row = srow0 + i * 32;
            uint32_t off = (uint32_t)(row * 128 + ((sc ^ (row & 7)) << 4));
            cp16(dst + off,         As + (size_t)(gm0 + row) * pitchA + kk + sc * 8);
            cp16(dst + TILEB + off, Bs + (size_t)(gn0 + row) * pitchB + kk + sc * 8);
        }
        cp_commit();
    };

    load_chunk(g0, 0);
    if (chunks_per_z > 1) load_chunk(g0 + 1, 1);
    else cp_commit();

    for (int c = 0; c < chunks_per_z; c++) {
        if (c + 1 < chunks_per_z) cp_wait<1>(); else cp_wait<0>();
        __syncthreads();
        if (c + 2 < chunks_per_z) load_chunk(g0 + c + 2, (c + 2) % NSTAGE);

        uint32_t abase = sbase + (c % NSTAGE) * STAGEB;
        uint32_t bbase = abase + TILEB;
        #pragma unroll
        for (int ks = 0; ks < 4; ks++) {
            uint32_t afrag[2][4];
            uint32_t bfrag[4][4];
            int c16 = ks * 2 + ldc16;
            #pragma unroll
            for (int mt = 0; mt < 2; mt++) {
                int row = wm + mt * 16 + ldrow;
                ldm4(afrag[mt], abase + row * 128 + ((c16 ^ (row & 7)) << 4));
            }
            #pragma unroll
            for (int p = 0; p < 4; p++) {
                int row = wn + p * 16 + ldrow;
                ldm4(bfrag[p], bbase + row * 128 + ((c16 ^ (row & 7)) << 4));
            }
            #pragma unroll
            for (int mt = 0; mt < 2; mt++) {
                #pragma unroll
                for (int p = 0; p < 4; p++) {
                    mma_f16(acc[mt][2 * p],     afrag[mt], bfrag[p][0], bfrag[p][2]);
                    mma_f16(acc[mt][2 * p + 1], afrag[mt], bfrag[p][1], bfrag[p][3]);
                }
            }
        }
    }

    // ---- epilogue ----
    const int r0 = lane >> 2;
    const int cl = 2 * (lane & 3);

    if (eff_mode == 1) {
        float* ex = (float*)smem;
        __syncthreads();
        for (int i = tid; i < BN; i += 256) {
            int n = gn0 + i;
            ex[i]           = __ldg(sp + 2 * n);
            ex[BN + i]      = __ldg(sp + 2 * n + 1);
            ex[2 * BN + i]  = g_sq[n];
            ex[3 * BN + i]  = g_f[n];
        }
        __syncthreads();
        #pragma unroll
        for (int mt = 0; mt < 2; mt++) {
            #pragma unroll
            for (int half = 0; half < 2; half++) {
                int m = gm0 + wm + mt * 16 + r0 + half * 8;
                float sp0 = __ldg(sp + 2 * m), sp1 = __ldg(sp + 2 * m + 1);
                float sqi = g_sq[m], ti = g_f[m];
                #pragma unroll
                for (int nt = 0; nt < 8; nt++) {
                    int nl = wn + nt * 8 + cl;
                    float ev[2];
                    #pragma unroll
                    for (int q = 0; q < 2; q++) {
                        int ci = nl + q;
                        float d2 = sqi + ex[2 * BN + ci]
                                 - 2.0f * (sp0 * ex[ci] + sp1 * ex[BN + ci]);
                        d2 = fmaxf(d2, 0.0f);
                        float tj = ex[3 * BN + ci];
                        float tb = __fdividef(ti - tj, fmaf(-ti, tj, 1.0f));
                        float lg = acc[mt][nt][half * 2 + q] + __expf(-0.5f * d2) + tb;
                        ev[q] = fminf(__expf(lg), 60000.0f);
                    }
                    *(__half2*)(g_Ahi + (size_t)m * Nn + gn0 + nl) =
                        __halves2half2(__float2half(ev[0]), __float2half(ev[1]));
                }
            }
        }
    } else if (eff_mode == 0) {
        float* Cz = C + zc * zCstride;
        #pragma unroll
        for (int mt = 0; mt < 2; mt++)
            #pragma unroll
            for (int half = 0; half < 2; half++) {
                int m = gm0 + wm + mt * 16 + r0 + half * 8;
                #pragma unroll
                for (int nt = 0; nt < 8; nt++) {
                    int n = gn0 + wn + nt * 8 + cl;
                    float b0v = bias ? __ldg(bias + n)     : 0.f;
                    float b1v = bias ? __ldg(bias + n + 1) : 0.f;
                    float2 v;
                    v.x = (acc[mt][nt][half * 2 + 0] + b0v) * alpha;
                    v.y = (acc[mt][nt][half * 2 + 1] + b1v) * alpha;
                    *(float2*)(Cz + (size_t)m * ldc + n) = v;
                }
            }
    } else { // eff_mode 6: QKV combined
        const float* bias6 = g_bias + z * 256;
        if (z == 2) {
            #pragma unroll
            for (int mt = 0; mt < 2; mt++)
                #pragma unroll
                for (int half = 0; half < 2; half++) {
                    int m = gm0 + wm + mt * 16 + r0 + half * 8;
                    #pragma unroll
                    for (int nt = 0; nt < 8; nt++) {
                        int n = gn0 + wn + nt * 8 + cl;
                        #pragma unroll
                        for (int q = 0; q < 2; q++) {
                            float v = acc[mt][nt][half * 2 + q] + bias6[n + q];
                            g_Vthi[(size_t)(n + q) * Nn + m] = __float2half(v);
                        }
                    }
                }
        } else {
            hf* Dh = z ? g_Zhi : g_Yhi;
            float al = z ? 1.0f : (1.0f / 16.0f);
            #pragma unroll
            for (int mt = 0; mt < 2; mt++)
                #pragma unroll
                for (int half = 0; half < 2; half++) {
                    int m = gm0 + wm + mt * 16 + r0 + half * 8;
                    #pragma unroll
                    for (int nt = 0; nt < 8; nt++) {
                        int n = gn0 + wn + nt * 8 + cl;
                        #pragma unroll
                        for (int q = 0; q < 2; q++) {
                            float v = (acc[mt][nt][half * 2 + q] + bias6[n + q]) * al;
                            Dh[(size_t)m * YK + n + q] = __float2half(v);
                        }
                    }
                }
        }
    }
}

// ---------------- normalize: row sum of fp16 e, write attn = e*inv + g_inv ----------------
__global__ __launch_bounds__(512) void normalize_kernel(float* __restrict__ attn) {
    int row = blockIdx.x;
    int tid = threadIdx.x;
    int lane = tid & 31, wrp = tid >> 5;
    const hf* E = g_Ahi + (size_t)row * Nn;
    __shared__ float red[16];
    // 4096 halves = 512 threads x 8 halves (one uint4 each)
    uint4 raw = *(const uint4*)(E + tid * 8);
    __half2 h2[4];
    h2[0] = *(__half2*)&raw.x; h2[1] = *(__half2*)&raw.y;
    h2[2] = *(__half2*)&raw.z; h2[3] = *(__half2*)&raw.w;
    float e[8];
    #pragma unroll
    for (int i = 0; i < 4; i++) {
        float2 f = __half22float2(h2[i]);
        e[2 * i] = f.x; e[2 * i + 1] = f.y;
    }
    float sum = ((e[0] + e[1]) + (e[2] + e[3])) + ((e[4] + e[5]) + (e[6] + e[7]));
    #pragma unroll
    for (int o = 16; o > 0; o >>= 1) sum += __shfl_xor_sync(0xFFFFFFFFu, sum, o);
    if (lane == 0) red[wrp] = sum;
    __syncthreads();
    sum = red[lane & 15];
    #pragma unroll
    for (int o = 8; o > 0; o >>= 1) sum += __shfl_xor_sync(0xFFFFFFFFu, sum, o);
    float inv = 1.0f / sum;
    if (tid == 0) g_inv[row] = inv;

    float4 o0, o1;
    o0.x = e[0] * inv; o0.y = e[1] * inv; o0.z = e[2] * inv; o0.w = e[3] * inv;
    o1.x = e[4] * inv; o1.y = e[5] * inv; o1.z = e[6] * inv; o1.w = e[7] * inv;
    __stcs((float4*)(attn + (size_t)row * Nn + tid * 8), o0);
    __stcs((float4*)(attn + (size_t)row * Nn + tid * 8 + 4), o1);
}

// ---------------- reduce A@V split-K partials (4-way) + row normalize ----------------
__global__ __launch_bounds__(256) void reduce_kernel(float* __restrict__ upd) {
    size_t i = ((size_t)blockIdx.x * 256 + threadIdx.x) * 4;
    float4 s = __ldcs((const float4*)(g_part + i));
    #pragma unroll
    for (int z = 1; z < 4; z++) {
        const float4 p = __ldcs((const float4*)(g_part + z * (size_t)Nn * OUTD + i));
        s.x += p.x; s.y += p.y; s.z += p.z; s.w += p.w;
    }
    float inv = g_inv[i >> 8];   // OUTD = 256
    s.x *= inv; s.y *= inv; s.z *= inv; s.w *= inv;
    __stcs((float4*)(upd + i), s);
}

// ---------------- launch ----------------
extern "C" void kernel_launch(void* const* d_in, const int* in_sizes, int n_in,
                              void* d_out, int out_size) {
    const float* gene = (const float*)d_in[0];
    const float* sp   = (const float*)d_in[1];
    const float* Wq   = (const float*)d_in[2];
    const float* bq   = (const float*)d_in[3];
    const float* Wk   = (const float*)d_in[4];
    const float* bk   = (const float*)d_in[5];
    const float* Wv   = (const float*)d_in[6];
    const float* bv   = (const float*)d_in[7];
    const float* Ws   = (const float*)d_in[8];
    const float* bs   = (const float*)d_in[9];
    const float* W1   = (const float*)d_in[10];
    const float* b1   = (const float*)d_in[11];
    const float* W2   = (const float*)d_in[12];
    const float* b2   = (const float*)d_in[13];
    const float* Wf   = (const float*)d_in[14];
    const float* bf_  = (const float*)d_in[15];

    float* out = (float*)d_out;
    long long total = (long long)Nn * Nn + (long long)Nn * OUTD;
    int has_attn = ((long long)out_size >= total) ? 1 : 0;
    float* attn = out;
    float* upd  = has_attn ? out + (size_t)Nn * Nn : out;

    hf *pGhi, *pYhi, *pZhi, *pAhi, *pVthi, *pWthi;
    float *pPart;
    cudaGetSymbolAddress((void**)&pGhi, g_Ghi);
    cudaGetSymbolAddress((void**)&pYhi, g_Yhi);
    cudaGetSymbolAddress((void**)&pZhi, g_Zhi);
    cudaGetSymbolAddress((void**)&pAhi, g_Ahi);
    cudaGetSymbolAddress((void**)&pVthi, g_Vthi);
    cudaGetSymbolAddress((void**)&pWthi, g_Wthi);
    cudaGetSymbolAddress((void**)&pPart, g_part);

    cudaFuncSetAttribute(hmma_gemm, cudaFuncAttributeMaxDynamicSharedMemorySize, SMEMSZ);

    // 0) combine MLP1 into rank-2 form
    combine_kernel<<<HID, 256>>>(Ws, bs, W1, b1);

    // 1) weight transposes + biases
    wsplit_all_kernel<<<1795, 256>>>(Wq, Wk, Wv, W2, bq, bk, bv);

    // 2) prep: Ghi, normalized rows, sq, h = tanh(MLP1) splits
    prep_kernel<<<Nn, 256>>>(gene, sp);

    // 3) FUSED: QKV (z=0..2, 8 chunks) + MLP2 split-K x4 (z=3..6, 2 chunks)  [mode 7]
    dim3 gFU(HID / BN, Nn / BM, 7);
    hmma_gemm<<<gFU, 256, SMEMSZ>>>(pGhi, pGhi, pGhi, pWthi, pWthi, pWthi,
                                    GENE, GENE, 8, 8, 8, 0, (size_t)HID * GENE, 7,
                                    nullptr, 0, 0, nullptr, 1.0f, nullptr);

    // 4) reduce2 + f (4 rows/block, float4)
    reduce_f_kernel<<<Nn / 4, 256>>>(b2, Wf, bf_);

    // 5) logits -> exp -> g_Ahi fp16 (single-segment Yhi·Zhi, 12 chunks)
    dim3 gLg(Nn / BN, Nn / BM, 1);
    hmma_gemm<<<gLg, 256, SMEMSZ>>>(pYhi, pYhi, pYhi, pZhi, pZhi, pZhi,
                                    YK, YK, 12, 12, 12, 0, 0, 1,
                                    nullptr, 0, 0, nullptr, 1.0f, sp);

    // 6) normalize: rowsum -> attn fp32 + g_inv
    normalize_kernel<<<Nn, 512>>>(attn);

    // 7) A@V split-K x4 on unnormalized e (hi-only: 64 chunks, 16/z)
    dim3 gAV(OUTD / BN, Nn / BM, 4);
    hmma_gemm<<<gAV, 256, SMEMSZ>>>(pAhi, pAhi, pAhi, pVthi, pVthi, pVthi,
                                    Nn, Nn, 64, 64, 16, 16, 0, 0,
                                    pPart, OUTD, (size_t)Nn * OUTD, nullptr, 1.0f, nullptr);
    // 8) reduce partials (x inv[row])
    reduce_kernel<<<(Nn * OUTD) / 1024, 256>>>(upd);
}

// round 16
// speedup vs baseline: 14.1059x; 1.0099x over previous
#include <cuda_runtime.h>
#include <cuda_fp16.h>
#include <math.h>
#include <stdint.h>

#define Nn    4096
#define GENE  512
#define HID   256
#define OUTD  256
#define YK    768     // HID + GENE fused logits depth

typedef __half hf;

// ---------------- scratch (static device globals; no runtime allocs) ----------------
__device__ __align__(16) hf    g_Ghi[Nn * GENE];
__device__ __align__(16) hf    g_Yhi[Nn * YK];
__device__ __align__(16) hf    g_Zhi[Nn * YK];
__device__ __align__(16) hf    g_Ahi[(size_t)Nn * Nn];    // unnormalized exp(logits), fp16
__device__ __align__(16) hf    g_Vthi[OUTD * Nn];
__device__ __align__(16) hf    g_Wthi[3 * HID * GENE];    // W^T hi (q,k,v)
__device__ __align__(16) hf    g_W2thi[HID * HID];
__device__ __align__(16) hf    g_hhi[Nn * HID];
__device__ __align__(16) hf    g_hlo[Nn * HID];
__device__ __align__(16) float g_part[4 * (size_t)Nn * OUTD];   // split-K partials
__device__ __align__(16) float g_bias[3 * 256];                  // bq|bk|bv
__device__ __align__(16) float g_W1c[2 * HID];                   // Ws @ W1
__device__ __align__(16) float g_b1c[HID];                       // bs @ W1 + b1
__device__ float g_f[Nn];     // clamp(tanh(f))
__device__ float g_sq[Nn];
__device__ float g_inv[Nn];   // 1 / rowsum(exp)

// ---------------- PTX helpers (sm_80+ baseline) ----------------
__device__ __forceinline__ uint32_t s2u(const void* p) {
    uint32_t a;
    asm("{ .reg .u64 t; cvta.to.shared.u64 t, %1; cvt.u32.u64 %0, t; }" : "=r"(a) : "l"(p));
    return a;
}
__device__ __forceinline__ void cp16(uint32_t dst, const void* src) {
    asm volatile("cp.async.cg.shared.global [%0], [%1], 16;" :: "r"(dst), "l"(src));
}
__device__ __forceinline__ void cp_commit() {
    asm volatile("cp.async.commit_group;" ::: "memory");
}
template <int N>
__device__ __forceinline__ void cp_wait() {
    asm volatile("cp.async.wait_group %0;" :: "n"(N) : "memory");
}
__device__ __forceinline__ void ldm4(uint32_t* r, uint32_t addr) {
    asm volatile("ldmatrix.sync.aligned.m8n8.x4.shared.b16 {%0,%1,%2,%3}, [%4];"
                 : "=r"(r[0]), "=r"(r[1]), "=r"(r[2]), "=r"(r[3]) : "r"(addr));
}
__device__ __forceinline__ void mma_f16(float* d, const uint32_t* a, uint32_t b0, uint32_t b1) {
    asm volatile(
        "mma.sync.aligned.m16n8k16.row.col.f32.f16.f16.f32 "
        "{%0,%1,%2,%3}, {%4,%5,%6,%7}, {%8,%9}, {%0,%1,%2,%3};"
        : "+f"(d[0]), "+f"(d[1]), "+f"(d[2]), "+f"(d[3])
        : "r"(a[0]), "r"(a[1]), "r"(a[2]), "r"(a[3]), "r"(b0), "r"(b1));
}
__device__ __forceinline__ void split2(float v, hf& h, hf& l) {
    h = __float2half(v);
    l = __float2half(v - __half2float(h));
}

// ---------------- weight transposes + biases + combine (merged) ----------------
// blocks [0, 1795): wsplit work; blocks [1795, 2051): combine W1c/b1c
__global__ __launch_bounds__(256) void wsplit_combine_kernel(
    const float* __restrict__ Wq, const float* __restrict__ Wk, const float* __restrict__ Wv,
    const float* __restrict__ W2,
    const float* __restrict__ bq, const float* __restrict__ bk, const float* __restrict__ bv,
    const float* __restrict__ Ws, const float* __restrict__ bs,
    const float* __restrict__ W1, const float* __restrict__ b1) {
    if (blockIdx.x >= 1795) {
        int h = blockIdx.x - 1795;
        int k = threadIdx.x;
        float w = __ldg(W1 + k * HID + h);
        __shared__ float r0[256], r1[256], r2[256];
        r0[k] = __ldg(Ws + k) * w;
        r1[k] = __ldg(Ws + HID + k) * w;
        r2[k] = __ldg(bs + k) * w;
        __syncthreads();
        for (int s = 128; s > 0; s >>= 1) {
            if (k < s) { r0[k] += r0[k + s]; r1[k] += r1[k + s]; r2[k] += r2[k + s]; }
            __syncthreads();
        }
        if (k == 0) {
            g_W1c[h]       = r0[0];
            g_W1c[HID + h] = r1[0];
            g_b1c[h]       = r2[0] + __ldg(b1 + h);
        }
        return;
    }
    int idx = blockIdx.x * 256 + threadIdx.x;
    if (idx < 393216) {                       // 3 x (256 x 512)
        int w = idx / 131072, r = idx % 131072;
        int n = r / GENE, k = r % GENE;
        const float* W = (w == 0) ? Wq : (w == 1) ? Wk : Wv;
        g_Wthi[idx] = __float2half(W[(size_t)k * HID + n]);
    } else if (idx < 458752) {                // W2 (256 x 256)
        int r = idx - 393216;
        int n = r / HID, k = r % HID;
        g_W2thi[r] = __float2half(W2[(size_t)k * HID + n]);
    } else if (idx < 459520) {                // biases
        int t = idx - 458752;
        if (t < 256)      g_bias[t] = bq[t];
        else if (t < 512) g_bias[t] = bk[t - 256];
        else              g_bias[t] = bv[t - 512];
    }
}

// ---------------- prep: gene fp16 + normalized rows + sq + h (=tanh MLP1) ----------------
__global__ __launch_bounds__(256) void prep_kernel(const float* __restrict__ gene,
                                                   const float* __restrict__ sp) {
    int row = blockIdx.x;
    const float* x = gene + (size_t)row * GENE;
    __shared__ float red[256];
    float a = __ldg(sp + 2 * row), b = __ldg(sp + 2 * row + 1);

    {
        int h = threadIdx.x;
        float v = a * g_W1c[h] + b * g_W1c[HID + h] + g_b1c[h];
        float t = tanhf(v);
        split2(t, g_hhi[row * HID + h], g_hlo[row * HID + h]);
    }

    float ss = 0.f;
    for (int c = threadIdx.x; c < GENE; c += 256) { float v = x[c]; ss += v * v; }
    red[threadIdx.x] = ss; __syncthreads();
    for (int s = 128; s > 0; s >>= 1) {
        if (threadIdx.x < s) red[threadIdx.x] += red[threadIdx.x + s];
        __syncthreads();
    }
    float inv = 1.0f / fmaxf(sqrtf(red[0]), 1e-12f);
    for (int c = threadIdx.x; c < GENE; c += 256) {
        float v = x[c];
        g_Ghi[(size_t)row * GENE + c] = __float2half(v);
        hf xh = __float2half(v * inv);
        size_t o = (size_t)row * YK + HID + c;
        g_Yhi[o] = xh;
        g_Zhi[o] = xh;
    }
    if (threadIdx.x == 0) g_sq[row] = a * a + b * b;
}

// ---------------- reduce MLP2 partials + f: 4 rows per block, float4 ----------------
__global__ __launch_bounds__(256) void reduce_f_kernel(const float* __restrict__ b2,
                                                       const float* __restrict__ Wf,
                                                       const float* __restrict__ bf_) {
    int rloc = threadIdx.x >> 6;              // 0..3
    int c4   = (threadIdx.x & 63) * 4;
    int row  = blockIdx.x * 4 + rloc;
    size_t i4 = (size_t)row * HID + c4;
    float4 s = __ldcs((const float4*)(g_part + i4));
    #pragma unroll
    for (int z = 1; z < 4; z++) {
        float4 p = __ldcs((const float4*)(g_part + z * (size_t)Nn * HID + i4));
        s.x += p.x; s.y += p.y; s.z += p.z; s.w += p.w;
    }
    float4 bb = *(const float4*)(b2 + c4);
    float4 wf = *(const float4*)(Wf + c4);
    float d = fmaxf(s.x + bb.x, 0.f) * wf.x + fmaxf(s.y + bb.y, 0.f) * wf.y
            + fmaxf(s.z + bb.z, 0.f) * wf.z + fmaxf(s.w + bb.w, 0.f) * wf.w;
    __shared__ float red[256];
    red[threadIdx.x] = d;
    __syncthreads();
    #pragma unroll
    for (int st = 32; st > 0; st >>= 1) {
        if ((threadIdx.x & 63) < st) red[threadIdx.x] += red[threadIdx.x + st];
        __syncthreads();
    }
    if ((threadIdx.x & 63) == 0) {
        float t = tanhf(red[rloc * 64] + bf_[0]);
        g_f[row] = fminf(fmaxf(t, -0.999999f), 0.999999f);
    }
}

// ---------------- HMMA fp16 GEMM, BK=64, XOR-swizzle, 3-stage pipeline ----------------
// modes: 0 = fp32 C (+bias)*alpha (per-z C offset)
//        1 = exp-logits epilogue -> g_Ahi fp16 (unnormalized softmax numerator)
//        6 = QKV combined (z: 0->Q into Y, 1->K into Z, 2->V transpose)
//        7 = fused QKV (z<3) + MLP2 split-K partials (z=3..6)
#define BM 128
#define BN 128
#define BK 64
#define TILEB  16384                 // 128 rows x 128B
#define STAGEB (2 * TILEB)           // A + B
#define NSTAGE 3
#define SMEMSZ (NSTAGE * STAGEB)     // 98304

__global__ __launch_bounds__(256, 2) void hmma_gemm(
    const hf* __restrict__ a0, const hf* __restrict__ a1, const hf* __restrict__ a2,
    const hf* __restrict__ b0, const hf* __restrict__ b1, const hf* __restrict__ b2,
    int pitchA, int pitchB, int cb1, int cb2, int chunks_per_z, int zchunks,
    size_t zBstride, int mode,
    float* __restrict__ C, int ldc, size_t zCstride,
    const float* __restrict__ bias, float alpha,
    const float* __restrict__ sp)
{
    extern __shared__ __align__(16) char smem[];
    const uint32_t sbase = s2u(smem);
    const int tid  = threadIdx.x;
    const int lane = tid & 31;
    const int wid  = tid >> 5;
    const int wm   = (wid & 3) * 32;
    const int wn   = (wid >> 2) * 64;
    const int gm0  = blockIdx.y * BM;
    const int gn0  = blockIdx.x * BN;
    const int z    = blockIdx.z;

    int eff_mode = mode;
    int zc = z;
    int g0 = z * zchunks;

    if (mode == 7) {
        if (z < 3) {
            eff_mode = 6;
            g0 = 0;
            b0 += z * zBstride; b1 += z * zBstride; b2 += z * zBstride;
        } else {
            eff_mode = 0; zc = z - 3;
            a0 = g_hhi; a1 = g_hlo; a2 = g_hhi;
            b0 = g_W2thi; b1 = g_W2thi; b2 = g_W2thi;
            pitchA = HID; pitchB = HID; cb1 = 4; cb2 = 8;
            chunks_per_z = 2; g0 = zc * 2;
            C = g_part; ldc = HID; zCstride = (size_t)Nn * HID;
            bias = nullptr; alpha = 1.0f;
        }
    } else if (zBstride) {
        b0 += z * zBstride; b1 += z * zBstride; b2 += z * zBstride;
    }

    const int mi    = lane >> 3;
    const int ldrow = ((mi & 1) << 3) + (lane & 7);
    const int ldc16 = mi >> 1;
    const int srow0 = tid >> 3;
    const int sc    = tid & 7;

    float acc[2][8][4];
    #pragma unroll
    for (int a = 0; a < 2; a++)
        #pragma unroll
        for (int b = 0; b < 8; b++)
            #pragma unroll
            for (int c = 0; c < 4; c++) acc[a][b][c] = 0.f;

    auto load_chunk = [&](int g, int stage) {
        const hf *As, *Bs; int kk;
        if (g < cb1)      { As = a0; Bs = b0; kk = g * BK; }
        else if (g < cb2) { As = a1; Bs = b1; kk = (g - cb1) * BK; }
        else              { As = a2; Bs = b2; kk = (g - cb2) * BK; }
        uint32_t dst = sbase + stage * STAGEB;
        #pragma unroll
        for (int i = 0; i < 4; i++) {
            int row = srow0 + i * 32;
            uint32_t off = (uint32_t)(row * 128 + ((sc ^ (row & 7)) << 4));
            cp16(dst + off,         As + (size_t)(gm0 + row) * pitchA + kk + sc * 8);
            cp16(dst + TILEB + off, Bs + (size_t)(gn0 + row) * pitchB + kk + sc * 8);
        }
        cp_commit();
    };

    load_chunk(g0, 0);
    if (chunks_per_z > 1) load_chunk(g0 + 1, 1);
    else cp_commit();

    for (int c = 0; c < chunks_per_z; c++) {
        if (c + 1 < chunks_per_z) cp_wait<1>(); else cp_wait<0>();
        __syncthreads();
        if (c + 2 < chunks_per_z) load_chunk(g0 + c + 2, (c + 2) % NSTAGE);

        uint32_t abase = sbase + (c % NSTAGE) * STAGEB;
        uint32_t bbase = abase + TILEB;
        #pragma unroll
        for (int ks = 0; ks < 4; ks++) {
            uint32_t afrag[2][4];
            uint32_t bfrag[4][4];
            int c16 = ks * 2 + ldc16;
            #pragma unroll
            for (int mt = 0; mt < 2; mt++) {
                int row = wm + mt * 16 + ldrow;
                ldm4(afrag[mt], abase + row * 128 + ((c16 ^ (row & 7)) << 4));
            }
            #pragma unroll
            for (int p = 0; p < 4; p++) {
                int row = wn + p * 16 + ldrow;
                ldm4(bfrag[p], bbase + row * 128 + ((c16 ^ (row & 7)) << 4));
            }
            #pragma unroll
            for (int mt = 0; mt < 2; mt++) {
                #pragma unroll
                for (int p = 0; p < 4; p++) {
                    mma_f16(acc[mt][2 * p],     afrag[mt], bfrag[p][0], bfrag[p][2]);
                    mma_f16(acc[mt][2 * p + 1], afrag[mt], bfrag[p][1], bfrag[p][3]);
                }
            }
        }
    }

    // ---- epilogue ----
    const int r0 = lane >> 2;
    const int cl = 2 * (lane & 3);

    if (eff_mode == 1) {
        float* ex = (float*)smem;
        __syncthreads();
        for (int i = tid; i < BN; i += 256) {
            int n = gn0 + i;
            ex[i]           = __ldg(sp + 2 * n);
            ex[BN + i]      = __ldg(sp + 2 * n + 1);
            ex[2 * BN + i]  = g_sq[n];
            ex[3 * BN + i]  = g_f[n];
        }
        __syncthreads();
        #pragma unroll
        for (int mt = 0; mt < 2; mt++) {
            #pragma unroll
            for (int half = 0; half < 2; half++) {
                int m = gm0 + wm + mt * 16 + r0 + half * 8;
                float sp0 = __ldg(sp + 2 * m), sp1 = __ldg(sp + 2 * m + 1);
                float sqi = g_sq[m], ti = g_f[m];
                #pragma unroll
                for (int nt = 0; nt < 8; nt++) {
                    int nl = wn + nt * 8 + cl;
                    float ev[2];
                    #pragma unroll
                    for (int q = 0; q < 2; q++) {
                        int ci = nl + q;
                        float d2 = sqi + ex[2 * BN + ci]
                                 - 2.0f * (sp0 * ex[ci] + sp1 * ex[BN + ci]);
                        d2 = fmaxf(d2, 0.0f);
                        float tj = ex[3 * BN + ci];
                        float tb = __fdividef(ti - tj, fmaf(-ti, tj, 1.0f));
                        float lg = acc[mt][nt][half * 2 + q] + __expf(-0.5f * d2) + tb;
                        ev[q] = fminf(__expf(lg), 60000.0f);
                    }
                    *(__half2*)(g_Ahi + (size_t)m * Nn + gn0 + nl) =
                        __halves2half2(__float2half(ev[0]), __float2half(ev[1]));
                }
            }
        }
    } else if (eff_mode == 0) {
        float* Cz = C + zc * zCstride;
        #pragma unroll
        for (int mt = 0; mt < 2; mt++)
            #pragma unroll
            for (int half = 0; half < 2; half++) {
                int m = gm0 + wm + mt * 16 + r0 + half * 8;
                #pragma unroll
                for (int nt = 0; nt < 8; nt++) {
                    int n = gn0 + wn + nt * 8 + cl;
                    float b0v = bias ? __ldg(bias + n)     : 0.f;
                    float b1v = bias ? __ldg(bias + n + 1) : 0.f;
                    float2 v;
                    v.x = (acc[mt][nt][half * 2 + 0] + b0v) * alpha;
                    v.y = (acc[mt][nt][half * 2 + 1] + b1v) * alpha;
                    *(float2*)(Cz + (size_t)m * ldc + n) = v;
                }
            }
    } else { // eff_mode 6: QKV combined
        const float* bias6 = g_bias + z * 256;
        if (z == 2) {
            #pragma unroll
            for (int mt = 0; mt < 2; mt++)
                #pragma unroll
                for (int half = 0; half < 2; half++) {
                    int m = gm0 + wm + mt * 16 + r0 + half * 8;
                    #pragma unroll
                    for (int nt = 0; nt < 8; nt++) {
                        int n = gn0 + wn + nt * 8 + cl;
                        #pragma unroll
                        for (int q = 0; q < 2; q++) {
                            float v = acc[mt][nt][half * 2 + q] + bias6[n + q];
                            g_Vthi[(size_t)(n + q) * Nn + m] = __float2half(v);
                        }
                    }
                }
        } else {
            hf* Dh = z ? g_Zhi : g_Yhi;
            float al = z ? 1.0f : (1.0f / 16.0f);
            #pragma unroll
            for (int mt = 0; mt < 2; mt++)
                #pragma unroll
                for (int half = 0; half < 2; half++) {
                    int m = gm0 + wm + mt * 16 + r0 + half * 8;
                    #pragma unroll
                    for (int nt = 0; nt < 8; nt++) {
                        int n = gn0 + wn + nt * 8 + cl;
                        #pragma unroll
                        for (int q = 0; q < 2; q++) {
                            float v = (acc[mt][nt][half * 2 + q] + bias6[n + q]) * al;
                            Dh[(size_t)m * YK + n + q] = __float2half(v);
                        }
                    }
                }
        }
    }
}

// ---------------- normalize: row sum of fp16 e, write attn = e*inv + g_inv ----------------
__global__ __launch_bounds__(512) void normalize_kernel(float* __restrict__ attn) {
    int row = blockIdx.x;
    int tid = threadIdx.x;
    int lane = tid & 31, wrp = tid >> 5;
    const hf* E = g_Ahi + (size_t)row * Nn;
    __shared__ float red[16];
    uint4 raw = __ldcs((const uint4*)(E + tid * 8));
    __half2 h2[4];
    h2[0] = *(__half2*)&raw.x; h2[1] = *(__half2*)&raw.y;
    h2[2] = *(__half2*)&raw.z; h2[3] = *(__half2*)&raw.w;
    float e[8];
    #pragma unroll
    for (int i = 0; i < 4; i++) {
        float2 f = __half22float2(h2[i]);
        e[2 * i] = f.x; e[2 * i + 1] = f.y;
    }
    float sum = ((e[0] + e[1]) + (e[2] + e[3])) + ((e[4] + e[5]) + (e[6] + e[7]));
    #pragma unroll
    for (int o = 16; o > 0; o >>= 1) sum += __shfl_xor_sync(0xFFFFFFFFu, sum, o);
    if (lane == 0) red[wrp] = sum;
    __syncthreads();
    sum = red[lane & 15];
    #pragma unroll
    for (int o = 8; o > 0; o >>= 1) sum += __shfl_xor_sync(0xFFFFFFFFu, sum, o);
    float inv = 1.0f / sum;
    if (tid == 0) g_inv[row] = inv;

    float4 o0, o1;
    o0.x = e[0] * inv; o0.y = e[1] * inv; o0.z = e[2] * inv; o0.w = e[3] * inv;
    o1.x = e[4] * inv; o1.y = e[5] * inv; o1.z = e[6] * inv; o1.w = e[7] * inv;
    __stcs((float4*)(attn + (size_t)row * Nn + tid * 8), o0);
    __stcs((float4*)(attn + (size_t)row * Nn + tid * 8 + 4), o1);
}

// ---------------- reduce A@V split-K partials (4-way) + row normalize ----------------
__global__ __launch_bounds__(256) void reduce_kernel(float* __restrict__ upd) {
    size_t i = ((size_t)blockIdx.x * 256 + threadIdx.x) * 4;
    float4 s = __ldcs((const float4*)(g_part + i));
    #pragma unroll
    for (int z = 1; z < 4; z++) {
        const float4 p = __ldcs((const float4*)(g_part + z * (size_t)Nn * OUTD + i));
        s.x += p.x; s.y += p.y; s.z += p.z; s.w += p.w;
    }
    float inv = g_inv[i >> 8];   // OUTD = 256
    s.x *= inv; s.y *= inv; s.z *= inv; s.w *= inv;
    __stcs((float4*)(upd + i), s);
}

// ---------------- launch ----------------
extern "C" void kernel_launch(void* const* d_in, const int* in_sizes, int n_in,
                              void* d_out, int out_size) {
    const float* gene = (const float*)d_in[0];
    const float* sp   = (const float*)d_in[1];
    const float* Wq   = (const float*)d_in[2];
    const float* bq   = (const float*)d_in[3];
    const float* Wk   = (const float*)d_in[4];
    const float* bk   = (const float*)d_in[5];
    const float* Wv   = (const float*)d_in[6];
    const float* bv   = (const float*)d_in[7];
    const float* Ws   = (const float*)d_in[8];
    const float* bs   = (const float*)d_in[9];
    const float* W1   = (const float*)d_in[10];
    const float* b1   = (const float*)d_in[11];
    const float* W2   = (const float*)d_in[12];
    const float* b2   = (const float*)d_in[13];
    const float* Wf   = (const float*)d_in[14];
    const float* bf_  = (const float*)d_in[15];

    float* out = (float*)d_out;
    long long total = (long long)Nn * Nn + (long long)Nn * OUTD;
    int has_attn = ((long long)out_size >= total) ? 1 : 0;
    float* attn = out;
    float* upd  = has_attn ? out + (size_t)Nn * Nn : out;

    hf *pGhi, *pYhi, *pZhi, *pAhi, *pVthi, *pWthi;
    float *pPart;
    cudaGetSymbolAddress((void**)&pGhi, g_Ghi);
    cudaGetSymbolAddress((void**)&pYhi, g_Yhi);
    cudaGetSymbolAddress((void**)&pZhi, g_Zhi);
    cudaGetSymbolAddress((void**)&pAhi, g_Ahi);
    cudaGetSymbolAddress((void**)&pVthi, g_Vthi);
    cudaGetSymbolAddress((void**)&pWthi, g_Wthi);
    cudaGetSymbolAddress((void**)&pPart, g_part);

    cudaFuncSetAttribute(hmma_gemm, cudaFuncAttributeMaxDynamicSharedMemorySize, SMEMSZ);

    // identify the default stream actually being captured (legacy vs per-thread)
    cudaStream_t cap = cudaStreamPerThread;
    {
        cudaStreamCaptureStatus st = cudaStreamCaptureStatusNone;
        if (cudaStreamIsCapturing(cudaStreamLegacy, &st) == cudaSuccess &&
            st == cudaStreamCaptureStatusActive) {
            cap = cudaStreamLegacy;
        }
    }
    cudaStream_t side;
    cudaStreamCreateWithFlags(&side, cudaStreamNonBlocking);
    cudaEvent_t evL, evN;
    cudaEventCreateWithFlags(&evL, cudaEventDisableTiming);
    cudaEventCreateWithFlags(&evN, cudaEventDisableTiming);

    // 0) weight transposes + biases + MLP1 rank-2 combine (merged)
    wsplit_combine_kernel<<<2051, 256>>>(Wq, Wk, Wv, W2, bq, bk, bv, Ws, bs, W1, b1);

    // 1) prep: Ghi, normalized rows, sq, h = tanh(MLP1) splits
    prep_kernel<<<Nn, 256>>>(gene, sp);

    // 2) FUSED: QKV (z=0..2, 8 chunks) + MLP2 split-K x4 (z=3..6, 2 chunks)  [mode 7]
    dim3 gFU(HID / BN, Nn / BM, 7);
    hmma_gemm<<<gFU, 256, SMEMSZ>>>(pGhi, pGhi, pGhi, pWthi, pWthi, pWthi,
                                    GENE, GENE, 8, 8, 8, 0, (size_t)HID * GENE, 7,
                                    nullptr, 0, 0, nullptr, 1.0f, nullptr);

    // 3) reduce2 + f (4 rows/block, float4)
    reduce_f_kernel<<<Nn / 4, 256>>>(b2, Wf, bf_);

    // 4) logits -> exp -> g_Ahi fp16 (single-segment Yhi·Zhi, 12 chunks)
    dim3 gLg(Nn / BN, Nn / BM, 1);
    hmma_gemm<<<gLg, 256, SMEMSZ>>>(pYhi, pYhi, pYhi, pZhi, pZhi, pZhi,
                                    YK, YK, 12, 12, 12, 0, 0, 1,
                                    nullptr, 0, 0, nullptr, 1.0f, sp);

    // fork: normalize on side stream, concurrent with A@V on default
    cudaEventRecord(evL, cap);
    cudaStreamWaitEvent(side, evL, 0);
    normalize_kernel<<<Nn, 512, 0, side>>>(attn);
    cudaEventRecord(evN, side);

    // 5) A@V split-K x4 on unnormalized e (hi-only: 64 chunks, 16/z)
    dim3 gAV(OUTD / BN, Nn / BM, 4);
    hmma_gemm<<<gAV, 256, SMEMSZ>>>(pAhi, pAhi, pAhi, pVthi, pVthi, pVthi,
                                    Nn, Nn, 64, 64, 16, 16, 0, 0,
                                    pPart, OUTD, (size_t)Nn * OUTD, nullptr, 1.0f, nullptr);

    // join: reduce needs partials (default) + g_inv (side)
    cudaStreamWaitEvent(cap, evN, 0);
    reduce_kernel<<<(Nn * OUTD) / 1024, 256>>>(upd);
}

// round 17
// speedup vs baseline: 14.1132x; 1.0005x over previous
#include <cuda_runtime.h>
#include <cuda_fp16.h>
#include <math.h>
#include <stdint.h>

#define Nn    4096
#define GENE  512
#define HID   256
#define OUTD  256
#define YK    768     // HID + GENE fused logits depth

typedef __half hf;

// ---------------- scratch (static device globals; no runtime allocs) ----------------
__device__ __align__(16) hf    g_Ghi[Nn * GENE];
__device__ __align__(16) hf    g_Yhi[Nn * YK];
__device__ __align__(16) hf    g_Zhi[Nn * YK];
__device__ __align__(16) hf    g_Ahi[(size_t)Nn * Nn];    // unnormalized exp(logits), fp16
__device__ __align__(16) hf    g_Vthi[OUTD * Nn];
__device__ __align__(16) hf    g_Wthi[3 * HID * GENE];    // W^T hi (q,k,v)
__device__ __align__(16) hf    g_W2thi[HID * HID];
__device__ __align__(16) hf    g_hhi[Nn * HID];
__device__ __align__(16) hf    g_hlo[Nn * HID];
__device__ __align__(16) float g_E[Nn * HID];                    // e = relu(MLP2)
__device__ __align__(16) float g_part[4 * (size_t)Nn * OUTD];   // A@V split-K partials
__device__ __align__(16) float g_bias[4 * 256];                  // bq|bk|bv|b2
__device__ __align__(16) float g_W1c[2 * HID];                   // Ws @ W1
__device__ __align__(16) float g_b1c[HID];                       // bs @ W1 + b1
__device__ float g_f[Nn];     // clamp(tanh(f))
__device__ float g_sq[Nn];
__device__ float g_inv[Nn];   // 1 / rowsum(exp)

// ---------------- PTX helpers (sm_80+ baseline) ----------------
__device__ __forceinline__ uint32_t s2u(const void* p) {
    uint32_t a;
    asm("{ .reg .u64 t; cvta.to.shared.u64 t, %1; cvt.u32.u64 %0, t; }" : "=r"(a) : "l"(p));
    return a;
}
__device__ __forceinline__ void cp16(uint32_t dst, const void* src) {
    asm volatile("cp.async.cg.shared.global [%0], [%1], 16;" :: "r"(dst), "l"(src));
}
__device__ __forceinline__ void cp_commit() {
    asm volatile("cp.async.commit_group;" ::: "memory");
}
template <int N>
__device__ __forceinline__ void cp_wait() {
    asm volatile("cp.async.wait_group %0;" :: "n"(N) : "memory");
}
__device__ __forceinline__ void ldm4(uint32_t* r, uint32_t addr) {
    asm volatile("ldmatrix.sync.aligned.m8n8.x4.shared.b16 {%0,%1,%2,%3}, [%4];"
                 : "=r"(r[0]), "=r"(r[1]), "=r"(r[2]), "=r"(r[3]) : "r"(addr));
}
__device__ __forceinline__ void mma_f16(float* d, const uint32_t* a, uint32_t b0, uint32_t b1) {
    asm volatile(
        "mma.sync.aligned.m16n8k16.row.col.f32.f16.f16.f32 "
        "{%0,%1,%2,%3}, {%4,%5,%6,%7}, {%8,%9}, {%0,%1,%2,%3};"
        : "+f"(d[0]), "+f"(d[1]), "+f"(d[2]), "+f"(d[3])
        : "r"(a[0]), "r"(a[1]), "r"(a[2]), "r"(a[3]), "r"(b0), "r"(b1));
}
__device__ __forceinline__ void split2(float v, hf& h, hf& l) {
    h = __float2half(v);
    l = __float2half(v - __half2float(h));
}

// ---------------- weight transposes + biases(+b2) + combine (merged) ----------------
__global__ __launch_bounds__(256) void wsplit_combine_kernel(
    const float* __restrict__ Wq, const float* __restrict__ Wk, const float* __restrict__ Wv,
    const float* __restrict__ W2,
    const float* __restrict__ bq, const float* __restrict__ bk, const float* __restrict__ bv,
    const float* __restrict__ b2,
    const float* __restrict__ Ws, const float* __restrict__ bs,
    const float* __restrict__ W1, const float* __restrict__ b1) {
    if (blockIdx.x >= 1796) {
        int h = blockIdx.x - 1796;
        int k = threadIdx.x;
        float w = __ldg(W1 + k * HID + h);
        __shared__ float r0[256], r1[256], r2[256];
        r0[k] = __ldg(Ws + k) * w;
        r1[k] = __ldg(Ws + HID + k) * w;
        r2[k] = __ldg(bs + k) * w;
        __syncthreads();
        for (int s = 128; s > 0; s >>= 1) {
            if (k < s) { r0[k] += r0[k + s]; r1[k] += r1[k + s]; r2[k] += r2[k + s]; }
            __syncthreads();
        }
        if (k == 0) {
            g_W1c[h]       = r0[0];
            g_W1c[HID + h] = r1[0];
            g_b1c[h]       = r2[0] + __ldg(b1 + h);
        }
        return;
    }
    int idx = blockIdx.x * 256 + threadIdx.x;
    if (idx < 393216) {                       // 3 x (256 x 512)
        int w = idx / 131072, r = idx % 131072;
        int n = r / GENE, k = r % GENE;
        const float* W = (w == 0) ? Wq : (w == 1) ? Wk : Wv;
        g_Wthi[idx] = __float2half(W[(size_t)k * HID + n]);
    } else if (idx < 458752) {                // W2 (256 x 256)
        int r = idx - 393216;
        int n = r / HID, k = r % HID;
        g_W2thi[r] = __float2half(W2[(size_t)k * HID + n]);
    } else if (idx < 459776) {                // biases (4 x 256)
        int t = idx - 458752;
        if (t < 256)      g_bias[t] = bq[t];
        else if (t < 512) g_bias[t] = bk[t - 256];
        else if (t < 768) g_bias[t] = bv[t - 512];
        else              g_bias[t] = b2[t - 768];
    }
}

// ---------------- prep: gene fp16 + normalized rows + sq + h (=tanh MLP1) ----------------
__global__ __launch_bounds__(256) void prep_kernel(const float* __restrict__ gene,
                                                   const float* __restrict__ sp) {
    int row = blockIdx.x;
    const float* x = gene + (size_t)row * GENE;
    __shared__ float red[256];
    float a = __ldg(sp + 2 * row), b = __ldg(sp + 2 * row + 1);

    {
        int h = threadIdx.x;
        float v = a * g_W1c[h] + b * g_W1c[HID + h] + g_b1c[h];
        float t = tanhf(v);
        split2(t, g_hhi[row * HID + h], g_hlo[row * HID + h]);
    }

    float ss = 0.f;
    for (int c = threadIdx.x; c < GENE; c += 256) { float v = x[c]; ss += v * v; }
    red[threadIdx.x] = ss; __syncthreads();
    for (int s = 128; s > 0; s >>= 1) {
        if (threadIdx.x < s) red[threadIdx.x] += red[threadIdx.x + s];
        __syncthreads();
    }
    float inv = 1.0f / fmaxf(sqrtf(red[0]), 1e-12f);
    for (int c = threadIdx.x; c < GENE; c += 256) {
        float v = x[c];
        g_Ghi[(size_t)row * GENE + c] = __float2half(v);
        hf xh = __float2half(v * inv);
        size_t o = (size_t)row * YK + HID + c;
        g_Yhi[o] = xh;
        g_Zhi[o] = xh;
    }
    if (threadIdx.x == 0) g_sq[row] = a * a + b * b;
}

// ---------------- f = e . Wf + bf (4 rows/block, float4) ----------------
__global__ __launch_bounds__(256) void reduce_f_kernel(const float* __restrict__ Wf,
                                                       const float* __restrict__ bf_) {
    int rloc = threadIdx.x >> 6;              // 0..3
    int c4   = (threadIdx.x & 63) * 4;
    int row  = blockIdx.x * 4 + rloc;
    float4 ev = __ldcs((const float4*)(g_E + (size_t)row * HID + c4));
    float4 wf = *(const float4*)(Wf + c4);
    float d = ev.x * wf.x + ev.y * wf.y + ev.z * wf.z + ev.w * wf.w;
    __shared__ float red[256];
    red[threadIdx.x] = d;
    __syncthreads();
    #pragma unroll
    for (int st = 32; st > 0; st >>= 1) {
        if ((threadIdx.x & 63) < st) red[threadIdx.x] += red[threadIdx.x + st];
        __syncthreads();
    }
    if ((threadIdx.x & 63) == 0) {
        float t = tanhf(red[rloc * 64] + bf_[0]);
        g_f[row] = fminf(fmaxf(t, -0.999999f), 0.999999f);
    }
}

// ---------------- HMMA fp16 GEMM, BK=64, XOR-swizzle, 3-stage pipeline ----------------
// modes: 0 = fp32 C (+bias)*alpha (per-z C offset)
//        1 = exp-logits epilogue -> g_Ahi fp16
//        5 = relu(acc + bias) fp32 -> C
//        6 = QKV combined
//        7 = fused QKV (z<3) + MLP2 direct-e (z=3)
#define BM 128
#define BN 128
#define BK 64
#define TILEB  16384                 // 128 rows x 128B
#define STAGEB (2 * TILEB)           // A + B
#define NSTAGE 3
#define SMEMSZ (NSTAGE * STAGEB)     // 98304

__global__ __launch_bounds__(256, 2) void hmma_gemm(
    const hf* __restrict__ a0, const hf* __restrict__ a1, const hf* __restrict__ a2,
    const hf* __restrict__ b0, const hf* __restrict__ b1, const hf* __restrict__ b2,
    int pitchA, int pitchB, int cb1, int cb2, int chunks_per_z, int zchunks,
    size_t zBstride, int mode,
    float* __restrict__ C, int ldc, size_t zCstride,
    const float* __restrict__ bias, float alpha,
    const float* __restrict__ sp)
{
    extern __shared__ __align__(16) char smem[];
    const uint32_t sbase = s2u(smem);
    const int tid  = threadIdx.x;
    const int lane = tid & 31;
    const int wid  = tid >> 5;
    const int wm   = (wid & 3) * 32;
    const int wn   = (wid >> 2) * 64;
    const int gm0  = blockIdx.y * BM;
    const int gn0  = blockIdx.x * BN;
    const int z    = blockIdx.z;

    int eff_mode = mode;
    int zc = z;
    int g0 = z * zchunks;

    if (mode == 7) {
        if (z < 3) {
            eff_mode = 6;
            g0 = 0;
            b0 += z * zBstride; b1 += z * zBstride; b2 += z * zBstride;
        } else {
            eff_mode = 5;
            a0 = g_hhi; a1 = g_hlo; a2 = g_hhi;
            b0 = g_W2thi; b1 = g_W2thi; b2 = g_W2thi;
            pitchA = HID; pitchB = HID; cb1 = 4; cb2 = 8;
            chunks_per_z = 8; g0 = 0;
            C = g_E; ldc = HID;
            bias = g_bias + 768; alpha = 1.0f;
        }
    } else if (zBstride) {
        b0 += z * zBstride; b1 += z * zBstride; b2 += z * zBstride;
    }

    const int mi    = lane >> 3;
    const int ldrow = ((mi & 1) << 3) + (lane & 7);
    const int ldc16 = mi >> 1;
    const int srow0 = tid >> 3;
    const int sc    = tid & 7;

    float acc[2][8][4];
    #pragma unroll
    for (int a = 0; a < 2; a++)
        #pragma unroll
        for (int b = 0; b < 8; b++)
            #pragma unroll
            for (int c = 0; c < 4; c++) acc[a][b][c] = 0.f;

    auto load_chunk = [&](int g, int stage) {
        const hf *As, *Bs; int kk;
        if (g < cb1)      { As = a0; Bs = b0; kk = g * BK; }
        else if (g < cb2) { As = a1; Bs = b1; kk = (g - cb1) * BK; }
        else              { As = a2; Bs = b2; kk = (g - cb2) * BK; }
        uint32_t dst = sbase + stage * STAGEB;
        #pragma unroll
        for (int i = 0; i < 4; i++) {
            int row = srow0 + i * 32;
            uint32_t off = (uint32_t)(row * 128 + ((sc ^ (row & 7)) << 4));
            cp16(dst + off,         As + (size_t)(gm0 + row) * pitchA + kk + sc * 8);
            cp16(dst + TILEB + off, Bs + (size_t)(gn0 + row) * pitchB + kk + sc * 8);
        }
        cp_commit();
    };

    load_chunk(g0, 0);
    if (chunks_per_z > 1) load_chunk(g0 + 1, 1);
    else cp_commit();

    for (int c = 0; c < chunks_per_z; c++) {
        if (c + 1 < chunks_per_z) cp_wait<1>(); else cp_wait<0>();
        __syncthreads();
        if (c + 2 < chunks_per_z) load_chunk(g0 + c + 2, (c + 2) % NSTAGE);

        uint32_t abase = sbase + (c % NSTAGE) * STAGEB;
        uint32_t bbase = abase + TILEB;
        #pragma unroll
        for (int ks = 0; ks < 4; ks++) {
            uint32_t afrag[2][4];
            uint32_t bfrag[4][4];
            int c16 = ks * 2 + ldc16;
            #pragma unroll
            for (int mt = 0; mt < 2; mt++) {
                int row = wm + mt * 16 + ldrow;
                ldm4(afrag[mt], abase + row * 128 + ((c16 ^ (row & 7)) << 4));
            }
            #pragma unroll
            for (int p = 0; p < 4; p++) {
                int row = wn + p * 16 + ldrow;
                ldm4(bfrag[p], bbase + row * 128 + ((c16 ^ (row & 7)) << 4));
            }
            #pragma unroll
            for (int mt = 0; mt < 2; mt++) {
                #pragma unroll
                for (int p = 0; p < 4; p++) {
                    mma_f16(acc[mt][2 * p],     afrag[mt], bfrag[p][0], bfrag[p][2]);
                    mma_f16(acc[mt][2 * p + 1], afrag[mt], bfrag[p][1], bfrag[p][3]);
                }
            }
        }
    }

    // ---- epilogue ----
    const int r0 = lane >> 2;
    const int cl = 2 * (lane & 3);

    if (eff_mode == 1) {
        float* ex = (float*)smem;
        __syncthreads();
        for (int i = tid; i < BN; i += 256) {
            int n = gn0 + i;
            ex[i]           = __ldg(sp + 2 * n);
            ex[BN + i]      = __ldg(sp + 2 * n + 1);
            ex[2 * BN + i]  = g_sq[n];
            ex[3 * BN + i]  = g_f[n];
        }
        __syncthreads();
        #pragma unroll
        for (int mt = 0; mt < 2; mt++) {
            #pragma unroll
            for (int half = 0; half < 2; half++) {
                int m = gm0 + wm + mt * 16 + r0 + half * 8;
                float sp0 = __ldg(sp + 2 * m), sp1 = __ldg(sp + 2 * m + 1);
                float sqi = g_sq[m], ti = g_f[m];
                #pragma unroll
                for (int nt = 0; nt < 8; nt++) {
                    int nl = wn + nt * 8 + cl;
                    float ev[2];
                    #pragma unroll
                    for (int q = 0; q < 2; q++) {
                        int ci = nl + q;
                        float d2 = sqi + ex[2 * BN + ci]
                                 - 2.0f * (sp0 * ex[ci] + sp1 * ex[BN + ci]);
                        d2 = fmaxf(d2, 0.0f);
                        float tj = ex[3 * BN + ci];
                        float tb = __fdividef(ti - tj, fmaf(-ti, tj, 1.0f));
                        float lg = acc[mt][nt][half * 2 + q] + __expf(-0.5f * d2) + tb;
                        ev[q] = fminf(__expf(lg), 60000.0f);
                    }
                    *(__half2*)(g_Ahi + (size_t)m * Nn + gn0 + nl) =
                        __halves2half2(__float2half(ev[0]), __float2half(ev[1]));
                }
            }
        }
    } else if (eff_mode == 0 || eff_mode == 5) {
        float* Cz = C + ((eff_mode == 0) ? zc * zCstride : 0);
        #pragma unroll
        for (int mt = 0; mt < 2; mt++)
            #pragma unroll
            for (int half = 0; half < 2; half++) {
                int m = gm0 + wm + mt * 16 + r0 + half * 8;
                #pragma unroll
                for (int nt = 0; nt < 8; nt++) {
                    int n = gn0 + wn + nt * 8 + cl;
                    float b0v = bias ? __ldg(bias + n)     : 0.f;
                    float b1v = bias ? __ldg(bias + n + 1) : 0.f;
                    float2 v;
                    v.x = (acc[mt][nt][half * 2 + 0] + b0v) * alpha;
                    v.y = (acc[mt][nt][half * 2 + 1] + b1v) * alpha;
                    if (eff_mode == 5) { v.x = fmaxf(v.x, 0.f); v.y = fmaxf(v.y, 0.f); }
                    *(float2*)(Cz + (size_t)m * ldc + n) = v;
                }
            }
    } else { // eff_mode 6: QKV combined
        const float* bias6 = g_bias + z * 256;
        if (z == 2) {
            #pragma unroll
            for (int mt = 0; mt < 2; mt++)
                #pragma unroll
                for (int half = 0; half < 2; half++) {
                    int m = gm0 + wm + mt * 16 + r0 + half * 8;
                    #pragma unroll
                    for (int nt = 0; nt < 8; nt++) {
                        int n = gn0 + wn + nt * 8 + cl;
                        #pragma unroll
                        for (int q = 0; q < 2; q++) {
                            float v = acc[mt][nt][half * 2 + q] + bias6[n + q];
                            g_Vthi[(size_t)(n + q) * Nn + m] = __float2half(v);
                        }
                    }
                }
        } else {
            hf* Dh = z ? g_Zhi : g_Yhi;
            float al = z ? 1.0f : (1.0f / 16.0f);
            #pragma unroll
            for (int mt = 0; mt < 2; mt++)
                #pragma unroll
                for (int half = 0; half < 2; half++) {
                    int m = gm0 + wm + mt * 16 + r0 + half * 8;
                    #pragma unroll
                    for (int nt = 0; nt < 8; nt++) {
                        int n = gn0 + wn + nt * 8 + cl;
                        #pragma unroll
                        for (int q = 0; q < 2; q++) {
                            float v = (acc[mt][nt][half * 2 + q] + bias6[n + q]) * al;
                            Dh[(size_t)m * YK + n + q] = __float2half(v);
                        }
                    }
                }
        }
    }
}

// ---------------- normalize: row sum of fp16 e, write attn = e*inv + g_inv ----------------
__global__ __launch_bounds__(512) void normalize_kernel(float* __restrict__ attn) {
    int row = blockIdx.x;
    int tid = threadIdx.x;
    int lane = tid & 31, wrp = tid >> 5;
    const hf* E = g_Ahi + (size_t)row * Nn;
    __shared__ float red[16];
    uint4 raw = __ldcs((const uint4*)(E + tid * 8));
    __half2 h2[4];
    h2[0] = *(__half2*)&raw.x; h2[1] = *(__half2*)&raw.y;
    h2[2] = *(__half2*)&raw.z; h2[3] = *(__half2*)&raw.w;
    float e[8];
    #pragma unroll
    for (int i = 0; i < 4; i++) {
        float2 f = __half22float2(h2[i]);
        e[2 * i] = f.x; e[2 * i + 1] = f.y;
    }
    float sum = ((e[0] + e[1]) + (e[2] + e[3])) + ((e[4] + e[5]) + (e[6] + e[7]));
    #pragma unroll
    for (int o = 16; o > 0; o >>= 1) sum += __shfl_xor_sync(0xFFFFFFFFu, sum, o);
    if (lane == 0) red[wrp] = sum;
    __syncthreads();
    sum = red[lane & 15];
    #pragma unroll
    for (int o = 8; o > 0; o >>= 1) sum += __shfl_xor_sync(0xFFFFFFFFu, sum, o);
    float inv = 1.0f / sum;
    if (tid == 0) g_inv[row] = inv;

    float4 o0, o1;
    o0.x = e[0] * inv; o0.y = e[1] * inv; o0.z = e[2] * inv; o0.w = e[3] * inv;
    o1.x = e[4] * inv; o1.y = e[5] * inv; o1.z = e[6] * inv; o1.w = e[7] * inv;
    __stcs((float4*)(attn + (size_t)row * Nn + tid * 8), o0);
    __stcs((float4*)(attn + (size_t)row * Nn + tid * 8 + 4), o1);
}

// ---------------- reduce A@V split-K partials (4-way) + row normalize ----------------
__global__ __launch_bounds__(256) void reduce_kernel(float* __restrict__ upd) {
    size_t i = ((size_t)blockIdx.x * 256 + threadIdx.x) * 4;
    float4 s = __ldcs((const float4*)(g_part + i));
    #pragma unroll
    for (int z = 1; z < 4; z++) {
        const float4 p = __ldcs((const float4*)(g_part + z * (size_t)Nn * OUTD + i));
        s.x += p.x; s.y += p.y; s.z += p.z; s.w += p.w;
    }
    float inv = g_inv[i >> 8];   // OUTD = 256
    s.x *= inv; s.y *= inv; s.z *= inv; s.w *= inv;
    __stcs((float4*)(upd + i), s);
}

// ---------------- launch ----------------
extern "C" void kernel_launch(void* const* d_in, const int* in_sizes, int n_in,
                              void* d_out, int out_size) {
    const float* gene = (const float*)d_in[0];
    const float* sp   = (const float*)d_in[1];
    const float* Wq   = (const float*)d_in[2];
    const float* bq   = (const float*)d_in[3];
    const float* Wk   = (const float*)d_in[4];
    const float* bk   = (const float*)d_in[5];
    const float* Wv   = (const float*)d_in[6];
    const float* bv   = (const float*)d_in[7];
    const float* Ws   = (const float*)d_in[8];
    const float* bs   = (const float*)d_in[9];
    const float* W1   = (const float*)d_in[10];
    const float* b1   = (const float*)d_in[11];
    const float* W2   = (const float*)d_in[12];
    const float* b2   = (const float*)d_in[13];
    const float* Wf   = (const float*)d_in[14];
    const float* bf_  = (const float*)d_in[15];

    float* out = (float*)d_out;
    long long total = (long long)Nn * Nn + (long long)Nn * OUTD;
    int has_attn = ((long long)out_size >= total) ? 1 : 0;
    float* attn = out;
    float* upd  = has_attn ? out + (size_t)Nn * Nn : out;

    hf *pGhi, *pYhi, *pZhi, *pAhi, *pVthi, *pWthi;
    float *pPart;
    cudaGetSymbolAddress((void**)&pGhi, g_Ghi);
    cudaGetSymbolAddress((void**)&pYhi, g_Yhi);
    cudaGetSymbolAddress((void**)&pZhi, g_Zhi);
    cudaGetSymbolAddress((void**)&pAhi, g_Ahi);
    cudaGetSymbolAddress((void**)&pVthi, g_Vthi);
    cudaGetSymbolAddress((void**)&pWthi, g_Wthi);
    cudaGetSymbolAddress((void**)&pPart, g_part);

    cudaFuncSetAttribute(hmma_gemm, cudaFuncAttributeMaxDynamicSharedMemorySize, SMEMSZ);

    // identify the default stream actually being captured (legacy vs per-thread)
    cudaStream_t cap = cudaStreamPerThread;
    {
        cudaStreamCaptureStatus st = cudaStreamCaptureStatusNone;
        if (cudaStreamIsCapturing(cudaStreamLegacy, &st) == cudaSuccess &&
            st == cudaStreamCaptureStatusActive) {
            cap = cudaStreamLegacy;
        }
    }
    cudaStream_t side;
    cudaStreamCreateWithFlags(&side, cudaStreamNonBlocking);
    cudaEvent_t evL, evN;
    cudaEventCreateWithFlags(&evL, cudaEventDisableTiming);
    cudaEventCreateWithFlags(&evN, cudaEventDisableTiming);

    // 0) weight transposes + biases(+b2) + MLP1 rank-2 combine
    wsplit_combine_kernel<<<2052, 256>>>(Wq, Wk, Wv, W2, bq, bk, bv, b2, Ws, bs, W1, b1);

    // 1) prep: Ghi, normalized rows, sq, h = tanh(MLP1) splits
    prep_kernel<<<Nn, 256>>>(gene, sp);

    // 2) FUSED: QKV (z=0..2) + MLP2 direct-e (z=3), all 8 chunks  [mode 7]
    dim3 gFU(HID / BN, Nn / BM, 4);
    hmma_gemm<<<gFU, 256, SMEMSZ>>>(pGhi, pGhi, pGhi, pWthi, pWthi, pWthi,
                                    GENE, GENE, 8, 8, 8, 0, (size_t)HID * GENE, 7,
                                    nullptr, 0, 0, nullptr, 1.0f, nullptr);

    // 3) f = e . Wf + bf
    reduce_f_kernel<<<Nn / 4, 256>>>(Wf, bf_);

    // 4) logits -> exp -> g_Ahi fp16 (single-segment Yhi·Zhi, 12 chunks)
    dim3 gLg(Nn / BN, Nn / BM, 1);
    hmma_gemm<<<gLg, 256, SMEMSZ>>>(pYhi, pYhi, pYhi, pZhi, pZhi, pZhi,
                                    YK, YK, 12, 12, 12, 0, 0, 1,
                                    nullptr, 0, 0, nullptr, 1.0f, sp);

    // fork: normalize on side stream, concurrent with A@V on default
    cudaEventRecord(evL, cap);
    cudaStreamWaitEvent(side, evL, 0);
    normalize_kernel<<<Nn, 512, 0, side>>>(attn);
    cudaEventRecord(evN, side);

    // 5) A@V split-K x4 on unnormalized e (hi-only: 64 chunks, 16/z)
    dim3 gAV(OUTD / BN, Nn / BM, 4);
    hmma_gemm<<<gAV, 256, SMEMSZ>>>(pAhi, pAhi, pAhi, pVthi, pVthi, pVthi,
                                    Nn, Nn, 64, 64, 16, 16, 0, 0,
                                    pPart, OUTD, (size_t)Nn * OUTD, nullptr, 1.0f, nullptr);

    // join: reduce needs partials (default) + g_inv (side)
    cudaStreamWaitEvent(cap, evN, 0);
    reduce_kernel<<<(Nn * OUTD) / 1024, 256>>>(upd);
}